// round 1
// baseline (speedup 1.0000x reference)
#include <cuda_runtime.h>
#include <math.h>

#define S_LEN 2048
#define HID 4096
#define NH 32
#define NKV 8
#define HD 128

// ---------------- scratch (device globals: no allocation allowed) ----------
__device__ float g_qraw[S_LEN * HID];        // x @ wq^T, row-major [s][h*HD+d]
__device__ float g_kraw[S_LEN * NKV * HD];   // x @ wk^T
__device__ float g_q[NH * S_LEN * HD];       // head-major, rope applied
__device__ float g_k[NKV * S_LEN * HD];
__device__ float g_v[NKV * S_LEN * HD];      // head-major (written by GEMM epilogue)
__device__ float g_att[S_LEN * HID];         // attention output [s][h*HD+d]

// ---------------------------------------------------------------------------
// Tiled NT GEMM: C[M,N] = A[M,K] @ B[N,K]^T   (both row-major, K contiguous)
// BM=BN=128, BK=16, 256 threads, 8x8 per-thread register tile.
// MODE 0: row-major store C[m*N+n]
// MODE 1: head-major store C[(n/128)*(M*128) + m*128 + (n%128)]
// Assumes M%128==0, N%128==0, K%16==0 (true for all calls here).
// ---------------------------------------------------------------------------
template <int MODE>
__launch_bounds__(256)
__global__ void gemm_nt(const float* __restrict__ A, const float* __restrict__ B,
                        float* __restrict__ C, int M, int N, int K) {
    __shared__ float As[16][132];   // transposed [k][m], pad to reduce conflicts
    __shared__ float Bs[16][132];   // transposed [k][n]

    const int bm = blockIdx.y * 128;
    const int bn = blockIdx.x * 128;
    const int tid = threadIdx.x;
    const int tx = tid & 15;
    const int ty = tid >> 4;

    float acc[8][8];
#pragma unroll
    for (int i = 0; i < 8; i++)
#pragma unroll
        for (int j = 0; j < 8; j++) acc[i][j] = 0.0f;

    const float* Ab = A + (size_t)bm * K;
    const float* Bb = B + (size_t)bn * K;

    const int lr = tid >> 2;        // 0..63  (row within tile, +64 on 2nd pass)
    const int lc = (tid & 3) * 4;   // 0,4,8,12 (k offset within 16)

    for (int k0 = 0; k0 < K; k0 += 16) {
#pragma unroll
        for (int h = 0; h < 2; h++) {
            const int r = lr + h * 64;
            float4 va = *(const float4*)(Ab + (size_t)r * K + k0 + lc);
            As[lc + 0][r] = va.x; As[lc + 1][r] = va.y;
            As[lc + 2][r] = va.z; As[lc + 3][r] = va.w;
            float4 vb = *(const float4*)(Bb + (size_t)r * K + k0 + lc);
            Bs[lc + 0][r] = vb.x; Bs[lc + 1][r] = vb.y;
            Bs[lc + 2][r] = vb.z; Bs[lc + 3][r] = vb.w;
        }
        __syncthreads();

#pragma unroll
        for (int kk = 0; kk < 16; kk++) {
            float a[8], b[8];
            *(float4*)(a)     = *(const float4*)&As[kk][ty * 8];
            *(float4*)(a + 4) = *(const float4*)&As[kk][ty * 8 + 4];
            *(float4*)(b)     = *(const float4*)&Bs[kk][tx * 8];
            *(float4*)(b + 4) = *(const float4*)&Bs[kk][tx * 8 + 4];
#pragma unroll
            for (int i = 0; i < 8; i++)
#pragma unroll
                for (int j = 0; j < 8; j++) acc[i][j] = fmaf(a[i], b[j], acc[i][j]);
        }
        __syncthreads();
    }

#pragma unroll
    for (int i = 0; i < 8; i++) {
        const int m = bm + ty * 8 + i;
#pragma unroll
        for (int j = 0; j < 8; j += 4) {
            const int n = bn + tx * 8 + j;
            float4 v = make_float4(acc[i][j], acc[i][j + 1], acc[i][j + 2], acc[i][j + 3]);
            if (MODE == 0) {
                *(float4*)(C + (size_t)m * N + n) = v;
            } else {
                const int hh = n >> 7;
                const int d = n & 127;
                *(float4*)(C + ((size_t)hh * M + m) * 128 + d) = v;
            }
        }
    }
}

// ---------------------------------------------------------------------------
// RoPE + reshape: raw[s][h*HD+d] -> out[h][s][d] with rotate-half rope.
// grid (S, nheads), 64 threads (one per rotation pair).
// ---------------------------------------------------------------------------
__global__ void rope_kernel(const float* __restrict__ raw, const float* __restrict__ cs,
                            const float* __restrict__ sn, float* __restrict__ out, int nh) {
    const int s = blockIdx.x;
    const int h = blockIdx.y;
    const int j = threadIdx.x;  // 0..63
    const float* r = raw + ((size_t)s * nh + h) * HD;
    const float x1 = r[j];
    const float x2 = r[j + 64];
    const float c = cs[s * 64 + j];
    const float si = sn[s * 64 + j];
    float* o = out + ((size_t)h * S_LEN + s) * HD;
    o[j]      = x1 * c - x2 * si;
    o[j + 64] = x2 * c + x1 * si;
}

// ---------------------------------------------------------------------------
// Flash attention (causal). grid (S/64, NH), 256 threads.
// Tiles: 64 queries x 64 keys, HD=128. Online softmax.
// Thread map for S-tile: rows m = ty+16i (i<4), cols n = tx+16j (j<4).
// Thread map for O: rows m = ty+16i, cols d = tx*8..tx*8+7.
// ---------------------------------------------------------------------------
#define ATTN_SMEM_FLOATS (3 * 64 * 132 + 64 * 65)

__launch_bounds__(256)
__global__ void flash_attn(const float* __restrict__ Q, const float* __restrict__ K,
                           const float* __restrict__ V, float* __restrict__ O) {
    extern __shared__ float sm[];
    float* Qs = sm;                   // [64][132]  (m x d)
    float* Ks = sm + 64 * 132;        // [64][132]  (n x d)
    float* Vs = sm + 2 * 64 * 132;    // [64][132]  (n x d)
    float* Ps = sm + 3 * 64 * 132;    // [64][65]   (n x m), padded

    const int qb = blockIdx.x;
    const int h  = blockIdx.y;
    const int q0 = qb * 64;
    const int kvh = h % NKV;          // jnp.tile semantics: head h -> kv head h % NKV
    const int tid = threadIdx.x;
    const int tx = tid & 15;
    const int ty = tid >> 4;
    const int warp = tid >> 5;
    const int lane = tid & 31;
    const float scale = 0.08838834764831845f;  // 1/sqrt(128)

    // load Q tile (scale folded in)
    const float* Qg = Q + ((size_t)h * S_LEN + q0) * HD;
#pragma unroll
    for (int r = warp; r < 64; r += 8) {
        float4 v = *(const float4*)(Qg + (size_t)r * HD + lane * 4);
        v.x *= scale; v.y *= scale; v.z *= scale; v.w *= scale;
        *(float4*)&Qs[r * 132 + lane * 4] = v;
    }

    float m_i[4], l_i[4], oa[4][8];
#pragma unroll
    for (int i = 0; i < 4; i++) {
        m_i[i] = -1e30f;
        l_i[i] = 0.0f;
#pragma unroll
        for (int d = 0; d < 8; d++) oa[i][d] = 0.0f;
    }

    const float* Kg = K + (size_t)kvh * S_LEN * HD;
    const float* Vg = V + (size_t)kvh * S_LEN * HD;

    for (int jb = 0; jb <= qb; jb++) {
        const int k0 = jb * 64;
        __syncthreads();  // previous PV readers done with Ks/Vs (also covers Qs on iter 0)
#pragma unroll
        for (int r = warp; r < 64; r += 8) {
            *(float4*)&Ks[r * 132 + lane * 4] =
                *(const float4*)(Kg + (size_t)(k0 + r) * HD + lane * 4);
            *(float4*)&Vs[r * 132 + lane * 4] =
                *(const float4*)(Vg + (size_t)(k0 + r) * HD + lane * 4);
        }
        __syncthreads();

        // S tile = Q @ K^T (scale already in Q)
        float sv[4][4];
#pragma unroll
        for (int i = 0; i < 4; i++)
#pragma unroll
            for (int j = 0; j < 4; j++) sv[i][j] = 0.0f;

#pragma unroll 8
        for (int d = 0; d < 128; d += 4) {
            float4 a[4], b[4];
#pragma unroll
            for (int i = 0; i < 4; i++) a[i] = *(const float4*)&Qs[(ty + 16 * i) * 132 + d];
#pragma unroll
            for (int j = 0; j < 4; j++) b[j] = *(const float4*)&Ks[(tx + 16 * j) * 132 + d];
#pragma unroll
            for (int i = 0; i < 4; i++)
#pragma unroll
                for (int j = 0; j < 4; j++) {
                    sv[i][j] = fmaf(a[i].x, b[j].x, sv[i][j]);
                    sv[i][j] = fmaf(a[i].y, b[j].y, sv[i][j]);
                    sv[i][j] = fmaf(a[i].z, b[j].z, sv[i][j]);
                    sv[i][j] = fmaf(a[i].w, b[j].w, sv[i][j]);
                }
        }

        const bool diag = (jb == qb);
#pragma unroll
        for (int i = 0; i < 4; i++) {
            const int qrow = ty + 16 * i;
            float rm = m_i[i];
#pragma unroll
            for (int j = 0; j < 4; j++) {
                const int kn = tx + 16 * j;
                float s = sv[i][j];
                if (diag && kn > qrow) s = -1e30f;
                sv[i][j] = s;
                rm = fmaxf(rm, s);
            }
            // row-max across the 16 lanes sharing this ty
#pragma unroll
            for (int off = 8; off >= 1; off >>= 1)
                rm = fmaxf(rm, __shfl_xor_sync(0xffffffffu, rm, off));

            const float corr = __expf(m_i[i] - rm);
            float rs = 0.0f;
            float p[4];
#pragma unroll
            for (int j = 0; j < 4; j++) {
                p[j] = __expf(sv[i][j] - rm);
                rs += p[j];
            }
#pragma unroll
            for (int off = 8; off >= 1; off >>= 1)
                rs += __shfl_xor_sync(0xffffffffu, rs, off);

            l_i[i] = l_i[i] * corr + rs;
            m_i[i] = rm;
#pragma unroll
            for (int j = 0; j < 4; j++)
                Ps[(tx + 16 * j) * 65 + (ty + 16 * i)] = p[j];
#pragma unroll
            for (int d = 0; d < 8; d++) oa[i][d] *= corr;
        }
        __syncthreads();

        // O += P @ V
#pragma unroll 4
        for (int k = 0; k < 64; k++) {
            float a[4];
#pragma unroll
            for (int i = 0; i < 4; i++) a[i] = Ps[k * 65 + ty + 16 * i];
            const float4 b0 = *(const float4*)&Vs[k * 132 + tx * 8];
            const float4 b1 = *(const float4*)&Vs[k * 132 + tx * 8 + 4];
#pragma unroll
            for (int i = 0; i < 4; i++) {
                oa[i][0] = fmaf(a[i], b0.x, oa[i][0]);
                oa[i][1] = fmaf(a[i], b0.y, oa[i][1]);
                oa[i][2] = fmaf(a[i], b0.z, oa[i][2]);
                oa[i][3] = fmaf(a[i], b0.w, oa[i][3]);
                oa[i][4] = fmaf(a[i], b1.x, oa[i][4]);
                oa[i][5] = fmaf(a[i], b1.y, oa[i][5]);
                oa[i][6] = fmaf(a[i], b1.z, oa[i][6]);
                oa[i][7] = fmaf(a[i], b1.w, oa[i][7]);
            }
        }
    }

    // normalize + store to [s][h*HD+d]
#pragma unroll
    for (int i = 0; i < 4; i++) {
        const int m = ty + 16 * i;
        const float inv = 1.0f / l_i[i];
        float4 v0 = make_float4(oa[i][0] * inv, oa[i][1] * inv, oa[i][2] * inv, oa[i][3] * inv);
        float4 v1 = make_float4(oa[i][4] * inv, oa[i][5] * inv, oa[i][6] * inv, oa[i][7] * inv);
        float* op = O + (size_t)(q0 + m) * HID + h * HD + tx * 8;
        *(float4*)(op)     = v0;
        *(float4*)(op + 4) = v1;
    }
}

// ---------------------------------------------------------------------------
extern "C" void kernel_launch(void* const* d_in, const int* in_sizes, int n_in,
                              void* d_out, int out_size) {
    const float* x  = (const float*)d_in[0];  // (1, 2048, 4096)
    const float* wq = (const float*)d_in[1];  // (4096, 4096)
    const float* wk = (const float*)d_in[2];  // (1024, 4096)
    const float* wv = (const float*)d_in[3];  // (1024, 4096)
    const float* wo = (const float*)d_in[4];  // (4096, 4096)
    const float* cs = (const float*)d_in[5];  // (1,1,2048,64)
    const float* sn = (const float*)d_in[6];  // (1,1,2048,64)
    // d_in[7] causal mask: unused (causal handled analytically)
    float* out = (float*)d_out;

    float *qraw, *kraw, *q, *k, *v, *att;
    cudaGetSymbolAddress((void**)&qraw, g_qraw);
    cudaGetSymbolAddress((void**)&kraw, g_kraw);
    cudaGetSymbolAddress((void**)&q, g_q);
    cudaGetSymbolAddress((void**)&k, g_k);
    cudaGetSymbolAddress((void**)&v, g_v);
    cudaGetSymbolAddress((void**)&att, g_att);

    const size_t attn_smem = (size_t)ATTN_SMEM_FLOATS * sizeof(float);
    cudaFuncSetAttribute(flash_attn, cudaFuncAttributeMaxDynamicSharedMemorySize,
                         (int)attn_smem);

    dim3 blk(256);
    // Q/K/V projections
    gemm_nt<0><<<dim3(HID / 128, S_LEN / 128), blk>>>(x, wq, qraw, S_LEN, HID, HID);
    gemm_nt<0><<<dim3((NKV * HD) / 128, S_LEN / 128), blk>>>(x, wk, kraw, S_LEN, NKV * HD, HID);
    gemm_nt<1><<<dim3((NKV * HD) / 128, S_LEN / 128), blk>>>(x, wv, v, S_LEN, NKV * HD, HID);
    // RoPE + head-major reshape
    rope_kernel<<<dim3(S_LEN, NH), 64>>>(qraw, cs, sn, q, NH);
    rope_kernel<<<dim3(S_LEN, NKV), 64>>>(kraw, cs, sn, k, NKV);
    // fused causal attention
    flash_attn<<<dim3(S_LEN / 64, NH), 256, attn_smem>>>(q, k, v, att);
    // output projection
    gemm_nt<0><<<dim3(HID / 128, S_LEN / 128), blk>>>(att, wo, out, S_LEN, HID, HID);
}

// round 3
// speedup vs baseline: 1.7798x; 1.7798x over previous
#include <cuda_runtime.h>
#include <cuda_bf16.h>
#include <stdint.h>
#include <math.h>

#define S_LEN 2048
#define HID 4096
#define NH 32
#define NKV 8
#define HD 128

// ---------------- scratch (device globals: no allocation allowed) ----------
__device__ float g_qraw[S_LEN * HID];          // x @ wq^T, [s][h*HD+d]
__device__ float g_kraw[S_LEN * NKV * HD];     // x @ wk^T
__device__ float g_q[NH * S_LEN * HD];         // head-major, rope applied
__device__ float g_k[NKV * S_LEN * HD];
__device__ float g_v[NKV * S_LEN * HD];        // head-major

__device__ __nv_bfloat16 g_xhi[S_LEN * HID],   g_xlo[S_LEN * HID];
__device__ __nv_bfloat16 g_wqhi[HID * HID],    g_wqlo[HID * HID];
__device__ __nv_bfloat16 g_wkhi[NKV*HD * HID], g_wklo[NKV*HD * HID];
__device__ __nv_bfloat16 g_wvhi[NKV*HD * HID], g_wvlo[NKV*HD * HID];
__device__ __nv_bfloat16 g_wohi[HID * HID],    g_wolo[HID * HID];
__device__ __nv_bfloat16 g_atthi[S_LEN * HID], g_attlo[S_LEN * HID];

// ======================= helpers ===========================================
__device__ __forceinline__ uint32_t smem_u32(const void* p) {
    uint32_t a;
    asm("{ .reg .u64 t; cvta.to.shared.u64 t, %1; cvt.u32.u64 %0, t; }" : "=r"(a) : "l"(p));
    return a;
}
__device__ __forceinline__ void cp_async16(uint32_t saddr, const void* g) {
    asm volatile("cp.async.cg.shared.global [%0], [%1], 16;" :: "r"(saddr), "l"(g));
}
#define CP_COMMIT() asm volatile("cp.async.commit_group;" ::: "memory")

// mma.sync m16n8k16 bf16 -> f32 (portable PTX, tensor pipe)
#define MMA_BF16(c, a, b0, b1)                                                 \
    asm volatile("mma.sync.aligned.m16n8k16.row.col.f32.bf16.bf16.f32 "        \
        "{%0,%1,%2,%3}, {%4,%5,%6,%7}, {%8,%9}, {%0,%1,%2,%3};"                \
        : "+f"((c)[0]), "+f"((c)[1]), "+f"((c)[2]), "+f"((c)[3])               \
        : "r"((a)[0]), "r"((a)[1]), "r"((a)[2]), "r"((a)[3]), "r"(b0), "r"(b1))

// ======================= split fp32 -> bf16 hi/lo ==========================
__global__ void split_kernel(const float4* __restrict__ in,
                             uint2* __restrict__ hi, uint2* __restrict__ lo, int n4) {
    int i = blockIdx.x * blockDim.x + threadIdx.x;
    if (i >= n4) return;
    float4 v = in[i];
    __nv_bfloat16 h[4], l[4];
    h[0] = __float2bfloat16_rn(v.x); l[0] = __float2bfloat16_rn(v.x - __bfloat162float(h[0]));
    h[1] = __float2bfloat16_rn(v.y); l[1] = __float2bfloat16_rn(v.y - __bfloat162float(h[1]));
    h[2] = __float2bfloat16_rn(v.z); l[2] = __float2bfloat16_rn(v.z - __bfloat162float(h[2]));
    h[3] = __float2bfloat16_rn(v.w); l[3] = __float2bfloat16_rn(v.w - __bfloat162float(h[3]));
    hi[i] = *(uint2*)h;
    lo[i] = *(uint2*)l;
}

// ======================= HMMA split-bf16 GEMM ==============================
// C[M,N] = (Ahi+Alo)[M,K] @ (Bhi+Blo)[N,K]^T  (fp32 result via 3 bf16 MMAs)
// Block 128x128x32, 256 threads = 8 warps (2m x 4n), warp tile 64x32.
// smem rows: 32 bf16 + pad -> 112B stride (16B aligned, conflict-free frags).
// mode 0: C row-major.  mode 1: C[(n>>7)][m][n&127] head-major.
#define RSTR 112                       // bytes per smem row
#define TILE_B (128 * RSTR)            // 14336 B per tile
#define STAGE_B (4 * TILE_B)           // Ah, Al, Bh, Bl
#define GEMM_SMEM (2 * STAGE_B)        // 114688 B

__device__ __forceinline__ uint32_t lds2(const char* base, int row, int col) {
    return *(const uint32_t*)(base + row * RSTR + col * 2);
}

__global__ __launch_bounds__(256, 1) void gemm_tc(
    const __nv_bfloat16* __restrict__ Ahi, const __nv_bfloat16* __restrict__ Alo,
    const __nv_bfloat16* __restrict__ Bhi, const __nv_bfloat16* __restrict__ Blo,
    float* __restrict__ C, int M, int N, int K, int mode)
{
    extern __shared__ char sm[];
    const uint32_t smb = smem_u32(sm);

    const int tid = threadIdx.x;
    const int warp = tid >> 5;
    const int lane = tid & 31;
    const int wm = warp >> 2;          // 0..1
    const int wn = warp & 3;           // 0..3
    const int g = lane >> 2;           // 0..7
    const int t = lane & 3;            // 0..3
    const int bm = blockIdx.y * 128;
    const int bn = blockIdx.x * 128;
    const int nk = K >> 5;             // K/32 chunks

    float acc[4][4][4];
#pragma unroll
    for (int i = 0; i < 4; i++)
#pragma unroll
        for (int j = 0; j < 4; j++)
#pragma unroll
            for (int r = 0; r < 4; r++) acc[i][j][r] = 0.0f;

    // stage loader: 4 tiles x 128 rows x 2 chunks(16B) ... id: 512 per tile
    auto load_stage = [&](int s, int c) {
        const uint32_t sb = smb + s * STAGE_B;
        const int k0 = c * 32;
#pragma unroll
        for (int it = 0; it < 2; it++) {
            const int id = tid + it * 256;          // 0..511
            const int r = id >> 2, ch = id & 3;     // row, 16B-chunk
            const uint32_t off = r * RSTR + ch * 16;
            const size_t ga = (size_t)(bm + r) * K + k0 + ch * 8;
            const size_t gb = (size_t)(bn + r) * K + k0 + ch * 8;
            cp_async16(sb + off,              Ahi + ga);
            cp_async16(sb + TILE_B + off,     Alo + ga);
            cp_async16(sb + 2 * TILE_B + off, Bhi + gb);
            cp_async16(sb + 3 * TILE_B + off, Blo + gb);
        }
        CP_COMMIT();
    };

    load_stage(0, 0);
    if (nk > 1) load_stage(1, 1);

    for (int c = 0; c < nk; c++) {
        const int s = c & 1;
        if (c + 1 < nk) asm volatile("cp.async.wait_group 1;" ::: "memory");
        else            asm volatile("cp.async.wait_group 0;" ::: "memory");
        __syncthreads();

        const char* Ahs = sm + s * STAGE_B;
        const char* Als = Ahs + TILE_B;
        const char* Bhs = Ahs + 2 * TILE_B;
        const char* Bls = Ahs + 3 * TILE_B;

#pragma unroll
        for (int ks = 0; ks < 2; ks++) {
            const int kb = ks * 16 + 2 * t;
            uint32_t ah[4][4], al[4][4];
#pragma unroll
            for (int i = 0; i < 4; i++) {
                const int r0 = wm * 64 + i * 16 + g;
                ah[i][0] = lds2(Ahs, r0,     kb);
                ah[i][1] = lds2(Ahs, r0 + 8, kb);
                ah[i][2] = lds2(Ahs, r0,     kb + 8);
                ah[i][3] = lds2(Ahs, r0 + 8, kb + 8);
                al[i][0] = lds2(Als, r0,     kb);
                al[i][1] = lds2(Als, r0 + 8, kb);
                al[i][2] = lds2(Als, r0,     kb + 8);
                al[i][3] = lds2(Als, r0 + 8, kb + 8);
            }
#pragma unroll
            for (int j = 0; j < 4; j++) {
                const int nr = wn * 32 + j * 8 + g;
                const uint32_t bh0 = lds2(Bhs, nr, kb);
                const uint32_t bh1 = lds2(Bhs, nr, kb + 8);
                const uint32_t bl0 = lds2(Bls, nr, kb);
                const uint32_t bl1 = lds2(Bls, nr, kb + 8);
#pragma unroll
                for (int i = 0; i < 4; i++) {
                    MMA_BF16(acc[i][j], ah[i], bh0, bh1);   // hi*hi
                    MMA_BF16(acc[i][j], ah[i], bl0, bl1);   // hi*lo
                    MMA_BF16(acc[i][j], al[i], bh0, bh1);   // lo*hi
                }
            }
        }
        __syncthreads();
        if (c + 2 < nk) load_stage(s, c + 2);
    }

    // epilogue
#pragma unroll
    for (int i = 0; i < 4; i++) {
        const int row0 = bm + wm * 64 + i * 16 + g;
#pragma unroll
        for (int j = 0; j < 4; j++) {
            const int col = bn + wn * 32 + j * 8 + 2 * t;
            float2 v0 = make_float2(acc[i][j][0], acc[i][j][1]);
            float2 v1 = make_float2(acc[i][j][2], acc[i][j][3]);
            if (mode == 0) {
                *(float2*)(C + (size_t)row0 * N + col) = v0;
                *(float2*)(C + (size_t)(row0 + 8) * N + col) = v1;
            } else {
                const int hh = col >> 7, d = col & 127;
                *(float2*)(C + ((size_t)hh * M + row0) * 128 + d) = v0;
                *(float2*)(C + ((size_t)hh * M + row0 + 8) * 128 + d) = v1;
            }
        }
    }
}

// ======================= RoPE + reshape =====================================
__global__ void rope_kernel(const float* __restrict__ raw, const float* __restrict__ cs,
                            const float* __restrict__ sn, float* __restrict__ out, int nh) {
    const int s = blockIdx.x;
    const int h = blockIdx.y;
    const int j = threadIdx.x;  // 0..63
    const float* r = raw + ((size_t)s * nh + h) * HD;
    const float x1 = r[j];
    const float x2 = r[j + 64];
    const float c = cs[s * 64 + j];
    const float si = sn[s * 64 + j];
    float* o = out + ((size_t)h * S_LEN + s) * HD;
    o[j]      = x1 * c - x2 * si;
    o[j + 64] = x2 * c + x1 * si;
}

// ======================= Flash attention (fp32) =============================
#define ATTN_SMEM_FLOATS (3 * 64 * 132 + 64 * 65)

__launch_bounds__(256)
__global__ void flash_attn(const float* __restrict__ Q, const float* __restrict__ K,
                           const float* __restrict__ V,
                           __nv_bfloat16* __restrict__ Ohi, __nv_bfloat16* __restrict__ Olo) {
    extern __shared__ float smf[];
    float* Qs = smf;
    float* Ks = smf + 64 * 132;
    float* Vs = smf + 2 * 64 * 132;
    float* Ps = smf + 3 * 64 * 132;

    const int qb = blockIdx.x;
    const int h  = blockIdx.y;
    const int q0 = qb * 64;
    const int kvh = h % NKV;
    const int tid = threadIdx.x;
    const int tx = tid & 15;
    const int ty = tid >> 4;
    const int warp = tid >> 5;
    const int lane = tid & 31;
    const float scale = 0.08838834764831845f;

    const float* Qg = Q + ((size_t)h * S_LEN + q0) * HD;
#pragma unroll
    for (int r = warp; r < 64; r += 8) {
        float4 v = *(const float4*)(Qg + (size_t)r * HD + lane * 4);
        v.x *= scale; v.y *= scale; v.z *= scale; v.w *= scale;
        *(float4*)&Qs[r * 132 + lane * 4] = v;
    }

    float m_i[4], l_i[4], oa[4][8];
#pragma unroll
    for (int i = 0; i < 4; i++) {
        m_i[i] = -1e30f; l_i[i] = 0.0f;
#pragma unroll
        for (int d = 0; d < 8; d++) oa[i][d] = 0.0f;
    }

    const float* Kg = K + (size_t)kvh * S_LEN * HD;
    const float* Vg = V + (size_t)kvh * S_LEN * HD;

    for (int jb = 0; jb <= qb; jb++) {
        const int k0 = jb * 64;
        __syncthreads();
#pragma unroll
        for (int r = warp; r < 64; r += 8) {
            *(float4*)&Ks[r * 132 + lane * 4] =
                *(const float4*)(Kg + (size_t)(k0 + r) * HD + lane * 4);
            *(float4*)&Vs[r * 132 + lane * 4] =
                *(const float4*)(Vg + (size_t)(k0 + r) * HD + lane * 4);
        }
        __syncthreads();

        float sv[4][4];
#pragma unroll
        for (int i = 0; i < 4; i++)
#pragma unroll
            for (int j = 0; j < 4; j++) sv[i][j] = 0.0f;

#pragma unroll 8
        for (int d = 0; d < 128; d += 4) {
            float4 a[4], b[4];
#pragma unroll
            for (int i = 0; i < 4; i++) a[i] = *(const float4*)&Qs[(ty + 16 * i) * 132 + d];
#pragma unroll
            for (int j = 0; j < 4; j++) b[j] = *(const float4*)&Ks[(tx + 16 * j) * 132 + d];
#pragma unroll
            for (int i = 0; i < 4; i++)
#pragma unroll
                for (int j = 0; j < 4; j++) {
                    sv[i][j] = fmaf(a[i].x, b[j].x, sv[i][j]);
                    sv[i][j] = fmaf(a[i].y, b[j].y, sv[i][j]);
                    sv[i][j] = fmaf(a[i].z, b[j].z, sv[i][j]);
                    sv[i][j] = fmaf(a[i].w, b[j].w, sv[i][j]);
                }
        }

        const bool diag = (jb == qb);
#pragma unroll
        for (int i = 0; i < 4; i++) {
            const int qrow = ty + 16 * i;
            float rm = m_i[i];
#pragma unroll
            for (int j = 0; j < 4; j++) {
                const int kn = tx + 16 * j;
                float s = sv[i][j];
                if (diag && kn > qrow) s = -1e30f;
                sv[i][j] = s;
                rm = fmaxf(rm, s);
            }
#pragma unroll
            for (int off = 8; off >= 1; off >>= 1)
                rm = fmaxf(rm, __shfl_xor_sync(0xffffffffu, rm, off));

            const float corr = __expf(m_i[i] - rm);
            float rs = 0.0f;
            float p[4];
#pragma unroll
            for (int j = 0; j < 4; j++) { p[j] = __expf(sv[i][j] - rm); rs += p[j]; }
#pragma unroll
            for (int off = 8; off >= 1; off >>= 1)
                rs += __shfl_xor_sync(0xffffffffu, rs, off);

            l_i[i] = l_i[i] * corr + rs;
            m_i[i] = rm;
#pragma unroll
            for (int j = 0; j < 4; j++)
                Ps[(tx + 16 * j) * 65 + (ty + 16 * i)] = p[j];
#pragma unroll
            for (int d = 0; d < 8; d++) oa[i][d] *= corr;
        }
        __syncthreads();

#pragma unroll 4
        for (int k = 0; k < 64; k++) {
            float a[4];
#pragma unroll
            for (int i = 0; i < 4; i++) a[i] = Ps[k * 65 + ty + 16 * i];
            const float4 b0 = *(const float4*)&Vs[k * 132 + tx * 8];
            const float4 b1 = *(const float4*)&Vs[k * 132 + tx * 8 + 4];
#pragma unroll
            for (int i = 0; i < 4; i++) {
                oa[i][0] = fmaf(a[i], b0.x, oa[i][0]);
                oa[i][1] = fmaf(a[i], b0.y, oa[i][1]);
                oa[i][2] = fmaf(a[i], b0.z, oa[i][2]);
                oa[i][3] = fmaf(a[i], b0.w, oa[i][3]);
                oa[i][4] = fmaf(a[i], b1.x, oa[i][4]);
                oa[i][5] = fmaf(a[i], b1.y, oa[i][5]);
                oa[i][6] = fmaf(a[i], b1.z, oa[i][6]);
                oa[i][7] = fmaf(a[i], b1.w, oa[i][7]);
            }
        }
    }

    // normalize + split to bf16 hi/lo at [s][h*HD+d]
#pragma unroll
    for (int i = 0; i < 4; i++) {
        const int m = ty + 16 * i;
        const float inv = 1.0f / l_i[i];
        __nv_bfloat16 hh[8], ll[8];
#pragma unroll
        for (int d = 0; d < 8; d++) {
            float v = oa[i][d] * inv;
            hh[d] = __float2bfloat16_rn(v);
            ll[d] = __float2bfloat16_rn(v - __bfloat162float(hh[d]));
        }
        const size_t idx = (size_t)(q0 + m) * HID + h * HD + tx * 8;
        *(uint4*)(Ohi + idx) = *(uint4*)hh;
        *(uint4*)(Olo + idx) = *(uint4*)ll;
    }
}

// ======================= launch ============================================
extern "C" void kernel_launch(void* const* d_in, const int* in_sizes, int n_in,
                              void* d_out, int out_size) {
    const float* x  = (const float*)d_in[0];
    const float* wq = (const float*)d_in[1];
    const float* wk = (const float*)d_in[2];
    const float* wv = (const float*)d_in[3];
    const float* wo = (const float*)d_in[4];
    const float* cs = (const float*)d_in[5];
    const float* sn = (const float*)d_in[6];
    float* out = (float*)d_out;

    float *qraw, *kraw, *q, *k, *v;
    __nv_bfloat16 *xhi, *xlo, *wqhi, *wqlo, *wkhi, *wklo, *wvhi, *wvlo, *wohi, *wolo, *atthi, *attlo;
    cudaGetSymbolAddress((void**)&qraw, g_qraw);
    cudaGetSymbolAddress((void**)&kraw, g_kraw);
    cudaGetSymbolAddress((void**)&q, g_q);
    cudaGetSymbolAddress((void**)&k, g_k);
    cudaGetSymbolAddress((void**)&v, g_v);
    cudaGetSymbolAddress((void**)&xhi, g_xhi);   cudaGetSymbolAddress((void**)&xlo, g_xlo);
    cudaGetSymbolAddress((void**)&wqhi, g_wqhi); cudaGetSymbolAddress((void**)&wqlo, g_wqlo);
    cudaGetSymbolAddress((void**)&wkhi, g_wkhi); cudaGetSymbolAddress((void**)&wklo, g_wklo);
    cudaGetSymbolAddress((void**)&wvhi, g_wvhi); cudaGetSymbolAddress((void**)&wvlo, g_wvlo);
    cudaGetSymbolAddress((void**)&wohi, g_wohi); cudaGetSymbolAddress((void**)&wolo, g_wolo);
    cudaGetSymbolAddress((void**)&atthi, g_atthi); cudaGetSymbolAddress((void**)&attlo, g_attlo);

    cudaFuncSetAttribute(gemm_tc, cudaFuncAttributeMaxDynamicSharedMemorySize, GEMM_SMEM);
    const size_t attn_smem = (size_t)ATTN_SMEM_FLOATS * sizeof(float);
    cudaFuncSetAttribute(flash_attn, cudaFuncAttributeMaxDynamicSharedMemorySize, (int)attn_smem);

    auto launch_split = [&](const float* src, __nv_bfloat16* hi, __nv_bfloat16* lo, int n) {
        int n4 = n / 4;
        split_kernel<<<(n4 + 255) / 256, 256>>>((const float4*)src, (uint2*)hi, (uint2*)lo, n4);
    };
    launch_split(x,  xhi,  xlo,  S_LEN * HID);
    launch_split(wq, wqhi, wqlo, HID * HID);
    launch_split(wk, wkhi, wklo, NKV * HD * HID);
    launch_split(wv, wvhi, wvlo, NKV * HD * HID);
    launch_split(wo, wohi, wolo, HID * HID);

    // projections on tensor cores (C = A @ B^T)
    gemm_tc<<<dim3(HID / 128, S_LEN / 128), 256, GEMM_SMEM>>>(
        xhi, xlo, wqhi, wqlo, qraw, S_LEN, HID, HID, 0);
    gemm_tc<<<dim3((NKV * HD) / 128, S_LEN / 128), 256, GEMM_SMEM>>>(
        xhi, xlo, wkhi, wklo, kraw, S_LEN, NKV * HD, HID, 0);
    gemm_tc<<<dim3((NKV * HD) / 128, S_LEN / 128), 256, GEMM_SMEM>>>(
        xhi, xlo, wvhi, wvlo, v, S_LEN, NKV * HD, HID, 1);

    // RoPE + head-major reshape
    rope_kernel<<<dim3(S_LEN, NH), 64>>>(qraw, cs, sn, q, NH);
    rope_kernel<<<dim3(S_LEN, NKV), 64>>>(kraw, cs, sn, k, NKV);

    // fused causal attention (writes bf16 hi/lo directly)
    flash_attn<<<dim3(S_LEN / 64, NH), 256, attn_smem>>>(q, k, v, atthi, attlo);

    // output projection
    gemm_tc<<<dim3(HID / 128, S_LEN / 128), 256, GEMM_SMEM>>>(
        atthi, attlo, wohi, wolo, out, S_LEN, HID, HID, 0);
}

// round 4
// speedup vs baseline: 2.4869x; 1.3973x over previous
#include <cuda_runtime.h>
#include <cuda_bf16.h>
#include <stdint.h>
#include <math.h>

#define S_LEN 2048
#define HID 4096
#define NH 32
#define NKV 8
#define HD 128

// ---------------- scratch (device globals: no allocation allowed) ----------
__device__ float g_qraw[S_LEN * HID];          // x @ wq^T, [s][h*HD+d]
__device__ float g_kraw[S_LEN * NKV * HD];     // x @ wk^T
__device__ float g_v[NKV * S_LEN * HD];        // head-major fp32 [kvh][s][d]

__device__ __nv_bfloat16 g_xhi[S_LEN * HID],   g_xlo[S_LEN * HID];
__device__ __nv_bfloat16 g_wqhi[HID * HID],    g_wqlo[HID * HID];
__device__ __nv_bfloat16 g_wkhi[NKV*HD * HID], g_wklo[NKV*HD * HID];
__device__ __nv_bfloat16 g_wvhi[NKV*HD * HID], g_wvlo[NKV*HD * HID];
__device__ __nv_bfloat16 g_wohi[HID * HID],    g_wolo[HID * HID];
__device__ __nv_bfloat16 g_atthi[S_LEN * HID], g_attlo[S_LEN * HID];

__device__ __nv_bfloat16 g_qbhi[NH * S_LEN * HD],  g_qblo[NH * S_LEN * HD];
__device__ __nv_bfloat16 g_kbhi[NKV * S_LEN * HD], g_kblo[NKV * S_LEN * HD];
__device__ __nv_bfloat16 g_vthi[NKV * HD * S_LEN], g_vtlo[NKV * HD * S_LEN];

// ======================= helpers ===========================================
__device__ __forceinline__ uint32_t smem_u32(const void* p) {
    uint32_t a;
    asm("{ .reg .u64 t; cvta.to.shared.u64 t, %1; cvt.u32.u64 %0, t; }" : "=r"(a) : "l"(p));
    return a;
}
__device__ __forceinline__ void cp_async16(uint32_t saddr, const void* g) {
    asm volatile("cp.async.cg.shared.global [%0], [%1], 16;" :: "r"(saddr), "l"(g));
}
#define CP_COMMIT() asm volatile("cp.async.commit_group;" ::: "memory")

// mma.sync m16n8k16 bf16 -> f32 (portable PTX, tensor pipe)
#define MMA_BF16(c, a, b0, b1)                                                 \
    asm volatile("mma.sync.aligned.m16n8k16.row.col.f32.bf16.bf16.f32 "        \
        "{%0,%1,%2,%3}, {%4,%5,%6,%7}, {%8,%9}, {%0,%1,%2,%3};"                \
        : "+f"((c)[0]), "+f"((c)[1]), "+f"((c)[2]), "+f"((c)[3])               \
        : "r"((a)[0]), "r"((a)[1]), "r"((a)[2]), "r"((a)[3]), "r"(b0), "r"(b1))

__device__ __forceinline__ void split2(float x, float y, uint32_t& hi, uint32_t& lo) {
    __nv_bfloat16 hx = __float2bfloat16_rn(x), hy = __float2bfloat16_rn(y);
    __nv_bfloat16 lx = __float2bfloat16_rn(x - __bfloat162float(hx));
    __nv_bfloat16 ly = __float2bfloat16_rn(y - __bfloat162float(hy));
    __nv_bfloat16 h2[2] = {hx, hy}, l2[2] = {lx, ly};
    hi = *(uint32_t*)h2;
    lo = *(uint32_t*)l2;
}

// ======================= split fp32 -> bf16 hi/lo ==========================
__global__ void split_kernel(const float4* __restrict__ in,
                             uint2* __restrict__ hi, uint2* __restrict__ lo, int n4) {
    int i = blockIdx.x * blockDim.x + threadIdx.x;
    if (i >= n4) return;
    float4 v = in[i];
    __nv_bfloat16 h[4], l[4];
    h[0] = __float2bfloat16_rn(v.x); l[0] = __float2bfloat16_rn(v.x - __bfloat162float(h[0]));
    h[1] = __float2bfloat16_rn(v.y); l[1] = __float2bfloat16_rn(v.y - __bfloat162float(h[1]));
    h[2] = __float2bfloat16_rn(v.z); l[2] = __float2bfloat16_rn(v.z - __bfloat162float(h[2]));
    h[3] = __float2bfloat16_rn(v.w); l[3] = __float2bfloat16_rn(v.w - __bfloat162float(h[3]));
    hi[i] = *(uint2*)h;
    lo[i] = *(uint2*)l;
}

// ======================= HMMA split-bf16 GEMM ==============================
#define RSTR 112
#define TILE_B (128 * RSTR)
#define STAGE_B (4 * TILE_B)
#define GEMM_SMEM (2 * STAGE_B)

__device__ __forceinline__ uint32_t lds2(const char* base, int row, int col) {
    return *(const uint32_t*)(base + row * RSTR + col * 2);
}

__global__ __launch_bounds__(256, 1) void gemm_tc(
    const __nv_bfloat16* __restrict__ Ahi, const __nv_bfloat16* __restrict__ Alo,
    const __nv_bfloat16* __restrict__ Bhi, const __nv_bfloat16* __restrict__ Blo,
    float* __restrict__ C, int M, int N, int K, int mode)
{
    extern __shared__ char sm[];
    const uint32_t smb = smem_u32(sm);

    const int tid = threadIdx.x;
    const int warp = tid >> 5;
    const int lane = tid & 31;
    const int wm = warp >> 2;
    const int wn = warp & 3;
    const int g = lane >> 2;
    const int t = lane & 3;
    const int bm = blockIdx.y * 128;
    const int bn = blockIdx.x * 128;
    const int nk = K >> 5;

    float acc[4][4][4];
#pragma unroll
    for (int i = 0; i < 4; i++)
#pragma unroll
        for (int j = 0; j < 4; j++)
#pragma unroll
            for (int r = 0; r < 4; r++) acc[i][j][r] = 0.0f;

    auto load_stage = [&](int s, int c) {
        const uint32_t sb = smb + s * STAGE_B;
        const int k0 = c * 32;
#pragma unroll
        for (int it = 0; it < 2; it++) {
            const int id = tid + it * 256;
            const int r = id >> 2, ch = id & 3;
            const uint32_t off = r * RSTR + ch * 16;
            const size_t ga = (size_t)(bm + r) * K + k0 + ch * 8;
            const size_t gb = (size_t)(bn + r) * K + k0 + ch * 8;
            cp_async16(sb + off,              Ahi + ga);
            cp_async16(sb + TILE_B + off,     Alo + ga);
            cp_async16(sb + 2 * TILE_B + off, Bhi + gb);
            cp_async16(sb + 3 * TILE_B + off, Blo + gb);
        }
        CP_COMMIT();
    };

    load_stage(0, 0);
    if (nk > 1) load_stage(1, 1);

    for (int c = 0; c < nk; c++) {
        const int s = c & 1;
        if (c + 1 < nk) asm volatile("cp.async.wait_group 1;" ::: "memory");
        else            asm volatile("cp.async.wait_group 0;" ::: "memory");
        __syncthreads();

        const char* Ahs = sm + s * STAGE_B;
        const char* Als = Ahs + TILE_B;
        const char* Bhs = Ahs + 2 * TILE_B;
        const char* Bls = Ahs + 3 * TILE_B;

#pragma unroll
        for (int ks = 0; ks < 2; ks++) {
            const int kb = ks * 16 + 2 * t;
            uint32_t ah[4][4], al[4][4];
#pragma unroll
            for (int i = 0; i < 4; i++) {
                const int r0 = wm * 64 + i * 16 + g;
                ah[i][0] = lds2(Ahs, r0,     kb);
                ah[i][1] = lds2(Ahs, r0 + 8, kb);
                ah[i][2] = lds2(Ahs, r0,     kb + 8);
                ah[i][3] = lds2(Ahs, r0 + 8, kb + 8);
                al[i][0] = lds2(Als, r0,     kb);
                al[i][1] = lds2(Als, r0 + 8, kb);
                al[i][2] = lds2(Als, r0,     kb + 8);
                al[i][3] = lds2(Als, r0 + 8, kb + 8);
            }
#pragma unroll
            for (int j = 0; j < 4; j++) {
                const int nr = wn * 32 + j * 8 + g;
                const uint32_t bh0 = lds2(Bhs, nr, kb);
                const uint32_t bh1 = lds2(Bhs, nr, kb + 8);
                const uint32_t bl0 = lds2(Bls, nr, kb);
                const uint32_t bl1 = lds2(Bls, nr, kb + 8);
#pragma unroll
                for (int i = 0; i < 4; i++) {
                    MMA_BF16(acc[i][j], ah[i], bh0, bh1);
                    MMA_BF16(acc[i][j], ah[i], bl0, bl1);
                    MMA_BF16(acc[i][j], al[i], bh0, bh1);
                }
            }
        }
        __syncthreads();
        if (c + 2 < nk) load_stage(s, c + 2);
    }

#pragma unroll
    for (int i = 0; i < 4; i++) {
        const int row0 = bm + wm * 64 + i * 16 + g;
#pragma unroll
        for (int j = 0; j < 4; j++) {
            const int col = bn + wn * 32 + j * 8 + 2 * t;
            float2 v0 = make_float2(acc[i][j][0], acc[i][j][1]);
            float2 v1 = make_float2(acc[i][j][2], acc[i][j][3]);
            if (mode == 0) {
                *(float2*)(C + (size_t)row0 * N + col) = v0;
                *(float2*)(C + (size_t)(row0 + 8) * N + col) = v1;
            } else {
                const int hh = col >> 7, d = col & 127;
                *(float2*)(C + ((size_t)hh * M + row0) * 128 + d) = v0;
                *(float2*)(C + ((size_t)hh * M + row0 + 8) * 128 + d) = v1;
            }
        }
    }
}

// ======================= RoPE + split to bf16 hi/lo ========================
// raw[s][h*HD+d] -> hi/lo[h][s][d], rope applied, scale folded.
__global__ void rope_split(const float* __restrict__ raw, const float* __restrict__ cs,
                           const float* __restrict__ sn,
                           __nv_bfloat16* __restrict__ hi, __nv_bfloat16* __restrict__ lo,
                           int nh, float scale) {
    const int s = blockIdx.x;
    const int h = blockIdx.y;
    const int j = threadIdx.x;  // 0..63
    const float* r = raw + ((size_t)s * nh + h) * HD;
    const float x1 = r[j];
    const float x2 = r[j + 64];
    const float c = cs[s * 64 + j];
    const float si = sn[s * 64 + j];
    const float y1 = (x1 * c - x2 * si) * scale;
    const float y2 = (x2 * c + x1 * si) * scale;
    const size_t base = ((size_t)h * S_LEN + s) * HD;
    __nv_bfloat16 h1 = __float2bfloat16_rn(y1);
    __nv_bfloat16 h2 = __float2bfloat16_rn(y2);
    hi[base + j]      = h1;
    hi[base + j + 64] = h2;
    lo[base + j]      = __float2bfloat16_rn(y1 - __bfloat162float(h1));
    lo[base + j + 64] = __float2bfloat16_rn(y2 - __bfloat162float(h2));
}

// ======================= V transpose + split ===============================
// v[kvh][s][d] fp32 -> vt hi/lo [kvh][d][s] bf16
__global__ void vt_split(const float* __restrict__ v,
                         __nv_bfloat16* __restrict__ vthi, __nv_bfloat16* __restrict__ vtlo) {
    __shared__ float tile[32][33];
    const int kvh = blockIdx.z;
    const int s0 = blockIdx.x * 32;
    const int d0 = blockIdx.y * 32;
    const int tx = threadIdx.x, ty = threadIdx.y;  // 32 x 8
    for (int i = ty; i < 32; i += 8)
        tile[i][tx] = v[((size_t)kvh * S_LEN + s0 + i) * HD + d0 + tx];
    __syncthreads();
    for (int i = ty; i < 32; i += 8) {
        const float val = tile[tx][i];             // s = s0+tx, d = d0+i
        __nv_bfloat16 h = __float2bfloat16_rn(val);
        const size_t idx = ((size_t)kvh * HD + d0 + i) * S_LEN + s0 + tx;
        vthi[idx] = h;
        vtlo[idx] = __float2bfloat16_rn(val - __bfloat162float(h));
    }
}

// ======================= Flash attention on tensor cores ===================
// q-tile 64 x k-tile 64, HD=128, 128 threads = 4 warps, warp owns 16 q rows.
#define KSTR 272                 // K/Q smem row stride bytes (128 bf16 + pad)
#define VSTR 144                 // Vt smem row stride bytes (64 bf16 + pad)
#define FA_QBYTES (64 * KSTR)    // 17408
#define FA_VBYTES (128 * VSTR)   // 18432
#define FA_STAGE (2 * FA_QBYTES + 2 * FA_VBYTES)    // 71680 (Kh,Kl,Vh,Vl)
#define FA_SMEM (2 * FA_QBYTES + 2 * FA_STAGE)      // 178176

__device__ __forceinline__ uint32_t ldsK(const char* base, int row, int col) {
    return *(const uint32_t*)(base + row * KSTR + col * 2);
}
__device__ __forceinline__ uint32_t ldsV(const char* base, int row, int col) {
    return *(const uint32_t*)(base + row * VSTR + col * 2);
}

__global__ __launch_bounds__(128, 1) void flash_attn_tc(
    const __nv_bfloat16* __restrict__ Qhi, const __nv_bfloat16* __restrict__ Qlo,
    const __nv_bfloat16* __restrict__ Khi, const __nv_bfloat16* __restrict__ Klo,
    const __nv_bfloat16* __restrict__ Vthi, const __nv_bfloat16* __restrict__ Vtlo,
    __nv_bfloat16* __restrict__ Ohi, __nv_bfloat16* __restrict__ Olo)
{
    extern __shared__ char fsm[];
    const uint32_t smb = smem_u32(fsm);
    const int qb = gridDim.x - 1 - blockIdx.x;   // heavy blocks first
    const int h  = blockIdx.y;
    const int kvh = h % NKV;
    const int q0 = qb * 64;
    const int tid = threadIdx.x;
    const int w = tid >> 5;
    const int lane = tid & 31;
    const int g = lane >> 2;
    const int t = lane & 3;

    // ---- Q tile load (once) ----
#pragma unroll
    for (int it = 0; it < 8; it++) {
        const int id = tid + 128 * it;           // 0..1023
        const int r = id >> 4, ch = id & 15;
        const uint32_t off = r * KSTR + ch * 16;
        const size_t gi = ((size_t)h * S_LEN + q0 + r) * HD + ch * 8;
        cp_async16(smb + off,             Qhi + gi);
        cp_async16(smb + FA_QBYTES + off, Qlo + gi);
    }

    auto fa_load = [&](int s, int jb) {
        const uint32_t sb = smb + 2 * FA_QBYTES + s * FA_STAGE;
        const int k0 = jb * 64;
#pragma unroll
        for (int it = 0; it < 8; it++) {
            const int id = tid + 128 * it;
            const int r = id >> 4, ch = id & 15;
            const uint32_t off = r * KSTR + ch * 16;
            const size_t gi = ((size_t)kvh * S_LEN + k0 + r) * HD + ch * 8;
            cp_async16(sb + off,             Khi + gi);
            cp_async16(sb + FA_QBYTES + off, Klo + gi);
        }
#pragma unroll
        for (int it = 0; it < 8; it++) {
            const int id = tid + 128 * it;
            const int r = id >> 3, ch = id & 7;
            const uint32_t off = r * VSTR + ch * 16;
            const size_t gi = ((size_t)kvh * HD + r) * S_LEN + k0 + ch * 8;
            cp_async16(sb + 2 * FA_QBYTES + off,             Vthi + gi);
            cp_async16(sb + 2 * FA_QBYTES + FA_VBYTES + off, Vtlo + gi);
        }
    };

    fa_load(0, 0);
    CP_COMMIT();                       // group: Q + stage0
    if (qb >= 1) fa_load(1, 1);
    CP_COMMIT();                       // group: stage1 (possibly empty)

    float oacc[16][4];
#pragma unroll
    for (int jd = 0; jd < 16; jd++)
#pragma unroll
        for (int r = 0; r < 4; r++) oacc[jd][r] = 0.0f;
    float m0 = -1e30f, m1 = -1e30f, l0 = 0.0f, l1 = 0.0f;

    const char* Qh = fsm;
    const char* Ql = fsm + FA_QBYTES;

    for (int jb = 0; jb <= qb; jb++) {
        const int s = jb & 1;
        if (jb < qb) asm volatile("cp.async.wait_group 1;" ::: "memory");
        else         asm volatile("cp.async.wait_group 0;" ::: "memory");
        __syncthreads();

        const char* Kh = fsm + 2 * FA_QBYTES + s * FA_STAGE;
        const char* Kl = Kh + FA_QBYTES;
        const char* Vh = Kh + 2 * FA_QBYTES;
        const char* Vl = Vh + FA_VBYTES;

        // ---- S = Q @ K^T (split-bf16, 3 MMAs) ----
        float sv[8][4];
#pragma unroll
        for (int j = 0; j < 8; j++)
#pragma unroll
            for (int r = 0; r < 4; r++) sv[j][r] = 0.0f;

#pragma unroll
        for (int kt = 0; kt < 8; kt++) {
            const int kb = kt * 16 + 2 * t;
            const int r0 = 16 * w + g;
            uint32_t qh[4], ql[4];
            qh[0] = ldsK(Qh, r0,     kb);
            qh[1] = ldsK(Qh, r0 + 8, kb);
            qh[2] = ldsK(Qh, r0,     kb + 8);
            qh[3] = ldsK(Qh, r0 + 8, kb + 8);
            ql[0] = ldsK(Ql, r0,     kb);
            ql[1] = ldsK(Ql, r0 + 8, kb);
            ql[2] = ldsK(Ql, r0,     kb + 8);
            ql[3] = ldsK(Ql, r0 + 8, kb + 8);
#pragma unroll
            for (int j = 0; j < 8; j++) {
                const int nr = 8 * j + g;
                const uint32_t bh0 = ldsK(Kh, nr, kb);
                const uint32_t bh1 = ldsK(Kh, nr, kb + 8);
                const uint32_t bl0 = ldsK(Kl, nr, kb);
                const uint32_t bl1 = ldsK(Kl, nr, kb + 8);
                MMA_BF16(sv[j], qh, bh0, bh1);
                MMA_BF16(sv[j], qh, bl0, bl1);
                MMA_BF16(sv[j], ql, bh0, bh1);
            }
        }

        // ---- causal mask (diag block only) ----
        if (jb == qb) {
#pragma unroll
            for (int j = 0; j < 8; j++) {
                const int c0 = 8 * j + 2 * t, c1 = c0 + 1;
                const int r0 = 16 * w + g, r1 = r0 + 8;
                if (c0 > r0) sv[j][0] = -1e30f;
                if (c1 > r0) sv[j][1] = -1e30f;
                if (c0 > r1) sv[j][2] = -1e30f;
                if (c1 > r1) sv[j][3] = -1e30f;
            }
        }

        // ---- online softmax ----
        float mn0 = m0, mn1 = m1;
#pragma unroll
        for (int j = 0; j < 8; j++) {
            mn0 = fmaxf(mn0, fmaxf(sv[j][0], sv[j][1]));
            mn1 = fmaxf(mn1, fmaxf(sv[j][2], sv[j][3]));
        }
        mn0 = fmaxf(mn0, __shfl_xor_sync(0xffffffffu, mn0, 1));
        mn0 = fmaxf(mn0, __shfl_xor_sync(0xffffffffu, mn0, 2));
        mn1 = fmaxf(mn1, __shfl_xor_sync(0xffffffffu, mn1, 1));
        mn1 = fmaxf(mn1, __shfl_xor_sync(0xffffffffu, mn1, 2));

        const float corr0 = __expf(m0 - mn0);
        const float corr1 = __expf(m1 - mn1);
        float rs0 = 0.0f, rs1 = 0.0f;
#pragma unroll
        for (int j = 0; j < 8; j++) {
            sv[j][0] = __expf(sv[j][0] - mn0);
            sv[j][1] = __expf(sv[j][1] - mn0);
            sv[j][2] = __expf(sv[j][2] - mn1);
            sv[j][3] = __expf(sv[j][3] - mn1);
            rs0 += sv[j][0] + sv[j][1];
            rs1 += sv[j][2] + sv[j][3];
        }
        rs0 += __shfl_xor_sync(0xffffffffu, rs0, 1);
        rs0 += __shfl_xor_sync(0xffffffffu, rs0, 2);
        rs1 += __shfl_xor_sync(0xffffffffu, rs1, 1);
        rs1 += __shfl_xor_sync(0xffffffffu, rs1, 2);
        l0 = l0 * corr0 + rs0;
        l1 = l1 * corr1 + rs1;
        m0 = mn0; m1 = mn1;

#pragma unroll
        for (int jd = 0; jd < 16; jd++) {
            oacc[jd][0] *= corr0; oacc[jd][1] *= corr0;
            oacc[jd][2] *= corr1; oacc[jd][3] *= corr1;
        }

        // ---- O += P @ V (P straight from S fragments) ----
#pragma unroll
        for (int kt = 0; kt < 4; kt++) {
            uint32_t ph[4], pl[4];
            split2(sv[2*kt][0],     sv[2*kt][1],     ph[0], pl[0]);
            split2(sv[2*kt][2],     sv[2*kt][3],     ph[1], pl[1]);
            split2(sv[2*kt+1][0],   sv[2*kt+1][1],   ph[2], pl[2]);
            split2(sv[2*kt+1][2],   sv[2*kt+1][3],   ph[3], pl[3]);
            const int kb = kt * 16 + 2 * t;
#pragma unroll
            for (int jd = 0; jd < 16; jd++) {
                const int nr = 8 * jd + g;
                const uint32_t bh0 = ldsV(Vh, nr, kb);
                const uint32_t bh1 = ldsV(Vh, nr, kb + 8);
                const uint32_t bl0 = ldsV(Vl, nr, kb);
                const uint32_t bl1 = ldsV(Vl, nr, kb + 8);
                MMA_BF16(oacc[jd], ph, bh0, bh1);
                MMA_BF16(oacc[jd], ph, bl0, bl1);
                MMA_BF16(oacc[jd], pl, bh0, bh1);
            }
        }

        __syncthreads();
        if (jb + 2 <= qb) { fa_load(s, jb + 2); CP_COMMIT(); }
    }

    // ---- normalize + split-store to att[s][h*HD+d] ----
    const float inv0 = 1.0f / l0;
    const float inv1 = 1.0f / l1;
    const int s0 = q0 + 16 * w + g;
    const int s1 = s0 + 8;
#pragma unroll
    for (int jd = 0; jd < 16; jd++) {
        const int d = 8 * jd + 2 * t;
        uint32_t hi0, lo0, hi1, lo1;
        split2(oacc[jd][0] * inv0, oacc[jd][1] * inv0, hi0, lo0);
        split2(oacc[jd][2] * inv1, oacc[jd][3] * inv1, hi1, lo1);
        const size_t i0 = (size_t)s0 * HID + h * HD + d;
        const size_t i1 = (size_t)s1 * HID + h * HD + d;
        *(uint32_t*)(Ohi + i0) = hi0;
        *(uint32_t*)(Olo + i0) = lo0;
        *(uint32_t*)(Ohi + i1) = hi1;
        *(uint32_t*)(Olo + i1) = lo1;
    }
}

// ======================= launch ============================================
extern "C" void kernel_launch(void* const* d_in, const int* in_sizes, int n_in,
                              void* d_out, int out_size) {
    const float* x  = (const float*)d_in[0];
    const float* wq = (const float*)d_in[1];
    const float* wk = (const float*)d_in[2];
    const float* wv = (const float*)d_in[3];
    const float* wo = (const float*)d_in[4];
    const float* cs = (const float*)d_in[5];
    const float* sn = (const float*)d_in[6];
    float* out = (float*)d_out;

    float *qraw, *kraw, *v;
    __nv_bfloat16 *xhi, *xlo, *wqhi, *wqlo, *wkhi, *wklo, *wvhi, *wvlo, *wohi, *wolo;
    __nv_bfloat16 *atthi, *attlo, *qbhi, *qblo, *kbhi, *kblo, *vthi, *vtlo;
    cudaGetSymbolAddress((void**)&qraw, g_qraw);
    cudaGetSymbolAddress((void**)&kraw, g_kraw);
    cudaGetSymbolAddress((void**)&v, g_v);
    cudaGetSymbolAddress((void**)&xhi, g_xhi);   cudaGetSymbolAddress((void**)&xlo, g_xlo);
    cudaGetSymbolAddress((void**)&wqhi, g_wqhi); cudaGetSymbolAddress((void**)&wqlo, g_wqlo);
    cudaGetSymbolAddress((void**)&wkhi, g_wkhi); cudaGetSymbolAddress((void**)&wklo, g_wklo);
    cudaGetSymbolAddress((void**)&wvhi, g_wvhi); cudaGetSymbolAddress((void**)&wvlo, g_wvlo);
    cudaGetSymbolAddress((void**)&wohi, g_wohi); cudaGetSymbolAddress((void**)&wolo, g_wolo);
    cudaGetSymbolAddress((void**)&atthi, g_atthi); cudaGetSymbolAddress((void**)&attlo, g_attlo);
    cudaGetSymbolAddress((void**)&qbhi, g_qbhi); cudaGetSymbolAddress((void**)&qblo, g_qblo);
    cudaGetSymbolAddress((void**)&kbhi, g_kbhi); cudaGetSymbolAddress((void**)&kblo, g_kblo);
    cudaGetSymbolAddress((void**)&vthi, g_vthi); cudaGetSymbolAddress((void**)&vtlo, g_vtlo);

    cudaFuncSetAttribute(gemm_tc, cudaFuncAttributeMaxDynamicSharedMemorySize, GEMM_SMEM);
    cudaFuncSetAttribute(flash_attn_tc, cudaFuncAttributeMaxDynamicSharedMemorySize, FA_SMEM);

    auto launch_split = [&](const float* src, __nv_bfloat16* hi, __nv_bfloat16* lo, int n) {
        int n4 = n / 4;
        split_kernel<<<(n4 + 255) / 256, 256>>>((const float4*)src, (uint2*)hi, (uint2*)lo, n4);
    };
    launch_split(x,  xhi,  xlo,  S_LEN * HID);
    launch_split(wq, wqhi, wqlo, HID * HID);
    launch_split(wk, wkhi, wklo, NKV * HD * HID);
    launch_split(wv, wvhi, wvlo, NKV * HD * HID);
    launch_split(wo, wohi, wolo, HID * HID);

    // projections on tensor cores (C = A @ B^T)
    gemm_tc<<<dim3(HID / 128, S_LEN / 128), 256, GEMM_SMEM>>>(
        xhi, xlo, wqhi, wqlo, qraw, S_LEN, HID, HID, 0);
    gemm_tc<<<dim3((NKV * HD) / 128, S_LEN / 128), 256, GEMM_SMEM>>>(
        xhi, xlo, wkhi, wklo, kraw, S_LEN, NKV * HD, HID, 0);
    gemm_tc<<<dim3((NKV * HD) / 128, S_LEN / 128), 256, GEMM_SMEM>>>(
        xhi, xlo, wvhi, wvlo, v, S_LEN, NKV * HD, HID, 1);

    // RoPE + split (scale folded into Q), V transpose + split
    const float scale = 0.08838834764831845f;
    rope_split<<<dim3(S_LEN, NH), 64>>>(qraw, cs, sn, qbhi, qblo, NH, scale);
    rope_split<<<dim3(S_LEN, NKV), 64>>>(kraw, cs, sn, kbhi, kblo, NKV, 1.0f);
    vt_split<<<dim3(S_LEN / 32, HD / 32, NKV), dim3(32, 8)>>>(v, vthi, vtlo);

    // tensor-core flash attention
    flash_attn_tc<<<dim3(S_LEN / 64, NH), 128, FA_SMEM>>>(
        qbhi, qblo, kbhi, kblo, vthi, vtlo, atthi, attlo);

    // output projection
    gemm_tc<<<dim3(HID / 128, S_LEN / 128), 256, GEMM_SMEM>>>(
        atthi, attlo, wohi, wolo, out, S_LEN, HID, HID, 0);
}

// round 5
// speedup vs baseline: 2.5526x; 1.0264x over previous
#include <cuda_runtime.h>
#include <cuda_bf16.h>
#include <stdint.h>
#include <math.h>

#define S_LEN 2048
#define HID 4096
#define NH 32
#define NKV 8
#define HD 128

// ---------------- scratch (device globals: no allocation allowed) ----------
__device__ float g_qraw[S_LEN * HID];
__device__ float g_kraw[S_LEN * NKV * HD];
__device__ float g_v[NKV * S_LEN * HD];

__device__ __nv_bfloat16 g_xhi[S_LEN * HID],   g_xlo[S_LEN * HID];
__device__ __nv_bfloat16 g_wqhi[HID * HID],    g_wqlo[HID * HID];
__device__ __nv_bfloat16 g_wkhi[NKV*HD * HID], g_wklo[NKV*HD * HID];
__device__ __nv_bfloat16 g_wvhi[NKV*HD * HID], g_wvlo[NKV*HD * HID];
__device__ __nv_bfloat16 g_wohi[HID * HID],    g_wolo[HID * HID];
__device__ __nv_bfloat16 g_atthi[S_LEN * HID], g_attlo[S_LEN * HID];

__device__ __nv_bfloat16 g_qbhi[NH * S_LEN * HD],  g_qblo[NH * S_LEN * HD];
__device__ __nv_bfloat16 g_kbhi[NKV * S_LEN * HD], g_kblo[NKV * S_LEN * HD];
__device__ __nv_bfloat16 g_vthi[NKV * HD * S_LEN], g_vtlo[NKV * HD * S_LEN];

// ======================= helpers ===========================================
__device__ __forceinline__ uint32_t smem_u32(const void* p) {
    uint32_t a;
    asm("{ .reg .u64 t; cvta.to.shared.u64 t, %1; cvt.u32.u64 %0, t; }" : "=r"(a) : "l"(p));
    return a;
}
__device__ __forceinline__ void cp_async16(uint32_t saddr, const void* g) {
    asm volatile("cp.async.cg.shared.global [%0], [%1], 16;" :: "r"(saddr), "l"(g));
}
#define CP_COMMIT() asm volatile("cp.async.commit_group;" ::: "memory")

#define MMA_BF16(c, a, b0, b1)                                                 \
    asm volatile("mma.sync.aligned.m16n8k16.row.col.f32.bf16.bf16.f32 "        \
        "{%0,%1,%2,%3}, {%4,%5,%6,%7}, {%8,%9}, {%0,%1,%2,%3};"                \
        : "+f"((c)[0]), "+f"((c)[1]), "+f"((c)[2]), "+f"((c)[3])               \
        : "r"((a)[0]), "r"((a)[1]), "r"((a)[2]), "r"((a)[3]), "r"(b0), "r"(b1))

__device__ __forceinline__ void ldsm_x4(uint32_t* r, uint32_t addr) {
    asm volatile("ldmatrix.sync.aligned.m8n8.x4.shared.b16 {%0,%1,%2,%3}, [%4];"
        : "=r"(r[0]), "=r"(r[1]), "=r"(r[2]), "=r"(r[3]) : "r"(addr));
}

__device__ __forceinline__ void split2(float x, float y, uint32_t& hi, uint32_t& lo) {
    __nv_bfloat16 hx = __float2bfloat16_rn(x), hy = __float2bfloat16_rn(y);
    __nv_bfloat16 lx = __float2bfloat16_rn(x - __bfloat162float(hx));
    __nv_bfloat16 ly = __float2bfloat16_rn(y - __bfloat162float(hy));
    __nv_bfloat16 h2[2] = {hx, hy}, l2[2] = {lx, ly};
    hi = *(uint32_t*)h2;
    lo = *(uint32_t*)l2;
}

// ======================= split fp32 -> bf16 hi/lo ==========================
__global__ void split_kernel(const float4* __restrict__ in,
                             uint2* __restrict__ hi, uint2* __restrict__ lo, int n4) {
    int i = blockIdx.x * blockDim.x + threadIdx.x;
    if (i >= n4) return;
    float4 v = in[i];
    __nv_bfloat16 h[4], l[4];
    h[0] = __float2bfloat16_rn(v.x); l[0] = __float2bfloat16_rn(v.x - __bfloat162float(h[0]));
    h[1] = __float2bfloat16_rn(v.y); l[1] = __float2bfloat16_rn(v.y - __bfloat162float(h[1]));
    h[2] = __float2bfloat16_rn(v.z); l[2] = __float2bfloat16_rn(v.z - __bfloat162float(h[2]));
    h[3] = __float2bfloat16_rn(v.w); l[3] = __float2bfloat16_rn(v.w - __bfloat162float(h[3]));
    hi[i] = *(uint2*)h;
    lo[i] = *(uint2*)l;
}

// ======================= HMMA split-bf16 GEMM (ldmatrix, 3-stage) ==========
#define RSTR 112
#define TILE_B (128 * RSTR)
#define STAGE_B (4 * TILE_B)           // Ah, Al, Bh, Bl
#define GEMM_SMEM (3 * STAGE_B)        // 172032

__global__ __launch_bounds__(256, 1) void gemm_tc(
    const __nv_bfloat16* __restrict__ Ahi, const __nv_bfloat16* __restrict__ Alo,
    const __nv_bfloat16* __restrict__ Bhi, const __nv_bfloat16* __restrict__ Blo,
    float* __restrict__ C, int M, int N, int K, int mode)
{
    extern __shared__ char sm[];
    const uint32_t smb = smem_u32(sm);

    const int tid = threadIdx.x;
    const int warp = tid >> 5;
    const int lane = tid & 31;
    const int wm = warp >> 2;
    const int wn = warp & 3;
    const int g = lane >> 2;
    const int t = lane & 3;
    const int bm = blockIdx.y * 128;
    const int bn = blockIdx.x * 128;
    const int nk = K >> 5;

    // ldmatrix per-lane row/col decomposition
    const int a_r  = (lane & 7) + ((lane >> 3) & 1) * 8;
    const int a_c8 = (lane >> 4) * 8;
    const int b_r  = lane & 7;
    const int b_j  = lane >> 4;
    const int b_c8 = ((lane >> 3) & 1) * 8;

    float acc[4][4][4];
#pragma unroll
    for (int i = 0; i < 4; i++)
#pragma unroll
        for (int j = 0; j < 4; j++)
#pragma unroll
            for (int r = 0; r < 4; r++) acc[i][j][r] = 0.0f;

    auto load_stage = [&](int s, int c) {
        const uint32_t sb = smb + s * STAGE_B;
        const int k0 = c * 32;
#pragma unroll
        for (int it = 0; it < 2; it++) {
            const int id = tid + it * 256;
            const int r = id >> 2, ch = id & 3;
            const uint32_t off = r * RSTR + ch * 16;
            const size_t ga = (size_t)(bm + r) * K + k0 + ch * 8;
            const size_t gb = (size_t)(bn + r) * K + k0 + ch * 8;
            cp_async16(sb + off,              Ahi + ga);
            cp_async16(sb + TILE_B + off,     Alo + ga);
            cp_async16(sb + 2 * TILE_B + off, Bhi + gb);
            cp_async16(sb + 3 * TILE_B + off, Blo + gb);
        }
        CP_COMMIT();
    };

    load_stage(0, 0);
    if (nk > 1) load_stage(1, 1);
    if (nk > 2) load_stage(2, 2);

    for (int c = 0; c < nk; c++) {
        const int s = c % 3;
        if (c + 2 < nk)      asm volatile("cp.async.wait_group 2;" ::: "memory");
        else if (c + 1 < nk) asm volatile("cp.async.wait_group 1;" ::: "memory");
        else                 asm volatile("cp.async.wait_group 0;" ::: "memory");
        __syncthreads();

        const uint32_t uAh = smb + s * STAGE_B;
        const uint32_t uAl = uAh + TILE_B;
        const uint32_t uBh = uAh + 2 * TILE_B;
        const uint32_t uBl = uAh + 3 * TILE_B;

#pragma unroll
        for (int ks = 0; ks < 2; ks++) {
            const uint32_t colA = (ks * 16 + a_c8) * 2;
            const uint32_t colB = (ks * 16 + b_c8) * 2;
            uint32_t ah[4][4], al[4][4];
#pragma unroll
            for (int i = 0; i < 4; i++) {
                const uint32_t ro = (wm * 64 + i * 16 + a_r) * RSTR + colA;
                ldsm_x4(ah[i], uAh + ro);
                ldsm_x4(al[i], uAl + ro);
            }
#pragma unroll
            for (int p = 0; p < 2; p++) {
                const uint32_t ro = (wn * 32 + (2 * p + b_j) * 8 + b_r) * RSTR + colB;
                uint32_t bh[4], bl[4];
                ldsm_x4(bh, uBh + ro);
                ldsm_x4(bl, uBl + ro);
#pragma unroll
                for (int i = 0; i < 4; i++) {
                    MMA_BF16(acc[i][2*p],   ah[i], bh[0], bh[1]);
                    MMA_BF16(acc[i][2*p],   ah[i], bl[0], bl[1]);
                    MMA_BF16(acc[i][2*p],   al[i], bh[0], bh[1]);
                    MMA_BF16(acc[i][2*p+1], ah[i], bh[2], bh[3]);
                    MMA_BF16(acc[i][2*p+1], ah[i], bl[2], bl[3]);
                    MMA_BF16(acc[i][2*p+1], al[i], bh[2], bh[3]);
                }
            }
        }
        __syncthreads();
        if (c + 3 < nk) load_stage(s, c + 3);
    }

#pragma unroll
    for (int i = 0; i < 4; i++) {
        const int row0 = bm + wm * 64 + i * 16 + g;
#pragma unroll
        for (int j = 0; j < 4; j++) {
            const int col = bn + wn * 32 + j * 8 + 2 * t;
            float2 v0 = make_float2(acc[i][j][0], acc[i][j][1]);
            float2 v1 = make_float2(acc[i][j][2], acc[i][j][3]);
            if (mode == 0) {
                *(float2*)(C + (size_t)row0 * N + col) = v0;
                *(float2*)(C + (size_t)(row0 + 8) * N + col) = v1;
            } else {
                const int hh = col >> 7, d = col & 127;
                *(float2*)(C + ((size_t)hh * M + row0) * 128 + d) = v0;
                *(float2*)(C + ((size_t)hh * M + row0 + 8) * 128 + d) = v1;
            }
        }
    }
}

// ======================= RoPE + split to bf16 hi/lo ========================
__global__ void rope_split(const float* __restrict__ raw, const float* __restrict__ cs,
                           const float* __restrict__ sn,
                           __nv_bfloat16* __restrict__ hi, __nv_bfloat16* __restrict__ lo,
                           int nh, float scale) {
    const int s = blockIdx.x;
    const int h = blockIdx.y;
    const int j = threadIdx.x;  // 0..63
    const float* r = raw + ((size_t)s * nh + h) * HD;
    const float x1 = r[j];
    const float x2 = r[j + 64];
    const float c = cs[s * 64 + j];
    const float si = sn[s * 64 + j];
    const float y1 = (x1 * c - x2 * si) * scale;
    const float y2 = (x2 * c + x1 * si) * scale;
    const size_t base = ((size_t)h * S_LEN + s) * HD;
    __nv_bfloat16 h1 = __float2bfloat16_rn(y1);
    __nv_bfloat16 h2 = __float2bfloat16_rn(y2);
    hi[base + j]      = h1;
    hi[base + j + 64] = h2;
    lo[base + j]      = __float2bfloat16_rn(y1 - __bfloat162float(h1));
    lo[base + j + 64] = __float2bfloat16_rn(y2 - __bfloat162float(h2));
}

// ======================= V transpose + split ===============================
__global__ void vt_split(const float* __restrict__ v,
                         __nv_bfloat16* __restrict__ vthi, __nv_bfloat16* __restrict__ vtlo) {
    __shared__ float tile[32][33];
    const int kvh = blockIdx.z;
    const int s0 = blockIdx.x * 32;
    const int d0 = blockIdx.y * 32;
    const int tx = threadIdx.x, ty = threadIdx.y;  // 32 x 8
    for (int i = ty; i < 32; i += 8)
        tile[i][tx] = v[((size_t)kvh * S_LEN + s0 + i) * HD + d0 + tx];
    __syncthreads();
    for (int i = ty; i < 32; i += 8) {
        const float val = tile[tx][i];
        __nv_bfloat16 h = __float2bfloat16_rn(val);
        const size_t idx = ((size_t)kvh * HD + d0 + i) * S_LEN + s0 + tx;
        vthi[idx] = h;
        vtlo[idx] = __float2bfloat16_rn(val - __bfloat162float(h));
    }
}

// ======================= Flash attention on tensor cores ===================
// q-tile 128 x k-tile 64, 256 threads = 8 warps, warp owns 16 q rows.
#define QSTR 272
#define VSTR 144
#define FA_QB (128 * QSTR)   // 34816 (per hi/lo)
#define FA_KB (64 * QSTR)    // 17408
#define FA_VB (128 * VSTR)   // 18432
#define FA_STAGE (2 * FA_KB + 2 * FA_VB)   // 71680
#define FA_SMEM (2 * FA_QB + 2 * FA_STAGE) // 212992

__global__ __launch_bounds__(256, 1) void flash_attn_tc(
    const __nv_bfloat16* __restrict__ Qhi, const __nv_bfloat16* __restrict__ Qlo,
    const __nv_bfloat16* __restrict__ Khi, const __nv_bfloat16* __restrict__ Klo,
    const __nv_bfloat16* __restrict__ Vthi, const __nv_bfloat16* __restrict__ Vtlo,
    __nv_bfloat16* __restrict__ Ohi, __nv_bfloat16* __restrict__ Olo)
{
    extern __shared__ char fsm[];
    const uint32_t smb = smem_u32(fsm);
    const int qb = gridDim.x - 1 - blockIdx.x;   // heavy blocks first
    const int h  = blockIdx.y;
    const int kvh = h % NKV;
    const int q0 = qb * 128;
    const int tid = threadIdx.x;
    const int w = tid >> 5;
    const int lane = tid & 31;
    const int g = lane >> 2;
    const int t = lane & 3;

    const int a_r  = (lane & 7) + ((lane >> 3) & 1) * 8;
    const int a_c8 = (lane >> 4) * 8;
    const int b_r  = lane & 7;
    const int b_j  = lane >> 4;
    const int b_c8 = ((lane >> 3) & 1) * 8;

    // ---- Q tile load (once): 128 rows x 16 chunks ----
#pragma unroll
    for (int it = 0; it < 8; it++) {
        const int id = tid + 256 * it;          // 0..2047
        const int r = id >> 4, ch = id & 15;
        const uint32_t off = r * QSTR + ch * 16;
        const size_t gi = ((size_t)h * S_LEN + q0 + r) * HD + ch * 8;
        cp_async16(smb + off,         Qhi + gi);
        cp_async16(smb + FA_QB + off, Qlo + gi);
    }

    auto fa_load = [&](int s, int jb) {
        const uint32_t sb = smb + 2 * FA_QB + s * FA_STAGE;
        const int k0 = jb * 64;
#pragma unroll
        for (int it = 0; it < 4; it++) {
            const int id = tid + 256 * it;      // 0..1023
            const int r = id >> 4, ch = id & 15;
            const uint32_t off = r * QSTR + ch * 16;
            const size_t gi = ((size_t)kvh * S_LEN + k0 + r) * HD + ch * 8;
            cp_async16(sb + off,         Khi + gi);
            cp_async16(sb + FA_KB + off, Klo + gi);
        }
#pragma unroll
        for (int it = 0; it < 4; it++) {
            const int id = tid + 256 * it;      // 0..1023
            const int r = id >> 3, ch = id & 7;
            const uint32_t off = r * VSTR + ch * 16;
            const size_t gi = ((size_t)kvh * HD + r) * S_LEN + k0 + ch * 8;
            cp_async16(sb + 2 * FA_KB + off,         Vthi + gi);
            cp_async16(sb + 2 * FA_KB + FA_VB + off, Vtlo + gi);
        }
    };

    const int njb = 2 * qb + 2;
    fa_load(0, 0);
    CP_COMMIT();
    fa_load(1, 1);
    CP_COMMIT();

    float oacc[16][4];
#pragma unroll
    for (int jd = 0; jd < 16; jd++)
#pragma unroll
        for (int r = 0; r < 4; r++) oacc[jd][r] = 0.0f;
    float m0 = -1e30f, m1 = -1e30f, l0 = 0.0f, l1 = 0.0f;

    const uint32_t uQh = smb;
    const uint32_t uQl = smb + FA_QB;

    for (int jb = 0; jb < njb; jb++) {
        const int s = jb & 1;
        if (jb + 1 < njb) asm volatile("cp.async.wait_group 1;" ::: "memory");
        else              asm volatile("cp.async.wait_group 0;" ::: "memory");
        __syncthreads();

        const uint32_t uKh = smb + 2 * FA_QB + s * FA_STAGE;
        const uint32_t uKl = uKh + FA_KB;
        const uint32_t uVh = uKh + 2 * FA_KB;
        const uint32_t uVl = uVh + FA_VB;

        // ---- S = Q @ K^T ----
        float sv[8][4];
#pragma unroll
        for (int j = 0; j < 8; j++)
#pragma unroll
            for (int r = 0; r < 4; r++) sv[j][r] = 0.0f;

#pragma unroll
        for (int kt = 0; kt < 8; kt++) {
            const uint32_t qro = (16 * w + a_r) * QSTR + (kt * 16 + a_c8) * 2;
            uint32_t qh[4], ql[4];
            ldsm_x4(qh, uQh + qro);
            ldsm_x4(ql, uQl + qro);
#pragma unroll
            for (int p = 0; p < 4; p++) {
                const uint32_t kro = ((2 * p + b_j) * 8 + b_r) * QSTR + (kt * 16 + b_c8) * 2;
                uint32_t kh[4], kl[4];
                ldsm_x4(kh, uKh + kro);
                ldsm_x4(kl, uKl + kro);
                MMA_BF16(sv[2*p],   qh, kh[0], kh[1]);
                MMA_BF16(sv[2*p],   qh, kl[0], kl[1]);
                MMA_BF16(sv[2*p],   ql, kh[0], kh[1]);
                MMA_BF16(sv[2*p+1], qh, kh[2], kh[3]);
                MMA_BF16(sv[2*p+1], qh, kl[2], kl[3]);
                MMA_BF16(sv[2*p+1], ql, kh[2], kh[3]);
            }
        }

        // ---- causal mask (only last two k-tiles can clip) ----
        if (jb >= 2 * qb) {
            const int r0g = q0 + 16 * w + g;
            const int r1g = r0g + 8;
            const int kg = jb * 64;
#pragma unroll
            for (int j = 0; j < 8; j++) {
                const int c0 = kg + 8 * j + 2 * t, c1 = c0 + 1;
                if (c0 > r0g) sv[j][0] = -1e30f;
                if (c1 > r0g) sv[j][1] = -1e30f;
                if (c0 > r1g) sv[j][2] = -1e30f;
                if (c1 > r1g) sv[j][3] = -1e30f;
            }
        }

        // ---- online softmax ----
        float mn0 = m0, mn1 = m1;
#pragma unroll
        for (int j = 0; j < 8; j++) {
            mn0 = fmaxf(mn0, fmaxf(sv[j][0], sv[j][1]));
            mn1 = fmaxf(mn1, fmaxf(sv[j][2], sv[j][3]));
        }
        mn0 = fmaxf(mn0, __shfl_xor_sync(0xffffffffu, mn0, 1));
        mn0 = fmaxf(mn0, __shfl_xor_sync(0xffffffffu, mn0, 2));
        mn1 = fmaxf(mn1, __shfl_xor_sync(0xffffffffu, mn1, 1));
        mn1 = fmaxf(mn1, __shfl_xor_sync(0xffffffffu, mn1, 2));

        const float corr0 = __expf(m0 - mn0);
        const float corr1 = __expf(m1 - mn1);
        float rs0 = 0.0f, rs1 = 0.0f;
#pragma unroll
        for (int j = 0; j < 8; j++) {
            sv[j][0] = __expf(sv[j][0] - mn0);
            sv[j][1] = __expf(sv[j][1] - mn0);
            sv[j][2] = __expf(sv[j][2] - mn1);
            sv[j][3] = __expf(sv[j][3] - mn1);
            rs0 += sv[j][0] + sv[j][1];
            rs1 += sv[j][2] + sv[j][3];
        }
        rs0 += __shfl_xor_sync(0xffffffffu, rs0, 1);
        rs0 += __shfl_xor_sync(0xffffffffu, rs0, 2);
        rs1 += __shfl_xor_sync(0xffffffffu, rs1, 1);
        rs1 += __shfl_xor_sync(0xffffffffu, rs1, 2);
        l0 = l0 * corr0 + rs0;
        l1 = l1 * corr1 + rs1;
        m0 = mn0; m1 = mn1;

#pragma unroll
        for (int jd = 0; jd < 16; jd++) {
            oacc[jd][0] *= corr0; oacc[jd][1] *= corr0;
            oacc[jd][2] *= corr1; oacc[jd][3] *= corr1;
        }

        // ---- O += P @ V ----
#pragma unroll
        for (int kt = 0; kt < 4; kt++) {
            uint32_t ph[4], pl[4];
            split2(sv[2*kt][0],   sv[2*kt][1],   ph[0], pl[0]);
            split2(sv[2*kt][2],   sv[2*kt][3],   ph[1], pl[1]);
            split2(sv[2*kt+1][0], sv[2*kt+1][1], ph[2], pl[2]);
            split2(sv[2*kt+1][2], sv[2*kt+1][3], ph[3], pl[3]);
#pragma unroll
            for (int p = 0; p < 8; p++) {
                const uint32_t vro = ((2 * p + b_j) * 8 + b_r) * VSTR + (kt * 16 + b_c8) * 2;
                uint32_t vh[4], vl[4];
                ldsm_x4(vh, uVh + vro);
                ldsm_x4(vl, uVl + vro);
                MMA_BF16(oacc[2*p],   ph, vh[0], vh[1]);
                MMA_BF16(oacc[2*p],   ph, vl[0], vl[1]);
                MMA_BF16(oacc[2*p],   pl, vh[0], vh[1]);
                MMA_BF16(oacc[2*p+1], ph, vh[2], vh[3]);
                MMA_BF16(oacc[2*p+1], ph, vl[2], vl[3]);
                MMA_BF16(oacc[2*p+1], pl, vh[2], vh[3]);
            }
        }

        __syncthreads();
        if (jb + 2 < njb) { fa_load(s, jb + 2); CP_COMMIT(); }
    }

    // ---- normalize + split-store ----
    const float inv0 = 1.0f / l0;
    const float inv1 = 1.0f / l1;
    const int s0 = q0 + 16 * w + g;
    const int s1 = s0 + 8;
#pragma unroll
    for (int jd = 0; jd < 16; jd++) {
        const int d = 8 * jd + 2 * t;
        uint32_t hi0, lo0, hi1, lo1;
        split2(oacc[jd][0] * inv0, oacc[jd][1] * inv0, hi0, lo0);
        split2(oacc[jd][2] * inv1, oacc[jd][3] * inv1, hi1, lo1);
        const size_t i0 = (size_t)s0 * HID + h * HD + d;
        const size_t i1 = (size_t)s1 * HID + h * HD + d;
        *(uint32_t*)(Ohi + i0) = hi0;
        *(uint32_t*)(Olo + i0) = lo0;
        *(uint32_t*)(Ohi + i1) = hi1;
        *(uint32_t*)(Olo + i1) = lo1;
    }
}

// ======================= launch ============================================
extern "C" void kernel_launch(void* const* d_in, const int* in_sizes, int n_in,
                              void* d_out, int out_size) {
    const float* x  = (const float*)d_in[0];
    const float* wq = (const float*)d_in[1];
    const float* wk = (const float*)d_in[2];
    const float* wv = (const float*)d_in[3];
    const float* wo = (const float*)d_in[4];
    const float* cs = (const float*)d_in[5];
    const float* sn = (const float*)d_in[6];
    float* out = (float*)d_out;

    float *qraw, *kraw, *v;
    __nv_bfloat16 *xhi, *xlo, *wqhi, *wqlo, *wkhi, *wklo, *wvhi, *wvlo, *wohi, *wolo;
    __nv_bfloat16 *atthi, *attlo, *qbhi, *qblo, *kbhi, *kblo, *vthi, *vtlo;
    cudaGetSymbolAddress((void**)&qraw, g_qraw);
    cudaGetSymbolAddress((void**)&kraw, g_kraw);
    cudaGetSymbolAddress((void**)&v, g_v);
    cudaGetSymbolAddress((void**)&xhi, g_xhi);   cudaGetSymbolAddress((void**)&xlo, g_xlo);
    cudaGetSymbolAddress((void**)&wqhi, g_wqhi); cudaGetSymbolAddress((void**)&wqlo, g_wqlo);
    cudaGetSymbolAddress((void**)&wkhi, g_wkhi); cudaGetSymbolAddress((void**)&wklo, g_wklo);
    cudaGetSymbolAddress((void**)&wvhi, g_wvhi); cudaGetSymbolAddress((void**)&wvlo, g_wvlo);
    cudaGetSymbolAddress((void**)&wohi, g_wohi); cudaGetSymbolAddress((void**)&wolo, g_wolo);
    cudaGetSymbolAddress((void**)&atthi, g_atthi); cudaGetSymbolAddress((void**)&attlo, g_attlo);
    cudaGetSymbolAddress((void**)&qbhi, g_qbhi); cudaGetSymbolAddress((void**)&qblo, g_qblo);
    cudaGetSymbolAddress((void**)&kbhi, g_kbhi); cudaGetSymbolAddress((void**)&kblo, g_kblo);
    cudaGetSymbolAddress((void**)&vthi, g_vthi); cudaGetSymbolAddress((void**)&vtlo, g_vtlo);

    cudaFuncSetAttribute(gemm_tc, cudaFuncAttributeMaxDynamicSharedMemorySize, GEMM_SMEM);
    cudaFuncSetAttribute(flash_attn_tc, cudaFuncAttributeMaxDynamicSharedMemorySize, FA_SMEM);

    auto launch_split = [&](const float* src, __nv_bfloat16* hi, __nv_bfloat16* lo, int n) {
        int n4 = n / 4;
        split_kernel<<<(n4 + 255) / 256, 256>>>((const float4*)src, (uint2*)hi, (uint2*)lo, n4);
    };
    launch_split(x,  xhi,  xlo,  S_LEN * HID);
    launch_split(wq, wqhi, wqlo, HID * HID);
    launch_split(wk, wkhi, wklo, NKV * HD * HID);
    launch_split(wv, wvhi, wvlo, NKV * HD * HID);
    launch_split(wo, wohi, wolo, HID * HID);

    // projections on tensor cores (C = A @ B^T)
    gemm_tc<<<dim3(HID / 128, S_LEN / 128), 256, GEMM_SMEM>>>(
        xhi, xlo, wqhi, wqlo, qraw, S_LEN, HID, HID, 0);
    gemm_tc<<<dim3((NKV * HD) / 128, S_LEN / 128), 256, GEMM_SMEM>>>(
        xhi, xlo, wkhi, wklo, kraw, S_LEN, NKV * HD, HID, 0);
    gemm_tc<<<dim3((NKV * HD) / 128, S_LEN / 128), 256, GEMM_SMEM>>>(
        xhi, xlo, wvhi, wvlo, v, S_LEN, NKV * HD, HID, 1);

    // RoPE + split (scale folded into Q), V transpose + split
    const float scale = 0.08838834764831845f;
    rope_split<<<dim3(S_LEN, NH), 64>>>(qraw, cs, sn, qbhi, qblo, NH, scale);
    rope_split<<<dim3(S_LEN, NKV), 64>>>(kraw, cs, sn, kbhi, kblo, NKV, 1.0f);
    vt_split<<<dim3(S_LEN / 32, HD / 32, NKV), dim3(32, 8)>>>(v, vthi, vtlo);

    // tensor-core flash attention (q-tile 128)
    flash_attn_tc<<<dim3(S_LEN / 128, NH), 256, FA_SMEM>>>(
        qbhi, qblo, kbhi, kblo, vthi, vtlo, atthi, attlo);

    // output projection
    gemm_tc<<<dim3(HID / 128, S_LEN / 128), 256, GEMM_SMEM>>>(
        atthi, attlo, wohi, wolo, out, S_LEN, HID, HID, 0);
}

// round 6
// speedup vs baseline: 2.9264x; 1.1464x over previous
#include <cuda_runtime.h>
#include <cuda_bf16.h>
#include <cuda_fp16.h>
#include <stdint.h>
#include <math.h>

#define S_LEN 2048
#define HID 4096
#define NH 32
#define NKV 8
#define HD 128

// ---------------- scratch (device globals: no allocation allowed) ----------
__device__ float g_qraw[S_LEN * HID];
__device__ float g_kraw[S_LEN * NKV * HD];
__device__ float g_v[NKV * S_LEN * HD];

__device__ __nv_bfloat16 g_xhi[S_LEN * HID],   g_xlo[S_LEN * HID];
__device__ __nv_bfloat16 g_wqhi[HID * HID],    g_wqlo[HID * HID];
__device__ __nv_bfloat16 g_wkhi[NKV*HD * HID], g_wklo[NKV*HD * HID];

__device__ __half g_xh16[S_LEN * HID], g_xl16[S_LEN * HID];
__device__ __half g_wv16[NKV*HD * HID];
__device__ __half g_wo16[HID * HID];
__device__ __half g_atth16[S_LEN * HID], g_attl16[S_LEN * HID];
__device__ __half g_vt16[NKV * HD * S_LEN];

__device__ __nv_bfloat16 g_qbhi[NH * S_LEN * HD],  g_qblo[NH * S_LEN * HD];
__device__ __nv_bfloat16 g_kbhi[NKV * S_LEN * HD], g_kblo[NKV * S_LEN * HD];

// ======================= helpers ===========================================
__device__ __forceinline__ uint32_t smem_u32(const void* p) {
    uint32_t a;
    asm("{ .reg .u64 t; cvta.to.shared.u64 t, %1; cvt.u32.u64 %0, t; }" : "=r"(a) : "l"(p));
    return a;
}
__device__ __forceinline__ void cp_async16(uint32_t saddr, const void* g) {
    asm volatile("cp.async.cg.shared.global [%0], [%1], 16;" :: "r"(saddr), "l"(g));
}
#define CP_COMMIT() asm volatile("cp.async.commit_group;" ::: "memory")

#define MMA_BF16(c, a, b0, b1)                                                 \
    asm volatile("mma.sync.aligned.m16n8k16.row.col.f32.bf16.bf16.f32 "        \
        "{%0,%1,%2,%3}, {%4,%5,%6,%7}, {%8,%9}, {%0,%1,%2,%3};"                \
        : "+f"((c)[0]), "+f"((c)[1]), "+f"((c)[2]), "+f"((c)[3])               \
        : "r"((a)[0]), "r"((a)[1]), "r"((a)[2]), "r"((a)[3]), "r"(b0), "r"(b1))

#define MMA_F16(c, a, b0, b1)                                                  \
    asm volatile("mma.sync.aligned.m16n8k16.row.col.f32.f16.f16.f32 "          \
        "{%0,%1,%2,%3}, {%4,%5,%6,%7}, {%8,%9}, {%0,%1,%2,%3};"                \
        : "+f"((c)[0]), "+f"((c)[1]), "+f"((c)[2]), "+f"((c)[3])               \
        : "r"((a)[0]), "r"((a)[1]), "r"((a)[2]), "r"((a)[3]), "r"(b0), "r"(b1))

__device__ __forceinline__ void ldsm_x4(uint32_t* r, uint32_t addr) {
    asm volatile("ldmatrix.sync.aligned.m8n8.x4.shared.b16 {%0,%1,%2,%3}, [%4];"
        : "=r"(r[0]), "=r"(r[1]), "=r"(r[2]), "=r"(r[3]) : "r"(addr));
}

__device__ __forceinline__ void split2h(float x, float y, uint32_t& hi, uint32_t& lo) {
    __half hx = __float2half_rn(x), hy = __float2half_rn(y);
    __half lx = __float2half_rn(x - __half2float(hx));
    __half ly = __float2half_rn(y - __half2float(hy));
    __half h2[2] = {hx, hy}, l2[2] = {lx, ly};
    hi = *(uint32_t*)h2;
    lo = *(uint32_t*)l2;
}

// ======================= split kernels =====================================
__global__ void split_kernel(const float4* __restrict__ in,
                             uint2* __restrict__ hi, uint2* __restrict__ lo, int n4) {
    int i = blockIdx.x * blockDim.x + threadIdx.x;
    if (i >= n4) return;
    float4 v = in[i];
    __nv_bfloat16 h[4], l[4];
    h[0] = __float2bfloat16_rn(v.x); l[0] = __float2bfloat16_rn(v.x - __bfloat162float(h[0]));
    h[1] = __float2bfloat16_rn(v.y); l[1] = __float2bfloat16_rn(v.y - __bfloat162float(h[1]));
    h[2] = __float2bfloat16_rn(v.z); l[2] = __float2bfloat16_rn(v.z - __bfloat162float(h[2]));
    h[3] = __float2bfloat16_rn(v.w); l[3] = __float2bfloat16_rn(v.w - __bfloat162float(h[3]));
    hi[i] = *(uint2*)h;
    lo[i] = *(uint2*)l;
}

__global__ void split16_kernel(const float4* __restrict__ in,
                               uint2* __restrict__ hi, uint2* __restrict__ lo, int n4) {
    int i = blockIdx.x * blockDim.x + threadIdx.x;
    if (i >= n4) return;
    float4 v = in[i];
    __half h[4], l[4];
    h[0] = __float2half_rn(v.x); l[0] = __float2half_rn(v.x - __half2float(h[0]));
    h[1] = __float2half_rn(v.y); l[1] = __float2half_rn(v.y - __half2float(h[1]));
    h[2] = __float2half_rn(v.z); l[2] = __float2half_rn(v.z - __half2float(h[2]));
    h[3] = __float2half_rn(v.w); l[3] = __float2half_rn(v.w - __half2float(h[3]));
    hi[i] = *(uint2*)h;
    lo[i] = *(uint2*)l;
}

__global__ void split16s_kernel(const float4* __restrict__ in,
                                uint2* __restrict__ hi, int n4) {
    int i = blockIdx.x * blockDim.x + threadIdx.x;
    if (i >= n4) return;
    float4 v = in[i];
    __half h[4];
    h[0] = __float2half_rn(v.x);
    h[1] = __float2half_rn(v.y);
    h[2] = __float2half_rn(v.z);
    h[3] = __float2half_rn(v.w);
    hi[i] = *(uint2*)h;
}

// ======================= bf16 3-MMA GEMM (Q/K projections) =================
#define RSTR 112
#define TILE_B (128 * RSTR)
#define STAGE_B (4 * TILE_B)
#define GEMM_SMEM (3 * STAGE_B)        // 172032

__global__ __launch_bounds__(256, 1) void gemm_tc(
    const __nv_bfloat16* __restrict__ Ahi, const __nv_bfloat16* __restrict__ Alo,
    const __nv_bfloat16* __restrict__ Bhi, const __nv_bfloat16* __restrict__ Blo,
    float* __restrict__ C, int M, int N, int K, int mode)
{
    extern __shared__ char sm[];
    const uint32_t smb = smem_u32(sm);

    const int tid = threadIdx.x;
    const int warp = tid >> 5;
    const int lane = tid & 31;
    const int wm = warp >> 2;
    const int wn = warp & 3;
    const int g = lane >> 2;
    const int t = lane & 3;
    const int bm = blockIdx.y * 128;
    const int bn = blockIdx.x * 128;
    const int nk = K >> 5;

    const int a_r  = (lane & 7) + ((lane >> 3) & 1) * 8;
    const int a_c8 = (lane >> 4) * 8;
    const int b_r  = lane & 7;
    const int b_j  = lane >> 4;
    const int b_c8 = ((lane >> 3) & 1) * 8;

    float acc[4][4][4];
#pragma unroll
    for (int i = 0; i < 4; i++)
#pragma unroll
        for (int j = 0; j < 4; j++)
#pragma unroll
            for (int r = 0; r < 4; r++) acc[i][j][r] = 0.0f;

    auto load_stage = [&](int s, int c) {
        const uint32_t sb = smb + s * STAGE_B;
        const int k0 = c * 32;
#pragma unroll
        for (int it = 0; it < 2; it++) {
            const int id = tid + it * 256;
            const int r = id >> 2, ch = id & 3;
            const uint32_t off = r * RSTR + ch * 16;
            const size_t ga = (size_t)(bm + r) * K + k0 + ch * 8;
            const size_t gb = (size_t)(bn + r) * K + k0 + ch * 8;
            cp_async16(sb + off,              Ahi + ga);
            cp_async16(sb + TILE_B + off,     Alo + ga);
            cp_async16(sb + 2 * TILE_B + off, Bhi + gb);
            cp_async16(sb + 3 * TILE_B + off, Blo + gb);
        }
        CP_COMMIT();
    };

    load_stage(0, 0);
    if (nk > 1) load_stage(1, 1);
    if (nk > 2) load_stage(2, 2);

    for (int c = 0; c < nk; c++) {
        const int s = c % 3;
        if (c + 2 < nk)      asm volatile("cp.async.wait_group 2;" ::: "memory");
        else if (c + 1 < nk) asm volatile("cp.async.wait_group 1;" ::: "memory");
        else                 asm volatile("cp.async.wait_group 0;" ::: "memory");
        __syncthreads();

        const uint32_t uAh = smb + s * STAGE_B;
        const uint32_t uAl = uAh + TILE_B;
        const uint32_t uBh = uAh + 2 * TILE_B;
        const uint32_t uBl = uAh + 3 * TILE_B;

#pragma unroll
        for (int ks = 0; ks < 2; ks++) {
            const uint32_t colA = (ks * 16 + a_c8) * 2;
            const uint32_t colB = (ks * 16 + b_c8) * 2;
            uint32_t ah[4][4], al[4][4];
#pragma unroll
            for (int i = 0; i < 4; i++) {
                const uint32_t ro = (wm * 64 + i * 16 + a_r) * RSTR + colA;
                ldsm_x4(ah[i], uAh + ro);
                ldsm_x4(al[i], uAl + ro);
            }
#pragma unroll
            for (int p = 0; p < 2; p++) {
                const uint32_t ro = (wn * 32 + (2 * p + b_j) * 8 + b_r) * RSTR + colB;
                uint32_t bh[4], bl[4];
                ldsm_x4(bh, uBh + ro);
                ldsm_x4(bl, uBl + ro);
#pragma unroll
                for (int i = 0; i < 4; i++) {
                    MMA_BF16(acc[i][2*p],   ah[i], bh[0], bh[1]);
                    MMA_BF16(acc[i][2*p],   ah[i], bl[0], bl[1]);
                    MMA_BF16(acc[i][2*p],   al[i], bh[0], bh[1]);
                    MMA_BF16(acc[i][2*p+1], ah[i], bh[2], bh[3]);
                    MMA_BF16(acc[i][2*p+1], ah[i], bl[2], bl[3]);
                    MMA_BF16(acc[i][2*p+1], al[i], bh[2], bh[3]);
                }
            }
        }
        __syncthreads();
        if (c + 3 < nk) load_stage(s, c + 3);
    }

#pragma unroll
    for (int i = 0; i < 4; i++) {
        const int row0 = bm + wm * 64 + i * 16 + g;
#pragma unroll
        for (int j = 0; j < 4; j++) {
            const int col = bn + wn * 32 + j * 8 + 2 * t;
            float2 v0 = make_float2(acc[i][j][0], acc[i][j][1]);
            float2 v1 = make_float2(acc[i][j][2], acc[i][j][3]);
            if (mode == 0) {
                *(float2*)(C + (size_t)row0 * N + col) = v0;
                *(float2*)(C + (size_t)(row0 + 8) * N + col) = v1;
            } else {
                const int hh = col >> 7, d = col & 127;
                *(float2*)(C + ((size_t)hh * M + row0) * 128 + d) = v0;
                *(float2*)(C + ((size_t)hh * M + row0 + 8) * 128 + d) = v1;
            }
        }
    }
}

// ======================= fp16 2-MMA GEMM (V/O projections) =================
#define STAGE2_B (3 * TILE_B)
#define GEMM2_SMEM (3 * STAGE2_B)      // 129024

__global__ __launch_bounds__(256, 1) void gemm_tc2(
    const __half* __restrict__ Ahi, const __half* __restrict__ Alo,
    const __half* __restrict__ B,
    float* __restrict__ C, int M, int N, int K, int mode)
{
    extern __shared__ char sm[];
    const uint32_t smb = smem_u32(sm);

    const int tid = threadIdx.x;
    const int warp = tid >> 5;
    const int lane = tid & 31;
    const int wm = warp >> 2;
    const int wn = warp & 3;
    const int g = lane >> 2;
    const int t = lane & 3;
    const int bm = blockIdx.y * 128;
    const int bn = blockIdx.x * 128;
    const int nk = K >> 5;

    const int a_r  = (lane & 7) + ((lane >> 3) & 1) * 8;
    const int a_c8 = (lane >> 4) * 8;
    const int b_r  = lane & 7;
    const int b_j  = lane >> 4;
    const int b_c8 = ((lane >> 3) & 1) * 8;

    float acc[4][4][4];
#pragma unroll
    for (int i = 0; i < 4; i++)
#pragma unroll
        for (int j = 0; j < 4; j++)
#pragma unroll
            for (int r = 0; r < 4; r++) acc[i][j][r] = 0.0f;

    auto load_stage = [&](int s, int c) {
        const uint32_t sb = smb + s * STAGE2_B;
        const int k0 = c * 32;
#pragma unroll
        for (int it = 0; it < 2; it++) {
            const int id = tid + it * 256;
            const int r = id >> 2, ch = id & 3;
            const uint32_t off = r * RSTR + ch * 16;
            const size_t ga = (size_t)(bm + r) * K + k0 + ch * 8;
            const size_t gb = (size_t)(bn + r) * K + k0 + ch * 8;
            cp_async16(sb + off,              Ahi + ga);
            cp_async16(sb + TILE_B + off,     Alo + ga);
            cp_async16(sb + 2 * TILE_B + off, B + gb);
        }
        CP_COMMIT();
    };

    load_stage(0, 0);
    if (nk > 1) load_stage(1, 1);
    if (nk > 2) load_stage(2, 2);

    for (int c = 0; c < nk; c++) {
        const int s = c % 3;
        if (c + 2 < nk)      asm volatile("cp.async.wait_group 2;" ::: "memory");
        else if (c + 1 < nk) asm volatile("cp.async.wait_group 1;" ::: "memory");
        else                 asm volatile("cp.async.wait_group 0;" ::: "memory");
        __syncthreads();

        const uint32_t uAh = smb + s * STAGE2_B;
        const uint32_t uAl = uAh + TILE_B;
        const uint32_t uB  = uAh + 2 * TILE_B;

#pragma unroll
        for (int ks = 0; ks < 2; ks++) {
            const uint32_t colA = (ks * 16 + a_c8) * 2;
            const uint32_t colB = (ks * 16 + b_c8) * 2;
            uint32_t ah[4][4], al[4][4];
#pragma unroll
            for (int i = 0; i < 4; i++) {
                const uint32_t ro = (wm * 64 + i * 16 + a_r) * RSTR + colA;
                ldsm_x4(ah[i], uAh + ro);
                ldsm_x4(al[i], uAl + ro);
            }
#pragma unroll
            for (int p = 0; p < 2; p++) {
                const uint32_t ro = (wn * 32 + (2 * p + b_j) * 8 + b_r) * RSTR + colB;
                uint32_t bh[4];
                ldsm_x4(bh, uB + ro);
#pragma unroll
                for (int i = 0; i < 4; i++) {
                    MMA_F16(acc[i][2*p],   ah[i], bh[0], bh[1]);
                    MMA_F16(acc[i][2*p],   al[i], bh[0], bh[1]);
                    MMA_F16(acc[i][2*p+1], ah[i], bh[2], bh[3]);
                    MMA_F16(acc[i][2*p+1], al[i], bh[2], bh[3]);
                }
            }
        }
        __syncthreads();
        if (c + 3 < nk) load_stage(s, c + 3);
    }

#pragma unroll
    for (int i = 0; i < 4; i++) {
        const int row0 = bm + wm * 64 + i * 16 + g;
#pragma unroll
        for (int j = 0; j < 4; j++) {
            const int col = bn + wn * 32 + j * 8 + 2 * t;
            float2 v0 = make_float2(acc[i][j][0], acc[i][j][1]);
            float2 v1 = make_float2(acc[i][j][2], acc[i][j][3]);
            if (mode == 0) {
                *(float2*)(C + (size_t)row0 * N + col) = v0;
                *(float2*)(C + (size_t)(row0 + 8) * N + col) = v1;
            } else {
                const int hh = col >> 7, d = col & 127;
                *(float2*)(C + ((size_t)hh * M + row0) * 128 + d) = v0;
                *(float2*)(C + ((size_t)hh * M + row0 + 8) * 128 + d) = v1;
            }
        }
    }
}

// ======================= RoPE + split to bf16 hi/lo ========================
__global__ void rope_split(const float* __restrict__ raw, const float* __restrict__ cs,
                           const float* __restrict__ sn,
                           __nv_bfloat16* __restrict__ hi, __nv_bfloat16* __restrict__ lo,
                           int nh, float scale) {
    const int s = blockIdx.x;
    const int h = blockIdx.y;
    const int j = threadIdx.x;  // 0..63
    const float* r = raw + ((size_t)s * nh + h) * HD;
    const float x1 = r[j];
    const float x2 = r[j + 64];
    const float c = cs[s * 64 + j];
    const float si = sn[s * 64 + j];
    const float y1 = (x1 * c - x2 * si) * scale;
    const float y2 = (x2 * c + x1 * si) * scale;
    const size_t base = ((size_t)h * S_LEN + s) * HD;
    __nv_bfloat16 h1 = __float2bfloat16_rn(y1);
    __nv_bfloat16 h2 = __float2bfloat16_rn(y2);
    hi[base + j]      = h1;
    hi[base + j + 64] = h2;
    lo[base + j]      = __float2bfloat16_rn(y1 - __bfloat162float(h1));
    lo[base + j + 64] = __float2bfloat16_rn(y2 - __bfloat162float(h2));
}

// ======================= V transpose + fp16 ================================
__global__ void vt_split16(const float* __restrict__ v, __half* __restrict__ vt) {
    __shared__ float tile[32][33];
    const int kvh = blockIdx.z;
    const int s0 = blockIdx.x * 32;
    const int d0 = blockIdx.y * 32;
    const int tx = threadIdx.x, ty = threadIdx.y;  // 32 x 8
    for (int i = ty; i < 32; i += 8)
        tile[i][tx] = v[((size_t)kvh * S_LEN + s0 + i) * HD + d0 + tx];
    __syncthreads();
    for (int i = ty; i < 32; i += 8) {
        const float val = tile[tx][i];
        vt[((size_t)kvh * HD + d0 + i) * S_LEN + s0 + tx] = __float2half_rn(val);
    }
}

// ======================= Flash attention on tensor cores ===================
// q-tile 128 x k-tile 64, 256 threads = 8 warps.
// QK^T: bf16 3-MMA.  P·V: fp16 2-MMA (P hi/lo fp16, V single fp16).
#define QSTR 272
#define VSTR 144
#define FA_QB (128 * QSTR)   // 34816
#define FA_KB (64 * QSTR)    // 17408
#define FA_VB (128 * VSTR)   // 18432
#define FA_STAGE (2 * FA_KB + FA_VB)       // 53248
#define FA_SMEM (2 * FA_QB + 2 * FA_STAGE) // 176128

__global__ __launch_bounds__(256, 1) void flash_attn_tc(
    const __nv_bfloat16* __restrict__ Qhi, const __nv_bfloat16* __restrict__ Qlo,
    const __nv_bfloat16* __restrict__ Khi, const __nv_bfloat16* __restrict__ Klo,
    const __half* __restrict__ Vt,
    __half* __restrict__ Ohi, __half* __restrict__ Olo)
{
    extern __shared__ char fsm[];
    const uint32_t smb = smem_u32(fsm);
    const int qb = gridDim.x - 1 - blockIdx.x;
    const int h  = blockIdx.y;
    const int kvh = h % NKV;
    const int q0 = qb * 128;
    const int tid = threadIdx.x;
    const int w = tid >> 5;
    const int lane = tid & 31;
    const int g = lane >> 2;
    const int t = lane & 3;

    const int a_r  = (lane & 7) + ((lane >> 3) & 1) * 8;
    const int a_c8 = (lane >> 4) * 8;
    const int b_r  = lane & 7;
    const int b_j  = lane >> 4;
    const int b_c8 = ((lane >> 3) & 1) * 8;

#pragma unroll
    for (int it = 0; it < 8; it++) {
        const int id = tid + 256 * it;
        const int r = id >> 4, ch = id & 15;
        const uint32_t off = r * QSTR + ch * 16;
        const size_t gi = ((size_t)h * S_LEN + q0 + r) * HD + ch * 8;
        cp_async16(smb + off,         Qhi + gi);
        cp_async16(smb + FA_QB + off, Qlo + gi);
    }

    auto fa_load = [&](int s, int jb) {
        const uint32_t sb = smb + 2 * FA_QB + s * FA_STAGE;
        const int k0 = jb * 64;
#pragma unroll
        for (int it = 0; it < 4; it++) {
            const int id = tid + 256 * it;
            const int r = id >> 4, ch = id & 15;
            const uint32_t off = r * QSTR + ch * 16;
            const size_t gi = ((size_t)kvh * S_LEN + k0 + r) * HD + ch * 8;
            cp_async16(sb + off,         Khi + gi);
            cp_async16(sb + FA_KB + off, Klo + gi);
        }
#pragma unroll
        for (int it = 0; it < 4; it++) {
            const int id = tid + 256 * it;
            const int r = id >> 3, ch = id & 7;
            const uint32_t off = r * VSTR + ch * 16;
            const size_t gi = ((size_t)kvh * HD + r) * S_LEN + k0 + ch * 8;
            cp_async16(sb + 2 * FA_KB + off, Vt + gi);
        }
    };

    const int njb = 2 * qb + 2;
    fa_load(0, 0);
    CP_COMMIT();
    fa_load(1, 1);
    CP_COMMIT();

    float oacc[16][4];
#pragma unroll
    for (int jd = 0; jd < 16; jd++)
#pragma unroll
        for (int r = 0; r < 4; r++) oacc[jd][r] = 0.0f;
    float m0 = -1e30f, m1 = -1e30f, l0 = 0.0f, l1 = 0.0f;

    const uint32_t uQh = smb;
    const uint32_t uQl = smb + FA_QB;

    for (int jb = 0; jb < njb; jb++) {
        const int s = jb & 1;
        if (jb + 1 < njb) asm volatile("cp.async.wait_group 1;" ::: "memory");
        else              asm volatile("cp.async.wait_group 0;" ::: "memory");
        __syncthreads();

        const uint32_t uKh = smb + 2 * FA_QB + s * FA_STAGE;
        const uint32_t uKl = uKh + FA_KB;
        const uint32_t uV  = uKh + 2 * FA_KB;

        // ---- S = Q @ K^T (bf16 3-MMA) ----
        float sv[8][4];
#pragma unroll
        for (int j = 0; j < 8; j++)
#pragma unroll
            for (int r = 0; r < 4; r++) sv[j][r] = 0.0f;

#pragma unroll
        for (int kt = 0; kt < 8; kt++) {
            const uint32_t qro = (16 * w + a_r) * QSTR + (kt * 16 + a_c8) * 2;
            uint32_t qh[4], ql[4];
            ldsm_x4(qh, uQh + qro);
            ldsm_x4(ql, uQl + qro);
#pragma unroll
            for (int p = 0; p < 4; p++) {
                const uint32_t kro = ((2 * p + b_j) * 8 + b_r) * QSTR + (kt * 16 + b_c8) * 2;
                uint32_t kh[4], kl[4];
                ldsm_x4(kh, uKh + kro);
                ldsm_x4(kl, uKl + kro);
                MMA_BF16(sv[2*p],   qh, kh[0], kh[1]);
                MMA_BF16(sv[2*p],   qh, kl[0], kl[1]);
                MMA_BF16(sv[2*p],   ql, kh[0], kh[1]);
                MMA_BF16(sv[2*p+1], qh, kh[2], kh[3]);
                MMA_BF16(sv[2*p+1], qh, kl[2], kl[3]);
                MMA_BF16(sv[2*p+1], ql, kh[2], kh[3]);
            }
        }

        // ---- causal mask ----
        if (jb >= 2 * qb) {
            const int r0g = q0 + 16 * w + g;
            const int r1g = r0g + 8;
            const int kg = jb * 64;
#pragma unroll
            for (int j = 0; j < 8; j++) {
                const int c0 = kg + 8 * j + 2 * t, c1 = c0 + 1;
                if (c0 > r0g) sv[j][0] = -1e30f;
                if (c1 > r0g) sv[j][1] = -1e30f;
                if (c0 > r1g) sv[j][2] = -1e30f;
                if (c1 > r1g) sv[j][3] = -1e30f;
            }
        }

        // ---- online softmax ----
        float mn0 = m0, mn1 = m1;
#pragma unroll
        for (int j = 0; j < 8; j++) {
            mn0 = fmaxf(mn0, fmaxf(sv[j][0], sv[j][1]));
            mn1 = fmaxf(mn1, fmaxf(sv[j][2], sv[j][3]));
        }
        mn0 = fmaxf(mn0, __shfl_xor_sync(0xffffffffu, mn0, 1));
        mn0 = fmaxf(mn0, __shfl_xor_sync(0xffffffffu, mn0, 2));
        mn1 = fmaxf(mn1, __shfl_xor_sync(0xffffffffu, mn1, 1));
        mn1 = fmaxf(mn1, __shfl_xor_sync(0xffffffffu, mn1, 2));

        const float corr0 = __expf(m0 - mn0);
        const float corr1 = __expf(m1 - mn1);
        float rs0 = 0.0f, rs1 = 0.0f;
#pragma unroll
        for (int j = 0; j < 8; j++) {
            sv[j][0] = __expf(sv[j][0] - mn0);
            sv[j][1] = __expf(sv[j][1] - mn0);
            sv[j][2] = __expf(sv[j][2] - mn1);
            sv[j][3] = __expf(sv[j][3] - mn1);
            rs0 += sv[j][0] + sv[j][1];
            rs1 += sv[j][2] + sv[j][3];
        }
        rs0 += __shfl_xor_sync(0xffffffffu, rs0, 1);
        rs0 += __shfl_xor_sync(0xffffffffu, rs0, 2);
        rs1 += __shfl_xor_sync(0xffffffffu, rs1, 1);
        rs1 += __shfl_xor_sync(0xffffffffu, rs1, 2);
        l0 = l0 * corr0 + rs0;
        l1 = l1 * corr1 + rs1;
        m0 = mn0; m1 = mn1;

#pragma unroll
        for (int jd = 0; jd < 16; jd++) {
            oacc[jd][0] *= corr0; oacc[jd][1] *= corr0;
            oacc[jd][2] *= corr1; oacc[jd][3] *= corr1;
        }

        // ---- O += P @ V (fp16 2-MMA: P hi/lo fp16 x V fp16) ----
#pragma unroll
        for (int kt = 0; kt < 4; kt++) {
            uint32_t ph[4], pl[4];
            split2h(sv[2*kt][0],   sv[2*kt][1],   ph[0], pl[0]);
            split2h(sv[2*kt][2],   sv[2*kt][3],   ph[1], pl[1]);
            split2h(sv[2*kt+1][0], sv[2*kt+1][1], ph[2], pl[2]);
            split2h(sv[2*kt+1][2], sv[2*kt+1][3], ph[3], pl[3]);
#pragma unroll
            for (int p = 0; p < 8; p++) {
                const uint32_t vro = ((2 * p + b_j) * 8 + b_r) * VSTR + (kt * 16 + b_c8) * 2;
                uint32_t vh[4];
                ldsm_x4(vh, uV + vro);
                MMA_F16(oacc[2*p],   ph, vh[0], vh[1]);
                MMA_F16(oacc[2*p],   pl, vh[0], vh[1]);
                MMA_F16(oacc[2*p+1], ph, vh[2], vh[3]);
                MMA_F16(oacc[2*p+1], pl, vh[2], vh[3]);
            }
        }

        __syncthreads();
        if (jb + 2 < njb) { fa_load(s, jb + 2); CP_COMMIT(); }
    }

    // ---- normalize + fp16 split-store ----
    const float inv0 = 1.0f / l0;
    const float inv1 = 1.0f / l1;
    const int s0 = q0 + 16 * w + g;
    const int s1 = s0 + 8;
#pragma unroll
    for (int jd = 0; jd < 16; jd++) {
        const int d = 8 * jd + 2 * t;
        uint32_t hi0, lo0, hi1, lo1;
        split2h(oacc[jd][0] * inv0, oacc[jd][1] * inv0, hi0, lo0);
        split2h(oacc[jd][2] * inv1, oacc[jd][3] * inv1, hi1, lo1);
        const size_t i0 = (size_t)s0 * HID + h * HD + d;
        const size_t i1 = (size_t)s1 * HID + h * HD + d;
        *(uint32_t*)(Ohi + i0) = hi0;
        *(uint32_t*)(Olo + i0) = lo0;
        *(uint32_t*)(Ohi + i1) = hi1;
        *(uint32_t*)(Olo + i1) = lo1;
    }
}

// ======================= launch ============================================
extern "C" void kernel_launch(void* const* d_in, const int* in_sizes, int n_in,
                              void* d_out, int out_size) {
    const float* x  = (const float*)d_in[0];
    const float* wq = (const float*)d_in[1];
    const float* wk = (const float*)d_in[2];
    const float* wv = (const float*)d_in[3];
    const float* wo = (const float*)d_in[4];
    const float* cs = (const float*)d_in[5];
    const float* sn = (const float*)d_in[6];
    float* out = (float*)d_out;

    float *qraw, *kraw, *v;
    __nv_bfloat16 *xhi, *xlo, *wqhi, *wqlo, *wkhi, *wklo;
    __nv_bfloat16 *qbhi, *qblo, *kbhi, *kblo;
    __half *xh16, *xl16, *wv16, *wo16, *atth16, *attl16, *vt16;
    cudaGetSymbolAddress((void**)&qraw, g_qraw);
    cudaGetSymbolAddress((void**)&kraw, g_kraw);
    cudaGetSymbolAddress((void**)&v, g_v);
    cudaGetSymbolAddress((void**)&xhi, g_xhi);   cudaGetSymbolAddress((void**)&xlo, g_xlo);
    cudaGetSymbolAddress((void**)&wqhi, g_wqhi); cudaGetSymbolAddress((void**)&wqlo, g_wqlo);
    cudaGetSymbolAddress((void**)&wkhi, g_wkhi); cudaGetSymbolAddress((void**)&wklo, g_wklo);
    cudaGetSymbolAddress((void**)&xh16, g_xh16); cudaGetSymbolAddress((void**)&xl16, g_xl16);
    cudaGetSymbolAddress((void**)&wv16, g_wv16); cudaGetSymbolAddress((void**)&wo16, g_wo16);
    cudaGetSymbolAddress((void**)&atth16, g_atth16); cudaGetSymbolAddress((void**)&attl16, g_attl16);
    cudaGetSymbolAddress((void**)&vt16, g_vt16);
    cudaGetSymbolAddress((void**)&qbhi, g_qbhi); cudaGetSymbolAddress((void**)&qblo, g_qblo);
    cudaGetSymbolAddress((void**)&kbhi, g_kbhi); cudaGetSymbolAddress((void**)&kblo, g_kblo);

    cudaFuncSetAttribute(gemm_tc, cudaFuncAttributeMaxDynamicSharedMemorySize, GEMM_SMEM);
    cudaFuncSetAttribute(gemm_tc2, cudaFuncAttributeMaxDynamicSharedMemorySize, GEMM2_SMEM);
    cudaFuncSetAttribute(flash_attn_tc, cudaFuncAttributeMaxDynamicSharedMemorySize, FA_SMEM);

    auto launch_split = [&](const float* src, __nv_bfloat16* hi, __nv_bfloat16* lo, int n) {
        int n4 = n / 4;
        split_kernel<<<(n4 + 255) / 256, 256>>>((const float4*)src, (uint2*)hi, (uint2*)lo, n4);
    };
    launch_split(x,  xhi,  xlo,  S_LEN * HID);
    launch_split(wq, wqhi, wqlo, HID * HID);
    launch_split(wk, wkhi, wklo, NKV * HD * HID);
    {
        int n4 = (S_LEN * HID) / 4;
        split16_kernel<<<(n4 + 255) / 256, 256>>>((const float4*)x, (uint2*)xh16, (uint2*)xl16, n4);
    }
    {
        int n4 = (NKV * HD * HID) / 4;
        split16s_kernel<<<(n4 + 255) / 256, 256>>>((const float4*)wv, (uint2*)wv16, n4);
    }
    {
        int n4 = (HID * HID) / 4;
        split16s_kernel<<<(n4 + 255) / 256, 256>>>((const float4*)wo, (uint2*)wo16, n4);
    }

    // projections (C = A @ B^T)
    gemm_tc<<<dim3(HID / 128, S_LEN / 128), 256, GEMM_SMEM>>>(
        xhi, xlo, wqhi, wqlo, qraw, S_LEN, HID, HID, 0);
    gemm_tc<<<dim3((NKV * HD) / 128, S_LEN / 128), 256, GEMM_SMEM>>>(
        xhi, xlo, wkhi, wklo, kraw, S_LEN, NKV * HD, HID, 0);
    gemm_tc2<<<dim3((NKV * HD) / 128, S_LEN / 128), 256, GEMM2_SMEM>>>(
        xh16, xl16, wv16, v, S_LEN, NKV * HD, HID, 1);

    // RoPE + split, V transpose to fp16
    const float scale = 0.08838834764831845f;
    rope_split<<<dim3(S_LEN, NH), 64>>>(qraw, cs, sn, qbhi, qblo, NH, scale);
    rope_split<<<dim3(S_LEN, NKV), 64>>>(kraw, cs, sn, kbhi, kblo, NKV, 1.0f);
    vt_split16<<<dim3(S_LEN / 32, HD / 32, NKV), dim3(32, 8)>>>(v, vt16);

    // tensor-core flash attention
    flash_attn_tc<<<dim3(S_LEN / 128, NH), 256, FA_SMEM>>>(
        qbhi, qblo, kbhi, kblo, vt16, atth16, attl16);

    // output projection (fp16 2-MMA)
    gemm_tc2<<<dim3(HID / 128, S_LEN / 128), 256, GEMM2_SMEM>>>(
        atth16, attl16, wo16, out, S_LEN, HID, HID, 0);
}

// round 7
// speedup vs baseline: 3.1409x; 1.0733x over previous
#include <cuda_runtime.h>
#include <cuda_bf16.h>
#include <cuda_fp16.h>
#include <stdint.h>
#include <math.h>

#define S_LEN 2048
#define HID 4096
#define NH 32
#define NKV 8
#define HD 128

// ---------------- scratch ---------------------------------------------------
__device__ float g_qraw[S_LEN * HID];
__device__ float g_kraw[S_LEN * NKV * HD];
__device__ float g_v[NKV * S_LEN * HD];

__device__ __nv_bfloat16 g_xhi[S_LEN * HID],   g_xlo[S_LEN * HID];
__device__ __nv_bfloat16 g_wqhi[HID * HID],    g_wqlo[HID * HID];
__device__ __nv_bfloat16 g_wkhi[NKV*HD * HID], g_wklo[NKV*HD * HID];

__device__ __half g_xh16[S_LEN * HID], g_xl16[S_LEN * HID];
__device__ __half g_wv16[NKV*HD * HID];
__device__ __half g_wo16[HID * HID];
__device__ __half g_atth16[S_LEN * HID], g_attl16[S_LEN * HID];
__device__ __half g_vt16[NKV * HD * S_LEN];

__device__ __nv_bfloat16 g_qbhi[NH * S_LEN * HD],  g_qblo[NH * S_LEN * HD];
__device__ __nv_bfloat16 g_kbhi[NKV * S_LEN * HD], g_kblo[NKV * S_LEN * HD];

// ======================= helpers ===========================================
__device__ __forceinline__ uint32_t smem_u32(const void* p) {
    uint32_t a;
    asm("{ .reg .u64 t; cvta.to.shared.u64 t, %1; cvt.u32.u64 %0, t; }" : "=r"(a) : "l"(p));
    return a;
}
__device__ __forceinline__ void cp_async16(uint32_t saddr, const void* g) {
    asm volatile("cp.async.cg.shared.global [%0], [%1], 16;" :: "r"(saddr), "l"(g));
}
#define CP_COMMIT() asm volatile("cp.async.commit_group;" ::: "memory")

#define MMA_BF16(c, a, b0, b1)                                                 \
    asm volatile("mma.sync.aligned.m16n8k16.row.col.f32.bf16.bf16.f32 "        \
        "{%0,%1,%2,%3}, {%4,%5,%6,%7}, {%8,%9}, {%0,%1,%2,%3};"                \
        : "+f"((c)[0]), "+f"((c)[1]), "+f"((c)[2]), "+f"((c)[3])               \
        : "r"((a)[0]), "r"((a)[1]), "r"((a)[2]), "r"((a)[3]), "r"(b0), "r"(b1))

#define MMA_F16(c, a, b0, b1)                                                  \
    asm volatile("mma.sync.aligned.m16n8k16.row.col.f32.f16.f16.f32 "          \
        "{%0,%1,%2,%3}, {%4,%5,%6,%7}, {%8,%9}, {%0,%1,%2,%3};"                \
        : "+f"((c)[0]), "+f"((c)[1]), "+f"((c)[2]), "+f"((c)[3])               \
        : "r"((a)[0]), "r"((a)[1]), "r"((a)[2]), "r"((a)[3]), "r"(b0), "r"(b1))

__device__ __forceinline__ void ldsm_x4(uint32_t* r, uint32_t addr) {
    asm volatile("ldmatrix.sync.aligned.m8n8.x4.shared.b16 {%0,%1,%2,%3}, [%4];"
        : "=r"(r[0]), "=r"(r[1]), "=r"(r[2]), "=r"(r[3]) : "r"(addr));
}

__device__ __forceinline__ void split2h(float x, float y, uint32_t& hi, uint32_t& lo) {
    __half hx = __float2half_rn(x), hy = __float2half_rn(y);
    __half lx = __float2half_rn(x - __half2float(hx));
    __half ly = __float2half_rn(y - __half2float(hy));
    __half h2[2] = {hx, hy}, l2[2] = {lx, ly};
    hi = *(uint32_t*)h2;
    lo = *(uint32_t*)l2;
}

// ======================= split kernels =====================================
__global__ void split_kernel(const float4* __restrict__ in,
                             uint2* __restrict__ hi, uint2* __restrict__ lo, int n4) {
    int i = blockIdx.x * blockDim.x + threadIdx.x;
    if (i >= n4) return;
    float4 v = in[i];
    __nv_bfloat16 h[4], l[4];
    h[0] = __float2bfloat16_rn(v.x); l[0] = __float2bfloat16_rn(v.x - __bfloat162float(h[0]));
    h[1] = __float2bfloat16_rn(v.y); l[1] = __float2bfloat16_rn(v.y - __bfloat162float(h[1]));
    h[2] = __float2bfloat16_rn(v.z); l[2] = __float2bfloat16_rn(v.z - __bfloat162float(h[2]));
    h[3] = __float2bfloat16_rn(v.w); l[3] = __float2bfloat16_rn(v.w - __bfloat162float(h[3]));
    hi[i] = *(uint2*)h;
    lo[i] = *(uint2*)l;
}

// x -> bf16 hi/lo AND fp16 hi/lo in one pass
__global__ void split_dual_kernel(const float4* __restrict__ in,
                                  uint2* __restrict__ bhi, uint2* __restrict__ blo,
                                  uint2* __restrict__ hhi, uint2* __restrict__ hlo, int n4) {
    int i = blockIdx.x * blockDim.x + threadIdx.x;
    if (i >= n4) return;
    float4 v = in[i];
    float f[4] = {v.x, v.y, v.z, v.w};
    __nv_bfloat16 bh[4], bl[4];
    __half hh[4], hl[4];
#pragma unroll
    for (int j = 0; j < 4; j++) {
        bh[j] = __float2bfloat16_rn(f[j]);
        bl[j] = __float2bfloat16_rn(f[j] - __bfloat162float(bh[j]));
        hh[j] = __float2half_rn(f[j]);
        hl[j] = __float2half_rn(f[j] - __half2float(hh[j]));
    }
    bhi[i] = *(uint2*)bh;
    blo[i] = *(uint2*)bl;
    hhi[i] = *(uint2*)hh;
    hlo[i] = *(uint2*)hl;
}

__global__ void split16s_kernel(const float4* __restrict__ in,
                                uint2* __restrict__ hi, int n4) {
    int i = blockIdx.x * blockDim.x + threadIdx.x;
    if (i >= n4) return;
    float4 v = in[i];
    __half h[4];
    h[0] = __float2half_rn(v.x);
    h[1] = __float2half_rn(v.y);
    h[2] = __float2half_rn(v.z);
    h[3] = __float2half_rn(v.w);
    hi[i] = *(uint2*)h;
}

// ======================= common tile constants =============================
#define RSTR 112
#define TILE_B (128 * RSTR)            // 14336 (128-row tile)
#define TILE_A2 (256 * RSTR)           // 28672 (256-row tile)

// ======================= 128-tile bf16 3-MMA GEMM (K proj) =================
#define STAGE_B (4 * TILE_B)
#define GEMM_SMEM (3 * STAGE_B)        // 172032

__global__ __launch_bounds__(256, 1) void gemm_tc(
    const __nv_bfloat16* __restrict__ Ahi, const __nv_bfloat16* __restrict__ Alo,
    const __nv_bfloat16* __restrict__ Bhi, const __nv_bfloat16* __restrict__ Blo,
    float* __restrict__ C, int M, int N, int K, int mode)
{
    extern __shared__ char sm[];
    const uint32_t smb = smem_u32(sm);

    const int tid = threadIdx.x;
    const int warp = tid >> 5;
    const int lane = tid & 31;
    const int wm = warp >> 2;
    const int wn = warp & 3;
    const int g = lane >> 2;
    const int t = lane & 3;
    const int bm = blockIdx.y * 128;
    const int bn = blockIdx.x * 128;
    const int nk = K >> 5;

    const int a_r  = (lane & 7) + ((lane >> 3) & 1) * 8;
    const int a_c8 = (lane >> 4) * 8;
    const int b_r  = lane & 7;
    const int b_j  = lane >> 4;
    const int b_c8 = ((lane >> 3) & 1) * 8;

    float acc[4][4][4];
#pragma unroll
    for (int i = 0; i < 4; i++)
#pragma unroll
        for (int j = 0; j < 4; j++)
#pragma unroll
            for (int r = 0; r < 4; r++) acc[i][j][r] = 0.0f;

    auto load_stage = [&](int s, int c) {
        const uint32_t sb = smb + s * STAGE_B;
        const int k0 = c * 32;
#pragma unroll
        for (int it = 0; it < 2; it++) {
            const int id = tid + it * 256;
            const int r = id >> 2, ch = id & 3;
            const uint32_t off = r * RSTR + ch * 16;
            const size_t ga = (size_t)(bm + r) * K + k0 + ch * 8;
            const size_t gb = (size_t)(bn + r) * K + k0 + ch * 8;
            cp_async16(sb + off,              Ahi + ga);
            cp_async16(sb + TILE_B + off,     Alo + ga);
            cp_async16(sb + 2 * TILE_B + off, Bhi + gb);
            cp_async16(sb + 3 * TILE_B + off, Blo + gb);
        }
        CP_COMMIT();
    };

    load_stage(0, 0);
    if (nk > 1) load_stage(1, 1);
    if (nk > 2) load_stage(2, 2);

    for (int c = 0; c < nk; c++) {
        const int s = c % 3;
        if (c + 2 < nk)      asm volatile("cp.async.wait_group 2;" ::: "memory");
        else if (c + 1 < nk) asm volatile("cp.async.wait_group 1;" ::: "memory");
        else                 asm volatile("cp.async.wait_group 0;" ::: "memory");
        __syncthreads();

        const uint32_t uAh = smb + s * STAGE_B;
        const uint32_t uAl = uAh + TILE_B;
        const uint32_t uBh = uAh + 2 * TILE_B;
        const uint32_t uBl = uAh + 3 * TILE_B;

#pragma unroll
        for (int ks = 0; ks < 2; ks++) {
            const uint32_t colA = (ks * 16 + a_c8) * 2;
            const uint32_t colB = (ks * 16 + b_c8) * 2;
            uint32_t ah[4][4], al[4][4];
#pragma unroll
            for (int i = 0; i < 4; i++) {
                const uint32_t ro = (wm * 64 + i * 16 + a_r) * RSTR + colA;
                ldsm_x4(ah[i], uAh + ro);
                ldsm_x4(al[i], uAl + ro);
            }
#pragma unroll
            for (int p = 0; p < 2; p++) {
                const uint32_t ro = (wn * 32 + (2 * p + b_j) * 8 + b_r) * RSTR + colB;
                uint32_t bh[4], bl[4];
                ldsm_x4(bh, uBh + ro);
                ldsm_x4(bl, uBl + ro);
#pragma unroll
                for (int i = 0; i < 4; i++) {
                    MMA_BF16(acc[i][2*p],   ah[i], bh[0], bh[1]);
                    MMA_BF16(acc[i][2*p],   ah[i], bl[0], bl[1]);
                    MMA_BF16(acc[i][2*p],   al[i], bh[0], bh[1]);
                    MMA_BF16(acc[i][2*p+1], ah[i], bh[2], bh[3]);
                    MMA_BF16(acc[i][2*p+1], ah[i], bl[2], bl[3]);
                    MMA_BF16(acc[i][2*p+1], al[i], bh[2], bh[3]);
                }
            }
        }
        __syncthreads();
        if (c + 3 < nk) load_stage(s, c + 3);
    }

#pragma unroll
    for (int i = 0; i < 4; i++) {
        const int row0 = bm + wm * 64 + i * 16 + g;
#pragma unroll
        for (int j = 0; j < 4; j++) {
            const int col = bn + wn * 32 + j * 8 + 2 * t;
            float2 v0 = make_float2(acc[i][j][0], acc[i][j][1]);
            float2 v1 = make_float2(acc[i][j][2], acc[i][j][3]);
            if (mode == 0) {
                *(float2*)(C + (size_t)row0 * N + col) = v0;
                *(float2*)(C + (size_t)(row0 + 8) * N + col) = v1;
            } else {
                const int hh = col >> 7, d = col & 127;
                *(float2*)(C + ((size_t)hh * M + row0) * 128 + d) = v0;
                *(float2*)(C + ((size_t)hh * M + row0 + 8) * 128 + d) = v1;
            }
        }
    }
}

// ======================= 128-tile fp16 2-MMA GEMM (V proj) =================
#define STAGE2_B (3 * TILE_B)
#define GEMM2_SMEM (3 * STAGE2_B)      // 129024

__global__ __launch_bounds__(256, 1) void gemm_tc2(
    const __half* __restrict__ Ahi, const __half* __restrict__ Alo,
    const __half* __restrict__ B,
    float* __restrict__ C, int M, int N, int K, int mode)
{
    extern __shared__ char sm[];
    const uint32_t smb = smem_u32(sm);

    const int tid = threadIdx.x;
    const int warp = tid >> 5;
    const int lane = tid & 31;
    const int wm = warp >> 2;
    const int wn = warp & 3;
    const int g = lane >> 2;
    const int t = lane & 3;
    const int bm = blockIdx.y * 128;
    const int bn = blockIdx.x * 128;
    const int nk = K >> 5;

    const int a_r  = (lane & 7) + ((lane >> 3) & 1) * 8;
    const int a_c8 = (lane >> 4) * 8;
    const int b_r  = lane & 7;
    const int b_j  = lane >> 4;
    const int b_c8 = ((lane >> 3) & 1) * 8;

    float acc[4][4][4];
#pragma unroll
    for (int i = 0; i < 4; i++)
#pragma unroll
        for (int j = 0; j < 4; j++)
#pragma unroll
            for (int r = 0; r < 4; r++) acc[i][j][r] = 0.0f;

    auto load_stage = [&](int s, int c) {
        const uint32_t sb = smb + s * STAGE2_B;
        const int k0 = c * 32;
#pragma unroll
        for (int it = 0; it < 2; it++) {
            const int id = tid + it * 256;
            const int r = id >> 2, ch = id & 3;
            const uint32_t off = r * RSTR + ch * 16;
            const size_t ga = (size_t)(bm + r) * K + k0 + ch * 8;
            const size_t gb = (size_t)(bn + r) * K + k0 + ch * 8;
            cp_async16(sb + off,              Ahi + ga);
            cp_async16(sb + TILE_B + off,     Alo + ga);
            cp_async16(sb + 2 * TILE_B + off, B + gb);
        }
        CP_COMMIT();
    };

    load_stage(0, 0);
    if (nk > 1) load_stage(1, 1);
    if (nk > 2) load_stage(2, 2);

    for (int c = 0; c < nk; c++) {
        const int s = c % 3;
        if (c + 2 < nk)      asm volatile("cp.async.wait_group 2;" ::: "memory");
        else if (c + 1 < nk) asm volatile("cp.async.wait_group 1;" ::: "memory");
        else                 asm volatile("cp.async.wait_group 0;" ::: "memory");
        __syncthreads();

        const uint32_t uAh = smb + s * STAGE2_B;
        const uint32_t uAl = uAh + TILE_B;
        const uint32_t uB  = uAh + 2 * TILE_B;

#pragma unroll
        for (int ks = 0; ks < 2; ks++) {
            const uint32_t colA = (ks * 16 + a_c8) * 2;
            const uint32_t colB = (ks * 16 + b_c8) * 2;
            uint32_t ah[4][4], al[4][4];
#pragma unroll
            for (int i = 0; i < 4; i++) {
                const uint32_t ro = (wm * 64 + i * 16 + a_r) * RSTR + colA;
                ldsm_x4(ah[i], uAh + ro);
                ldsm_x4(al[i], uAl + ro);
            }
#pragma unroll
            for (int p = 0; p < 2; p++) {
                const uint32_t ro = (wn * 32 + (2 * p + b_j) * 8 + b_r) * RSTR + colB;
                uint32_t bh[4];
                ldsm_x4(bh, uB + ro);
#pragma unroll
                for (int i = 0; i < 4; i++) {
                    MMA_F16(acc[i][2*p],   ah[i], bh[0], bh[1]);
                    MMA_F16(acc[i][2*p],   al[i], bh[0], bh[1]);
                    MMA_F16(acc[i][2*p+1], ah[i], bh[2], bh[3]);
                    MMA_F16(acc[i][2*p+1], al[i], bh[2], bh[3]);
                }
            }
        }
        __syncthreads();
        if (c + 3 < nk) load_stage(s, c + 3);
    }

#pragma unroll
    for (int i = 0; i < 4; i++) {
        const int row0 = bm + wm * 64 + i * 16 + g;
#pragma unroll
        for (int j = 0; j < 4; j++) {
            const int col = bn + wn * 32 + j * 8 + 2 * t;
            float2 v0 = make_float2(acc[i][j][0], acc[i][j][1]);
            float2 v1 = make_float2(acc[i][j][2], acc[i][j][3]);
            if (mode == 0) {
                *(float2*)(C + (size_t)row0 * N + col) = v0;
                *(float2*)(C + (size_t)(row0 + 8) * N + col) = v1;
            } else {
                const int hh = col >> 7, d = col & 127;
                *(float2*)(C + ((size_t)hh * M + row0) * 128 + d) = v0;
                *(float2*)(C + ((size_t)hh * M + row0 + 8) * 128 + d) = v1;
            }
        }
    }
}

// ======================= 256x128 bf16 3-MMA GEMM (Q proj) ==================
// 8 warps as 4m x 2n, warp tile 64x64, 2 stages.
#define STG256 (2 * TILE_A2 + 2 * TILE_B)      // 86016
#define GEMM256_SMEM (2 * STG256)              // 172032

__global__ __launch_bounds__(256, 1) void gemm_tc256(
    const __nv_bfloat16* __restrict__ Ahi, const __nv_bfloat16* __restrict__ Alo,
    const __nv_bfloat16* __restrict__ Bhi, const __nv_bfloat16* __restrict__ Blo,
    float* __restrict__ C, int M, int N, int K)
{
    extern __shared__ char sm[];
    const uint32_t smb = smem_u32(sm);

    const int tid = threadIdx.x;
    const int warp = tid >> 5;
    const int lane = tid & 31;
    const int wm = warp >> 1;          // 0..3
    const int wn = warp & 1;           // 0..1
    const int g = lane >> 2;
    const int t = lane & 3;
    const int bm = blockIdx.y * 256;
    const int bn = blockIdx.x * 128;
    const int nk = K >> 5;

    const int a_r  = (lane & 7) + ((lane >> 3) & 1) * 8;
    const int a_c8 = (lane >> 4) * 8;
    const int b_r  = lane & 7;
    const int b_j  = lane >> 4;
    const int b_c8 = ((lane >> 3) & 1) * 8;

    float acc[4][8][4];
#pragma unroll
    for (int i = 0; i < 4; i++)
#pragma unroll
        for (int j = 0; j < 8; j++)
#pragma unroll
            for (int r = 0; r < 4; r++) acc[i][j][r] = 0.0f;

    auto load_stage = [&](int s, int c) {
        const uint32_t sb = smb + s * STG256;
        const int k0 = c * 32;
#pragma unroll
        for (int it = 0; it < 4; it++) {           // A: 256 rows
            const int id = tid + it * 256;
            const int r = id >> 2, ch = id & 3;
            const uint32_t off = r * RSTR + ch * 16;
            const size_t ga = (size_t)(bm + r) * K + k0 + ch * 8;
            cp_async16(sb + off,           Ahi + ga);
            cp_async16(sb + TILE_A2 + off, Alo + ga);
        }
#pragma unroll
        for (int it = 0; it < 2; it++) {           // B: 128 rows
            const int id = tid + it * 256;
            const int r = id >> 2, ch = id & 3;
            const uint32_t off = r * RSTR + ch * 16;
            const size_t gb = (size_t)(bn + r) * K + k0 + ch * 8;
            cp_async16(sb + 2 * TILE_A2 + off,          Bhi + gb);
            cp_async16(sb + 2 * TILE_A2 + TILE_B + off, Blo + gb);
        }
        CP_COMMIT();
    };

    load_stage(0, 0);
    if (nk > 1) load_stage(1, 1);

    for (int c = 0; c < nk; c++) {
        const int s = c & 1;
        if (c + 1 < nk) asm volatile("cp.async.wait_group 1;" ::: "memory");
        else            asm volatile("cp.async.wait_group 0;" ::: "memory");
        __syncthreads();

        const uint32_t uAh = smb + s * STG256;
        const uint32_t uAl = uAh + TILE_A2;
        const uint32_t uBh = uAh + 2 * TILE_A2;
        const uint32_t uBl = uBh + TILE_B;

#pragma unroll
        for (int ks = 0; ks < 2; ks++) {
            const uint32_t colA = (ks * 16 + a_c8) * 2;
            const uint32_t colB = (ks * 16 + b_c8) * 2;
            uint32_t ah[4][4], al[4][4];
#pragma unroll
            for (int i = 0; i < 4; i++) {
                const uint32_t ro = (wm * 64 + i * 16 + a_r) * RSTR + colA;
                ldsm_x4(ah[i], uAh + ro);
                ldsm_x4(al[i], uAl + ro);
            }
#pragma unroll
            for (int p = 0; p < 4; p++) {
                const uint32_t ro = (wn * 64 + (2 * p + b_j) * 8 + b_r) * RSTR + colB;
                uint32_t bh[4], bl[4];
                ldsm_x4(bh, uBh + ro);
                ldsm_x4(bl, uBl + ro);
#pragma unroll
                for (int i = 0; i < 4; i++) {
                    MMA_BF16(acc[i][2*p],   ah[i], bh[0], bh[1]);
                    MMA_BF16(acc[i][2*p],   ah[i], bl[0], bl[1]);
                    MMA_BF16(acc[i][2*p],   al[i], bh[0], bh[1]);
                    MMA_BF16(acc[i][2*p+1], ah[i], bh[2], bh[3]);
                    MMA_BF16(acc[i][2*p+1], ah[i], bl[2], bl[3]);
                    MMA_BF16(acc[i][2*p+1], al[i], bh[2], bh[3]);
                }
            }
        }
        __syncthreads();
        if (c + 2 < nk) load_stage(s, c + 2);
    }

#pragma unroll
    for (int i = 0; i < 4; i++) {
        const int row0 = bm + wm * 64 + i * 16 + g;
#pragma unroll
        for (int j = 0; j < 8; j++) {
            const int col = bn + wn * 64 + j * 8 + 2 * t;
            *(float2*)(C + (size_t)row0 * N + col) = make_float2(acc[i][j][0], acc[i][j][1]);
            *(float2*)(C + (size_t)(row0 + 8) * N + col) = make_float2(acc[i][j][2], acc[i][j][3]);
        }
    }
}

// ======================= 256x128 fp16 2-MMA GEMM (O proj) ==================
#define STG256H (2 * TILE_A2 + TILE_B)          // 71680
#define GEMM256H_SMEM (2 * STG256H)             // 143360

__global__ __launch_bounds__(256, 1) void gemm_tc256h(
    const __half* __restrict__ Ahi, const __half* __restrict__ Alo,
    const __half* __restrict__ B,
    float* __restrict__ C, int M, int N, int K)
{
    extern __shared__ char sm[];
    const uint32_t smb = smem_u32(sm);

    const int tid = threadIdx.x;
    const int warp = tid >> 5;
    const int lane = tid & 31;
    const int wm = warp >> 1;
    const int wn = warp & 1;
    const int g = lane >> 2;
    const int t = lane & 3;
    const int bm = blockIdx.y * 256;
    const int bn = blockIdx.x * 128;
    const int nk = K >> 5;

    const int a_r  = (lane & 7) + ((lane >> 3) & 1) * 8;
    const int a_c8 = (lane >> 4) * 8;
    const int b_r  = lane & 7;
    const int b_j  = lane >> 4;
    const int b_c8 = ((lane >> 3) & 1) * 8;

    float acc[4][8][4];
#pragma unroll
    for (int i = 0; i < 4; i++)
#pragma unroll
        for (int j = 0; j < 8; j++)
#pragma unroll
            for (int r = 0; r < 4; r++) acc[i][j][r] = 0.0f;

    auto load_stage = [&](int s, int c) {
        const uint32_t sb = smb + s * STG256H;
        const int k0 = c * 32;
#pragma unroll
        for (int it = 0; it < 4; it++) {
            const int id = tid + it * 256;
            const int r = id >> 2, ch = id & 3;
            const uint32_t off = r * RSTR + ch * 16;
            const size_t ga = (size_t)(bm + r) * K + k0 + ch * 8;
            cp_async16(sb + off,           Ahi + ga);
            cp_async16(sb + TILE_A2 + off, Alo + ga);
        }
#pragma unroll
        for (int it = 0; it < 2; it++) {
            const int id = tid + it * 256;
            const int r = id >> 2, ch = id & 3;
            const uint32_t off = r * RSTR + ch * 16;
            const size_t gb = (size_t)(bn + r) * K + k0 + ch * 8;
            cp_async16(sb + 2 * TILE_A2 + off, B + gb);
        }
        CP_COMMIT();
    };

    load_stage(0, 0);
    if (nk > 1) load_stage(1, 1);

    for (int c = 0; c < nk; c++) {
        const int s = c & 1;
        if (c + 1 < nk) asm volatile("cp.async.wait_group 1;" ::: "memory");
        else            asm volatile("cp.async.wait_group 0;" ::: "memory");
        __syncthreads();

        const uint32_t uAh = smb + s * STG256H;
        const uint32_t uAl = uAh + TILE_A2;
        const uint32_t uB  = uAh + 2 * TILE_A2;

#pragma unroll
        for (int ks = 0; ks < 2; ks++) {
            const uint32_t colA = (ks * 16 + a_c8) * 2;
            const uint32_t colB = (ks * 16 + b_c8) * 2;
            uint32_t ah[4][4], al[4][4];
#pragma unroll
            for (int i = 0; i < 4; i++) {
                const uint32_t ro = (wm * 64 + i * 16 + a_r) * RSTR + colA;
                ldsm_x4(ah[i], uAh + ro);
                ldsm_x4(al[i], uAl + ro);
            }
#pragma unroll
            for (int p = 0; p < 4; p++) {
                const uint32_t ro = (wn * 64 + (2 * p + b_j) * 8 + b_r) * RSTR + colB;
                uint32_t bh[4];
                ldsm_x4(bh, uB + ro);
#pragma unroll
                for (int i = 0; i < 4; i++) {
                    MMA_F16(acc[i][2*p],   ah[i], bh[0], bh[1]);
                    MMA_F16(acc[i][2*p],   al[i], bh[0], bh[1]);
                    MMA_F16(acc[i][2*p+1], ah[i], bh[2], bh[3]);
                    MMA_F16(acc[i][2*p+1], al[i], bh[2], bh[3]);
                }
            }
        }
        __syncthreads();
        if (c + 2 < nk) load_stage(s, c + 2);
    }

#pragma unroll
    for (int i = 0; i < 4; i++) {
        const int row0 = bm + wm * 64 + i * 16 + g;
#pragma unroll
        for (int j = 0; j < 8; j++) {
            const int col = bn + wn * 64 + j * 8 + 2 * t;
            *(float2*)(C + (size_t)row0 * N + col) = make_float2(acc[i][j][0], acc[i][j][1]);
            *(float2*)(C + (size_t)(row0 + 8) * N + col) = make_float2(acc[i][j][2], acc[i][j][3]);
        }
    }
}

// ======================= RoPE + split to bf16 hi/lo ========================
__global__ void rope_split(const float* __restrict__ raw, const float* __restrict__ cs,
                           const float* __restrict__ sn,
                           __nv_bfloat16* __restrict__ hi, __nv_bfloat16* __restrict__ lo,
                           int nh, float scale) {
    const int s = blockIdx.x;
    const int h = blockIdx.y;
    const int j = threadIdx.x;  // 0..63
    const float* r = raw + ((size_t)s * nh + h) * HD;
    const float x1 = r[j];
    const float x2 = r[j + 64];
    const float c = cs[s * 64 + j];
    const float si = sn[s * 64 + j];
    const float y1 = (x1 * c - x2 * si) * scale;
    const float y2 = (x2 * c + x1 * si) * scale;
    const size_t base = ((size_t)h * S_LEN + s) * HD;
    __nv_bfloat16 h1 = __float2bfloat16_rn(y1);
    __nv_bfloat16 h2 = __float2bfloat16_rn(y2);
    hi[base + j]      = h1;
    hi[base + j + 64] = h2;
    lo[base + j]      = __float2bfloat16_rn(y1 - __bfloat162float(h1));
    lo[base + j + 64] = __float2bfloat16_rn(y2 - __bfloat162float(h2));
}

// ======================= V transpose + fp16 ================================
__global__ void vt_split16(const float* __restrict__ v, __half* __restrict__ vt) {
    __shared__ float tile[32][33];
    const int kvh = blockIdx.z;
    const int s0 = blockIdx.x * 32;
    const int d0 = blockIdx.y * 32;
    const int tx = threadIdx.x, ty = threadIdx.y;  // 32 x 8
    for (int i = ty; i < 32; i += 8)
        tile[i][tx] = v[((size_t)kvh * S_LEN + s0 + i) * HD + d0 + tx];
    __syncthreads();
    for (int i = ty; i < 32; i += 8) {
        const float val = tile[tx][i];
        vt[((size_t)kvh * HD + d0 + i) * S_LEN + s0 + tx] = __float2half_rn(val);
    }
}

// ======================= Flash attention on tensor cores ===================
#define QSTR 272
#define VSTR 144
#define FA_QB (128 * QSTR)
#define FA_KB (64 * QSTR)
#define FA_VB (128 * VSTR)
#define FA_STAGE (2 * FA_KB + FA_VB)
#define FA_SMEM (2 * FA_QB + 2 * FA_STAGE)

__global__ __launch_bounds__(256, 1) void flash_attn_tc(
    const __nv_bfloat16* __restrict__ Qhi, const __nv_bfloat16* __restrict__ Qlo,
    const __nv_bfloat16* __restrict__ Khi, const __nv_bfloat16* __restrict__ Klo,
    const __half* __restrict__ Vt,
    __half* __restrict__ Ohi, __half* __restrict__ Olo)
{
    extern __shared__ char fsm[];
    const uint32_t smb = smem_u32(fsm);
    const int qb = gridDim.x - 1 - blockIdx.x;
    const int h  = blockIdx.y;
    const int kvh = h % NKV;
    const int q0 = qb * 128;
    const int tid = threadIdx.x;
    const int w = tid >> 5;
    const int lane = tid & 31;
    const int g = lane >> 2;
    const int t = lane & 3;

    const int a_r  = (lane & 7) + ((lane >> 3) & 1) * 8;
    const int a_c8 = (lane >> 4) * 8;
    const int b_r  = lane & 7;
    const int b_j  = lane >> 4;
    const int b_c8 = ((lane >> 3) & 1) * 8;

#pragma unroll
    for (int it = 0; it < 8; it++) {
        const int id = tid + 256 * it;
        const int r = id >> 4, ch = id & 15;
        const uint32_t off = r * QSTR + ch * 16;
        const size_t gi = ((size_t)h * S_LEN + q0 + r) * HD + ch * 8;
        cp_async16(smb + off,         Qhi + gi);
        cp_async16(smb + FA_QB + off, Qlo + gi);
    }

    auto fa_load = [&](int s, int jb) {
        const uint32_t sb = smb + 2 * FA_QB + s * FA_STAGE;
        const int k0 = jb * 64;
#pragma unroll
        for (int it = 0; it < 4; it++) {
            const int id = tid + 256 * it;
            const int r = id >> 4, ch = id & 15;
            const uint32_t off = r * QSTR + ch * 16;
            const size_t gi = ((size_t)kvh * S_LEN + k0 + r) * HD + ch * 8;
            cp_async16(sb + off,         Khi + gi);
            cp_async16(sb + FA_KB + off, Klo + gi);
        }
#pragma unroll
        for (int it = 0; it < 4; it++) {
            const int id = tid + 256 * it;
            const int r = id >> 3, ch = id & 7;
            const uint32_t off = r * VSTR + ch * 16;
            const size_t gi = ((size_t)kvh * HD + r) * S_LEN + k0 + ch * 8;
            cp_async16(sb + 2 * FA_KB + off, Vt + gi);
        }
    };

    const int njb = 2 * qb + 2;
    fa_load(0, 0);
    CP_COMMIT();
    fa_load(1, 1);
    CP_COMMIT();

    float oacc[16][4];
#pragma unroll
    for (int jd = 0; jd < 16; jd++)
#pragma unroll
        for (int r = 0; r < 4; r++) oacc[jd][r] = 0.0f;
    float m0 = -1e30f, m1 = -1e30f, l0 = 0.0f, l1 = 0.0f;

    const uint32_t uQh = smb;
    const uint32_t uQl = smb + FA_QB;

    for (int jb = 0; jb < njb; jb++) {
        const int s = jb & 1;
        if (jb + 1 < njb) asm volatile("cp.async.wait_group 1;" ::: "memory");
        else              asm volatile("cp.async.wait_group 0;" ::: "memory");
        __syncthreads();

        const uint32_t uKh = smb + 2 * FA_QB + s * FA_STAGE;
        const uint32_t uKl = uKh + FA_KB;
        const uint32_t uV  = uKh + 2 * FA_KB;

        float sv[8][4];
#pragma unroll
        for (int j = 0; j < 8; j++)
#pragma unroll
            for (int r = 0; r < 4; r++) sv[j][r] = 0.0f;

#pragma unroll
        for (int kt = 0; kt < 8; kt++) {
            const uint32_t qro = (16 * w + a_r) * QSTR + (kt * 16 + a_c8) * 2;
            uint32_t qh[4], ql[4];
            ldsm_x4(qh, uQh + qro);
            ldsm_x4(ql, uQl + qro);
#pragma unroll
            for (int p = 0; p < 4; p++) {
                const uint32_t kro = ((2 * p + b_j) * 8 + b_r) * QSTR + (kt * 16 + b_c8) * 2;
                uint32_t kh[4], kl[4];
                ldsm_x4(kh, uKh + kro);
                ldsm_x4(kl, uKl + kro);
                MMA_BF16(sv[2*p],   qh, kh[0], kh[1]);
                MMA_BF16(sv[2*p],   qh, kl[0], kl[1]);
                MMA_BF16(sv[2*p],   ql, kh[0], kh[1]);
                MMA_BF16(sv[2*p+1], qh, kh[2], kh[3]);
                MMA_BF16(sv[2*p+1], qh, kl[2], kl[3]);
                MMA_BF16(sv[2*p+1], ql, kh[2], kh[3]);
            }
        }

        if (jb >= 2 * qb) {
            const int r0g = q0 + 16 * w + g;
            const int r1g = r0g + 8;
            const int kg = jb * 64;
#pragma unroll
            for (int j = 0; j < 8; j++) {
                const int c0 = kg + 8 * j + 2 * t, c1 = c0 + 1;
                if (c0 > r0g) sv[j][0] = -1e30f;
                if (c1 > r0g) sv[j][1] = -1e30f;
                if (c0 > r1g) sv[j][2] = -1e30f;
                if (c1 > r1g) sv[j][3] = -1e30f;
            }
        }

        float mn0 = m0, mn1 = m1;
#pragma unroll
        for (int j = 0; j < 8; j++) {
            mn0 = fmaxf(mn0, fmaxf(sv[j][0], sv[j][1]));
            mn1 = fmaxf(mn1, fmaxf(sv[j][2], sv[j][3]));
        }
        mn0 = fmaxf(mn0, __shfl_xor_sync(0xffffffffu, mn0, 1));
        mn0 = fmaxf(mn0, __shfl_xor_sync(0xffffffffu, mn0, 2));
        mn1 = fmaxf(mn1, __shfl_xor_sync(0xffffffffu, mn1, 1));
        mn1 = fmaxf(mn1, __shfl_xor_sync(0xffffffffu, mn1, 2));

        const float corr0 = __expf(m0 - mn0);
        const float corr1 = __expf(m1 - mn1);
        float rs0 = 0.0f, rs1 = 0.0f;
#pragma unroll
        for (int j = 0; j < 8; j++) {
            sv[j][0] = __expf(sv[j][0] - mn0);
            sv[j][1] = __expf(sv[j][1] - mn0);
            sv[j][2] = __expf(sv[j][2] - mn1);
            sv[j][3] = __expf(sv[j][3] - mn1);
            rs0 += sv[j][0] + sv[j][1];
            rs1 += sv[j][2] + sv[j][3];
        }
        rs0 += __shfl_xor_sync(0xffffffffu, rs0, 1);
        rs0 += __shfl_xor_sync(0xffffffffu, rs0, 2);
        rs1 += __shfl_xor_sync(0xffffffffu, rs1, 1);
        rs1 += __shfl_xor_sync(0xffffffffu, rs1, 2);
        l0 = l0 * corr0 + rs0;
        l1 = l1 * corr1 + rs1;
        m0 = mn0; m1 = mn1;

#pragma unroll
        for (int jd = 0; jd < 16; jd++) {
            oacc[jd][0] *= corr0; oacc[jd][1] *= corr0;
            oacc[jd][2] *= corr1; oacc[jd][3] *= corr1;
        }

#pragma unroll
        for (int kt = 0; kt < 4; kt++) {
            uint32_t ph[4], pl[4];
            split2h(sv[2*kt][0],   sv[2*kt][1],   ph[0], pl[0]);
            split2h(sv[2*kt][2],   sv[2*kt][3],   ph[1], pl[1]);
            split2h(sv[2*kt+1][0], sv[2*kt+1][1], ph[2], pl[2]);
            split2h(sv[2*kt+1][2], sv[2*kt+1][3], ph[3], pl[3]);
#pragma unroll
            for (int p = 0; p < 8; p++) {
                const uint32_t vro = ((2 * p + b_j) * 8 + b_r) * VSTR + (kt * 16 + b_c8) * 2;
                uint32_t vh[4];
                ldsm_x4(vh, uV + vro);
                MMA_F16(oacc[2*p],   ph, vh[0], vh[1]);
                MMA_F16(oacc[2*p],   pl, vh[0], vh[1]);
                MMA_F16(oacc[2*p+1], ph, vh[2], vh[3]);
                MMA_F16(oacc[2*p+1], pl, vh[2], vh[3]);
            }
        }

        __syncthreads();
        if (jb + 2 < njb) { fa_load(s, jb + 2); CP_COMMIT(); }
    }

    const float inv0 = 1.0f / l0;
    const float inv1 = 1.0f / l1;
    const int s0 = q0 + 16 * w + g;
    const int s1 = s0 + 8;
#pragma unroll
    for (int jd = 0; jd < 16; jd++) {
        const int d = 8 * jd + 2 * t;
        uint32_t hi0, lo0, hi1, lo1;
        split2h(oacc[jd][0] * inv0, oacc[jd][1] * inv0, hi0, lo0);
        split2h(oacc[jd][2] * inv1, oacc[jd][3] * inv1, hi1, lo1);
        const size_t i0 = (size_t)s0 * HID + h * HD + d;
        const size_t i1 = (size_t)s1 * HID + h * HD + d;
        *(uint32_t*)(Ohi + i0) = hi0;
        *(uint32_t*)(Olo + i0) = lo0;
        *(uint32_t*)(Ohi + i1) = hi1;
        *(uint32_t*)(Olo + i1) = lo1;
    }
}

// ======================= launch ============================================
extern "C" void kernel_launch(void* const* d_in, const int* in_sizes, int n_in,
                              void* d_out, int out_size) {
    const float* x  = (const float*)d_in[0];
    const float* wq = (const float*)d_in[1];
    const float* wk = (const float*)d_in[2];
    const float* wv = (const float*)d_in[3];
    const float* wo = (const float*)d_in[4];
    const float* cs = (const float*)d_in[5];
    const float* sn = (const float*)d_in[6];
    float* out = (float*)d_out;

    float *qraw, *kraw, *v;
    __nv_bfloat16 *xhi, *xlo, *wqhi, *wqlo, *wkhi, *wklo;
    __nv_bfloat16 *qbhi, *qblo, *kbhi, *kblo;
    __half *xh16, *xl16, *wv16, *wo16, *atth16, *attl16, *vt16;
    cudaGetSymbolAddress((void**)&qraw, g_qraw);
    cudaGetSymbolAddress((void**)&kraw, g_kraw);
    cudaGetSymbolAddress((void**)&v, g_v);
    cudaGetSymbolAddress((void**)&xhi, g_xhi);   cudaGetSymbolAddress((void**)&xlo, g_xlo);
    cudaGetSymbolAddress((void**)&wqhi, g_wqhi); cudaGetSymbolAddress((void**)&wqlo, g_wqlo);
    cudaGetSymbolAddress((void**)&wkhi, g_wkhi); cudaGetSymbolAddress((void**)&wklo, g_wklo);
    cudaGetSymbolAddress((void**)&xh16, g_xh16); cudaGetSymbolAddress((void**)&xl16, g_xl16);
    cudaGetSymbolAddress((void**)&wv16, g_wv16); cudaGetSymbolAddress((void**)&wo16, g_wo16);
    cudaGetSymbolAddress((void**)&atth16, g_atth16); cudaGetSymbolAddress((void**)&attl16, g_attl16);
    cudaGetSymbolAddress((void**)&vt16, g_vt16);
    cudaGetSymbolAddress((void**)&qbhi, g_qbhi); cudaGetSymbolAddress((void**)&qblo, g_qblo);
    cudaGetSymbolAddress((void**)&kbhi, g_kbhi); cudaGetSymbolAddress((void**)&kblo, g_kblo);

    cudaFuncSetAttribute(gemm_tc, cudaFuncAttributeMaxDynamicSharedMemorySize, GEMM_SMEM);
    cudaFuncSetAttribute(gemm_tc2, cudaFuncAttributeMaxDynamicSharedMemorySize, GEMM2_SMEM);
    cudaFuncSetAttribute(gemm_tc256, cudaFuncAttributeMaxDynamicSharedMemorySize, GEMM256_SMEM);
    cudaFuncSetAttribute(gemm_tc256h, cudaFuncAttributeMaxDynamicSharedMemorySize, GEMM256H_SMEM);
    cudaFuncSetAttribute(flash_attn_tc, cudaFuncAttributeMaxDynamicSharedMemorySize, FA_SMEM);

    // x: bf16 + fp16 splits in one pass
    {
        int n4 = (S_LEN * HID) / 4;
        split_dual_kernel<<<(n4 + 255) / 256, 256>>>(
            (const float4*)x, (uint2*)xhi, (uint2*)xlo, (uint2*)xh16, (uint2*)xl16, n4);
    }
    {
        int n4 = (HID * HID) / 4;
        split_kernel<<<(n4 + 255) / 256, 256>>>((const float4*)wq, (uint2*)wqhi, (uint2*)wqlo, n4);
    }
    {
        int n4 = (NKV * HD * HID) / 4;
        split_kernel<<<(n4 + 255) / 256, 256>>>((const float4*)wk, (uint2*)wkhi, (uint2*)wklo, n4);
        split16s_kernel<<<(n4 + 255) / 256, 256>>>((const float4*)wv, (uint2*)wv16, n4);
    }
    {
        int n4 = (HID * HID) / 4;
        split16s_kernel<<<(n4 + 255) / 256, 256>>>((const float4*)wo, (uint2*)wo16, n4);
    }

    // projections (C = A @ B^T)
    gemm_tc256<<<dim3(HID / 128, S_LEN / 256), 256, GEMM256_SMEM>>>(
        xhi, xlo, wqhi, wqlo, qraw, S_LEN, HID, HID);
    gemm_tc<<<dim3((NKV * HD) / 128, S_LEN / 128), 256, GEMM_SMEM>>>(
        xhi, xlo, wkhi, wklo, kraw, S_LEN, NKV * HD, HID, 0);
    gemm_tc2<<<dim3((NKV * HD) / 128, S_LEN / 128), 256, GEMM2_SMEM>>>(
        xh16, xl16, wv16, v, S_LEN, NKV * HD, HID, 1);

    // RoPE + split, V transpose to fp16
    const float scale = 0.08838834764831845f;
    rope_split<<<dim3(S_LEN, NH), 64>>>(qraw, cs, sn, qbhi, qblo, NH, scale);
    rope_split<<<dim3(S_LEN, NKV), 64>>>(kraw, cs, sn, kbhi, kblo, NKV, 1.0f);
    vt_split16<<<dim3(S_LEN / 32, HD / 32, NKV), dim3(32, 8)>>>(v, vt16);

    // tensor-core flash attention
    flash_attn_tc<<<dim3(S_LEN / 128, NH), 256, FA_SMEM>>>(
        qbhi, qblo, kbhi, kblo, vt16, atth16, attl16);

    // output projection (fp16 2-MMA, 256-tile)
    gemm_tc256h<<<dim3(HID / 128, S_LEN / 256), 256, GEMM256H_SMEM>>>(
        atth16, attl16, wo16, out, S_LEN, HID, HID);
}

// round 8
// speedup vs baseline: 3.1614x; 1.0065x over previous
#include <cuda_runtime.h>
#include <cuda_bf16.h>
#include <cuda_fp16.h>
#include <stdint.h>
#include <math.h>

#define S_LEN 2048
#define HID 4096
#define NH 32
#define NKV 8
#define HD 128

// ---------------- scratch ---------------------------------------------------
__device__ float g_qraw[S_LEN * HID];
__device__ float g_kraw[S_LEN * NKV * HD];
__device__ float g_v[NKV * S_LEN * HD];

__device__ __nv_bfloat16 g_xhi[S_LEN * HID],   g_xlo[S_LEN * HID];
__device__ __nv_bfloat16 g_wqhi[HID * HID],    g_wqlo[HID * HID];
__device__ __nv_bfloat16 g_wkhi[NKV*HD * HID], g_wklo[NKV*HD * HID];

__device__ __half g_xh16[S_LEN * HID], g_xl16[S_LEN * HID];
__device__ __half g_wv16[NKV*HD * HID];
__device__ __half g_wo16[HID * HID];
__device__ __half g_atth16[S_LEN * HID], g_attl16[S_LEN * HID];
__device__ __half g_vt16[NKV * HD * S_LEN];

__device__ __half g_qh16[NH * S_LEN * HD], g_ql16[NH * S_LEN * HD];
__device__ __half g_k16[NKV * S_LEN * HD];

// ======================= helpers ===========================================
__device__ __forceinline__ uint32_t smem_u32(const void* p) {
    uint32_t a;
    asm("{ .reg .u64 t; cvta.to.shared.u64 t, %1; cvt.u32.u64 %0, t; }" : "=r"(a) : "l"(p));
    return a;
}
__device__ __forceinline__ void cp_async16(uint32_t saddr, const void* g) {
    asm volatile("cp.async.cg.shared.global [%0], [%1], 16;" :: "r"(saddr), "l"(g));
}
#define CP_COMMIT() asm volatile("cp.async.commit_group;" ::: "memory")

#define MMA_BF16(c, a, b0, b1)                                                 \
    asm volatile("mma.sync.aligned.m16n8k16.row.col.f32.bf16.bf16.f32 "        \
        "{%0,%1,%2,%3}, {%4,%5,%6,%7}, {%8,%9}, {%0,%1,%2,%3};"                \
        : "+f"((c)[0]), "+f"((c)[1]), "+f"((c)[2]), "+f"((c)[3])               \
        : "r"((a)[0]), "r"((a)[1]), "r"((a)[2]), "r"((a)[3]), "r"(b0), "r"(b1))

#define MMA_F16(c, a, b0, b1)                                                  \
    asm volatile("mma.sync.aligned.m16n8k16.row.col.f32.f16.f16.f32 "          \
        "{%0,%1,%2,%3}, {%4,%5,%6,%7}, {%8,%9}, {%0,%1,%2,%3};"                \
        : "+f"((c)[0]), "+f"((c)[1]), "+f"((c)[2]), "+f"((c)[3])               \
        : "r"((a)[0]), "r"((a)[1]), "r"((a)[2]), "r"((a)[3]), "r"(b0), "r"(b1))

__device__ __forceinline__ void ldsm_x4(uint32_t* r, uint32_t addr) {
    asm volatile("ldmatrix.sync.aligned.m8n8.x4.shared.b16 {%0,%1,%2,%3}, [%4];"
        : "=r"(r[0]), "=r"(r[1]), "=r"(r[2]), "=r"(r[3]) : "r"(addr));
}

__device__ __forceinline__ void split2h(float x, float y, uint32_t& hi, uint32_t& lo) {
    __half hx = __float2half_rn(x), hy = __float2half_rn(y);
    __half lx = __float2half_rn(x - __half2float(hx));
    __half ly = __float2half_rn(y - __half2float(hy));
    __half h2[2] = {hx, hy}, l2[2] = {lx, ly};
    hi = *(uint32_t*)h2;
    lo = *(uint32_t*)l2;
}

// ======================= split kernels =====================================
__global__ void split_kernel(const float4* __restrict__ in,
                             uint2* __restrict__ hi, uint2* __restrict__ lo, int n4) {
    int i = blockIdx.x * blockDim.x + threadIdx.x;
    if (i >= n4) return;
    float4 v = in[i];
    __nv_bfloat16 h[4], l[4];
    h[0] = __float2bfloat16_rn(v.x); l[0] = __float2bfloat16_rn(v.x - __bfloat162float(h[0]));
    h[1] = __float2bfloat16_rn(v.y); l[1] = __float2bfloat16_rn(v.y - __bfloat162float(h[1]));
    h[2] = __float2bfloat16_rn(v.z); l[2] = __float2bfloat16_rn(v.z - __bfloat162float(h[2]));
    h[3] = __float2bfloat16_rn(v.w); l[3] = __float2bfloat16_rn(v.w - __bfloat162float(h[3]));
    hi[i] = *(uint2*)h;
    lo[i] = *(uint2*)l;
}

// x -> bf16 hi/lo AND fp16 hi/lo in one pass
__global__ void split_dual_kernel(const float4* __restrict__ in,
                                  uint2* __restrict__ bhi, uint2* __restrict__ blo,
                                  uint2* __restrict__ hhi, uint2* __restrict__ hlo, int n4) {
    int i = blockIdx.x * blockDim.x + threadIdx.x;
    if (i >= n4) return;
    float4 v = in[i];
    float f[4] = {v.x, v.y, v.z, v.w};
    __nv_bfloat16 bh[4], bl[4];
    __half hh[4], hl[4];
#pragma unroll
    for (int j = 0; j < 4; j++) {
        bh[j] = __float2bfloat16_rn(f[j]);
        bl[j] = __float2bfloat16_rn(f[j] - __bfloat162float(bh[j]));
        hh[j] = __float2half_rn(f[j]);
        hl[j] = __float2half_rn(f[j] - __half2float(hh[j]));
    }
    bhi[i] = *(uint2*)bh;
    blo[i] = *(uint2*)bl;
    hhi[i] = *(uint2*)hh;
    hlo[i] = *(uint2*)hl;
}

__global__ void split16s_kernel(const float4* __restrict__ in,
                                uint2* __restrict__ hi, int n4) {
    int i = blockIdx.x * blockDim.x + threadIdx.x;
    if (i >= n4) return;
    float4 v = in[i];
    __half h[4];
    h[0] = __float2half_rn(v.x);
    h[1] = __float2half_rn(v.y);
    h[2] = __float2half_rn(v.z);
    h[3] = __float2half_rn(v.w);
    hi[i] = *(uint2*)h;
}

// ======================= common tile constants =============================
#define RSTR 112
#define TILE_B (128 * RSTR)            // 14336 (128-row tile)
#define TILE_A2 (256 * RSTR)           // 28672 (256-row tile)
#define STAGE_B (4 * TILE_B)
#define GEMM_SMEM (3 * STAGE_B)        // 172032
#define STAGE2_B (3 * TILE_B)

// ======================= fused K(bf16-3MMA)+V(fp16-2MMA) projections =======
// grid (16, 16): bx<8 -> K tile, bx>=8 -> V tile. M=2048, N=1024, K=4096.
__global__ __launch_bounds__(256, 1) void gemm_kv(
    const __nv_bfloat16* __restrict__ Xbh, const __nv_bfloat16* __restrict__ Xbl,
    const __nv_bfloat16* __restrict__ Wkh, const __nv_bfloat16* __restrict__ Wkl,
    float* __restrict__ Ck,
    const __half* __restrict__ Xhh, const __half* __restrict__ Xhl,
    const __half* __restrict__ Wv, float* __restrict__ Cv)
{
    extern __shared__ char sm[];
    const uint32_t smb = smem_u32(sm);

    const int tid = threadIdx.x;
    const int warp = tid >> 5;
    const int lane = tid & 31;
    const int wm = warp >> 2;
    const int wn = warp & 3;
    const int g = lane >> 2;
    const int t = lane & 3;
    const int bm = blockIdx.y * 128;
    const int K = HID, M = S_LEN, N = NKV * HD;
    const int nk = K >> 5;

    const int a_r  = (lane & 7) + ((lane >> 3) & 1) * 8;
    const int a_c8 = (lane >> 4) * 8;
    const int b_r  = lane & 7;
    const int b_j  = lane >> 4;
    const int b_c8 = ((lane >> 3) & 1) * 8;

    float acc[4][4][4];
#pragma unroll
    for (int i = 0; i < 4; i++)
#pragma unroll
        for (int j = 0; j < 4; j++)
#pragma unroll
            for (int r = 0; r < 4; r++) acc[i][j][r] = 0.0f;

    if (blockIdx.x < 8) {
        // ---------------- K path: bf16 3-MMA ----------------
        const int bn = blockIdx.x * 128;
        auto load_stage = [&](int s, int c) {
            const uint32_t sb = smb + s * STAGE_B;
            const int k0 = c * 32;
#pragma unroll
            for (int it = 0; it < 2; it++) {
                const int id = tid + it * 256;
                const int r = id >> 2, ch = id & 3;
                const uint32_t off = r * RSTR + ch * 16;
                const size_t ga = (size_t)(bm + r) * K + k0 + ch * 8;
                const size_t gb = (size_t)(bn + r) * K + k0 + ch * 8;
                cp_async16(sb + off,              Xbh + ga);
                cp_async16(sb + TILE_B + off,     Xbl + ga);
                cp_async16(sb + 2 * TILE_B + off, Wkh + gb);
                cp_async16(sb + 3 * TILE_B + off, Wkl + gb);
            }
            CP_COMMIT();
        };
        load_stage(0, 0);
        load_stage(1, 1);
        load_stage(2, 2);
        for (int c = 0; c < nk; c++) {
            const int s = c % 3;
            if (c + 2 < nk)      asm volatile("cp.async.wait_group 2;" ::: "memory");
            else if (c + 1 < nk) asm volatile("cp.async.wait_group 1;" ::: "memory");
            else                 asm volatile("cp.async.wait_group 0;" ::: "memory");
            __syncthreads();
            const uint32_t uAh = smb + s * STAGE_B;
            const uint32_t uAl = uAh + TILE_B;
            const uint32_t uBh = uAh + 2 * TILE_B;
            const uint32_t uBl = uAh + 3 * TILE_B;
#pragma unroll
            for (int ks = 0; ks < 2; ks++) {
                const uint32_t colA = (ks * 16 + a_c8) * 2;
                const uint32_t colB = (ks * 16 + b_c8) * 2;
                uint32_t ah[4][4], al[4][4];
#pragma unroll
                for (int i = 0; i < 4; i++) {
                    const uint32_t ro = (wm * 64 + i * 16 + a_r) * RSTR + colA;
                    ldsm_x4(ah[i], uAh + ro);
                    ldsm_x4(al[i], uAl + ro);
                }
#pragma unroll
                for (int p = 0; p < 2; p++) {
                    const uint32_t ro = (wn * 32 + (2 * p + b_j) * 8 + b_r) * RSTR + colB;
                    uint32_t bh[4], bl[4];
                    ldsm_x4(bh, uBh + ro);
                    ldsm_x4(bl, uBl + ro);
#pragma unroll
                    for (int i = 0; i < 4; i++) {
                        MMA_BF16(acc[i][2*p],   ah[i], bh[0], bh[1]);
                        MMA_BF16(acc[i][2*p],   ah[i], bl[0], bl[1]);
                        MMA_BF16(acc[i][2*p],   al[i], bh[0], bh[1]);
                        MMA_BF16(acc[i][2*p+1], ah[i], bh[2], bh[3]);
                        MMA_BF16(acc[i][2*p+1], ah[i], bl[2], bl[3]);
                        MMA_BF16(acc[i][2*p+1], al[i], bh[2], bh[3]);
                    }
                }
            }
            __syncthreads();
            if (c + 3 < nk) load_stage(s, c + 3);
        }
#pragma unroll
        for (int i = 0; i < 4; i++) {
            const int row0 = bm + wm * 64 + i * 16 + g;
#pragma unroll
            for (int j = 0; j < 4; j++) {
                const int col = bn + wn * 32 + j * 8 + 2 * t;
                *(float2*)(Ck + (size_t)row0 * N + col) = make_float2(acc[i][j][0], acc[i][j][1]);
                *(float2*)(Ck + (size_t)(row0 + 8) * N + col) = make_float2(acc[i][j][2], acc[i][j][3]);
            }
        }
    } else {
        // ---------------- V path: fp16 2-MMA, head-major store --------------
        const int bn = (blockIdx.x - 8) * 128;
        auto load_stage = [&](int s, int c) {
            const uint32_t sb = smb + s * STAGE2_B;
            const int k0 = c * 32;
#pragma unroll
            for (int it = 0; it < 2; it++) {
                const int id = tid + it * 256;
                const int r = id >> 2, ch = id & 3;
                const uint32_t off = r * RSTR + ch * 16;
                const size_t ga = (size_t)(bm + r) * K + k0 + ch * 8;
                const size_t gb = (size_t)(bn + r) * K + k0 + ch * 8;
                cp_async16(sb + off,              Xhh + ga);
                cp_async16(sb + TILE_B + off,     Xhl + ga);
                cp_async16(sb + 2 * TILE_B + off, Wv + gb);
            }
            CP_COMMIT();
        };
        load_stage(0, 0);
        load_stage(1, 1);
        load_stage(2, 2);
        for (int c = 0; c < nk; c++) {
            const int s = c % 3;
            if (c + 2 < nk)      asm volatile("cp.async.wait_group 2;" ::: "memory");
            else if (c + 1 < nk) asm volatile("cp.async.wait_group 1;" ::: "memory");
            else                 asm volatile("cp.async.wait_group 0;" ::: "memory");
            __syncthreads();
            const uint32_t uAh = smb + s * STAGE2_B;
            const uint32_t uAl = uAh + TILE_B;
            const uint32_t uB  = uAh + 2 * TILE_B;
#pragma unroll
            for (int ks = 0; ks < 2; ks++) {
                const uint32_t colA = (ks * 16 + a_c8) * 2;
                const uint32_t colB = (ks * 16 + b_c8) * 2;
                uint32_t ah[4][4], al[4][4];
#pragma unroll
                for (int i = 0; i < 4; i++) {
                    const uint32_t ro = (wm * 64 + i * 16 + a_r) * RSTR + colA;
                    ldsm_x4(ah[i], uAh + ro);
                    ldsm_x4(al[i], uAl + ro);
                }
#pragma unroll
                for (int p = 0; p < 2; p++) {
                    const uint32_t ro = (wn * 32 + (2 * p + b_j) * 8 + b_r) * RSTR + colB;
                    uint32_t bh[4];
                    ldsm_x4(bh, uB + ro);
#pragma unroll
                    for (int i = 0; i < 4; i++) {
                        MMA_F16(acc[i][2*p],   ah[i], bh[0], bh[1]);
                        MMA_F16(acc[i][2*p],   al[i], bh[0], bh[1]);
                        MMA_F16(acc[i][2*p+1], ah[i], bh[2], bh[3]);
                        MMA_F16(acc[i][2*p+1], al[i], bh[2], bh[3]);
                    }
                }
            }
            __syncthreads();
            if (c + 3 < nk) load_stage(s, c + 3);
        }
#pragma unroll
        for (int i = 0; i < 4; i++) {
            const int row0 = bm + wm * 64 + i * 16 + g;
#pragma unroll
            for (int j = 0; j < 4; j++) {
                const int col = bn + wn * 32 + j * 8 + 2 * t;
                const int hh = col >> 7, d = col & 127;
                *(float2*)(Cv + ((size_t)hh * M + row0) * 128 + d) =
                    make_float2(acc[i][j][0], acc[i][j][1]);
                *(float2*)(Cv + ((size_t)hh * M + row0 + 8) * 128 + d) =
                    make_float2(acc[i][j][2], acc[i][j][3]);
            }
        }
    }
}

// ======================= 256x128 bf16 3-MMA GEMM (Q proj) ==================
#define STG256 (2 * TILE_A2 + 2 * TILE_B)      // 86016
#define GEMM256_SMEM (2 * STG256)              // 172032

__global__ __launch_bounds__(256, 1) void gemm_tc256(
    const __nv_bfloat16* __restrict__ Ahi, const __nv_bfloat16* __restrict__ Alo,
    const __nv_bfloat16* __restrict__ Bhi, const __nv_bfloat16* __restrict__ Blo,
    float* __restrict__ C, int M, int N, int K)
{
    extern __shared__ char sm[];
    const uint32_t smb = smem_u32(sm);

    const int tid = threadIdx.x;
    const int warp = tid >> 5;
    const int lane = tid & 31;
    const int wm = warp >> 1;
    const int wn = warp & 1;
    const int g = lane >> 2;
    const int t = lane & 3;
    const int bm = blockIdx.y * 256;
    const int bn = blockIdx.x * 128;
    const int nk = K >> 5;

    const int a_r  = (lane & 7) + ((lane >> 3) & 1) * 8;
    const int a_c8 = (lane >> 4) * 8;
    const int b_r  = lane & 7;
    const int b_j  = lane >> 4;
    const int b_c8 = ((lane >> 3) & 1) * 8;

    float acc[4][8][4];
#pragma unroll
    for (int i = 0; i < 4; i++)
#pragma unroll
        for (int j = 0; j < 8; j++)
#pragma unroll
            for (int r = 0; r < 4; r++) acc[i][j][r] = 0.0f;

    auto load_stage = [&](int s, int c) {
        const uint32_t sb = smb + s * STG256;
        const int k0 = c * 32;
#pragma unroll
        for (int it = 0; it < 4; it++) {
            const int id = tid + it * 256;
            const int r = id >> 2, ch = id & 3;
            const uint32_t off = r * RSTR + ch * 16;
            const size_t ga = (size_t)(bm + r) * K + k0 + ch * 8;
            cp_async16(sb + off,           Ahi + ga);
            cp_async16(sb + TILE_A2 + off, Alo + ga);
        }
#pragma unroll
        for (int it = 0; it < 2; it++) {
            const int id = tid + it * 256;
            const int r = id >> 2, ch = id & 3;
            const uint32_t off = r * RSTR + ch * 16;
            const size_t gb = (size_t)(bn + r) * K + k0 + ch * 8;
            cp_async16(sb + 2 * TILE_A2 + off,          Bhi + gb);
            cp_async16(sb + 2 * TILE_A2 + TILE_B + off, Blo + gb);
        }
        CP_COMMIT();
    };

    load_stage(0, 0);
    if (nk > 1) load_stage(1, 1);

    for (int c = 0; c < nk; c++) {
        const int s = c & 1;
        if (c + 1 < nk) asm volatile("cp.async.wait_group 1;" ::: "memory");
        else            asm volatile("cp.async.wait_group 0;" ::: "memory");
        __syncthreads();

        const uint32_t uAh = smb + s * STG256;
        const uint32_t uAl = uAh + TILE_A2;
        const uint32_t uBh = uAh + 2 * TILE_A2;
        const uint32_t uBl = uBh + TILE_B;

#pragma unroll
        for (int ks = 0; ks < 2; ks++) {
            const uint32_t colA = (ks * 16 + a_c8) * 2;
            const uint32_t colB = (ks * 16 + b_c8) * 2;
            uint32_t ah[4][4], al[4][4];
#pragma unroll
            for (int i = 0; i < 4; i++) {
                const uint32_t ro = (wm * 64 + i * 16 + a_r) * RSTR + colA;
                ldsm_x4(ah[i], uAh + ro);
                ldsm_x4(al[i], uAl + ro);
            }
#pragma unroll
            for (int p = 0; p < 4; p++) {
                const uint32_t ro = (wn * 64 + (2 * p + b_j) * 8 + b_r) * RSTR + colB;
                uint32_t bh[4], bl[4];
                ldsm_x4(bh, uBh + ro);
                ldsm_x4(bl, uBl + ro);
#pragma unroll
                for (int i = 0; i < 4; i++) {
                    MMA_BF16(acc[i][2*p],   ah[i], bh[0], bh[1]);
                    MMA_BF16(acc[i][2*p],   ah[i], bl[0], bl[1]);
                    MMA_BF16(acc[i][2*p],   al[i], bh[0], bh[1]);
                    MMA_BF16(acc[i][2*p+1], ah[i], bh[2], bh[3]);
                    MMA_BF16(acc[i][2*p+1], ah[i], bl[2], bl[3]);
                    MMA_BF16(acc[i][2*p+1], al[i], bh[2], bh[3]);
                }
            }
        }
        __syncthreads();
        if (c + 2 < nk) load_stage(s, c + 2);
    }

#pragma unroll
    for (int i = 0; i < 4; i++) {
        const int row0 = bm + wm * 64 + i * 16 + g;
#pragma unroll
        for (int j = 0; j < 8; j++) {
            const int col = bn + wn * 64 + j * 8 + 2 * t;
            *(float2*)(C + (size_t)row0 * N + col) = make_float2(acc[i][j][0], acc[i][j][1]);
            *(float2*)(C + (size_t)(row0 + 8) * N + col) = make_float2(acc[i][j][2], acc[i][j][3]);
        }
    }
}

// ======================= 256x128 fp16 2-MMA GEMM (O proj) ==================
#define STG256H (2 * TILE_A2 + TILE_B)          // 71680
#define GEMM256H_SMEM (2 * STG256H)             // 143360

__global__ __launch_bounds__(256, 1) void gemm_tc256h(
    const __half* __restrict__ Ahi, const __half* __restrict__ Alo,
    const __half* __restrict__ B,
    float* __restrict__ C, int M, int N, int K)
{
    extern __shared__ char sm[];
    const uint32_t smb = smem_u32(sm);

    const int tid = threadIdx.x;
    const int warp = tid >> 5;
    const int lane = tid & 31;
    const int wm = warp >> 1;
    const int wn = warp & 1;
    const int g = lane >> 2;
    const int t = lane & 3;
    const int bm = blockIdx.y * 256;
    const int bn = blockIdx.x * 128;
    const int nk = K >> 5;

    const int a_r  = (lane & 7) + ((lane >> 3) & 1) * 8;
    const int a_c8 = (lane >> 4) * 8;
    const int b_r  = lane & 7;
    const int b_j  = lane >> 4;
    const int b_c8 = ((lane >> 3) & 1) * 8;

    float acc[4][8][4];
#pragma unroll
    for (int i = 0; i < 4; i++)
#pragma unroll
        for (int j = 0; j < 8; j++)
#pragma unroll
            for (int r = 0; r < 4; r++) acc[i][j][r] = 0.0f;

    auto load_stage = [&](int s, int c) {
        const uint32_t sb = smb + s * STG256H;
        const int k0 = c * 32;
#pragma unroll
        for (int it = 0; it < 4; it++) {
            const int id = tid + it * 256;
            const int r = id >> 2, ch = id & 3;
            const uint32_t off = r * RSTR + ch * 16;
            const size_t ga = (size_t)(bm + r) * K + k0 + ch * 8;
            cp_async16(sb + off,           Ahi + ga);
            cp_async16(sb + TILE_A2 + off, Alo + ga);
        }
#pragma unroll
        for (int it = 0; it < 2; it++) {
            const int id = tid + it * 256;
            const int r = id >> 2, ch = id & 3;
            const uint32_t off = r * RSTR + ch * 16;
            const size_t gb = (size_t)(bn + r) * K + k0 + ch * 8;
            cp_async16(sb + 2 * TILE_A2 + off, B + gb);
        }
        CP_COMMIT();
    };

    load_stage(0, 0);
    if (nk > 1) load_stage(1, 1);

    for (int c = 0; c < nk; c++) {
        const int s = c & 1;
        if (c + 1 < nk) asm volatile("cp.async.wait_group 1;" ::: "memory");
        else            asm volatile("cp.async.wait_group 0;" ::: "memory");
        __syncthreads();

        const uint32_t uAh = smb + s * STG256H;
        const uint32_t uAl = uAh + TILE_A2;
        const uint32_t uB  = uAh + 2 * TILE_A2;

#pragma unroll
        for (int ks = 0; ks < 2; ks++) {
            const uint32_t colA = (ks * 16 + a_c8) * 2;
            const uint32_t colB = (ks * 16 + b_c8) * 2;
            uint32_t ah[4][4], al[4][4];
#pragma unroll
            for (int i = 0; i < 4; i++) {
                const uint32_t ro = (wm * 64 + i * 16 + a_r) * RSTR + colA;
                ldsm_x4(ah[i], uAh + ro);
                ldsm_x4(al[i], uAl + ro);
            }
#pragma unroll
            for (int p = 0; p < 4; p++) {
                const uint32_t ro = (wn * 64 + (2 * p + b_j) * 8 + b_r) * RSTR + colB;
                uint32_t bh[4];
                ldsm_x4(bh, uB + ro);
#pragma unroll
                for (int i = 0; i < 4; i++) {
                    MMA_F16(acc[i][2*p],   ah[i], bh[0], bh[1]);
                    MMA_F16(acc[i][2*p],   al[i], bh[0], bh[1]);
                    MMA_F16(acc[i][2*p+1], ah[i], bh[2], bh[3]);
                    MMA_F16(acc[i][2*p+1], al[i], bh[2], bh[3]);
                }
            }
        }
        __syncthreads();
        if (c + 2 < nk) load_stage(s, c + 2);
    }

#pragma unroll
    for (int i = 0; i < 4; i++) {
        const int row0 = bm + wm * 64 + i * 16 + g;
#pragma unroll
        for (int j = 0; j < 8; j++) {
            const int col = bn + wn * 64 + j * 8 + 2 * t;
            *(float2*)(C + (size_t)row0 * N + col) = make_float2(acc[i][j][0], acc[i][j][1]);
            *(float2*)(C + (size_t)(row0 + 8) * N + col) = make_float2(acc[i][j][2], acc[i][j][3]);
        }
    }
}

// ======================= RoPE kernels ======================================
// Q: raw[s][h*HD+d] -> fp16 hi/lo [h][s][d], scale folded.
__global__ void rope_split_q16(const float* __restrict__ raw, const float* __restrict__ cs,
                               const float* __restrict__ sn,
                               __half* __restrict__ hi, __half* __restrict__ lo,
                               int nh, float scale) {
    const int s = blockIdx.x;
    const int h = blockIdx.y;
    const int j = threadIdx.x;  // 0..63
    const float* r = raw + ((size_t)s * nh + h) * HD;
    const float x1 = r[j];
    const float x2 = r[j + 64];
    const float c = cs[s * 64 + j];
    const float si = sn[s * 64 + j];
    const float y1 = (x1 * c - x2 * si) * scale;
    const float y2 = (x2 * c + x1 * si) * scale;
    const size_t base = ((size_t)h * S_LEN + s) * HD;
    __half h1 = __float2half_rn(y1);
    __half h2 = __float2half_rn(y2);
    hi[base + j]      = h1;
    hi[base + j + 64] = h2;
    lo[base + j]      = __float2half_rn(y1 - __half2float(h1));
    lo[base + j + 64] = __float2half_rn(y2 - __half2float(h2));
}

// K: raw[s][h*HD+d] -> single fp16 [h][s][d]
__global__ void rope_k16(const float* __restrict__ raw, const float* __restrict__ cs,
                         const float* __restrict__ sn, __half* __restrict__ out, int nh) {
    const int s = blockIdx.x;
    const int h = blockIdx.y;
    const int j = threadIdx.x;  // 0..63
    const float* r = raw + ((size_t)s * nh + h) * HD;
    const float x1 = r[j];
    const float x2 = r[j + 64];
    const float c = cs[s * 64 + j];
    const float si = sn[s * 64 + j];
    const size_t base = ((size_t)h * S_LEN + s) * HD;
    out[base + j]      = __float2half_rn(x1 * c - x2 * si);
    out[base + j + 64] = __float2half_rn(x2 * c + x1 * si);
}

// ======================= V transpose + fp16 ================================
__global__ void vt_split16(const float* __restrict__ v, __half* __restrict__ vt) {
    __shared__ float tile[32][33];
    const int kvh = blockIdx.z;
    const int s0 = blockIdx.x * 32;
    const int d0 = blockIdx.y * 32;
    const int tx = threadIdx.x, ty = threadIdx.y;  // 32 x 8
    for (int i = ty; i < 32; i += 8)
        tile[i][tx] = v[((size_t)kvh * S_LEN + s0 + i) * HD + d0 + tx];
    __syncthreads();
    for (int i = ty; i < 32; i += 8) {
        const float val = tile[tx][i];
        vt[((size_t)kvh * HD + d0 + i) * S_LEN + s0 + tx] = __float2half_rn(val);
    }
}

// ======================= Flash attention on tensor cores ===================
// QK^T: fp16 2-MMA (Q hi/lo fp16, K single fp16). P·V: fp16 2-MMA.
#define QSTR 272
#define VSTR 144
#define FA_QB (128 * QSTR)                 // 34816
#define FA_KB (64 * QSTR)                  // 17408
#define FA_VB (128 * VSTR)                 // 18432
#define FA_STAGE (FA_KB + FA_VB)           // 35840
#define FA_SMEM (2 * FA_QB + 2 * FA_STAGE) // 141312

__global__ __launch_bounds__(256, 1) void flash_attn_tc(
    const __half* __restrict__ Qhi, const __half* __restrict__ Qlo,
    const __half* __restrict__ Kf, const __half* __restrict__ Vt,
    __half* __restrict__ Ohi, __half* __restrict__ Olo)
{
    extern __shared__ char fsm[];
    const uint32_t smb = smem_u32(fsm);
    const int qb = gridDim.x - 1 - blockIdx.x;
    const int h  = blockIdx.y;
    const int kvh = h % NKV;
    const int q0 = qb * 128;
    const int tid = threadIdx.x;
    const int w = tid >> 5;
    const int lane = tid & 31;
    const int g = lane >> 2;
    const int t = lane & 3;

    const int a_r  = (lane & 7) + ((lane >> 3) & 1) * 8;
    const int a_c8 = (lane >> 4) * 8;
    const int b_r  = lane & 7;
    const int b_j  = lane >> 4;
    const int b_c8 = ((lane >> 3) & 1) * 8;

#pragma unroll
    for (int it = 0; it < 8; it++) {
        const int id = tid + 256 * it;
        const int r = id >> 4, ch = id & 15;
        const uint32_t off = r * QSTR + ch * 16;
        const size_t gi = ((size_t)h * S_LEN + q0 + r) * HD + ch * 8;
        cp_async16(smb + off,         Qhi + gi);
        cp_async16(smb + FA_QB + off, Qlo + gi);
    }

    auto fa_load = [&](int s, int jb) {
        const uint32_t sb = smb + 2 * FA_QB + s * FA_STAGE;
        const int k0 = jb * 64;
#pragma unroll
        for (int it = 0; it < 4; it++) {
            const int id = tid + 256 * it;
            const int r = id >> 4, ch = id & 15;
            const uint32_t off = r * QSTR + ch * 16;
            const size_t gi = ((size_t)kvh * S_LEN + k0 + r) * HD + ch * 8;
            cp_async16(sb + off, Kf + gi);
        }
#pragma unroll
        for (int it = 0; it < 4; it++) {
            const int id = tid + 256 * it;
            const int r = id >> 3, ch = id & 7;
            const uint32_t off = r * VSTR + ch * 16;
            const size_t gi = ((size_t)kvh * HD + r) * S_LEN + k0 + ch * 8;
            cp_async16(sb + FA_KB + off, Vt + gi);
        }
    };

    const int njb = 2 * qb + 2;
    fa_load(0, 0);
    CP_COMMIT();
    fa_load(1, 1);
    CP_COMMIT();

    float oacc[16][4];
#pragma unroll
    for (int jd = 0; jd < 16; jd++)
#pragma unroll
        for (int r = 0; r < 4; r++) oacc[jd][r] = 0.0f;
    float m0 = -1e30f, m1 = -1e30f, l0 = 0.0f, l1 = 0.0f;

    const uint32_t uQh = smb;
    const uint32_t uQl = smb + FA_QB;

    for (int jb = 0; jb < njb; jb++) {
        const int s = jb & 1;
        if (jb + 1 < njb) asm volatile("cp.async.wait_group 1;" ::: "memory");
        else              asm volatile("cp.async.wait_group 0;" ::: "memory");
        __syncthreads();

        const uint32_t uK = smb + 2 * FA_QB + s * FA_STAGE;
        const uint32_t uV = uK + FA_KB;

        // ---- S = Q @ K^T (fp16 2-MMA) ----
        float sv[8][4];
#pragma unroll
        for (int j = 0; j < 8; j++)
#pragma unroll
            for (int r = 0; r < 4; r++) sv[j][r] = 0.0f;

#pragma unroll
        for (int kt = 0; kt < 8; kt++) {
            const uint32_t qro = (16 * w + a_r) * QSTR + (kt * 16 + a_c8) * 2;
            uint32_t qh[4], ql[4];
            ldsm_x4(qh, uQh + qro);
            ldsm_x4(ql, uQl + qro);
#pragma unroll
            for (int p = 0; p < 4; p++) {
                const uint32_t kro = ((2 * p + b_j) * 8 + b_r) * QSTR + (kt * 16 + b_c8) * 2;
                uint32_t kh[4];
                ldsm_x4(kh, uK + kro);
                MMA_F16(sv[2*p],   qh, kh[0], kh[1]);
                MMA_F16(sv[2*p],   ql, kh[0], kh[1]);
                MMA_F16(sv[2*p+1], qh, kh[2], kh[3]);
                MMA_F16(sv[2*p+1], ql, kh[2], kh[3]);
            }
        }

        if (jb >= 2 * qb) {
            const int r0g = q0 + 16 * w + g;
            const int r1g = r0g + 8;
            const int kg = jb * 64;
#pragma unroll
            for (int j = 0; j < 8; j++) {
                const int c0 = kg + 8 * j + 2 * t, c1 = c0 + 1;
                if (c0 > r0g) sv[j][0] = -1e30f;
                if (c1 > r0g) sv[j][1] = -1e30f;
                if (c0 > r1g) sv[j][2] = -1e30f;
                if (c1 > r1g) sv[j][3] = -1e30f;
            }
        }

        float mn0 = m0, mn1 = m1;
#pragma unroll
        for (int j = 0; j < 8; j++) {
            mn0 = fmaxf(mn0, fmaxf(sv[j][0], sv[j][1]));
            mn1 = fmaxf(mn1, fmaxf(sv[j][2], sv[j][3]));
        }
        mn0 = fmaxf(mn0, __shfl_xor_sync(0xffffffffu, mn0, 1));
        mn0 = fmaxf(mn0, __shfl_xor_sync(0xffffffffu, mn0, 2));
        mn1 = fmaxf(mn1, __shfl_xor_sync(0xffffffffu, mn1, 1));
        mn1 = fmaxf(mn1, __shfl_xor_sync(0xffffffffu, mn1, 2));

        const float corr0 = __expf(m0 - mn0);
        const float corr1 = __expf(m1 - mn1);
        float rs0 = 0.0f, rs1 = 0.0f;
#pragma unroll
        for (int j = 0; j < 8; j++) {
            sv[j][0] = __expf(sv[j][0] - mn0);
            sv[j][1] = __expf(sv[j][1] - mn0);
            sv[j][2] = __expf(sv[j][2] - mn1);
            sv[j][3] = __expf(sv[j][3] - mn1);
            rs0 += sv[j][0] + sv[j][1];
            rs1 += sv[j][2] + sv[j][3];
        }
        rs0 += __shfl_xor_sync(0xffffffffu, rs0, 1);
        rs0 += __shfl_xor_sync(0xffffffffu, rs0, 2);
        rs1 += __shfl_xor_sync(0xffffffffu, rs1, 1);
        rs1 += __shfl_xor_sync(0xffffffffu, rs1, 2);
        l0 = l0 * corr0 + rs0;
        l1 = l1 * corr1 + rs1;
        m0 = mn0; m1 = mn1;

#pragma unroll
        for (int jd = 0; jd < 16; jd++) {
            oacc[jd][0] *= corr0; oacc[jd][1] *= corr0;
            oacc[jd][2] *= corr1; oacc[jd][3] *= corr1;
        }

        // ---- O += P @ V (fp16 2-MMA) ----
#pragma unroll
        for (int kt = 0; kt < 4; kt++) {
            uint32_t ph[4], pl[4];
            split2h(sv[2*kt][0],   sv[2*kt][1],   ph[0], pl[0]);
            split2h(sv[2*kt][2],   sv[2*kt][3],   ph[1], pl[1]);
            split2h(sv[2*kt+1][0], sv[2*kt+1][1], ph[2], pl[2]);
            split2h(sv[2*kt+1][2], sv[2*kt+1][3], ph[3], pl[3]);
#pragma unroll
            for (int p = 0; p < 8; p++) {
                const uint32_t vro = ((2 * p + b_j) * 8 + b_r) * VSTR + (kt * 16 + b_c8) * 2;
                uint32_t vh[4];
                ldsm_x4(vh, uV + vro);
                MMA_F16(oacc[2*p],   ph, vh[0], vh[1]);
                MMA_F16(oacc[2*p],   pl, vh[0], vh[1]);
                MMA_F16(oacc[2*p+1], ph, vh[2], vh[3]);
                MMA_F16(oacc[2*p+1], pl, vh[2], vh[3]);
            }
        }

        __syncthreads();
        if (jb + 2 < njb) { fa_load(s, jb + 2); CP_COMMIT(); }
    }

    const float inv0 = 1.0f / l0;
    const float inv1 = 1.0f / l1;
    const int s0 = q0 + 16 * w + g;
    const int s1 = s0 + 8;
#pragma unroll
    for (int jd = 0; jd < 16; jd++) {
        const int d = 8 * jd + 2 * t;
        uint32_t hi0, lo0, hi1, lo1;
        split2h(oacc[jd][0] * inv0, oacc[jd][1] * inv0, hi0, lo0);
        split2h(oacc[jd][2] * inv1, oacc[jd][3] * inv1, hi1, lo1);
        const size_t i0 = (size_t)s0 * HID + h * HD + d;
        const size_t i1 = (size_t)s1 * HID + h * HD + d;
        *(uint32_t*)(Ohi + i0) = hi0;
        *(uint32_t*)(Olo + i0) = lo0;
        *(uint32_t*)(Ohi + i1) = hi1;
        *(uint32_t*)(Olo + i1) = lo1;
    }
}

// ======================= launch ============================================
extern "C" void kernel_launch(void* const* d_in, const int* in_sizes, int n_in,
                              void* d_out, int out_size) {
    const float* x  = (const float*)d_in[0];
    const float* wq = (const float*)d_in[1];
    const float* wk = (const float*)d_in[2];
    const float* wv = (const float*)d_in[3];
    const float* wo = (const float*)d_in[4];
    const float* cs = (const float*)d_in[5];
    const float* sn = (const float*)d_in[6];
    float* out = (float*)d_out;

    float *qraw, *kraw, *v;
    __nv_bfloat16 *xhi, *xlo, *wqhi, *wqlo, *wkhi, *wklo;
    __half *xh16, *xl16, *wv16, *wo16, *atth16, *attl16, *vt16;
    __half *qh16, *ql16, *k16;
    cudaGetSymbolAddress((void**)&qraw, g_qraw);
    cudaGetSymbolAddress((void**)&kraw, g_kraw);
    cudaGetSymbolAddress((void**)&v, g_v);
    cudaGetSymbolAddress((void**)&xhi, g_xhi);   cudaGetSymbolAddress((void**)&xlo, g_xlo);
    cudaGetSymbolAddress((void**)&wqhi, g_wqhi); cudaGetSymbolAddress((void**)&wqlo, g_wqlo);
    cudaGetSymbolAddress((void**)&wkhi, g_wkhi); cudaGetSymbolAddress((void**)&wklo, g_wklo);
    cudaGetSymbolAddress((void**)&xh16, g_xh16); cudaGetSymbolAddress((void**)&xl16, g_xl16);
    cudaGetSymbolAddress((void**)&wv16, g_wv16); cudaGetSymbolAddress((void**)&wo16, g_wo16);
    cudaGetSymbolAddress((void**)&atth16, g_atth16); cudaGetSymbolAddress((void**)&attl16, g_attl16);
    cudaGetSymbolAddress((void**)&vt16, g_vt16);
    cudaGetSymbolAddress((void**)&qh16, g_qh16); cudaGetSymbolAddress((void**)&ql16, g_ql16);
    cudaGetSymbolAddress((void**)&k16, g_k16);

    cudaFuncSetAttribute(gemm_kv, cudaFuncAttributeMaxDynamicSharedMemorySize, GEMM_SMEM);
    cudaFuncSetAttribute(gemm_tc256, cudaFuncAttributeMaxDynamicSharedMemorySize, GEMM256_SMEM);
    cudaFuncSetAttribute(gemm_tc256h, cudaFuncAttributeMaxDynamicSharedMemorySize, GEMM256H_SMEM);
    cudaFuncSetAttribute(flash_attn_tc, cudaFuncAttributeMaxDynamicSharedMemorySize, FA_SMEM);

    // x: bf16 + fp16 splits in one pass
    {
        int n4 = (S_LEN * HID) / 4;
        split_dual_kernel<<<(n4 + 255) / 256, 256>>>(
            (const float4*)x, (uint2*)xhi, (uint2*)xlo, (uint2*)xh16, (uint2*)xl16, n4);
    }
    {
        int n4 = (HID * HID) / 4;
        split_kernel<<<(n4 + 255) / 256, 256>>>((const float4*)wq, (uint2*)wqhi, (uint2*)wqlo, n4);
    }
    {
        int n4 = (NKV * HD * HID) / 4;
        split_kernel<<<(n4 + 255) / 256, 256>>>((const float4*)wk, (uint2*)wkhi, (uint2*)wklo, n4);
        split16s_kernel<<<(n4 + 255) / 256, 256>>>((const float4*)wv, (uint2*)wv16, n4);
    }
    {
        int n4 = (HID * HID) / 4;
        split16s_kernel<<<(n4 + 255) / 256, 256>>>((const float4*)wo, (uint2*)wo16, n4);
    }

    // Q projection (bf16 3-MMA, 256-tile)
    gemm_tc256<<<dim3(HID / 128, S_LEN / 256), 256, GEMM256_SMEM>>>(
        xhi, xlo, wqhi, wqlo, qraw, S_LEN, HID, HID);
    // fused K (bf16 3-MMA) + V (fp16 2-MMA) projections — one full wave
    gemm_kv<<<dim3(16, S_LEN / 128), 256, GEMM_SMEM>>>(
        xhi, xlo, wkhi, wklo, kraw, xh16, xl16, wv16, v);

    // RoPE: Q -> fp16 hi/lo (scale folded), K -> single fp16; V transpose fp16
    const float scale = 0.08838834764831845f;
    rope_split_q16<<<dim3(S_LEN, NH), 64>>>(qraw, cs, sn, qh16, ql16, NH, scale);
    rope_k16<<<dim3(S_LEN, NKV), 64>>>(kraw, cs, sn, k16, NKV);
    vt_split16<<<dim3(S_LEN / 32, HD / 32, NKV), dim3(32, 8)>>>(v, vt16);

    // tensor-core flash attention (all fp16 MMAs)
    flash_attn_tc<<<dim3(S_LEN / 128, NH), 256, FA_SMEM>>>(
        qh16, ql16, k16, vt16, atth16, attl16);

    // output projection (fp16 2-MMA, 256-tile)
    gemm_tc256h<<<dim3(HID / 128, S_LEN / 256), 256, GEMM256H_SMEM>>>(
        atth16, attl16, wo16, out, S_LEN, HID, HID);
}

// round 9
// speedup vs baseline: 3.6509x; 1.1548x over previous
#include <cuda_runtime.h>
#include <cuda_bf16.h>
#include <cuda_fp16.h>
#include <stdint.h>
#include <math.h>

#define S_LEN 2048
#define HID 4096
#define NH 32
#define NKV 8
#define HD 128

// ---------------- scratch ---------------------------------------------------
__device__ float g_qraw[S_LEN * HID];
__device__ float g_kraw[S_LEN * NKV * HD];
__device__ float g_v[NKV * S_LEN * HD];

__device__ __nv_bfloat16 g_xhi[S_LEN * HID],   g_xlo[S_LEN * HID];
__device__ __nv_bfloat16 g_wkhi[NKV*HD * HID], g_wklo[NKV*HD * HID];

__device__ __half g_xh16[S_LEN * HID], g_xl16[S_LEN * HID];
__device__ __half g_wq16[HID * HID];
__device__ __half g_wv16[NKV*HD * HID];
__device__ __half g_wo16[HID * HID];
__device__ __half g_atth16[S_LEN * HID], g_attl16[S_LEN * HID];
__device__ __half g_vt16[NKV * HD * S_LEN];

__device__ __half g_qh16[NH * S_LEN * HD];
__device__ __half g_k16[NKV * S_LEN * HD];

// ======================= helpers ===========================================
__device__ __forceinline__ uint32_t smem_u32(const void* p) {
    uint32_t a;
    asm("{ .reg .u64 t; cvta.to.shared.u64 t, %1; cvt.u32.u64 %0, t; }" : "=r"(a) : "l"(p));
    return a;
}
__device__ __forceinline__ void cp_async16(uint32_t saddr, const void* g) {
    asm volatile("cp.async.cg.shared.global [%0], [%1], 16;" :: "r"(saddr), "l"(g));
}
#define CP_COMMIT() asm volatile("cp.async.commit_group;" ::: "memory")

#define MMA_BF16(c, a, b0, b1)                                                 \
    asm volatile("mma.sync.aligned.m16n8k16.row.col.f32.bf16.bf16.f32 "        \
        "{%0,%1,%2,%3}, {%4,%5,%6,%7}, {%8,%9}, {%0,%1,%2,%3};"                \
        : "+f"((c)[0]), "+f"((c)[1]), "+f"((c)[2]), "+f"((c)[3])               \
        : "r"((a)[0]), "r"((a)[1]), "r"((a)[2]), "r"((a)[3]), "r"(b0), "r"(b1))

#define MMA_F16(c, a, b0, b1)                                                  \
    asm volatile("mma.sync.aligned.m16n8k16.row.col.f32.f16.f16.f32 "          \
        "{%0,%1,%2,%3}, {%4,%5,%6,%7}, {%8,%9}, {%0,%1,%2,%3};"                \
        : "+f"((c)[0]), "+f"((c)[1]), "+f"((c)[2]), "+f"((c)[3])               \
        : "r"((a)[0]), "r"((a)[1]), "r"((a)[2]), "r"((a)[3]), "r"(b0), "r"(b1))

__device__ __forceinline__ void ldsm_x4(uint32_t* r, uint32_t addr) {
    asm volatile("ldmatrix.sync.aligned.m8n8.x4.shared.b16 {%0,%1,%2,%3}, [%4];"
        : "=r"(r[0]), "=r"(r[1]), "=r"(r[2]), "=r"(r[3]) : "r"(addr));
}

__device__ __forceinline__ void split2h(float x, float y, uint32_t& hi, uint32_t& lo) {
    __half hx = __float2half_rn(x), hy = __float2half_rn(y);
    __half lx = __float2half_rn(x - __half2float(hx));
    __half ly = __float2half_rn(y - __half2float(hy));
    __half h2[2] = {hx, hy}, l2[2] = {lx, ly};
    hi = *(uint32_t*)h2;
    lo = *(uint32_t*)l2;
}
__device__ __forceinline__ uint32_t pack2h(float x, float y) {
    __half2 h = __floats2half2_rn(x, y);
    return *(uint32_t*)&h;
}

// ======================= split kernels =====================================
__global__ void split_kernel(const float4* __restrict__ in,
                             uint2* __restrict__ hi, uint2* __restrict__ lo, int n4) {
    int i = blockIdx.x * blockDim.x + threadIdx.x;
    if (i >= n4) return;
    float4 v = in[i];
    __nv_bfloat16 h[4], l[4];
    h[0] = __float2bfloat16_rn(v.x); l[0] = __float2bfloat16_rn(v.x - __bfloat162float(h[0]));
    h[1] = __float2bfloat16_rn(v.y); l[1] = __float2bfloat16_rn(v.y - __bfloat162float(h[1]));
    h[2] = __float2bfloat16_rn(v.z); l[2] = __float2bfloat16_rn(v.z - __bfloat162float(h[2]));
    h[3] = __float2bfloat16_rn(v.w); l[3] = __float2bfloat16_rn(v.w - __bfloat162float(h[3]));
    hi[i] = *(uint2*)h;
    lo[i] = *(uint2*)l;
}

// x -> bf16 hi/lo AND fp16 hi/lo in one pass
__global__ void split_dual_kernel(const float4* __restrict__ in,
                                  uint2* __restrict__ bhi, uint2* __restrict__ blo,
                                  uint2* __restrict__ hhi, uint2* __restrict__ hlo, int n4) {
    int i = blockIdx.x * blockDim.x + threadIdx.x;
    if (i >= n4) return;
    float4 v = in[i];
    float f[4] = {v.x, v.y, v.z, v.w};
    __nv_bfloat16 bh[4], bl[4];
    __half hh[4], hl[4];
#pragma unroll
    for (int j = 0; j < 4; j++) {
        bh[j] = __float2bfloat16_rn(f[j]);
        bl[j] = __float2bfloat16_rn(f[j] - __bfloat162float(bh[j]));
        hh[j] = __float2half_rn(f[j]);
        hl[j] = __float2half_rn(f[j] - __half2float(hh[j]));
    }
    bhi[i] = *(uint2*)bh;
    blo[i] = *(uint2*)bl;
    hhi[i] = *(uint2*)hh;
    hlo[i] = *(uint2*)hl;
}

__global__ void split16s_kernel(const float4* __restrict__ in,
                                uint2* __restrict__ hi, int n4) {
    int i = blockIdx.x * blockDim.x + threadIdx.x;
    if (i >= n4) return;
    float4 v = in[i];
    __half h[4];
    h[0] = __float2half_rn(v.x);
    h[1] = __float2half_rn(v.y);
    h[2] = __float2half_rn(v.z);
    h[3] = __float2half_rn(v.w);
    hi[i] = *(uint2*)h;
}

// ======================= common tile constants =============================
#define RSTR 112
#define TILE_B (128 * RSTR)            // 14336 (128-row tile)
#define TILE_A2 (256 * RSTR)           // 28672 (256-row tile)
#define STAGE_B (4 * TILE_B)
#define GEMM_SMEM (3 * STAGE_B)        // 172032
#define STAGE2_B (3 * TILE_B)

// ======================= fused K(bf16-3MMA)+V(fp16-2MMA) projections =======
__global__ __launch_bounds__(256, 1) void gemm_kv(
    const __nv_bfloat16* __restrict__ Xbh, const __nv_bfloat16* __restrict__ Xbl,
    const __nv_bfloat16* __restrict__ Wkh, const __nv_bfloat16* __restrict__ Wkl,
    float* __restrict__ Ck,
    const __half* __restrict__ Xhh, const __half* __restrict__ Xhl,
    const __half* __restrict__ Wv, float* __restrict__ Cv)
{
    extern __shared__ char sm[];
    const uint32_t smb = smem_u32(sm);

    const int tid = threadIdx.x;
    const int warp = tid >> 5;
    const int lane = tid & 31;
    const int wm = warp >> 2;
    const int wn = warp & 3;
    const int g = lane >> 2;
    const int t = lane & 3;
    const int bm = blockIdx.y * 128;
    const int K = HID, M = S_LEN, N = NKV * HD;
    const int nk = K >> 5;

    const int a_r  = (lane & 7) + ((lane >> 3) & 1) * 8;
    const int a_c8 = (lane >> 4) * 8;
    const int b_r  = lane & 7;
    const int b_j  = lane >> 4;
    const int b_c8 = ((lane >> 3) & 1) * 8;

    float acc[4][4][4];
#pragma unroll
    for (int i = 0; i < 4; i++)
#pragma unroll
        for (int j = 0; j < 4; j++)
#pragma unroll
            for (int r = 0; r < 4; r++) acc[i][j][r] = 0.0f;

    if (blockIdx.x < 8) {
        const int bn = blockIdx.x * 128;
        auto load_stage = [&](int s, int c) {
            const uint32_t sb = smb + s * STAGE_B;
            const int k0 = c * 32;
#pragma unroll
            for (int it = 0; it < 2; it++) {
                const int id = tid + it * 256;
                const int r = id >> 2, ch = id & 3;
                const uint32_t off = r * RSTR + ch * 16;
                const size_t ga = (size_t)(bm + r) * K + k0 + ch * 8;
                const size_t gb = (size_t)(bn + r) * K + k0 + ch * 8;
                cp_async16(sb + off,              Xbh + ga);
                cp_async16(sb + TILE_B + off,     Xbl + ga);
                cp_async16(sb + 2 * TILE_B + off, Wkh + gb);
                cp_async16(sb + 3 * TILE_B + off, Wkl + gb);
            }
            CP_COMMIT();
        };
        load_stage(0, 0);
        load_stage(1, 1);
        load_stage(2, 2);
        for (int c = 0; c < nk; c++) {
            const int s = c % 3;
            if (c + 2 < nk)      asm volatile("cp.async.wait_group 2;" ::: "memory");
            else if (c + 1 < nk) asm volatile("cp.async.wait_group 1;" ::: "memory");
            else                 asm volatile("cp.async.wait_group 0;" ::: "memory");
            __syncthreads();
            const uint32_t uAh = smb + s * STAGE_B;
            const uint32_t uAl = uAh + TILE_B;
            const uint32_t uBh = uAh + 2 * TILE_B;
            const uint32_t uBl = uAh + 3 * TILE_B;
#pragma unroll
            for (int ks = 0; ks < 2; ks++) {
                const uint32_t colA = (ks * 16 + a_c8) * 2;
                const uint32_t colB = (ks * 16 + b_c8) * 2;
                uint32_t ah[4][4], al[4][4];
#pragma unroll
                for (int i = 0; i < 4; i++) {
                    const uint32_t ro = (wm * 64 + i * 16 + a_r) * RSTR + colA;
                    ldsm_x4(ah[i], uAh + ro);
                    ldsm_x4(al[i], uAl + ro);
                }
#pragma unroll
                for (int p = 0; p < 2; p++) {
                    const uint32_t ro = (wn * 32 + (2 * p + b_j) * 8 + b_r) * RSTR + colB;
                    uint32_t bh[4], bl[4];
                    ldsm_x4(bh, uBh + ro);
                    ldsm_x4(bl, uBl + ro);
#pragma unroll
                    for (int i = 0; i < 4; i++) {
                        MMA_BF16(acc[i][2*p],   ah[i], bh[0], bh[1]);
                        MMA_BF16(acc[i][2*p],   ah[i], bl[0], bl[1]);
                        MMA_BF16(acc[i][2*p],   al[i], bh[0], bh[1]);
                        MMA_BF16(acc[i][2*p+1], ah[i], bh[2], bh[3]);
                        MMA_BF16(acc[i][2*p+1], ah[i], bl[2], bl[3]);
                        MMA_BF16(acc[i][2*p+1], al[i], bh[2], bh[3]);
                    }
                }
            }
            __syncthreads();
            if (c + 3 < nk) load_stage(s, c + 3);
        }
#pragma unroll
        for (int i = 0; i < 4; i++) {
            const int row0 = bm + wm * 64 + i * 16 + g;
#pragma unroll
            for (int j = 0; j < 4; j++) {
                const int col = bn + wn * 32 + j * 8 + 2 * t;
                *(float2*)(Ck + (size_t)row0 * N + col) = make_float2(acc[i][j][0], acc[i][j][1]);
                *(float2*)(Ck + (size_t)(row0 + 8) * N + col) = make_float2(acc[i][j][2], acc[i][j][3]);
            }
        }
    } else {
        const int bn = (blockIdx.x - 8) * 128;
        auto load_stage = [&](int s, int c) {
            const uint32_t sb = smb + s * STAGE2_B;
            const int k0 = c * 32;
#pragma unroll
            for (int it = 0; it < 2; it++) {
                const int id = tid + it * 256;
                const int r = id >> 2, ch = id & 3;
                const uint32_t off = r * RSTR + ch * 16;
                const size_t ga = (size_t)(bm + r) * K + k0 + ch * 8;
                const size_t gb = (size_t)(bn + r) * K + k0 + ch * 8;
                cp_async16(sb + off,              Xhh + ga);
                cp_async16(sb + TILE_B + off,     Xhl + ga);
                cp_async16(sb + 2 * TILE_B + off, Wv + gb);
            }
            CP_COMMIT();
        };
        load_stage(0, 0);
        load_stage(1, 1);
        load_stage(2, 2);
        for (int c = 0; c < nk; c++) {
            const int s = c % 3;
            if (c + 2 < nk)      asm volatile("cp.async.wait_group 2;" ::: "memory");
            else if (c + 1 < nk) asm volatile("cp.async.wait_group 1;" ::: "memory");
            else                 asm volatile("cp.async.wait_group 0;" ::: "memory");
            __syncthreads();
            const uint32_t uAh = smb + s * STAGE2_B;
            const uint32_t uAl = uAh + TILE_B;
            const uint32_t uB  = uAh + 2 * TILE_B;
#pragma unroll
            for (int ks = 0; ks < 2; ks++) {
                const uint32_t colA = (ks * 16 + a_c8) * 2;
                const uint32_t colB = (ks * 16 + b_c8) * 2;
                uint32_t ah[4][4], al[4][4];
#pragma unroll
                for (int i = 0; i < 4; i++) {
                    const uint32_t ro = (wm * 64 + i * 16 + a_r) * RSTR + colA;
                    ldsm_x4(ah[i], uAh + ro);
                    ldsm_x4(al[i], uAl + ro);
                }
#pragma unroll
                for (int p = 0; p < 2; p++) {
                    const uint32_t ro = (wn * 32 + (2 * p + b_j) * 8 + b_r) * RSTR + colB;
                    uint32_t bh[4];
                    ldsm_x4(bh, uB + ro);
#pragma unroll
                    for (int i = 0; i < 4; i++) {
                        MMA_F16(acc[i][2*p],   ah[i], bh[0], bh[1]);
                        MMA_F16(acc[i][2*p],   al[i], bh[0], bh[1]);
                        MMA_F16(acc[i][2*p+1], ah[i], bh[2], bh[3]);
                        MMA_F16(acc[i][2*p+1], al[i], bh[2], bh[3]);
                    }
                }
            }
            __syncthreads();
            if (c + 3 < nk) load_stage(s, c + 3);
        }
#pragma unroll
        for (int i = 0; i < 4; i++) {
            const int row0 = bm + wm * 64 + i * 16 + g;
#pragma unroll
            for (int j = 0; j < 4; j++) {
                const int col = bn + wn * 32 + j * 8 + 2 * t;
                const int hh = col >> 7, d = col & 127;
                *(float2*)(Cv + ((size_t)hh * M + row0) * 128 + d) =
                    make_float2(acc[i][j][0], acc[i][j][1]);
                *(float2*)(Cv + ((size_t)hh * M + row0 + 8) * 128 + d) =
                    make_float2(acc[i][j][2], acc[i][j][3]);
            }
        }
    }
}

// ======================= 256x128 fp16 2-MMA GEMM (Q & O projections) =======
#define STG256H (2 * TILE_A2 + TILE_B)          // 71680
#define GEMM256H_SMEM (2 * STG256H)             // 143360

__global__ __launch_bounds__(256, 1) void gemm_tc256h(
    const __half* __restrict__ Ahi, const __half* __restrict__ Alo,
    const __half* __restrict__ B,
    float* __restrict__ C, int M, int N, int K)
{
    extern __shared__ char sm[];
    const uint32_t smb = smem_u32(sm);

    const int tid = threadIdx.x;
    const int warp = tid >> 5;
    const int lane = tid & 31;
    const int wm = warp >> 1;
    const int wn = warp & 1;
    const int g = lane >> 2;
    const int t = lane & 3;
    const int bm = blockIdx.y * 256;
    const int bn = blockIdx.x * 128;
    const int nk = K >> 5;

    const int a_r  = (lane & 7) + ((lane >> 3) & 1) * 8;
    const int a_c8 = (lane >> 4) * 8;
    const int b_r  = lane & 7;
    const int b_j  = lane >> 4;
    const int b_c8 = ((lane >> 3) & 1) * 8;

    float acc[4][8][4];
#pragma unroll
    for (int i = 0; i < 4; i++)
#pragma unroll
        for (int j = 0; j < 8; j++)
#pragma unroll
            for (int r = 0; r < 4; r++) acc[i][j][r] = 0.0f;

    auto load_stage = [&](int s, int c) {
        const uint32_t sb = smb + s * STG256H;
        const int k0 = c * 32;
#pragma unroll
        for (int it = 0; it < 4; it++) {
            const int id = tid + it * 256;
            const int r = id >> 2, ch = id & 3;
            const uint32_t off = r * RSTR + ch * 16;
            const size_t ga = (size_t)(bm + r) * K + k0 + ch * 8;
            cp_async16(sb + off,           Ahi + ga);
            cp_async16(sb + TILE_A2 + off, Alo + ga);
        }
#pragma unroll
        for (int it = 0; it < 2; it++) {
            const int id = tid + it * 256;
            const int r = id >> 2, ch = id & 3;
            const uint32_t off = r * RSTR + ch * 16;
            const size_t gb = (size_t)(bn + r) * K + k0 + ch * 8;
            cp_async16(sb + 2 * TILE_A2 + off, B + gb);
        }
        CP_COMMIT();
    };

    load_stage(0, 0);
    if (nk > 1) load_stage(1, 1);

    for (int c = 0; c < nk; c++) {
        const int s = c & 1;
        if (c + 1 < nk) asm volatile("cp.async.wait_group 1;" ::: "memory");
        else            asm volatile("cp.async.wait_group 0;" ::: "memory");
        __syncthreads();

        const uint32_t uAh = smb + s * STG256H;
        const uint32_t uAl = uAh + TILE_A2;
        const uint32_t uB  = uAh + 2 * TILE_A2;

#pragma unroll
        for (int ks = 0; ks < 2; ks++) {
            const uint32_t colA = (ks * 16 + a_c8) * 2;
            const uint32_t colB = (ks * 16 + b_c8) * 2;
            uint32_t ah[4][4], al[4][4];
#pragma unroll
            for (int i = 0; i < 4; i++) {
                const uint32_t ro = (wm * 64 + i * 16 + a_r) * RSTR + colA;
                ldsm_x4(ah[i], uAh + ro);
                ldsm_x4(al[i], uAl + ro);
            }
#pragma unroll
            for (int p = 0; p < 4; p++) {
                const uint32_t ro = (wn * 64 + (2 * p + b_j) * 8 + b_r) * RSTR + colB;
                uint32_t bh[4];
                ldsm_x4(bh, uB + ro);
#pragma unroll
                for (int i = 0; i < 4; i++) {
                    MMA_F16(acc[i][2*p],   ah[i], bh[0], bh[1]);
                    MMA_F16(acc[i][2*p],   al[i], bh[0], bh[1]);
                    MMA_F16(acc[i][2*p+1], ah[i], bh[2], bh[3]);
                    MMA_F16(acc[i][2*p+1], al[i], bh[2], bh[3]);
                }
            }
        }
        __syncthreads();
        if (c + 2 < nk) load_stage(s, c + 2);
    }

#pragma unroll
    for (int i = 0; i < 4; i++) {
        const int row0 = bm + wm * 64 + i * 16 + g;
#pragma unroll
        for (int j = 0; j < 8; j++) {
            const int col = bn + wn * 64 + j * 8 + 2 * t;
            *(float2*)(C + (size_t)row0 * N + col) = make_float2(acc[i][j][0], acc[i][j][1]);
            *(float2*)(C + (size_t)(row0 + 8) * N + col) = make_float2(acc[i][j][2], acc[i][j][3]);
        }
    }
}

// ======================= RoPE: fp16 single out =============================
__global__ void rope16(const float* __restrict__ raw, const float* __restrict__ cs,
                       const float* __restrict__ sn, __half* __restrict__ out,
                       int nh, float scale) {
    const int s = blockIdx.x;
    const int h = blockIdx.y;
    const int j = threadIdx.x;  // 0..63
    const float* r = raw + ((size_t)s * nh + h) * HD;
    const float x1 = r[j];
    const float x2 = r[j + 64];
    const float c = cs[s * 64 + j];
    const float si = sn[s * 64 + j];
    const size_t base = ((size_t)h * S_LEN + s) * HD;
    out[base + j]      = __float2half_rn((x1 * c - x2 * si) * scale);
    out[base + j + 64] = __float2half_rn((x2 * c + x1 * si) * scale);
}

// ======================= V transpose + fp16 ================================
__global__ void vt_split16(const float* __restrict__ v, __half* __restrict__ vt) {
    __shared__ float tile[32][33];
    const int kvh = blockIdx.z;
    const int s0 = blockIdx.x * 32;
    const int d0 = blockIdx.y * 32;
    const int tx = threadIdx.x, ty = threadIdx.y;  // 32 x 8
    for (int i = ty; i < 32; i += 8)
        tile[i][tx] = v[((size_t)kvh * S_LEN + s0 + i) * HD + d0 + tx];
    __syncthreads();
    for (int i = ty; i < 32; i += 8) {
        const float val = tile[tx][i];
        vt[((size_t)kvh * HD + d0 + i) * S_LEN + s0 + tx] = __float2half_rn(val);
    }
}

// ======================= Flash attention (all single-fp16 MMA) =============
// QK^T: 1 MMA (Q fp16 x K fp16). P·V: 1 MMA (P fp16 x V fp16).
// smem 104KB -> 2 CTAs/SM: softmax of one CTA overlaps MMAs of the other.
#define QSTR 272
#define VSTR 144
#define FA_QB (128 * QSTR)                 // 34816
#define FA_KB (64 * QSTR)                  // 17408
#define FA_VB (128 * VSTR)                 // 18432
#define FA_STAGE (FA_KB + FA_VB)           // 35840
#define FA_SMEM (FA_QB + 2 * FA_STAGE)     // 106496

__global__ __launch_bounds__(256, 2) void flash_attn_tc(
    const __half* __restrict__ Qf, const __half* __restrict__ Kf,
    const __half* __restrict__ Vt,
    __half* __restrict__ Ohi, __half* __restrict__ Olo)
{
    extern __shared__ char fsm[];
    const uint32_t smb = smem_u32(fsm);
    const int qb = gridDim.x - 1 - blockIdx.x;
    const int h  = blockIdx.y;
    const int kvh = h % NKV;
    const int q0 = qb * 128;
    const int tid = threadIdx.x;
    const int w = tid >> 5;
    const int lane = tid & 31;
    const int g = lane >> 2;
    const int t = lane & 3;

    const int a_r  = (lane & 7) + ((lane >> 3) & 1) * 8;
    const int a_c8 = (lane >> 4) * 8;
    const int b_r  = lane & 7;
    const int b_j  = lane >> 4;
    const int b_c8 = ((lane >> 3) & 1) * 8;

#pragma unroll
    for (int it = 0; it < 8; it++) {
        const int id = tid + 256 * it;
        const int r = id >> 4, ch = id & 15;
        const uint32_t off = r * QSTR + ch * 16;
        const size_t gi = ((size_t)h * S_LEN + q0 + r) * HD + ch * 8;
        cp_async16(smb + off, Qf + gi);
    }

    auto fa_load = [&](int s, int jb) {
        const uint32_t sb = smb + FA_QB + s * FA_STAGE;
        const int k0 = jb * 64;
#pragma unroll
        for (int it = 0; it < 4; it++) {
            const int id = tid + 256 * it;
            const int r = id >> 4, ch = id & 15;
            const uint32_t off = r * QSTR + ch * 16;
            const size_t gi = ((size_t)kvh * S_LEN + k0 + r) * HD + ch * 8;
            cp_async16(sb + off, Kf + gi);
        }
#pragma unroll
        for (int it = 0; it < 4; it++) {
            const int id = tid + 256 * it;
            const int r = id >> 3, ch = id & 7;
            const uint32_t off = r * VSTR + ch * 16;
            const size_t gi = ((size_t)kvh * HD + r) * S_LEN + k0 + ch * 8;
            cp_async16(sb + FA_KB + off, Vt + gi);
        }
    };

    const int njb = 2 * qb + 2;
    fa_load(0, 0);
    CP_COMMIT();
    fa_load(1, 1);
    CP_COMMIT();

    float oacc[16][4];
#pragma unroll
    for (int jd = 0; jd < 16; jd++)
#pragma unroll
        for (int r = 0; r < 4; r++) oacc[jd][r] = 0.0f;
    float m0 = -1e30f, m1 = -1e30f, l0 = 0.0f, l1 = 0.0f;

    const uint32_t uQ = smb;

    for (int jb = 0; jb < njb; jb++) {
        const int s = jb & 1;
        if (jb + 1 < njb) asm volatile("cp.async.wait_group 1;" ::: "memory");
        else              asm volatile("cp.async.wait_group 0;" ::: "memory");
        __syncthreads();

        const uint32_t uK = smb + FA_QB + s * FA_STAGE;
        const uint32_t uV = uK + FA_KB;

        // ---- S = Q @ K^T (single fp16 MMA) ----
        float sv[8][4];
#pragma unroll
        for (int j = 0; j < 8; j++)
#pragma unroll
            for (int r = 0; r < 4; r++) sv[j][r] = 0.0f;

#pragma unroll
        for (int kt = 0; kt < 8; kt++) {
            const uint32_t qro = (16 * w + a_r) * QSTR + (kt * 16 + a_c8) * 2;
            uint32_t qh[4];
            ldsm_x4(qh, uQ + qro);
#pragma unroll
            for (int p = 0; p < 4; p++) {
                const uint32_t kro = ((2 * p + b_j) * 8 + b_r) * QSTR + (kt * 16 + b_c8) * 2;
                uint32_t kh[4];
                ldsm_x4(kh, uK + kro);
                MMA_F16(sv[2*p],   qh, kh[0], kh[1]);
                MMA_F16(sv[2*p+1], qh, kh[2], kh[3]);
            }
        }

        if (jb >= 2 * qb) {
            const int r0g = q0 + 16 * w + g;
            const int r1g = r0g + 8;
            const int kg = jb * 64;
#pragma unroll
            for (int j = 0; j < 8; j++) {
                const int c0 = kg + 8 * j + 2 * t, c1 = c0 + 1;
                if (c0 > r0g) sv[j][0] = -1e30f;
                if (c1 > r0g) sv[j][1] = -1e30f;
                if (c0 > r1g) sv[j][2] = -1e30f;
                if (c1 > r1g) sv[j][3] = -1e30f;
            }
        }

        float mn0 = m0, mn1 = m1;
#pragma unroll
        for (int j = 0; j < 8; j++) {
            mn0 = fmaxf(mn0, fmaxf(sv[j][0], sv[j][1]));
            mn1 = fmaxf(mn1, fmaxf(sv[j][2], sv[j][3]));
        }
        mn0 = fmaxf(mn0, __shfl_xor_sync(0xffffffffu, mn0, 1));
        mn0 = fmaxf(mn0, __shfl_xor_sync(0xffffffffu, mn0, 2));
        mn1 = fmaxf(mn1, __shfl_xor_sync(0xffffffffu, mn1, 1));
        mn1 = fmaxf(mn1, __shfl_xor_sync(0xffffffffu, mn1, 2));

        const float corr0 = __expf(m0 - mn0);
        const float corr1 = __expf(m1 - mn1);
        float rs0 = 0.0f, rs1 = 0.0f;
#pragma unroll
        for (int j = 0; j < 8; j++) {
            sv[j][0] = __expf(sv[j][0] - mn0);
            sv[j][1] = __expf(sv[j][1] - mn0);
            sv[j][2] = __expf(sv[j][2] - mn1);
            sv[j][3] = __expf(sv[j][3] - mn1);
            rs0 += sv[j][0] + sv[j][1];
            rs1 += sv[j][2] + sv[j][3];
        }
        rs0 += __shfl_xor_sync(0xffffffffu, rs0, 1);
        rs0 += __shfl_xor_sync(0xffffffffu, rs0, 2);
        rs1 += __shfl_xor_sync(0xffffffffu, rs1, 1);
        rs1 += __shfl_xor_sync(0xffffffffu, rs1, 2);
        l0 = l0 * corr0 + rs0;
        l1 = l1 * corr1 + rs1;
        m0 = mn0; m1 = mn1;

#pragma unroll
        for (int jd = 0; jd < 16; jd++) {
            oacc[jd][0] *= corr0; oacc[jd][1] *= corr0;
            oacc[jd][2] *= corr1; oacc[jd][3] *= corr1;
        }

        // ---- O += P @ V (single fp16 MMA) ----
#pragma unroll
        for (int kt = 0; kt < 4; kt++) {
            uint32_t ph[4];
            ph[0] = pack2h(sv[2*kt][0],   sv[2*kt][1]);
            ph[1] = pack2h(sv[2*kt][2],   sv[2*kt][3]);
            ph[2] = pack2h(sv[2*kt+1][0], sv[2*kt+1][1]);
            ph[3] = pack2h(sv[2*kt+1][2], sv[2*kt+1][3]);
#pragma unroll
            for (int p = 0; p < 8; p++) {
                const uint32_t vro = ((2 * p + b_j) * 8 + b_r) * VSTR + (kt * 16 + b_c8) * 2;
                uint32_t vh[4];
                ldsm_x4(vh, uV + vro);
                MMA_F16(oacc[2*p],   ph, vh[0], vh[1]);
                MMA_F16(oacc[2*p+1], ph, vh[2], vh[3]);
            }
        }

        __syncthreads();
        if (jb + 2 < njb) { fa_load(s, jb + 2); CP_COMMIT(); }
    }

    const float inv0 = 1.0f / l0;
    const float inv1 = 1.0f / l1;
    const int s0 = q0 + 16 * w + g;
    const int s1 = s0 + 8;
#pragma unroll
    for (int jd = 0; jd < 16; jd++) {
        const int d = 8 * jd + 2 * t;
        uint32_t hi0, lo0, hi1, lo1;
        split2h(oacc[jd][0] * inv0, oacc[jd][1] * inv0, hi0, lo0);
        split2h(oacc[jd][2] * inv1, oacc[jd][3] * inv1, hi1, lo1);
        const size_t i0 = (size_t)s0 * HID + h * HD + d;
        const size_t i1 = (size_t)s1 * HID + h * HD + d;
        *(uint32_t*)(Ohi + i0) = hi0;
        *(uint32_t*)(Olo + i0) = lo0;
        *(uint32_t*)(Ohi + i1) = hi1;
        *(uint32_t*)(Olo + i1) = lo1;
    }
}

// ======================= launch ============================================
extern "C" void kernel_launch(void* const* d_in, const int* in_sizes, int n_in,
                              void* d_out, int out_size) {
    const float* x  = (const float*)d_in[0];
    const float* wq = (const float*)d_in[1];
    const float* wk = (const float*)d_in[2];
    const float* wv = (const float*)d_in[3];
    const float* wo = (const float*)d_in[4];
    const float* cs = (const float*)d_in[5];
    const float* sn = (const float*)d_in[6];
    float* out = (float*)d_out;

    float *qraw, *kraw, *v;
    __nv_bfloat16 *xhi, *xlo, *wkhi, *wklo;
    __half *xh16, *xl16, *wq16, *wv16, *wo16, *atth16, *attl16, *vt16, *qh16, *k16;
    cudaGetSymbolAddress((void**)&qraw, g_qraw);
    cudaGetSymbolAddress((void**)&kraw, g_kraw);
    cudaGetSymbolAddress((void**)&v, g_v);
    cudaGetSymbolAddress((void**)&xhi, g_xhi);   cudaGetSymbolAddress((void**)&xlo, g_xlo);
    cudaGetSymbolAddress((void**)&wkhi, g_wkhi); cudaGetSymbolAddress((void**)&wklo, g_wklo);
    cudaGetSymbolAddress((void**)&xh16, g_xh16); cudaGetSymbolAddress((void**)&xl16, g_xl16);
    cudaGetSymbolAddress((void**)&wq16, g_wq16);
    cudaGetSymbolAddress((void**)&wv16, g_wv16); cudaGetSymbolAddress((void**)&wo16, g_wo16);
    cudaGetSymbolAddress((void**)&atth16, g_atth16); cudaGetSymbolAddress((void**)&attl16, g_attl16);
    cudaGetSymbolAddress((void**)&vt16, g_vt16);
    cudaGetSymbolAddress((void**)&qh16, g_qh16);
    cudaGetSymbolAddress((void**)&k16, g_k16);

    cudaFuncSetAttribute(gemm_kv, cudaFuncAttributeMaxDynamicSharedMemorySize, GEMM_SMEM);
    cudaFuncSetAttribute(gemm_tc256h, cudaFuncAttributeMaxDynamicSharedMemorySize, GEMM256H_SMEM);
    cudaFuncSetAttribute(flash_attn_tc, cudaFuncAttributeMaxDynamicSharedMemorySize, FA_SMEM);

    // splits
    {
        int n4 = (S_LEN * HID) / 4;
        split_dual_kernel<<<(n4 + 255) / 256, 256>>>(
            (const float4*)x, (uint2*)xhi, (uint2*)xlo, (uint2*)xh16, (uint2*)xl16, n4);
    }
    {
        int n4 = (HID * HID) / 4;
        split16s_kernel<<<(n4 + 255) / 256, 256>>>((const float4*)wq, (uint2*)wq16, n4);
        split16s_kernel<<<(n4 + 255) / 256, 256>>>((const float4*)wo, (uint2*)wo16, n4);
    }
    {
        int n4 = (NKV * HD * HID) / 4;
        split_kernel<<<(n4 + 255) / 256, 256>>>((const float4*)wk, (uint2*)wkhi, (uint2*)wklo, n4);
        split16s_kernel<<<(n4 + 255) / 256, 256>>>((const float4*)wv, (uint2*)wv16, n4);
    }

    // Q projection (fp16 2-MMA, 256-tile)
    gemm_tc256h<<<dim3(HID / 128, S_LEN / 256), 256, GEMM256H_SMEM>>>(
        xh16, xl16, wq16, qraw, S_LEN, HID, HID);
    // fused K (bf16 3-MMA) + V (fp16 2-MMA) projections
    gemm_kv<<<dim3(16, S_LEN / 128), 256, GEMM_SMEM>>>(
        xhi, xlo, wkhi, wklo, kraw, xh16, xl16, wv16, v);

    // RoPE: Q -> fp16 (scale folded), K -> fp16; V transpose fp16
    const float scale = 0.08838834764831845f;
    rope16<<<dim3(S_LEN, NH), 64>>>(qraw, cs, sn, qh16, NH, scale);
    rope16<<<dim3(S_LEN, NKV), 64>>>(kraw, cs, sn, k16, NKV, 1.0f);
    vt_split16<<<dim3(S_LEN / 32, HD / 32, NKV), dim3(32, 8)>>>(v, vt16);

    // tensor-core flash attention (1-MMA QK, 1-MMA PV, 2 CTAs/SM)
    flash_attn_tc<<<dim3(S_LEN / 128, NH), 256, FA_SMEM>>>(
        qh16, k16, vt16, atth16, attl16);

    // output projection (fp16 2-MMA, 256-tile)
    gemm_tc256h<<<dim3(HID / 128, S_LEN / 256), 256, GEMM256H_SMEM>>>(
        atth16, attl16, wo16, out, S_LEN, HID, HID);
}

// round 10
// speedup vs baseline: 4.2315x; 1.1590x over previous
#include <cuda_runtime.h>
#include <cuda_bf16.h>
#include <cuda_fp16.h>
#include <stdint.h>
#include <math.h>

#define S_LEN 2048
#define HID 4096
#define NH 32
#define NKV 8
#define HD 128

// ---------------- scratch ---------------------------------------------------
__device__ float g_qraw[S_LEN * HID];
__device__ float g_kraw[S_LEN * NKV * HD];
__device__ float g_v[NKV * S_LEN * HD];

__device__ __nv_bfloat16 g_xhi[S_LEN * HID],   g_xlo[S_LEN * HID];
__device__ __nv_bfloat16 g_wkhi[NKV*HD * HID], g_wklo[NKV*HD * HID];

__device__ __half g_xh16[S_LEN * HID], g_xl16[S_LEN * HID];
__device__ __half g_wq16[HID * HID];
__device__ __half g_wv16[NKV*HD * HID];
__device__ __half g_wo16[HID * HID];
__device__ __half g_att16[S_LEN * HID];
__device__ __half g_vt16[NKV * HD * S_LEN];

__device__ __half g_qh16[NH * S_LEN * HD];
__device__ __half g_k16[NKV * S_LEN * HD];

// ======================= helpers ===========================================
__device__ __forceinline__ uint32_t smem_u32(const void* p) {
    uint32_t a;
    asm("{ .reg .u64 t; cvta.to.shared.u64 t, %1; cvt.u32.u64 %0, t; }" : "=r"(a) : "l"(p));
    return a;
}
__device__ __forceinline__ void cp_async16(uint32_t saddr, const void* g) {
    asm volatile("cp.async.cg.shared.global [%0], [%1], 16;" :: "r"(saddr), "l"(g));
}
#define CP_COMMIT() asm volatile("cp.async.commit_group;" ::: "memory")

#define MMA_BF16(c, a, b0, b1)                                                 \
    asm volatile("mma.sync.aligned.m16n8k16.row.col.f32.bf16.bf16.f32 "        \
        "{%0,%1,%2,%3}, {%4,%5,%6,%7}, {%8,%9}, {%0,%1,%2,%3};"                \
        : "+f"((c)[0]), "+f"((c)[1]), "+f"((c)[2]), "+f"((c)[3])               \
        : "r"((a)[0]), "r"((a)[1]), "r"((a)[2]), "r"((a)[3]), "r"(b0), "r"(b1))

#define MMA_F16(c, a, b0, b1)                                                  \
    asm volatile("mma.sync.aligned.m16n8k16.row.col.f32.f16.f16.f32 "          \
        "{%0,%1,%2,%3}, {%4,%5,%6,%7}, {%8,%9}, {%0,%1,%2,%3};"                \
        : "+f"((c)[0]), "+f"((c)[1]), "+f"((c)[2]), "+f"((c)[3])               \
        : "r"((a)[0]), "r"((a)[1]), "r"((a)[2]), "r"((a)[3]), "r"(b0), "r"(b1))

__device__ __forceinline__ void ldsm_x4(uint32_t* r, uint32_t addr) {
    asm volatile("ldmatrix.sync.aligned.m8n8.x4.shared.b16 {%0,%1,%2,%3}, [%4];"
        : "=r"(r[0]), "=r"(r[1]), "=r"(r[2]), "=r"(r[3]) : "r"(addr));
}
__device__ __forceinline__ uint32_t pack2h(float x, float y) {
    __half2 h = __floats2half2_rn(x, y);
    return *(uint32_t*)&h;
}

// ======================= split kernels =====================================
__global__ void split_kernel(const float4* __restrict__ in,
                             uint2* __restrict__ hi, uint2* __restrict__ lo, int n4) {
    int i = blockIdx.x * blockDim.x + threadIdx.x;
    if (i >= n4) return;
    float4 v = in[i];
    __nv_bfloat16 h[4], l[4];
    h[0] = __float2bfloat16_rn(v.x); l[0] = __float2bfloat16_rn(v.x - __bfloat162float(h[0]));
    h[1] = __float2bfloat16_rn(v.y); l[1] = __float2bfloat16_rn(v.y - __bfloat162float(h[1]));
    h[2] = __float2bfloat16_rn(v.z); l[2] = __float2bfloat16_rn(v.z - __bfloat162float(h[2]));
    h[3] = __float2bfloat16_rn(v.w); l[3] = __float2bfloat16_rn(v.w - __bfloat162float(h[3]));
    hi[i] = *(uint2*)h;
    lo[i] = *(uint2*)l;
}

// x -> bf16 hi/lo AND fp16 hi/lo in one pass
__global__ void split_dual_kernel(const float4* __restrict__ in,
                                  uint2* __restrict__ bhi, uint2* __restrict__ blo,
                                  uint2* __restrict__ hhi, uint2* __restrict__ hlo, int n4) {
    int i = blockIdx.x * blockDim.x + threadIdx.x;
    if (i >= n4) return;
    float4 v = in[i];
    float f[4] = {v.x, v.y, v.z, v.w};
    __nv_bfloat16 bh[4], bl[4];
    __half hh[4], hl[4];
#pragma unroll
    for (int j = 0; j < 4; j++) {
        bh[j] = __float2bfloat16_rn(f[j]);
        bl[j] = __float2bfloat16_rn(f[j] - __bfloat162float(bh[j]));
        hh[j] = __float2half_rn(f[j]);
        hl[j] = __float2half_rn(f[j] - __half2float(hh[j]));
    }
    bhi[i] = *(uint2*)bh;
    blo[i] = *(uint2*)bl;
    hhi[i] = *(uint2*)hh;
    hlo[i] = *(uint2*)hl;
}

__global__ void split16s_kernel(const float4* __restrict__ in,
                                uint2* __restrict__ hi, int n4) {
    int i = blockIdx.x * blockDim.x + threadIdx.x;
    if (i >= n4) return;
    float4 v = in[i];
    __half h[4];
    h[0] = __float2half_rn(v.x);
    h[1] = __float2half_rn(v.y);
    h[2] = __float2half_rn(v.z);
    h[3] = __float2half_rn(v.w);
    hi[i] = *(uint2*)h;
}

// ======================= common tile constants =============================
#define RSTR 112
#define TILE_B (128 * RSTR)            // 14336
#define TILE_A2 (256 * RSTR)           // 28672
#define STAGE_B (4 * TILE_B)
#define GEMM_SMEM (3 * STAGE_B)        // 172032
#define STAGE2_B (3 * TILE_B)

// ======================= fused K(bf16-3MMA)+V(fp16-2MMA) projections =======
__global__ __launch_bounds__(256, 1) void gemm_kv(
    const __nv_bfloat16* __restrict__ Xbh, const __nv_bfloat16* __restrict__ Xbl,
    const __nv_bfloat16* __restrict__ Wkh, const __nv_bfloat16* __restrict__ Wkl,
    float* __restrict__ Ck,
    const __half* __restrict__ Xhh, const __half* __restrict__ Xhl,
    const __half* __restrict__ Wv, float* __restrict__ Cv)
{
    extern __shared__ char sm[];
    const uint32_t smb = smem_u32(sm);

    const int tid = threadIdx.x;
    const int warp = tid >> 5;
    const int lane = tid & 31;
    const int wm = warp >> 2;
    const int wn = warp & 3;
    const int g = lane >> 2;
    const int t = lane & 3;
    const int bm = blockIdx.y * 128;
    const int K = HID, M = S_LEN, N = NKV * HD;
    const int nk = K >> 5;

    const int a_r  = (lane & 7) + ((lane >> 3) & 1) * 8;
    const int a_c8 = (lane >> 4) * 8;
    const int b_r  = lane & 7;
    const int b_j  = lane >> 4;
    const int b_c8 = ((lane >> 3) & 1) * 8;

    float acc[4][4][4];
#pragma unroll
    for (int i = 0; i < 4; i++)
#pragma unroll
        for (int j = 0; j < 4; j++)
#pragma unroll
            for (int r = 0; r < 4; r++) acc[i][j][r] = 0.0f;

    if (blockIdx.x < 8) {
        const int bn = blockIdx.x * 128;
        auto load_stage = [&](int s, int c) {
            const uint32_t sb = smb + s * STAGE_B;
            const int k0 = c * 32;
#pragma unroll
            for (int it = 0; it < 2; it++) {
                const int id = tid + it * 256;
                const int r = id >> 2, ch = id & 3;
                const uint32_t off = r * RSTR + ch * 16;
                const size_t ga = (size_t)(bm + r) * K + k0 + ch * 8;
                const size_t gb = (size_t)(bn + r) * K + k0 + ch * 8;
                cp_async16(sb + off,              Xbh + ga);
                cp_async16(sb + TILE_B + off,     Xbl + ga);
                cp_async16(sb + 2 * TILE_B + off, Wkh + gb);
                cp_async16(sb + 3 * TILE_B + off, Wkl + gb);
            }
            CP_COMMIT();
        };
        load_stage(0, 0);
        load_stage(1, 1);
        load_stage(2, 2);
        for (int c = 0; c < nk; c++) {
            const int s = c % 3;
            if (c + 2 < nk)      asm volatile("cp.async.wait_group 2;" ::: "memory");
            else if (c + 1 < nk) asm volatile("cp.async.wait_group 1;" ::: "memory");
            else                 asm volatile("cp.async.wait_group 0;" ::: "memory");
            __syncthreads();
            const uint32_t uAh = smb + s * STAGE_B;
            const uint32_t uAl = uAh + TILE_B;
            const uint32_t uBh = uAh + 2 * TILE_B;
            const uint32_t uBl = uAh + 3 * TILE_B;
#pragma unroll
            for (int ks = 0; ks < 2; ks++) {
                const uint32_t colA = (ks * 16 + a_c8) * 2;
                const uint32_t colB = (ks * 16 + b_c8) * 2;
                uint32_t ah[4][4], al[4][4];
#pragma unroll
                for (int i = 0; i < 4; i++) {
                    const uint32_t ro = (wm * 64 + i * 16 + a_r) * RSTR + colA;
                    ldsm_x4(ah[i], uAh + ro);
                    ldsm_x4(al[i], uAl + ro);
                }
#pragma unroll
                for (int p = 0; p < 2; p++) {
                    const uint32_t ro = (wn * 32 + (2 * p + b_j) * 8 + b_r) * RSTR + colB;
                    uint32_t bh[4], bl[4];
                    ldsm_x4(bh, uBh + ro);
                    ldsm_x4(bl, uBl + ro);
#pragma unroll
                    for (int i = 0; i < 4; i++) {
                        MMA_BF16(acc[i][2*p],   ah[i], bh[0], bh[1]);
                        MMA_BF16(acc[i][2*p],   ah[i], bl[0], bl[1]);
                        MMA_BF16(acc[i][2*p],   al[i], bh[0], bh[1]);
                        MMA_BF16(acc[i][2*p+1], ah[i], bh[2], bh[3]);
                        MMA_BF16(acc[i][2*p+1], ah[i], bl[2], bl[3]);
                        MMA_BF16(acc[i][2*p+1], al[i], bh[2], bh[3]);
                    }
                }
            }
            __syncthreads();
            if (c + 3 < nk) load_stage(s, c + 3);
        }
#pragma unroll
        for (int i = 0; i < 4; i++) {
            const int row0 = bm + wm * 64 + i * 16 + g;
#pragma unroll
            for (int j = 0; j < 4; j++) {
                const int col = bn + wn * 32 + j * 8 + 2 * t;
                *(float2*)(Ck + (size_t)row0 * N + col) = make_float2(acc[i][j][0], acc[i][j][1]);
                *(float2*)(Ck + (size_t)(row0 + 8) * N + col) = make_float2(acc[i][j][2], acc[i][j][3]);
            }
        }
    } else {
        const int bn = (blockIdx.x - 8) * 128;
        auto load_stage = [&](int s, int c) {
            const uint32_t sb = smb + s * STAGE2_B;
            const int k0 = c * 32;
#pragma unroll
            for (int it = 0; it < 2; it++) {
                const int id = tid + it * 256;
                const int r = id >> 2, ch = id & 3;
                const uint32_t off = r * RSTR + ch * 16;
                const size_t ga = (size_t)(bm + r) * K + k0 + ch * 8;
                const size_t gb = (size_t)(bn + r) * K + k0 + ch * 8;
                cp_async16(sb + off,              Xhh + ga);
                cp_async16(sb + TILE_B + off,     Xhl + ga);
                cp_async16(sb + 2 * TILE_B + off, Wv + gb);
            }
            CP_COMMIT();
        };
        load_stage(0, 0);
        load_stage(1, 1);
        load_stage(2, 2);
        for (int c = 0; c < nk; c++) {
            const int s = c % 3;
            if (c + 2 < nk)      asm volatile("cp.async.wait_group 2;" ::: "memory");
            else if (c + 1 < nk) asm volatile("cp.async.wait_group 1;" ::: "memory");
            else                 asm volatile("cp.async.wait_group 0;" ::: "memory");
            __syncthreads();
            const uint32_t uAh = smb + s * STAGE2_B;
            const uint32_t uAl = uAh + TILE_B;
            const uint32_t uB  = uAh + 2 * TILE_B;
#pragma unroll
            for (int ks = 0; ks < 2; ks++) {
                const uint32_t colA = (ks * 16 + a_c8) * 2;
                const uint32_t colB = (ks * 16 + b_c8) * 2;
                uint32_t ah[4][4], al[4][4];
#pragma unroll
                for (int i = 0; i < 4; i++) {
                    const uint32_t ro = (wm * 64 + i * 16 + a_r) * RSTR + colA;
                    ldsm_x4(ah[i], uAh + ro);
                    ldsm_x4(al[i], uAl + ro);
                }
#pragma unroll
                for (int p = 0; p < 2; p++) {
                    const uint32_t ro = (wn * 32 + (2 * p + b_j) * 8 + b_r) * RSTR + colB;
                    uint32_t bh[4];
                    ldsm_x4(bh, uB + ro);
#pragma unroll
                    for (int i = 0; i < 4; i++) {
                        MMA_F16(acc[i][2*p],   ah[i], bh[0], bh[1]);
                        MMA_F16(acc[i][2*p],   al[i], bh[0], bh[1]);
                        MMA_F16(acc[i][2*p+1], ah[i], bh[2], bh[3]);
                        MMA_F16(acc[i][2*p+1], al[i], bh[2], bh[3]);
                    }
                }
            }
            __syncthreads();
            if (c + 3 < nk) load_stage(s, c + 3);
        }
#pragma unroll
        for (int i = 0; i < 4; i++) {
            const int row0 = bm + wm * 64 + i * 16 + g;
#pragma unroll
            for (int j = 0; j < 4; j++) {
                const int col = bn + wn * 32 + j * 8 + 2 * t;
                const int hh = col >> 7, d = col & 127;
                *(float2*)(Cv + ((size_t)hh * M + row0) * 128 + d) =
                    make_float2(acc[i][j][0], acc[i][j][1]);
                *(float2*)(Cv + ((size_t)hh * M + row0 + 8) * 128 + d) =
                    make_float2(acc[i][j][2], acc[i][j][3]);
            }
        }
    }
}

// ======================= 256x128 fp16 2-MMA GEMM (Q projection) ============
#define STG256H (2 * TILE_A2 + TILE_B)          // 71680
#define GEMM256H_SMEM (2 * STG256H)             // 143360

__global__ __launch_bounds__(256, 1) void gemm_tc256h(
    const __half* __restrict__ Ahi, const __half* __restrict__ Alo,
    const __half* __restrict__ B,
    float* __restrict__ C, int M, int N, int K)
{
    extern __shared__ char sm[];
    const uint32_t smb = smem_u32(sm);

    const int tid = threadIdx.x;
    const int warp = tid >> 5;
    const int lane = tid & 31;
    const int wm = warp >> 1;
    const int wn = warp & 1;
    const int g = lane >> 2;
    const int t = lane & 3;
    const int bm = blockIdx.y * 256;
    const int bn = blockIdx.x * 128;
    const int nk = K >> 5;

    const int a_r  = (lane & 7) + ((lane >> 3) & 1) * 8;
    const int a_c8 = (lane >> 4) * 8;
    const int b_r  = lane & 7;
    const int b_j  = lane >> 4;
    const int b_c8 = ((lane >> 3) & 1) * 8;

    float acc[4][8][4];
#pragma unroll
    for (int i = 0; i < 4; i++)
#pragma unroll
        for (int j = 0; j < 8; j++)
#pragma unroll
            for (int r = 0; r < 4; r++) acc[i][j][r] = 0.0f;

    auto load_stage = [&](int s, int c) {
        const uint32_t sb = smb + s * STG256H;
        const int k0 = c * 32;
#pragma unroll
        for (int it = 0; it < 4; it++) {
            const int id = tid + it * 256;
            const int r = id >> 2, ch = id & 3;
            const uint32_t off = r * RSTR + ch * 16;
            const size_t ga = (size_t)(bm + r) * K + k0 + ch * 8;
            cp_async16(sb + off,           Ahi + ga);
            cp_async16(sb + TILE_A2 + off, Alo + ga);
        }
#pragma unroll
        for (int it = 0; it < 2; it++) {
            const int id = tid + it * 256;
            const int r = id >> 2, ch = id & 3;
            const uint32_t off = r * RSTR + ch * 16;
            const size_t gb = (size_t)(bn + r) * K + k0 + ch * 8;
            cp_async16(sb + 2 * TILE_A2 + off, B + gb);
        }
        CP_COMMIT();
    };

    load_stage(0, 0);
    if (nk > 1) load_stage(1, 1);

    for (int c = 0; c < nk; c++) {
        const int s = c & 1;
        if (c + 1 < nk) asm volatile("cp.async.wait_group 1;" ::: "memory");
        else            asm volatile("cp.async.wait_group 0;" ::: "memory");
        __syncthreads();

        const uint32_t uAh = smb + s * STG256H;
        const uint32_t uAl = uAh + TILE_A2;
        const uint32_t uB  = uAh + 2 * TILE_A2;

#pragma unroll
        for (int ks = 0; ks < 2; ks++) {
            const uint32_t colA = (ks * 16 + a_c8) * 2;
            const uint32_t colB = (ks * 16 + b_c8) * 2;
            uint32_t ah[4][4], al[4][4];
#pragma unroll
            for (int i = 0; i < 4; i++) {
                const uint32_t ro = (wm * 64 + i * 16 + a_r) * RSTR + colA;
                ldsm_x4(ah[i], uAh + ro);
                ldsm_x4(al[i], uAl + ro);
            }
#pragma unroll
            for (int p = 0; p < 4; p++) {
                const uint32_t ro = (wn * 64 + (2 * p + b_j) * 8 + b_r) * RSTR + colB;
                uint32_t bh[4];
                ldsm_x4(bh, uB + ro);
#pragma unroll
                for (int i = 0; i < 4; i++) {
                    MMA_F16(acc[i][2*p],   ah[i], bh[0], bh[1]);
                    MMA_F16(acc[i][2*p],   al[i], bh[0], bh[1]);
                    MMA_F16(acc[i][2*p+1], ah[i], bh[2], bh[3]);
                    MMA_F16(acc[i][2*p+1], al[i], bh[2], bh[3]);
                }
            }
        }
        __syncthreads();
        if (c + 2 < nk) load_stage(s, c + 2);
    }

#pragma unroll
    for (int i = 0; i < 4; i++) {
        const int row0 = bm + wm * 64 + i * 16 + g;
#pragma unroll
        for (int j = 0; j < 8; j++) {
            const int col = bn + wn * 64 + j * 8 + 2 * t;
            *(float2*)(C + (size_t)row0 * N + col) = make_float2(acc[i][j][0], acc[i][j][1]);
            *(float2*)(C + (size_t)(row0 + 8) * N + col) = make_float2(acc[i][j][2], acc[i][j][3]);
        }
    }
}

// ======================= 256x128 fp16 1-MMA GEMM (O projection) ============
// Single-A fp16, 3 stages.
#define STG256S (TILE_A2 + TILE_B)              // 43008
#define GEMM256S_SMEM (3 * STG256S)             // 129024

__global__ __launch_bounds__(256, 1) void gemm_tc256s(
    const __half* __restrict__ A, const __half* __restrict__ B,
    float* __restrict__ C, int M, int N, int K)
{
    extern __shared__ char sm[];
    const uint32_t smb = smem_u32(sm);

    const int tid = threadIdx.x;
    const int warp = tid >> 5;
    const int lane = tid & 31;
    const int wm = warp >> 1;
    const int wn = warp & 1;
    const int g = lane >> 2;
    const int t = lane & 3;
    const int bm = blockIdx.y * 256;
    const int bn = blockIdx.x * 128;
    const int nk = K >> 5;

    const int a_r  = (lane & 7) + ((lane >> 3) & 1) * 8;
    const int a_c8 = (lane >> 4) * 8;
    const int b_r  = lane & 7;
    const int b_j  = lane >> 4;
    const int b_c8 = ((lane >> 3) & 1) * 8;

    float acc[4][8][4];
#pragma unroll
    for (int i = 0; i < 4; i++)
#pragma unroll
        for (int j = 0; j < 8; j++)
#pragma unroll
            for (int r = 0; r < 4; r++) acc[i][j][r] = 0.0f;

    auto load_stage = [&](int s, int c) {
        const uint32_t sb = smb + s * STG256S;
        const int k0 = c * 32;
#pragma unroll
        for (int it = 0; it < 4; it++) {
            const int id = tid + it * 256;
            const int r = id >> 2, ch = id & 3;
            const uint32_t off = r * RSTR + ch * 16;
            const size_t ga = (size_t)(bm + r) * K + k0 + ch * 8;
            cp_async16(sb + off, A + ga);
        }
#pragma unroll
        for (int it = 0; it < 2; it++) {
            const int id = tid + it * 256;
            const int r = id >> 2, ch = id & 3;
            const uint32_t off = r * RSTR + ch * 16;
            const size_t gb = (size_t)(bn + r) * K + k0 + ch * 8;
            cp_async16(sb + TILE_A2 + off, B + gb);
        }
        CP_COMMIT();
    };

    load_stage(0, 0);
    if (nk > 1) load_stage(1, 1);
    if (nk > 2) load_stage(2, 2);

    for (int c = 0; c < nk; c++) {
        const int s = c % 3;
        if (c + 2 < nk)      asm volatile("cp.async.wait_group 2;" ::: "memory");
        else if (c + 1 < nk) asm volatile("cp.async.wait_group 1;" ::: "memory");
        else                 asm volatile("cp.async.wait_group 0;" ::: "memory");
        __syncthreads();

        const uint32_t uA = smb + s * STG256S;
        const uint32_t uB = uA + TILE_A2;

#pragma unroll
        for (int ks = 0; ks < 2; ks++) {
            const uint32_t colA = (ks * 16 + a_c8) * 2;
            const uint32_t colB = (ks * 16 + b_c8) * 2;
            uint32_t ah[4][4];
#pragma unroll
            for (int i = 0; i < 4; i++) {
                const uint32_t ro = (wm * 64 + i * 16 + a_r) * RSTR + colA;
                ldsm_x4(ah[i], uA + ro);
            }
#pragma unroll
            for (int p = 0; p < 4; p++) {
                const uint32_t ro = (wn * 64 + (2 * p + b_j) * 8 + b_r) * RSTR + colB;
                uint32_t bh[4];
                ldsm_x4(bh, uB + ro);
#pragma unroll
                for (int i = 0; i < 4; i++) {
                    MMA_F16(acc[i][2*p],   ah[i], bh[0], bh[1]);
                    MMA_F16(acc[i][2*p+1], ah[i], bh[2], bh[3]);
                }
            }
        }
        __syncthreads();
        if (c + 3 < nk) load_stage(s, c + 3);
    }

#pragma unroll
    for (int i = 0; i < 4; i++) {
        const int row0 = bm + wm * 64 + i * 16 + g;
#pragma unroll
        for (int j = 0; j < 8; j++) {
            const int col = bn + wn * 64 + j * 8 + 2 * t;
            *(float2*)(C + (size_t)row0 * N + col) = make_float2(acc[i][j][0], acc[i][j][1]);
            *(float2*)(C + (size_t)(row0 + 8) * N + col) = make_float2(acc[i][j][2], acc[i][j][3]);
        }
    }
}

// ======================= RoPE: fp16 single out (256-thread blocks) =========
__global__ void rope16(const float* __restrict__ raw, const float* __restrict__ cs,
                       const float* __restrict__ sn, __half* __restrict__ out,
                       int nh, float scale) {
    const int tid = threadIdx.x;
    const int j = tid & 63;
    const int so = tid >> 6;                 // 0..3
    const int s = blockIdx.x * 4 + so;
    const int h = blockIdx.y;
    const float* r = raw + ((size_t)s * nh + h) * HD;
    const float x1 = r[j];
    const float x2 = r[j + 64];
    const float c = cs[s * 64 + j];
    const float si = sn[s * 64 + j];
    const size_t base = ((size_t)h * S_LEN + s) * HD;
    out[base + j]      = __float2half_rn((x1 * c - x2 * si) * scale);
    out[base + j + 64] = __float2half_rn((x2 * c + x1 * si) * scale);
}

// ======================= V transpose + fp16 ================================
__global__ void vt_split16(const float* __restrict__ v, __half* __restrict__ vt) {
    __shared__ float tile[32][33];
    const int kvh = blockIdx.z;
    const int s0 = blockIdx.x * 32;
    const int d0 = blockIdx.y * 32;
    const int tx = threadIdx.x, ty = threadIdx.y;  // 32 x 8
    for (int i = ty; i < 32; i += 8)
        tile[i][tx] = v[((size_t)kvh * S_LEN + s0 + i) * HD + d0 + tx];
    __syncthreads();
    for (int i = ty; i < 32; i += 8) {
        const float val = tile[tx][i];
        vt[((size_t)kvh * HD + d0 + i) * S_LEN + s0 + tx] = __float2half_rn(val);
    }
}

// ======================= Flash attention (all single-fp16 MMA) =============
#define QSTR 272
#define VSTR 144
#define FA_QB (128 * QSTR)                 // 34816
#define FA_KB (64 * QSTR)                  // 17408
#define FA_VB (128 * VSTR)                 // 18432
#define FA_STAGE (FA_KB + FA_VB)           // 35840
#define FA_SMEM (FA_QB + 2 * FA_STAGE)     // 106496

__global__ __launch_bounds__(256, 2) void flash_attn_tc(
    const __half* __restrict__ Qf, const __half* __restrict__ Kf,
    const __half* __restrict__ Vt, __half* __restrict__ O)
{
    extern __shared__ char fsm[];
    const uint32_t smb = smem_u32(fsm);
    const int qb = gridDim.x - 1 - blockIdx.x;
    const int h  = blockIdx.y;
    const int kvh = h % NKV;
    const int q0 = qb * 128;
    const int tid = threadIdx.x;
    const int w = tid >> 5;
    const int lane = tid & 31;
    const int g = lane >> 2;
    const int t = lane & 3;

    const int a_r  = (lane & 7) + ((lane >> 3) & 1) * 8;
    const int a_c8 = (lane >> 4) * 8;
    const int b_r  = lane & 7;
    const int b_j  = lane >> 4;
    const int b_c8 = ((lane >> 3) & 1) * 8;

#pragma unroll
    for (int it = 0; it < 8; it++) {
        const int id = tid + 256 * it;
        const int r = id >> 4, ch = id & 15;
        const uint32_t off = r * QSTR + ch * 16;
        const size_t gi = ((size_t)h * S_LEN + q0 + r) * HD + ch * 8;
        cp_async16(smb + off, Qf + gi);
    }

    auto fa_load = [&](int s, int jb) {
        const uint32_t sb = smb + FA_QB + s * FA_STAGE;
        const int k0 = jb * 64;
#pragma unroll
        for (int it = 0; it < 4; it++) {
            const int id = tid + 256 * it;
            const int r = id >> 4, ch = id & 15;
            const uint32_t off = r * QSTR + ch * 16;
            const size_t gi = ((size_t)kvh * S_LEN + k0 + r) * HD + ch * 8;
            cp_async16(sb + off, Kf + gi);
        }
#pragma unroll
        for (int it = 0; it < 4; it++) {
            const int id = tid + 256 * it;
            const int r = id >> 3, ch = id & 7;
            const uint32_t off = r * VSTR + ch * 16;
            const size_t gi = ((size_t)kvh * HD + r) * S_LEN + k0 + ch * 8;
            cp_async16(sb + FA_KB + off, Vt + gi);
        }
    };

    const int njb = 2 * qb + 2;
    fa_load(0, 0);
    CP_COMMIT();
    fa_load(1, 1);
    CP_COMMIT();

    float oacc[16][4];
#pragma unroll
    for (int jd = 0; jd < 16; jd++)
#pragma unroll
        for (int r = 0; r < 4; r++) oacc[jd][r] = 0.0f;
    float m0 = -1e30f, m1 = -1e30f, l0 = 0.0f, l1 = 0.0f;

    const uint32_t uQ = smb;

    for (int jb = 0; jb < njb; jb++) {
        const int s = jb & 1;
        if (jb + 1 < njb) asm volatile("cp.async.wait_group 1;" ::: "memory");
        else              asm volatile("cp.async.wait_group 0;" ::: "memory");
        __syncthreads();

        const uint32_t uK = smb + FA_QB + s * FA_STAGE;
        const uint32_t uV = uK + FA_KB;

        // ---- S = Q @ K^T ----
        float sv[8][4];
#pragma unroll
        for (int j = 0; j < 8; j++)
#pragma unroll
            for (int r = 0; r < 4; r++) sv[j][r] = 0.0f;

#pragma unroll
        for (int kt = 0; kt < 8; kt++) {
            const uint32_t qro = (16 * w + a_r) * QSTR + (kt * 16 + a_c8) * 2;
            uint32_t qh[4];
            ldsm_x4(qh, uQ + qro);
#pragma unroll
            for (int p = 0; p < 4; p++) {
                const uint32_t kro = ((2 * p + b_j) * 8 + b_r) * QSTR + (kt * 16 + b_c8) * 2;
                uint32_t kh[4];
                ldsm_x4(kh, uK + kro);
                MMA_F16(sv[2*p],   qh, kh[0], kh[1]);
                MMA_F16(sv[2*p+1], qh, kh[2], kh[3]);
            }
        }

        if (jb >= 2 * qb) {
            const int r0g = q0 + 16 * w + g;
            const int r1g = r0g + 8;
            const int kg = jb * 64;
#pragma unroll
            for (int j = 0; j < 8; j++) {
                const int c0 = kg + 8 * j + 2 * t, c1 = c0 + 1;
                if (c0 > r0g) sv[j][0] = -1e30f;
                if (c1 > r0g) sv[j][1] = -1e30f;
                if (c0 > r1g) sv[j][2] = -1e30f;
                if (c1 > r1g) sv[j][3] = -1e30f;
            }
        }

        float mn0 = m0, mn1 = m1;
#pragma unroll
        for (int j = 0; j < 8; j++) {
            mn0 = fmaxf(mn0, fmaxf(sv[j][0], sv[j][1]));
            mn1 = fmaxf(mn1, fmaxf(sv[j][2], sv[j][3]));
        }
        mn0 = fmaxf(mn0, __shfl_xor_sync(0xffffffffu, mn0, 1));
        mn0 = fmaxf(mn0, __shfl_xor_sync(0xffffffffu, mn0, 2));
        mn1 = fmaxf(mn1, __shfl_xor_sync(0xffffffffu, mn1, 1));
        mn1 = fmaxf(mn1, __shfl_xor_sync(0xffffffffu, mn1, 2));

        const float corr0 = __expf(m0 - mn0);
        const float corr1 = __expf(m1 - mn1);
        float rs0 = 0.0f, rs1 = 0.0f;
#pragma unroll
        for (int j = 0; j < 8; j++) {
            sv[j][0] = __expf(sv[j][0] - mn0);
            sv[j][1] = __expf(sv[j][1] - mn0);
            sv[j][2] = __expf(sv[j][2] - mn1);
            sv[j][3] = __expf(sv[j][3] - mn1);
            rs0 += sv[j][0] + sv[j][1];
            rs1 += sv[j][2] + sv[j][3];
        }
        rs0 += __shfl_xor_sync(0xffffffffu, rs0, 1);
        rs0 += __shfl_xor_sync(0xffffffffu, rs0, 2);
        rs1 += __shfl_xor_sync(0xffffffffu, rs1, 1);
        rs1 += __shfl_xor_sync(0xffffffffu, rs1, 2);
        l0 = l0 * corr0 + rs0;
        l1 = l1 * corr1 + rs1;
        m0 = mn0; m1 = mn1;

#pragma unroll
        for (int jd = 0; jd < 16; jd++) {
            oacc[jd][0] *= corr0; oacc[jd][1] *= corr0;
            oacc[jd][2] *= corr1; oacc[jd][3] *= corr1;
        }

        // ---- O += P @ V ----
#pragma unroll
        for (int kt = 0; kt < 4; kt++) {
            uint32_t ph[4];
            ph[0] = pack2h(sv[2*kt][0],   sv[2*kt][1]);
            ph[1] = pack2h(sv[2*kt][2],   sv[2*kt][3]);
            ph[2] = pack2h(sv[2*kt+1][0], sv[2*kt+1][1]);
            ph[3] = pack2h(sv[2*kt+1][2], sv[2*kt+1][3]);
#pragma unroll
            for (int p = 0; p < 8; p++) {
                const uint32_t vro = ((2 * p + b_j) * 8 + b_r) * VSTR + (kt * 16 + b_c8) * 2;
                uint32_t vh[4];
                ldsm_x4(vh, uV + vro);
                MMA_F16(oacc[2*p],   ph, vh[0], vh[1]);
                MMA_F16(oacc[2*p+1], ph, vh[2], vh[3]);
            }
        }

        __syncthreads();
        if (jb + 2 < njb) { fa_load(s, jb + 2); CP_COMMIT(); }
    }

    // ---- normalize + single-fp16 store ----
    const float inv0 = 1.0f / l0;
    const float inv1 = 1.0f / l1;
    const int s0 = q0 + 16 * w + g;
    const int s1 = s0 + 8;
#pragma unroll
    for (int jd = 0; jd < 16; jd++) {
        const int d = 8 * jd + 2 * t;
        const size_t i0 = (size_t)s0 * HID + h * HD + d;
        const size_t i1 = (size_t)s1 * HID + h * HD + d;
        *(uint32_t*)(O + i0) = pack2h(oacc[jd][0] * inv0, oacc[jd][1] * inv0);
        *(uint32_t*)(O + i1) = pack2h(oacc[jd][2] * inv1, oacc[jd][3] * inv1);
    }
}

// ======================= launch ============================================
extern "C" void kernel_launch(void* const* d_in, const int* in_sizes, int n_in,
                              void* d_out, int out_size) {
    const float* x  = (const float*)d_in[0];
    const float* wq = (const float*)d_in[1];
    const float* wk = (const float*)d_in[2];
    const float* wv = (const float*)d_in[3];
    const float* wo = (const float*)d_in[4];
    const float* cs = (const float*)d_in[5];
    const float* sn = (const float*)d_in[6];
    float* out = (float*)d_out;

    float *qraw, *kraw, *v;
    __nv_bfloat16 *xhi, *xlo, *wkhi, *wklo;
    __half *xh16, *xl16, *wq16, *wv16, *wo16, *att16, *vt16, *qh16, *k16;
    cudaGetSymbolAddress((void**)&qraw, g_qraw);
    cudaGetSymbolAddress((void**)&kraw, g_kraw);
    cudaGetSymbolAddress((void**)&v, g_v);
    cudaGetSymbolAddress((void**)&xhi, g_xhi);   cudaGetSymbolAddress((void**)&xlo, g_xlo);
    cudaGetSymbolAddress((void**)&wkhi, g_wkhi); cudaGetSymbolAddress((void**)&wklo, g_wklo);
    cudaGetSymbolAddress((void**)&xh16, g_xh16); cudaGetSymbolAddress((void**)&xl16, g_xl16);
    cudaGetSymbolAddress((void**)&wq16, g_wq16);
    cudaGetSymbolAddress((void**)&wv16, g_wv16); cudaGetSymbolAddress((void**)&wo16, g_wo16);
    cudaGetSymbolAddress((void**)&att16, g_att16);
    cudaGetSymbolAddress((void**)&vt16, g_vt16);
    cudaGetSymbolAddress((void**)&qh16, g_qh16);
    cudaGetSymbolAddress((void**)&k16, g_k16);

    cudaFuncSetAttribute(gemm_kv, cudaFuncAttributeMaxDynamicSharedMemorySize, GEMM_SMEM);
    cudaFuncSetAttribute(gemm_tc256h, cudaFuncAttributeMaxDynamicSharedMemorySize, GEMM256H_SMEM);
    cudaFuncSetAttribute(gemm_tc256s, cudaFuncAttributeMaxDynamicSharedMemorySize, GEMM256S_SMEM);
    cudaFuncSetAttribute(flash_attn_tc, cudaFuncAttributeMaxDynamicSharedMemorySize, FA_SMEM);

    // splits
    {
        int n4 = (S_LEN * HID) / 4;
        split_dual_kernel<<<(n4 + 255) / 256, 256>>>(
            (const float4*)x, (uint2*)xhi, (uint2*)xlo, (uint2*)xh16, (uint2*)xl16, n4);
    }
    {
        int n4 = (HID * HID) / 4;
        split16s_kernel<<<(n4 + 255) / 256, 256>>>((const float4*)wq, (uint2*)wq16, n4);
        split16s_kernel<<<(n4 + 255) / 256, 256>>>((const float4*)wo, (uint2*)wo16, n4);
    }
    {
        int n4 = (NKV * HD * HID) / 4;
        split_kernel<<<(n4 + 255) / 256, 256>>>((const float4*)wk, (uint2*)wkhi, (uint2*)wklo, n4);
        split16s_kernel<<<(n4 + 255) / 256, 256>>>((const float4*)wv, (uint2*)wv16, n4);
    }

    // Q projection (fp16 2-MMA, 256-tile)
    gemm_tc256h<<<dim3(HID / 128, S_LEN / 256), 256, GEMM256H_SMEM>>>(
        xh16, xl16, wq16, qraw, S_LEN, HID, HID);
    // fused K (bf16 3-MMA) + V (fp16 2-MMA) projections
    gemm_kv<<<dim3(16, S_LEN / 128), 256, GEMM_SMEM>>>(
        xhi, xlo, wkhi, wklo, kraw, xh16, xl16, wv16, v);

    // RoPE: Q -> fp16 (scale folded), K -> fp16; V transpose fp16
    const float scale = 0.08838834764831845f;
    rope16<<<dim3(S_LEN / 4, NH), 256>>>(qraw, cs, sn, qh16, NH, scale);
    rope16<<<dim3(S_LEN / 4, NKV), 256>>>(kraw, cs, sn, k16, NKV, 1.0f);
    vt_split16<<<dim3(S_LEN / 32, HD / 32, NKV), dim3(32, 8)>>>(v, vt16);

    // tensor-core flash attention (single fp16 att output)
    flash_attn_tc<<<dim3(S_LEN / 128, NH), 256, FA_SMEM>>>(
        qh16, k16, vt16, att16);

    // output projection (fp16 1-MMA, 256-tile, 3-stage)
    gemm_tc256s<<<dim3(HID / 128, S_LEN / 256), 256, GEMM256S_SMEM>>>(
        att16, wo16, out, S_LEN, HID, HID);
}

// round 11
// speedup vs baseline: 4.9506x; 1.1699x over previous
#include <cuda_runtime.h>
#include <cuda_bf16.h>
#include <cuda_fp16.h>
#include <stdint.h>
#include <math.h>

#define S_LEN 2048
#define HID 4096
#define NH 32
#define NKV 8
#define HD 128

// ---------------- scratch ---------------------------------------------------
__device__ float g_qraw[S_LEN * HID];
__device__ float g_kraw[S_LEN * NKV * HD];
__device__ float g_v[NKV * S_LEN * HD];

__device__ __nv_bfloat16 g_xhi[S_LEN * HID],   g_xlo[S_LEN * HID];
__device__ __nv_bfloat16 g_wkhi[NKV*HD * HID], g_wklo[NKV*HD * HID];

__device__ __half g_xh16[S_LEN * HID], g_xl16[S_LEN * HID];
__device__ __half g_wq16[HID * HID];
__device__ __half g_wv16[NKV*HD * HID];
__device__ __half g_wo16[HID * HID];
__device__ __half g_att16[S_LEN * HID];
__device__ __half g_vt16[NKV * HD * S_LEN];

__device__ __half g_qh16[NH * S_LEN * HD];
__device__ __half g_k16[NKV * S_LEN * HD];

// ======================= helpers ===========================================
__device__ __forceinline__ uint32_t smem_u32(const void* p) {
    uint32_t a;
    asm("{ .reg .u64 t; cvta.to.shared.u64 t, %1; cvt.u32.u64 %0, t; }" : "=r"(a) : "l"(p));
    return a;
}
__device__ __forceinline__ void cp_async16(uint32_t saddr, const void* g) {
    asm volatile("cp.async.cg.shared.global [%0], [%1], 16;" :: "r"(saddr), "l"(g));
}
#define CP_COMMIT() asm volatile("cp.async.commit_group;" ::: "memory")

#define MMA_BF16(c, a, b0, b1)                                                 \
    asm volatile("mma.sync.aligned.m16n8k16.row.col.f32.bf16.bf16.f32 "        \
        "{%0,%1,%2,%3}, {%4,%5,%6,%7}, {%8,%9}, {%0,%1,%2,%3};"                \
        : "+f"((c)[0]), "+f"((c)[1]), "+f"((c)[2]), "+f"((c)[3])               \
        : "r"((a)[0]), "r"((a)[1]), "r"((a)[2]), "r"((a)[3]), "r"(b0), "r"(b1))

#define MMA_F16(c, a, b0, b1)                                                  \
    asm volatile("mma.sync.aligned.m16n8k16.row.col.f32.f16.f16.f32 "          \
        "{%0,%1,%2,%3}, {%4,%5,%6,%7}, {%8,%9}, {%0,%1,%2,%3};"                \
        : "+f"((c)[0]), "+f"((c)[1]), "+f"((c)[2]), "+f"((c)[3])               \
        : "r"((a)[0]), "r"((a)[1]), "r"((a)[2]), "r"((a)[3]), "r"(b0), "r"(b1))

__device__ __forceinline__ void ldsm_x4(uint32_t* r, uint32_t addr) {
    asm volatile("ldmatrix.sync.aligned.m8n8.x4.shared.b16 {%0,%1,%2,%3}, [%4];"
        : "=r"(r[0]), "=r"(r[1]), "=r"(r[2]), "=r"(r[3]) : "r"(addr));
}
__device__ __forceinline__ uint32_t pack2h(float x, float y) {
    __half2 h = __floats2half2_rn(x, y);
    return *(uint32_t*)&h;
}

// ======================= split kernels =====================================
__global__ void split_kernel(const float4* __restrict__ in,
                             uint2* __restrict__ hi, uint2* __restrict__ lo, int n4) {
    int i = blockIdx.x * blockDim.x + threadIdx.x;
    if (i >= n4) return;
    float4 v = in[i];
    __nv_bfloat16 h[4], l[4];
    h[0] = __float2bfloat16_rn(v.x); l[0] = __float2bfloat16_rn(v.x - __bfloat162float(h[0]));
    h[1] = __float2bfloat16_rn(v.y); l[1] = __float2bfloat16_rn(v.y - __bfloat162float(h[1]));
    h[2] = __float2bfloat16_rn(v.z); l[2] = __float2bfloat16_rn(v.z - __bfloat162float(h[2]));
    h[3] = __float2bfloat16_rn(v.w); l[3] = __float2bfloat16_rn(v.w - __bfloat162float(h[3]));
    hi[i] = *(uint2*)h;
    lo[i] = *(uint2*)l;
}

// x -> bf16 hi/lo AND fp16 hi/lo in one pass
__global__ void split_dual_kernel(const float4* __restrict__ in,
                                  uint2* __restrict__ bhi, uint2* __restrict__ blo,
                                  uint2* __restrict__ hhi, uint2* __restrict__ hlo, int n4) {
    int i = blockIdx.x * blockDim.x + threadIdx.x;
    if (i >= n4) return;
    float4 v = in[i];
    float f[4] = {v.x, v.y, v.z, v.w};
    __nv_bfloat16 bh[4], bl[4];
    __half hh[4], hl[4];
#pragma unroll
    for (int j = 0; j < 4; j++) {
        bh[j] = __float2bfloat16_rn(f[j]);
        bl[j] = __float2bfloat16_rn(f[j] - __bfloat162float(bh[j]));
        hh[j] = __float2half_rn(f[j]);
        hl[j] = __float2half_rn(f[j] - __half2float(hh[j]));
    }
    bhi[i] = *(uint2*)bh;
    blo[i] = *(uint2*)bl;
    hhi[i] = *(uint2*)hh;
    hlo[i] = *(uint2*)hl;
}

__global__ void split16s_kernel(const float4* __restrict__ in,
                                uint2* __restrict__ hi, int n4) {
    int i = blockIdx.x * blockDim.x + threadIdx.x;
    if (i >= n4) return;
    float4 v = in[i];
    __half h[4];
    h[0] = __float2half_rn(v.x);
    h[1] = __float2half_rn(v.y);
    h[2] = __float2half_rn(v.z);
    h[3] = __float2half_rn(v.w);
    hi[i] = *(uint2*)h;
}

// ======================= common tile constants =============================
#define RSTR 112
#define TILE_B (128 * RSTR)            // 14336
#define TILE_A2 (256 * RSTR)           // 28672
#define STAGE_B (4 * TILE_B)
#define GEMM_SMEM (3 * STAGE_B)        // 172032
#define STAGE2_B (3 * TILE_B)

// ======================= fused K(bf16-3MMA)+V(fp16-2MMA) projections =======
__global__ __launch_bounds__(256, 1) void gemm_kv(
    const __nv_bfloat16* __restrict__ Xbh, const __nv_bfloat16* __restrict__ Xbl,
    const __nv_bfloat16* __restrict__ Wkh, const __nv_bfloat16* __restrict__ Wkl,
    float* __restrict__ Ck,
    const __half* __restrict__ Xhh, const __half* __restrict__ Xhl,
    const __half* __restrict__ Wv, float* __restrict__ Cv)
{
    extern __shared__ char sm[];
    const uint32_t smb = smem_u32(sm);

    const int tid = threadIdx.x;
    const int warp = tid >> 5;
    const int lane = tid & 31;
    const int wm = warp >> 2;
    const int wn = warp & 3;
    const int g = lane >> 2;
    const int t = lane & 3;
    const int bm = blockIdx.y * 128;
    const int K = HID, M = S_LEN, N = NKV * HD;
    const int nk = K >> 5;

    const int a_r  = (lane & 7) + ((lane >> 3) & 1) * 8;
    const int a_c8 = (lane >> 4) * 8;
    const int b_r  = lane & 7;
    const int b_j  = lane >> 4;
    const int b_c8 = ((lane >> 3) & 1) * 8;

    float acc[4][4][4];
#pragma unroll
    for (int i = 0; i < 4; i++)
#pragma unroll
        for (int j = 0; j < 4; j++)
#pragma unroll
            for (int r = 0; r < 4; r++) acc[i][j][r] = 0.0f;

    if (blockIdx.x < 8) {
        const int bn = blockIdx.x * 128;
        auto load_stage = [&](int s, int c) {
            const uint32_t sb = smb + s * STAGE_B;
            const int k0 = c * 32;
#pragma unroll
            for (int it = 0; it < 2; it++) {
                const int id = tid + it * 256;
                const int r = id >> 2, ch = id & 3;
                const uint32_t off = r * RSTR + ch * 16;
                const size_t ga = (size_t)(bm + r) * K + k0 + ch * 8;
                const size_t gb = (size_t)(bn + r) * K + k0 + ch * 8;
                cp_async16(sb + off,              Xbh + ga);
                cp_async16(sb + TILE_B + off,     Xbl + ga);
                cp_async16(sb + 2 * TILE_B + off, Wkh + gb);
                cp_async16(sb + 3 * TILE_B + off, Wkl + gb);
            }
            CP_COMMIT();
        };
        load_stage(0, 0);
        load_stage(1, 1);
        load_stage(2, 2);
        for (int c = 0; c < nk; c++) {
            const int s = c % 3;
            if (c + 2 < nk)      asm volatile("cp.async.wait_group 2;" ::: "memory");
            else if (c + 1 < nk) asm volatile("cp.async.wait_group 1;" ::: "memory");
            else                 asm volatile("cp.async.wait_group 0;" ::: "memory");
            __syncthreads();
            const uint32_t uAh = smb + s * STAGE_B;
            const uint32_t uAl = uAh + TILE_B;
            const uint32_t uBh = uAh + 2 * TILE_B;
            const uint32_t uBl = uAh + 3 * TILE_B;
#pragma unroll
            for (int ks = 0; ks < 2; ks++) {
                const uint32_t colA = (ks * 16 + a_c8) * 2;
                const uint32_t colB = (ks * 16 + b_c8) * 2;
                uint32_t ah[4][4], al[4][4];
#pragma unroll
                for (int i = 0; i < 4; i++) {
                    const uint32_t ro = (wm * 64 + i * 16 + a_r) * RSTR + colA;
                    ldsm_x4(ah[i], uAh + ro);
                    ldsm_x4(al[i], uAl + ro);
                }
#pragma unroll
                for (int p = 0; p < 2; p++) {
                    const uint32_t ro = (wn * 32 + (2 * p + b_j) * 8 + b_r) * RSTR + colB;
                    uint32_t bh[4], bl[4];
                    ldsm_x4(bh, uBh + ro);
                    ldsm_x4(bl, uBl + ro);
#pragma unroll
                    for (int i = 0; i < 4; i++) {
                        MMA_BF16(acc[i][2*p],   ah[i], bh[0], bh[1]);
                        MMA_BF16(acc[i][2*p],   ah[i], bl[0], bl[1]);
                        MMA_BF16(acc[i][2*p],   al[i], bh[0], bh[1]);
                        MMA_BF16(acc[i][2*p+1], ah[i], bh[2], bh[3]);
                        MMA_BF16(acc[i][2*p+1], ah[i], bl[2], bl[3]);
                        MMA_BF16(acc[i][2*p+1], al[i], bh[2], bh[3]);
                    }
                }
            }
            __syncthreads();
            if (c + 3 < nk) load_stage(s, c + 3);
        }
#pragma unroll
        for (int i = 0; i < 4; i++) {
            const int row0 = bm + wm * 64 + i * 16 + g;
#pragma unroll
            for (int j = 0; j < 4; j++) {
                const int col = bn + wn * 32 + j * 8 + 2 * t;
                *(float2*)(Ck + (size_t)row0 * N + col) = make_float2(acc[i][j][0], acc[i][j][1]);
                *(float2*)(Ck + (size_t)(row0 + 8) * N + col) = make_float2(acc[i][j][2], acc[i][j][3]);
            }
        }
    } else {
        const int bn = (blockIdx.x - 8) * 128;
        auto load_stage = [&](int s, int c) {
            const uint32_t sb = smb + s * STAGE2_B;
            const int k0 = c * 32;
#pragma unroll
            for (int it = 0; it < 2; it++) {
                const int id = tid + it * 256;
                const int r = id >> 2, ch = id & 3;
                const uint32_t off = r * RSTR + ch * 16;
                const size_t ga = (size_t)(bm + r) * K + k0 + ch * 8;
                const size_t gb = (size_t)(bn + r) * K + k0 + ch * 8;
                cp_async16(sb + off,              Xhh + ga);
                cp_async16(sb + TILE_B + off,     Xhl + ga);
                cp_async16(sb + 2 * TILE_B + off, Wv + gb);
            }
            CP_COMMIT();
        };
        load_stage(0, 0);
        load_stage(1, 1);
        load_stage(2, 2);
        for (int c = 0; c < nk; c++) {
            const int s = c % 3;
            if (c + 2 < nk)      asm volatile("cp.async.wait_group 2;" ::: "memory");
            else if (c + 1 < nk) asm volatile("cp.async.wait_group 1;" ::: "memory");
            else                 asm volatile("cp.async.wait_group 0;" ::: "memory");
            __syncthreads();
            const uint32_t uAh = smb + s * STAGE2_B;
            const uint32_t uAl = uAh + TILE_B;
            const uint32_t uB  = uAh + 2 * TILE_B;
#pragma unroll
            for (int ks = 0; ks < 2; ks++) {
                const uint32_t colA = (ks * 16 + a_c8) * 2;
                const uint32_t colB = (ks * 16 + b_c8) * 2;
                uint32_t ah[4][4], al[4][4];
#pragma unroll
                for (int i = 0; i < 4; i++) {
                    const uint32_t ro = (wm * 64 + i * 16 + a_r) * RSTR + colA;
                    ldsm_x4(ah[i], uAh + ro);
                    ldsm_x4(al[i], uAl + ro);
                }
#pragma unroll
                for (int p = 0; p < 2; p++) {
                    const uint32_t ro = (wn * 32 + (2 * p + b_j) * 8 + b_r) * RSTR + colB;
                    uint32_t bh[4];
                    ldsm_x4(bh, uB + ro);
#pragma unroll
                    for (int i = 0; i < 4; i++) {
                        MMA_F16(acc[i][2*p],   ah[i], bh[0], bh[1]);
                        MMA_F16(acc[i][2*p],   al[i], bh[0], bh[1]);
                        MMA_F16(acc[i][2*p+1], ah[i], bh[2], bh[3]);
                        MMA_F16(acc[i][2*p+1], al[i], bh[2], bh[3]);
                    }
                }
            }
            __syncthreads();
            if (c + 3 < nk) load_stage(s, c + 3);
        }
#pragma unroll
        for (int i = 0; i < 4; i++) {
            const int row0 = bm + wm * 64 + i * 16 + g;
#pragma unroll
            for (int j = 0; j < 4; j++) {
                const int col = bn + wn * 32 + j * 8 + 2 * t;
                const int hh = col >> 7, d = col & 127;
                *(float2*)(Cv + ((size_t)hh * M + row0) * 128 + d) =
                    make_float2(acc[i][j][0], acc[i][j][1]);
                *(float2*)(Cv + ((size_t)hh * M + row0 + 8) * 128 + d) =
                    make_float2(acc[i][j][2], acc[i][j][3]);
            }
        }
    }
}

// ======================= 256x128 fp16 1-MMA GEMM (Q & O projections) =======
// Single-A fp16, 3 stages.
#define STG256S (TILE_A2 + TILE_B)              // 43008
#define GEMM256S_SMEM (3 * STG256S)             // 129024

__global__ __launch_bounds__(256, 1) void gemm_tc256s(
    const __half* __restrict__ A, const __half* __restrict__ B,
    float* __restrict__ C, int M, int N, int K)
{
    extern __shared__ char sm[];
    const uint32_t smb = smem_u32(sm);

    const int tid = threadIdx.x;
    const int warp = tid >> 5;
    const int lane = tid & 31;
    const int wm = warp >> 1;
    const int wn = warp & 1;
    const int g = lane >> 2;
    const int t = lane & 3;
    const int bm = blockIdx.y * 256;
    const int bn = blockIdx.x * 128;
    const int nk = K >> 5;

    const int a_r  = (lane & 7) + ((lane >> 3) & 1) * 8;
    const int a_c8 = (lane >> 4) * 8;
    const int b_r  = lane & 7;
    const int b_j  = lane >> 4;
    const int b_c8 = ((lane >> 3) & 1) * 8;

    float acc[4][8][4];
#pragma unroll
    for (int i = 0; i < 4; i++)
#pragma unroll
        for (int j = 0; j < 8; j++)
#pragma unroll
            for (int r = 0; r < 4; r++) acc[i][j][r] = 0.0f;

    auto load_stage = [&](int s, int c) {
        const uint32_t sb = smb + s * STG256S;
        const int k0 = c * 32;
#pragma unroll
        for (int it = 0; it < 4; it++) {
            const int id = tid + it * 256;
            const int r = id >> 2, ch = id & 3;
            const uint32_t off = r * RSTR + ch * 16;
            const size_t ga = (size_t)(bm + r) * K + k0 + ch * 8;
            cp_async16(sb + off, A + ga);
        }
#pragma unroll
        for (int it = 0; it < 2; it++) {
            const int id = tid + it * 256;
            const int r = id >> 2, ch = id & 3;
            const uint32_t off = r * RSTR + ch * 16;
            const size_t gb = (size_t)(bn + r) * K + k0 + ch * 8;
            cp_async16(sb + TILE_A2 + off, B + gb);
        }
        CP_COMMIT();
    };

    load_stage(0, 0);
    if (nk > 1) load_stage(1, 1);
    if (nk > 2) load_stage(2, 2);

    for (int c = 0; c < nk; c++) {
        const int s = c % 3;
        if (c + 2 < nk)      asm volatile("cp.async.wait_group 2;" ::: "memory");
        else if (c + 1 < nk) asm volatile("cp.async.wait_group 1;" ::: "memory");
        else                 asm volatile("cp.async.wait_group 0;" ::: "memory");
        __syncthreads();

        const uint32_t uA = smb + s * STG256S;
        const uint32_t uB = uA + TILE_A2;

#pragma unroll
        for (int ks = 0; ks < 2; ks++) {
            const uint32_t colA = (ks * 16 + a_c8) * 2;
            const uint32_t colB = (ks * 16 + b_c8) * 2;
            uint32_t ah[4][4];
#pragma unroll
            for (int i = 0; i < 4; i++) {
                const uint32_t ro = (wm * 64 + i * 16 + a_r) * RSTR + colA;
                ldsm_x4(ah[i], uA + ro);
            }
#pragma unroll
            for (int p = 0; p < 4; p++) {
                const uint32_t ro = (wn * 64 + (2 * p + b_j) * 8 + b_r) * RSTR + colB;
                uint32_t bh[4];
                ldsm_x4(bh, uB + ro);
#pragma unroll
                for (int i = 0; i < 4; i++) {
                    MMA_F16(acc[i][2*p],   ah[i], bh[0], bh[1]);
                    MMA_F16(acc[i][2*p+1], ah[i], bh[2], bh[3]);
                }
            }
        }
        __syncthreads();
        if (c + 3 < nk) load_stage(s, c + 3);
    }

#pragma unroll
    for (int i = 0; i < 4; i++) {
        const int row0 = bm + wm * 64 + i * 16 + g;
#pragma unroll
        for (int j = 0; j < 8; j++) {
            const int col = bn + wn * 64 + j * 8 + 2 * t;
            *(float2*)(C + (size_t)row0 * N + col) = make_float2(acc[i][j][0], acc[i][j][1]);
            *(float2*)(C + (size_t)(row0 + 8) * N + col) = make_float2(acc[i][j][2], acc[i][j][3]);
        }
    }
}

// ======================= RoPE: fp16 single out (256-thread blocks) =========
__global__ void rope16(const float* __restrict__ raw, const float* __restrict__ cs,
                       const float* __restrict__ sn, __half* __restrict__ out,
                       int nh, float scale) {
    const int tid = threadIdx.x;
    const int j = tid & 63;
    const int so = tid >> 6;                 // 0..3
    const int s = blockIdx.x * 4 + so;
    const int h = blockIdx.y;
    const float* r = raw + ((size_t)s * nh + h) * HD;
    const float x1 = r[j];
    const float x2 = r[j + 64];
    const float c = cs[s * 64 + j];
    const float si = sn[s * 64 + j];
    const size_t base = ((size_t)h * S_LEN + s) * HD;
    out[base + j]      = __float2half_rn((x1 * c - x2 * si) * scale);
    out[base + j + 64] = __float2half_rn((x2 * c + x1 * si) * scale);
}

// ======================= V transpose + fp16 ================================
__global__ void vt_split16(const float* __restrict__ v, __half* __restrict__ vt) {
    __shared__ float tile[32][33];
    const int kvh = blockIdx.z;
    const int s0 = blockIdx.x * 32;
    const int d0 = blockIdx.y * 32;
    const int tx = threadIdx.x, ty = threadIdx.y;  // 32 x 8
    for (int i = ty; i < 32; i += 8)
        tile[i][tx] = v[((size_t)kvh * S_LEN + s0 + i) * HD + d0 + tx];
    __syncthreads();
    for (int i = ty; i < 32; i += 8) {
        const float val = tile[tx][i];
        vt[((size_t)kvh * HD + d0 + i) * S_LEN + s0 + tx] = __float2half_rn(val);
    }
}

// ======================= Flash attention (all single-fp16 MMA) =============
#define QSTR 272
#define VSTR 144
#define FA_QB (128 * QSTR)                 // 34816
#define FA_KB (64 * QSTR)                  // 17408
#define FA_VB (128 * VSTR)                 // 18432
#define FA_STAGE (FA_KB + FA_VB)           // 35840
#define FA_SMEM (FA_QB + 2 * FA_STAGE)     // 106496

__global__ __launch_bounds__(256, 2) void flash_attn_tc(
    const __half* __restrict__ Qf, const __half* __restrict__ Kf,
    const __half* __restrict__ Vt, __half* __restrict__ O)
{
    extern __shared__ char fsm[];
    const uint32_t smb = smem_u32(fsm);
    const int qb = gridDim.x - 1 - blockIdx.x;
    const int h  = blockIdx.y;
    const int kvh = h % NKV;
    const int q0 = qb * 128;
    const int tid = threadIdx.x;
    const int w = tid >> 5;
    const int lane = tid & 31;
    const int g = lane >> 2;
    const int t = lane & 3;

    const int a_r  = (lane & 7) + ((lane >> 3) & 1) * 8;
    const int a_c8 = (lane >> 4) * 8;
    const int b_r  = lane & 7;
    const int b_j  = lane >> 4;
    const int b_c8 = ((lane >> 3) & 1) * 8;

#pragma unroll
    for (int it = 0; it < 8; it++) {
        const int id = tid + 256 * it;
        const int r = id >> 4, ch = id & 15;
        const uint32_t off = r * QSTR + ch * 16;
        const size_t gi = ((size_t)h * S_LEN + q0 + r) * HD + ch * 8;
        cp_async16(smb + off, Qf + gi);
    }

    auto fa_load = [&](int s, int jb) {
        const uint32_t sb = smb + FA_QB + s * FA_STAGE;
        const int k0 = jb * 64;
#pragma unroll
        for (int it = 0; it < 4; it++) {
            const int id = tid + 256 * it;
            const int r = id >> 4, ch = id & 15;
            const uint32_t off = r * QSTR + ch * 16;
            const size_t gi = ((size_t)kvh * S_LEN + k0 + r) * HD + ch * 8;
            cp_async16(sb + off, Kf + gi);
        }
#pragma unroll
        for (int it = 0; it < 4; it++) {
            const int id = tid + 256 * it;
            const int r = id >> 3, ch = id & 7;
            const uint32_t off = r * VSTR + ch * 16;
            const size_t gi = ((size_t)kvh * HD + r) * S_LEN + k0 + ch * 8;
            cp_async16(sb + FA_KB + off, Vt + gi);
        }
    };

    const int njb = 2 * qb + 2;
    fa_load(0, 0);
    CP_COMMIT();
    fa_load(1, 1);
    CP_COMMIT();

    float oacc[16][4];
#pragma unroll
    for (int jd = 0; jd < 16; jd++)
#pragma unroll
        for (int r = 0; r < 4; r++) oacc[jd][r] = 0.0f;
    float m0 = -1e30f, m1 = -1e30f, l0 = 0.0f, l1 = 0.0f;

    const uint32_t uQ = smb;

    for (int jb = 0; jb < njb; jb++) {
        const int s = jb & 1;
        if (jb + 1 < njb) asm volatile("cp.async.wait_group 1;" ::: "memory");
        else              asm volatile("cp.async.wait_group 0;" ::: "memory");
        __syncthreads();

        const uint32_t uK = smb + FA_QB + s * FA_STAGE;
        const uint32_t uV = uK + FA_KB;

        // ---- S = Q @ K^T ----
        float sv[8][4];
#pragma unroll
        for (int j = 0; j < 8; j++)
#pragma unroll
            for (int r = 0; r < 4; r++) sv[j][r] = 0.0f;

#pragma unroll
        for (int kt = 0; kt < 8; kt++) {
            const uint32_t qro = (16 * w + a_r) * QSTR + (kt * 16 + a_c8) * 2;
            uint32_t qh[4];
            ldsm_x4(qh, uQ + qro);
#pragma unroll
            for (int p = 0; p < 4; p++) {
                const uint32_t kro = ((2 * p + b_j) * 8 + b_r) * QSTR + (kt * 16 + b_c8) * 2;
                uint32_t kh[4];
                ldsm_x4(kh, uK + kro);
                MMA_F16(sv[2*p],   qh, kh[0], kh[1]);
                MMA_F16(sv[2*p+1], qh, kh[2], kh[3]);
            }
        }

        if (jb >= 2 * qb) {
            const int r0g = q0 + 16 * w + g;
            const int r1g = r0g + 8;
            const int kg = jb * 64;
#pragma unroll
            for (int j = 0; j < 8; j++) {
                const int c0 = kg + 8 * j + 2 * t, c1 = c0 + 1;
                if (c0 > r0g) sv[j][0] = -1e30f;
                if (c1 > r0g) sv[j][1] = -1e30f;
                if (c0 > r1g) sv[j][2] = -1e30f;
                if (c1 > r1g) sv[j][3] = -1e30f;
            }
        }

        float mn0 = m0, mn1 = m1;
#pragma unroll
        for (int j = 0; j < 8; j++) {
            mn0 = fmaxf(mn0, fmaxf(sv[j][0], sv[j][1]));
            mn1 = fmaxf(mn1, fmaxf(sv[j][2], sv[j][3]));
        }
        mn0 = fmaxf(mn0, __shfl_xor_sync(0xffffffffu, mn0, 1));
        mn0 = fmaxf(mn0, __shfl_xor_sync(0xffffffffu, mn0, 2));
        mn1 = fmaxf(mn1, __shfl_xor_sync(0xffffffffu, mn1, 1));
        mn1 = fmaxf(mn1, __shfl_xor_sync(0xffffffffu, mn1, 2));

        const float corr0 = __expf(m0 - mn0);
        const float corr1 = __expf(m1 - mn1);
        float rs0 = 0.0f, rs1 = 0.0f;
#pragma unroll
        for (int j = 0; j < 8; j++) {
            sv[j][0] = __expf(sv[j][0] - mn0);
            sv[j][1] = __expf(sv[j][1] - mn0);
            sv[j][2] = __expf(sv[j][2] - mn1);
            sv[j][3] = __expf(sv[j][3] - mn1);
            rs0 += sv[j][0] + sv[j][1];
            rs1 += sv[j][2] + sv[j][3];
        }
        rs0 += __shfl_xor_sync(0xffffffffu, rs0, 1);
        rs0 += __shfl_xor_sync(0xffffffffu, rs0, 2);
        rs1 += __shfl_xor_sync(0xffffffffu, rs1, 1);
        rs1 += __shfl_xor_sync(0xffffffffu, rs1, 2);
        l0 = l0 * corr0 + rs0;
        l1 = l1 * corr1 + rs1;
        m0 = mn0; m1 = mn1;

#pragma unroll
        for (int jd = 0; jd < 16; jd++) {
            oacc[jd][0] *= corr0; oacc[jd][1] *= corr0;
            oacc[jd][2] *= corr1; oacc[jd][3] *= corr1;
        }

        // ---- O += P @ V ----
#pragma unroll
        for (int kt = 0; kt < 4; kt++) {
            uint32_t ph[4];
            ph[0] = pack2h(sv[2*kt][0],   sv[2*kt][1]);
            ph[1] = pack2h(sv[2*kt][2],   sv[2*kt][3]);
            ph[2] = pack2h(sv[2*kt+1][0], sv[2*kt+1][1]);
            ph[3] = pack2h(sv[2*kt+1][2], sv[2*kt+1][3]);
#pragma unroll
            for (int p = 0; p < 8; p++) {
                const uint32_t vro = ((2 * p + b_j) * 8 + b_r) * VSTR + (kt * 16 + b_c8) * 2;
                uint32_t vh[4];
                ldsm_x4(vh, uV + vro);
                MMA_F16(oacc[2*p],   ph, vh[0], vh[1]);
                MMA_F16(oacc[2*p+1], ph, vh[2], vh[3]);
            }
        }

        __syncthreads();
        if (jb + 2 < njb) { fa_load(s, jb + 2); CP_COMMIT(); }
    }

    // ---- normalize + single-fp16 store ----
    const float inv0 = 1.0f / l0;
    const float inv1 = 1.0f / l1;
    const int s0 = q0 + 16 * w + g;
    const int s1 = s0 + 8;
#pragma unroll
    for (int jd = 0; jd < 16; jd++) {
        const int d = 8 * jd + 2 * t;
        const size_t i0 = (size_t)s0 * HID + h * HD + d;
        const size_t i1 = (size_t)s1 * HID + h * HD + d;
        *(uint32_t*)(O + i0) = pack2h(oacc[jd][0] * inv0, oacc[jd][1] * inv0);
        *(uint32_t*)(O + i1) = pack2h(oacc[jd][2] * inv1, oacc[jd][3] * inv1);
    }
}

// ======================= launch ============================================
extern "C" void kernel_launch(void* const* d_in, const int* in_sizes, int n_in,
                              void* d_out, int out_size) {
    const float* x  = (const float*)d_in[0];
    const float* wq = (const float*)d_in[1];
    const float* wk = (const float*)d_in[2];
    const float* wv = (const float*)d_in[3];
    const float* wo = (const float*)d_in[4];
    const float* cs = (const float*)d_in[5];
    const float* sn = (const float*)d_in[6];
    float* out = (float*)d_out;

    float *qraw, *kraw, *v;
    __nv_bfloat16 *xhi, *xlo, *wkhi, *wklo;
    __half *xh16, *xl16, *wq16, *wv16, *wo16, *att16, *vt16, *qh16, *k16;
    cudaGetSymbolAddress((void**)&qraw, g_qraw);
    cudaGetSymbolAddress((void**)&kraw, g_kraw);
    cudaGetSymbolAddress((void**)&v, g_v);
    cudaGetSymbolAddress((void**)&xhi, g_xhi);   cudaGetSymbolAddress((void**)&xlo, g_xlo);
    cudaGetSymbolAddress((void**)&wkhi, g_wkhi); cudaGetSymbolAddress((void**)&wklo, g_wklo);
    cudaGetSymbolAddress((void**)&xh16, g_xh16); cudaGetSymbolAddress((void**)&xl16, g_xl16);
    cudaGetSymbolAddress((void**)&wq16, g_wq16);
    cudaGetSymbolAddress((void**)&wv16, g_wv16); cudaGetSymbolAddress((void**)&wo16, g_wo16);
    cudaGetSymbolAddress((void**)&att16, g_att16);
    cudaGetSymbolAddress((void**)&vt16, g_vt16);
    cudaGetSymbolAddress((void**)&qh16, g_qh16);
    cudaGetSymbolAddress((void**)&k16, g_k16);

    cudaFuncSetAttribute(gemm_kv, cudaFuncAttributeMaxDynamicSharedMemorySize, GEMM_SMEM);
    cudaFuncSetAttribute(gemm_tc256s, cudaFuncAttributeMaxDynamicSharedMemorySize, GEMM256S_SMEM);
    cudaFuncSetAttribute(flash_attn_tc, cudaFuncAttributeMaxDynamicSharedMemorySize, FA_SMEM);

    // splits
    {
        int n4 = (S_LEN * HID) / 4;
        split_dual_kernel<<<(n4 + 255) / 256, 256>>>(
            (const float4*)x, (uint2*)xhi, (uint2*)xlo, (uint2*)xh16, (uint2*)xl16, n4);
    }
    {
        int n4 = (HID * HID) / 4;
        split16s_kernel<<<(n4 + 255) / 256, 256>>>((const float4*)wq, (uint2*)wq16, n4);
        split16s_kernel<<<(n4 + 255) / 256, 256>>>((const float4*)wo, (uint2*)wo16, n4);
    }
    {
        int n4 = (NKV * HD * HID) / 4;
        split_kernel<<<(n4 + 255) / 256, 256>>>((const float4*)wk, (uint2*)wkhi, (uint2*)wklo, n4);
        split16s_kernel<<<(n4 + 255) / 256, 256>>>((const float4*)wv, (uint2*)wv16, n4);
    }

    // Q projection (fp16 1-MMA, 256-tile, 3-stage)
    gemm_tc256s<<<dim3(HID / 128, S_LEN / 256), 256, GEMM256S_SMEM>>>(
        xh16, wq16, qraw, S_LEN, HID, HID);
    // fused K (bf16 3-MMA) + V (fp16 2-MMA) projections
    gemm_kv<<<dim3(16, S_LEN / 128), 256, GEMM_SMEM>>>(
        xhi, xlo, wkhi, wklo, kraw, xh16, xl16, wv16, v);

    // RoPE: Q -> fp16 (scale folded), K -> fp16; V transpose fp16
    const float scale = 0.08838834764831845f;
    rope16<<<dim3(S_LEN / 4, NH), 256>>>(qraw, cs, sn, qh16, NH, scale);
    rope16<<<dim3(S_LEN / 4, NKV), 256>>>(kraw, cs, sn, k16, NKV, 1.0f);
    vt_split16<<<dim3(S_LEN / 32, HD / 32, NKV), dim3(32, 8)>>>(v, vt16);

    // tensor-core flash attention (single fp16 att output)
    flash_attn_tc<<<dim3(S_LEN / 128, NH), 256, FA_SMEM>>>(
        qh16, k16, vt16, att16);

    // output projection (fp16 1-MMA, 256-tile, 3-stage)
    gemm_tc256s<<<dim3(HID / 128, S_LEN / 256), 256, GEMM256S_SMEM>>>(
        att16, wo16, out, S_LEN, HID, HID);
}

// round 12
// speedup vs baseline: 5.4290x; 1.0966x over previous
#include <cuda_runtime.h>
#include <cuda_bf16.h>
#include <cuda_fp16.h>
#include <stdint.h>
#include <math.h>

#define S_LEN 2048
#define HID 4096
#define NH 32
#define NKV 8
#define HD 128

// ---------------- scratch ---------------------------------------------------
__device__ float g_qraw[S_LEN * HID];
__device__ float g_kraw[S_LEN * NKV * HD];

__device__ __half g_xh16[S_LEN * HID], g_xl16[S_LEN * HID];
__device__ __half g_wq16[HID * HID];
__device__ __half g_wk16[NKV*HD * HID];
__device__ __half g_wv16[NKV*HD * HID];
__device__ __half g_wo16[HID * HID];
__device__ __half g_att16[S_LEN * HID];
__device__ __half g_vt16[NKV * HD * S_LEN];

__device__ __half g_qh16[NH * S_LEN * HD];
__device__ __half g_k16[NKV * S_LEN * HD];

// ======================= helpers ===========================================
__device__ __forceinline__ uint32_t smem_u32(const void* p) {
    uint32_t a;
    asm("{ .reg .u64 t; cvta.to.shared.u64 t, %1; cvt.u32.u64 %0, t; }" : "=r"(a) : "l"(p));
    return a;
}
__device__ __forceinline__ void cp_async16(uint32_t saddr, const void* g) {
    asm volatile("cp.async.cg.shared.global [%0], [%1], 16;" :: "r"(saddr), "l"(g));
}
#define CP_COMMIT() asm volatile("cp.async.commit_group;" ::: "memory")

#define MMA_F16(c, a, b0, b1)                                                  \
    asm volatile("mma.sync.aligned.m16n8k16.row.col.f32.f16.f16.f32 "          \
        "{%0,%1,%2,%3}, {%4,%5,%6,%7}, {%8,%9}, {%0,%1,%2,%3};"                \
        : "+f"((c)[0]), "+f"((c)[1]), "+f"((c)[2]), "+f"((c)[3])               \
        : "r"((a)[0]), "r"((a)[1]), "r"((a)[2]), "r"((a)[3]), "r"(b0), "r"(b1))

__device__ __forceinline__ void ldsm_x4(uint32_t* r, uint32_t addr) {
    asm volatile("ldmatrix.sync.aligned.m8n8.x4.shared.b16 {%0,%1,%2,%3}, [%4];"
        : "=r"(r[0]), "=r"(r[1]), "=r"(r[2]), "=r"(r[3]) : "r"(addr));
}
__device__ __forceinline__ uint32_t pack2h(float x, float y) {
    __half2 h = __floats2half2_rn(x, y);
    return *(uint32_t*)&h;
}

// ======================= split kernels =====================================
// fp32 -> fp16 hi/lo
__global__ void split16hl_kernel(const float4* __restrict__ in,
                                 uint2* __restrict__ hi, uint2* __restrict__ lo, int n4) {
    int i = blockIdx.x * blockDim.x + threadIdx.x;
    if (i >= n4) return;
    float4 v = in[i];
    __half h[4], l[4];
    h[0] = __float2half_rn(v.x); l[0] = __float2half_rn(v.x - __half2float(h[0]));
    h[1] = __float2half_rn(v.y); l[1] = __float2half_rn(v.y - __half2float(h[1]));
    h[2] = __float2half_rn(v.z); l[2] = __float2half_rn(v.z - __half2float(h[2]));
    h[3] = __float2half_rn(v.w); l[3] = __float2half_rn(v.w - __half2float(h[3]));
    hi[i] = *(uint2*)h;
    lo[i] = *(uint2*)l;
}

__global__ void split16s_kernel(const float4* __restrict__ in,
                                uint2* __restrict__ hi, int n4) {
    int i = blockIdx.x * blockDim.x + threadIdx.x;
    if (i >= n4) return;
    float4 v = in[i];
    __half h[4];
    h[0] = __float2half_rn(v.x);
    h[1] = __float2half_rn(v.y);
    h[2] = __float2half_rn(v.z);
    h[3] = __float2half_rn(v.w);
    hi[i] = *(uint2*)h;
}

// ======================= common tile constants =============================
#define RSTR 112
#define TILE_B (128 * RSTR)            // 14336
#define TILE_A2 (256 * RSTR)           // 28672
#define STAGE2_B (3 * TILE_B)          // 43008
#define KV_SMEM (3 * STAGE2_B)         // 129024

// ======================= fused K+V projections (both fp16 2-MMA) ===========
// grid (16, 16): bx<8 -> K tile (fp32 row-major out), bx>=8 -> V tile
// (fp16 transposed out via smem-staged epilogue). M=2048, N=1024, K=4096.
__global__ __launch_bounds__(256, 1) void gemm_kv(
    const __half* __restrict__ Xhh, const __half* __restrict__ Xhl,
    const __half* __restrict__ Wk, float* __restrict__ Ck,
    const __half* __restrict__ Wv, __half* __restrict__ Vt)
{
    extern __shared__ char sm[];
    const uint32_t smb = smem_u32(sm);

    const int tid = threadIdx.x;
    const int warp = tid >> 5;
    const int lane = tid & 31;
    const int wm = warp >> 2;
    const int wn = warp & 3;
    const int g = lane >> 2;
    const int t = lane & 3;
    const int bm = blockIdx.y * 128;
    const int K = HID, N = NKV * HD;
    const int nk = K >> 5;
    const bool isK = blockIdx.x < 8;
    const int bn = (blockIdx.x & 7) * 128;
    const __half* B = isK ? Wk : Wv;

    const int a_r  = (lane & 7) + ((lane >> 3) & 1) * 8;
    const int a_c8 = (lane >> 4) * 8;
    const int b_r  = lane & 7;
    const int b_j  = lane >> 4;
    const int b_c8 = ((lane >> 3) & 1) * 8;

    float acc[4][4][4];
#pragma unroll
    for (int i = 0; i < 4; i++)
#pragma unroll
        for (int j = 0; j < 4; j++)
#pragma unroll
            for (int r = 0; r < 4; r++) acc[i][j][r] = 0.0f;

    auto load_stage = [&](int s, int c) {
        const uint32_t sb = smb + s * STAGE2_B;
        const int k0 = c * 32;
#pragma unroll
        for (int it = 0; it < 2; it++) {
            const int id = tid + it * 256;
            const int r = id >> 2, ch = id & 3;
            const uint32_t off = r * RSTR + ch * 16;
            const size_t ga = (size_t)(bm + r) * K + k0 + ch * 8;
            const size_t gb = (size_t)(bn + r) * K + k0 + ch * 8;
            cp_async16(sb + off,              Xhh + ga);
            cp_async16(sb + TILE_B + off,     Xhl + ga);
            cp_async16(sb + 2 * TILE_B + off, B + gb);
        }
        CP_COMMIT();
    };

    load_stage(0, 0);
    load_stage(1, 1);
    load_stage(2, 2);

    for (int c = 0; c < nk; c++) {
        const int s = c % 3;
        if (c + 2 < nk)      asm volatile("cp.async.wait_group 2;" ::: "memory");
        else if (c + 1 < nk) asm volatile("cp.async.wait_group 1;" ::: "memory");
        else                 asm volatile("cp.async.wait_group 0;" ::: "memory");
        __syncthreads();

        const uint32_t uAh = smb + s * STAGE2_B;
        const uint32_t uAl = uAh + TILE_B;
        const uint32_t uB  = uAh + 2 * TILE_B;

#pragma unroll
        for (int ks = 0; ks < 2; ks++) {
            const uint32_t colA = (ks * 16 + a_c8) * 2;
            const uint32_t colB = (ks * 16 + b_c8) * 2;
            uint32_t ah[4][4], al[4][4];
#pragma unroll
            for (int i = 0; i < 4; i++) {
                const uint32_t ro = (wm * 64 + i * 16 + a_r) * RSTR + colA;
                ldsm_x4(ah[i], uAh + ro);
                ldsm_x4(al[i], uAl + ro);
            }
#pragma unroll
            for (int p = 0; p < 2; p++) {
                const uint32_t ro = (wn * 32 + (2 * p + b_j) * 8 + b_r) * RSTR + colB;
                uint32_t bh[4];
                ldsm_x4(bh, uB + ro);
#pragma unroll
                for (int i = 0; i < 4; i++) {
                    MMA_F16(acc[i][2*p],   ah[i], bh[0], bh[1]);
                    MMA_F16(acc[i][2*p],   al[i], bh[0], bh[1]);
                    MMA_F16(acc[i][2*p+1], ah[i], bh[2], bh[3]);
                    MMA_F16(acc[i][2*p+1], al[i], bh[2], bh[3]);
                }
            }
        }
        __syncthreads();
        if (c + 3 < nk) load_stage(s, c + 3);
    }

    if (isK) {
        // K: fp32 row-major (rope follows)
#pragma unroll
        for (int i = 0; i < 4; i++) {
            const int row0 = bm + wm * 64 + i * 16 + g;
#pragma unroll
            for (int j = 0; j < 4; j++) {
                const int col = bn + wn * 32 + j * 8 + 2 * t;
                *(float2*)(Ck + (size_t)row0 * N + col) = make_float2(acc[i][j][0], acc[i][j][1]);
                *(float2*)(Ck + (size_t)(row0 + 8) * N + col) = make_float2(acc[i][j][2], acc[i][j][3]);
            }
        }
    } else {
        // V: fused transpose via smem staging -> vt16[kvh][d][s] fp16
        __half* st = (__half*)sm;    // [128 d][136 stride] halves (34KB)
#pragma unroll
        for (int i = 0; i < 4; i++) {
            const int sl = wm * 64 + i * 16 + g;
#pragma unroll
            for (int j = 0; j < 4; j++) {
                const int d0 = wn * 32 + j * 8 + 2 * t;
                st[(d0    ) * 136 + sl    ] = __float2half_rn(acc[i][j][0]);
                st[(d0 + 1) * 136 + sl    ] = __float2half_rn(acc[i][j][1]);
                st[(d0    ) * 136 + sl + 8] = __float2half_rn(acc[i][j][2]);
                st[(d0 + 1) * 136 + sl + 8] = __float2half_rn(acc[i][j][3]);
            }
        }
        __syncthreads();
        const int kvh = blockIdx.x - 8;
#pragma unroll
        for (int it = 0; it < 8; it++) {
            const int id = tid + 256 * it;      // 0..2047
            const int d = id >> 4, seg = id & 15;
            uint4 val = *(uint4*)&st[d * 136 + seg * 8];
            *(uint4*)(g_vt16 + ((size_t)(kvh * HD + d)) * S_LEN + bm + seg * 8) = val;
        }
        (void)Vt;
    }
}

// ======================= 256x128 fp16 1-MMA GEMM (Q & O projections) =======
#define STG256S (TILE_A2 + TILE_B)              // 43008
#define GEMM256S_SMEM (3 * STG256S)             // 129024

__global__ __launch_bounds__(256, 1) void gemm_tc256s(
    const __half* __restrict__ A, const __half* __restrict__ B,
    float* __restrict__ C, int M, int N, int K)
{
    extern __shared__ char sm[];
    const uint32_t smb = smem_u32(sm);

    const int tid = threadIdx.x;
    const int warp = tid >> 5;
    const int lane = tid & 31;
    const int wm = warp >> 1;
    const int wn = warp & 1;
    const int g = lane >> 2;
    const int t = lane & 3;
    const int bm = blockIdx.y * 256;
    const int bn = blockIdx.x * 128;
    const int nk = K >> 5;

    const int a_r  = (lane & 7) + ((lane >> 3) & 1) * 8;
    const int a_c8 = (lane >> 4) * 8;
    const int b_r  = lane & 7;
    const int b_j  = lane >> 4;
    const int b_c8 = ((lane >> 3) & 1) * 8;

    float acc[4][8][4];
#pragma unroll
    for (int i = 0; i < 4; i++)
#pragma unroll
        for (int j = 0; j < 8; j++)
#pragma unroll
            for (int r = 0; r < 4; r++) acc[i][j][r] = 0.0f;

    auto load_stage = [&](int s, int c) {
        const uint32_t sb = smb + s * STG256S;
        const int k0 = c * 32;
#pragma unroll
        for (int it = 0; it < 4; it++) {
            const int id = tid + it * 256;
            const int r = id >> 2, ch = id & 3;
            const uint32_t off = r * RSTR + ch * 16;
            const size_t ga = (size_t)(bm + r) * K + k0 + ch * 8;
            cp_async16(sb + off, A + ga);
        }
#pragma unroll
        for (int it = 0; it < 2; it++) {
            const int id = tid + it * 256;
            const int r = id >> 2, ch = id & 3;
            const uint32_t off = r * RSTR + ch * 16;
            const size_t gb = (size_t)(bn + r) * K + k0 + ch * 8;
            cp_async16(sb + TILE_A2 + off, B + gb);
        }
        CP_COMMIT();
    };

    load_stage(0, 0);
    if (nk > 1) load_stage(1, 1);
    if (nk > 2) load_stage(2, 2);

    for (int c = 0; c < nk; c++) {
        const int s = c % 3;
        if (c + 2 < nk)      asm volatile("cp.async.wait_group 2;" ::: "memory");
        else if (c + 1 < nk) asm volatile("cp.async.wait_group 1;" ::: "memory");
        else                 asm volatile("cp.async.wait_group 0;" ::: "memory");
        __syncthreads();

        const uint32_t uA = smb + s * STG256S;
        const uint32_t uB = uA + TILE_A2;

#pragma unroll
        for (int ks = 0; ks < 2; ks++) {
            const uint32_t colA = (ks * 16 + a_c8) * 2;
            const uint32_t colB = (ks * 16 + b_c8) * 2;
            uint32_t ah[4][4];
#pragma unroll
            for (int i = 0; i < 4; i++) {
                const uint32_t ro = (wm * 64 + i * 16 + a_r) * RSTR + colA;
                ldsm_x4(ah[i], uA + ro);
            }
#pragma unroll
            for (int p = 0; p < 4; p++) {
                const uint32_t ro = (wn * 64 + (2 * p + b_j) * 8 + b_r) * RSTR + colB;
                uint32_t bh[4];
                ldsm_x4(bh, uB + ro);
#pragma unroll
                for (int i = 0; i < 4; i++) {
                    MMA_F16(acc[i][2*p],   ah[i], bh[0], bh[1]);
                    MMA_F16(acc[i][2*p+1], ah[i], bh[2], bh[3]);
                }
            }
        }
        __syncthreads();
        if (c + 3 < nk) load_stage(s, c + 3);
    }

#pragma unroll
    for (int i = 0; i < 4; i++) {
        const int row0 = bm + wm * 64 + i * 16 + g;
#pragma unroll
        for (int j = 0; j < 8; j++) {
            const int col = bn + wn * 64 + j * 8 + 2 * t;
            *(float2*)(C + (size_t)row0 * N + col) = make_float2(acc[i][j][0], acc[i][j][1]);
            *(float2*)(C + (size_t)(row0 + 8) * N + col) = make_float2(acc[i][j][2], acc[i][j][3]);
        }
    }
}

// ======================= RoPE: fp16 single out (256-thread blocks) =========
__global__ void rope16(const float* __restrict__ raw, const float* __restrict__ cs,
                       const float* __restrict__ sn, __half* __restrict__ out,
                       int nh, float scale) {
    const int tid = threadIdx.x;
    const int j = tid & 63;
    const int so = tid >> 6;                 // 0..3
    const int s = blockIdx.x * 4 + so;
    const int h = blockIdx.y;
    const float* r = raw + ((size_t)s * nh + h) * HD;
    const float x1 = r[j];
    const float x2 = r[j + 64];
    const float c = cs[s * 64 + j];
    const float si = sn[s * 64 + j];
    const size_t base = ((size_t)h * S_LEN + s) * HD;
    out[base + j]      = __float2half_rn((x1 * c - x2 * si) * scale);
    out[base + j + 64] = __float2half_rn((x2 * c + x1 * si) * scale);
}

// ======================= Flash attention (all single-fp16 MMA) =============
#define QSTR 272
#define VSTR 144
#define FA_QB (128 * QSTR)                 // 34816
#define FA_KB (64 * QSTR)                  // 17408
#define FA_VB (128 * VSTR)                 // 18432
#define FA_STAGE (FA_KB + FA_VB)           // 35840
#define FA_SMEM (FA_QB + 2 * FA_STAGE)     // 106496

__global__ __launch_bounds__(256, 2) void flash_attn_tc(
    const __half* __restrict__ Qf, const __half* __restrict__ Kf,
    const __half* __restrict__ Vt, __half* __restrict__ O)
{
    extern __shared__ char fsm[];
    const uint32_t smb = smem_u32(fsm);
    const int qb = gridDim.x - 1 - blockIdx.x;
    const int h  = blockIdx.y;
    const int kvh = h % NKV;
    const int q0 = qb * 128;
    const int tid = threadIdx.x;
    const int w = tid >> 5;
    const int lane = tid & 31;
    const int g = lane >> 2;
    const int t = lane & 3;

    const int a_r  = (lane & 7) + ((lane >> 3) & 1) * 8;
    const int a_c8 = (lane >> 4) * 8;
    const int b_r  = lane & 7;
    const int b_j  = lane >> 4;
    const int b_c8 = ((lane >> 3) & 1) * 8;

#pragma unroll
    for (int it = 0; it < 8; it++) {
        const int id = tid + 256 * it;
        const int r = id >> 4, ch = id & 15;
        const uint32_t off = r * QSTR + ch * 16;
        const size_t gi = ((size_t)h * S_LEN + q0 + r) * HD + ch * 8;
        cp_async16(smb + off, Qf + gi);
    }

    auto fa_load = [&](int s, int jb) {
        const uint32_t sb = smb + FA_QB + s * FA_STAGE;
        const int k0 = jb * 64;
#pragma unroll
        for (int it = 0; it < 4; it++) {
            const int id = tid + 256 * it;
            const int r = id >> 4, ch = id & 15;
            const uint32_t off = r * QSTR + ch * 16;
            const size_t gi = ((size_t)kvh * S_LEN + k0 + r) * HD + ch * 8;
            cp_async16(sb + off, Kf + gi);
        }
#pragma unroll
        for (int it = 0; it < 4; it++) {
            const int id = tid + 256 * it;
            const int r = id >> 3, ch = id & 7;
            const uint32_t off = r * VSTR + ch * 16;
            const size_t gi = ((size_t)kvh * HD + r) * S_LEN + k0 + ch * 8;
            cp_async16(sb + FA_KB + off, Vt + gi);
        }
    };

    const int njb = 2 * qb + 2;
    fa_load(0, 0);
    CP_COMMIT();
    fa_load(1, 1);
    CP_COMMIT();

    float oacc[16][4];
#pragma unroll
    for (int jd = 0; jd < 16; jd++)
#pragma unroll
        for (int r = 0; r < 4; r++) oacc[jd][r] = 0.0f;
    float m0 = -1e30f, m1 = -1e30f, l0 = 0.0f, l1 = 0.0f;

    const uint32_t uQ = smb;

    for (int jb = 0; jb < njb; jb++) {
        const int s = jb & 1;
        if (jb + 1 < njb) asm volatile("cp.async.wait_group 1;" ::: "memory");
        else              asm volatile("cp.async.wait_group 0;" ::: "memory");
        __syncthreads();

        const uint32_t uK = smb + FA_QB + s * FA_STAGE;
        const uint32_t uV = uK + FA_KB;

        // ---- S = Q @ K^T ----
        float sv[8][4];
#pragma unroll
        for (int j = 0; j < 8; j++)
#pragma unroll
            for (int r = 0; r < 4; r++) sv[j][r] = 0.0f;

#pragma unroll
        for (int kt = 0; kt < 8; kt++) {
            const uint32_t qro = (16 * w + a_r) * QSTR + (kt * 16 + a_c8) * 2;
            uint32_t qh[4];
            ldsm_x4(qh, uQ + qro);
#pragma unroll
            for (int p = 0; p < 4; p++) {
                const uint32_t kro = ((2 * p + b_j) * 8 + b_r) * QSTR + (kt * 16 + b_c8) * 2;
                uint32_t kh[4];
                ldsm_x4(kh, uK + kro);
                MMA_F16(sv[2*p],   qh, kh[0], kh[1]);
                MMA_F16(sv[2*p+1], qh, kh[2], kh[3]);
            }
        }

        if (jb >= 2 * qb) {
            const int r0g = q0 + 16 * w + g;
            const int r1g = r0g + 8;
            const int kg = jb * 64;
#pragma unroll
            for (int j = 0; j < 8; j++) {
                const int c0 = kg + 8 * j + 2 * t, c1 = c0 + 1;
                if (c0 > r0g) sv[j][0] = -1e30f;
                if (c1 > r0g) sv[j][1] = -1e30f;
                if (c0 > r1g) sv[j][2] = -1e30f;
                if (c1 > r1g) sv[j][3] = -1e30f;
            }
        }

        float mn0 = m0, mn1 = m1;
#pragma unroll
        for (int j = 0; j < 8; j++) {
            mn0 = fmaxf(mn0, fmaxf(sv[j][0], sv[j][1]));
            mn1 = fmaxf(mn1, fmaxf(sv[j][2], sv[j][3]));
        }
        mn0 = fmaxf(mn0, __shfl_xor_sync(0xffffffffu, mn0, 1));
        mn0 = fmaxf(mn0, __shfl_xor_sync(0xffffffffu, mn0, 2));
        mn1 = fmaxf(mn1, __shfl_xor_sync(0xffffffffu, mn1, 1));
        mn1 = fmaxf(mn1, __shfl_xor_sync(0xffffffffu, mn1, 2));

        const float corr0 = __expf(m0 - mn0);
        const float corr1 = __expf(m1 - mn1);
        float rs0 = 0.0f, rs1 = 0.0f;
#pragma unroll
        for (int j = 0; j < 8; j++) {
            sv[j][0] = __expf(sv[j][0] - mn0);
            sv[j][1] = __expf(sv[j][1] - mn0);
            sv[j][2] = __expf(sv[j][2] - mn1);
            sv[j][3] = __expf(sv[j][3] - mn1);
            rs0 += sv[j][0] + sv[j][1];
            rs1 += sv[j][2] + sv[j][3];
        }
        rs0 += __shfl_xor_sync(0xffffffffu, rs0, 1);
        rs0 += __shfl_xor_sync(0xffffffffu, rs0, 2);
        rs1 += __shfl_xor_sync(0xffffffffu, rs1, 1);
        rs1 += __shfl_xor_sync(0xffffffffu, rs1, 2);
        l0 = l0 * corr0 + rs0;
        l1 = l1 * corr1 + rs1;
        m0 = mn0; m1 = mn1;

#pragma unroll
        for (int jd = 0; jd < 16; jd++) {
            oacc[jd][0] *= corr0; oacc[jd][1] *= corr0;
            oacc[jd][2] *= corr1; oacc[jd][3] *= corr1;
        }

        // ---- O += P @ V ----
#pragma unroll
        for (int kt = 0; kt < 4; kt++) {
            uint32_t ph[4];
            ph[0] = pack2h(sv[2*kt][0],   sv[2*kt][1]);
            ph[1] = pack2h(sv[2*kt][2],   sv[2*kt][3]);
            ph[2] = pack2h(sv[2*kt+1][0], sv[2*kt+1][1]);
            ph[3] = pack2h(sv[2*kt+1][2], sv[2*kt+1][3]);
#pragma unroll
            for (int p = 0; p < 8; p++) {
                const uint32_t vro = ((2 * p + b_j) * 8 + b_r) * VSTR + (kt * 16 + b_c8) * 2;
                uint32_t vh[4];
                ldsm_x4(vh, uV + vro);
                MMA_F16(oacc[2*p],   ph, vh[0], vh[1]);
                MMA_F16(oacc[2*p+1], ph, vh[2], vh[3]);
            }
        }

        __syncthreads();
        if (jb + 2 < njb) { fa_load(s, jb + 2); CP_COMMIT(); }
    }

    // ---- normalize + single-fp16 store ----
    const float inv0 = 1.0f / l0;
    const float inv1 = 1.0f / l1;
    const int s0 = q0 + 16 * w + g;
    const int s1 = s0 + 8;
#pragma unroll
    for (int jd = 0; jd < 16; jd++) {
        const int d = 8 * jd + 2 * t;
        const size_t i0 = (size_t)s0 * HID + h * HD + d;
        const size_t i1 = (size_t)s1 * HID + h * HD + d;
        *(uint32_t*)(O + i0) = pack2h(oacc[jd][0] * inv0, oacc[jd][1] * inv0);
        *(uint32_t*)(O + i1) = pack2h(oacc[jd][2] * inv1, oacc[jd][3] * inv1);
    }
}

// ======================= launch ============================================
extern "C" void kernel_launch(void* const* d_in, const int* in_sizes, int n_in,
                              void* d_out, int out_size) {
    const float* x  = (const float*)d_in[0];
    const float* wq = (const float*)d_in[1];
    const float* wk = (const float*)d_in[2];
    const float* wv = (const float*)d_in[3];
    const float* wo = (const float*)d_in[4];
    const float* cs = (const float*)d_in[5];
    const float* sn = (const float*)d_in[6];
    float* out = (float*)d_out;

    float *qraw, *kraw;
    __half *xh16, *xl16, *wq16, *wk16, *wv16, *wo16, *att16, *vt16, *qh16, *k16;
    cudaGetSymbolAddress((void**)&qraw, g_qraw);
    cudaGetSymbolAddress((void**)&kraw, g_kraw);
    cudaGetSymbolAddress((void**)&xh16, g_xh16); cudaGetSymbolAddress((void**)&xl16, g_xl16);
    cudaGetSymbolAddress((void**)&wq16, g_wq16); cudaGetSymbolAddress((void**)&wk16, g_wk16);
    cudaGetSymbolAddress((void**)&wv16, g_wv16); cudaGetSymbolAddress((void**)&wo16, g_wo16);
    cudaGetSymbolAddress((void**)&att16, g_att16);
    cudaGetSymbolAddress((void**)&vt16, g_vt16);
    cudaGetSymbolAddress((void**)&qh16, g_qh16);
    cudaGetSymbolAddress((void**)&k16, g_k16);

    cudaFuncSetAttribute(gemm_kv, cudaFuncAttributeMaxDynamicSharedMemorySize, KV_SMEM);
    cudaFuncSetAttribute(gemm_tc256s, cudaFuncAttributeMaxDynamicSharedMemorySize, GEMM256S_SMEM);
    cudaFuncSetAttribute(flash_attn_tc, cudaFuncAttributeMaxDynamicSharedMemorySize, FA_SMEM);

    // splits (all fp16 now)
    {
        int n4 = (S_LEN * HID) / 4;
        split16hl_kernel<<<(n4 + 255) / 256, 256>>>(
            (const float4*)x, (uint2*)xh16, (uint2*)xl16, n4);
    }
    {
        int n4 = (HID * HID) / 4;
        split16s_kernel<<<(n4 + 255) / 256, 256>>>((const float4*)wq, (uint2*)wq16, n4);
        split16s_kernel<<<(n4 + 255) / 256, 256>>>((const float4*)wo, (uint2*)wo16, n4);
    }
    {
        int n4 = (NKV * HD * HID) / 4;
        split16s_kernel<<<(n4 + 255) / 256, 256>>>((const float4*)wk, (uint2*)wk16, n4);
        split16s_kernel<<<(n4 + 255) / 256, 256>>>((const float4*)wv, (uint2*)wv16, n4);
    }

    // Q projection (fp16 1-MMA, 256-tile, 3-stage)
    gemm_tc256s<<<dim3(HID / 128, S_LEN / 256), 256, GEMM256S_SMEM>>>(
        xh16, wq16, qraw, S_LEN, HID, HID);
    // fused K + V projections (both fp16 2-MMA; V transposed fp16 in-epilogue)
    gemm_kv<<<dim3(16, S_LEN / 128), 256, KV_SMEM>>>(
        xh16, xl16, wk16, kraw, wv16, vt16);

    // RoPE: Q -> fp16 (scale folded), K -> fp16
    const float scale = 0.08838834764831845f;
    rope16<<<dim3(S_LEN / 4, NH), 256>>>(qraw, cs, sn, qh16, NH, scale);
    rope16<<<dim3(S_LEN / 4, NKV), 256>>>(kraw, cs, sn, k16, NKV, 1.0f);

    // tensor-core flash attention
    flash_attn_tc<<<dim3(S_LEN / 128, NH), 256, FA_SMEM>>>(
        qh16, k16, vt16, att16);

    // output projection (fp16 1-MMA, 256-tile, 3-stage)
    gemm_tc256s<<<dim3(HID / 128, S_LEN / 256), 256, GEMM256S_SMEM>>>(
        att16, wo16, out, S_LEN, HID, HID);
}

// round 13
// speedup vs baseline: 5.6192x; 1.0350x over previous
#include <cuda_runtime.h>
#include <cuda_fp16.h>
#include <stdint.h>
#include <math.h>

#define S_LEN 2048
#define HID 4096
#define NH 32
#define NKV 8
#define HD 128

// ---------------- scratch ---------------------------------------------------
__device__ __half g_xh16[S_LEN * HID], g_xl16[S_LEN * HID];
__device__ __half g_wq16[HID * HID];
__device__ __half g_wk16[NKV*HD * HID];
__device__ __half g_wv16[NKV*HD * HID];
__device__ __half g_wo16[HID * HID];
__device__ __half g_att16[S_LEN * HID];
__device__ __half g_vt16[NKV * HD * S_LEN];
__device__ __half g_qh16[NH * S_LEN * HD];
__device__ __half g_k16[NKV * S_LEN * HD];

// ======================= helpers ===========================================
__device__ __forceinline__ uint32_t smem_u32(const void* p) {
    uint32_t a;
    asm("{ .reg .u64 t; cvta.to.shared.u64 t, %1; cvt.u32.u64 %0, t; }" : "=r"(a) : "l"(p));
    return a;
}
__device__ __forceinline__ void cp_async16(uint32_t saddr, const void* g) {
    asm volatile("cp.async.cg.shared.global [%0], [%1], 16;" :: "r"(saddr), "l"(g));
}
#define CP_COMMIT() asm volatile("cp.async.commit_group;" ::: "memory")

#define MMA_F16(c, a, b0, b1)                                                  \
    asm volatile("mma.sync.aligned.m16n8k16.row.col.f32.f16.f16.f32 "          \
        "{%0,%1,%2,%3}, {%4,%5,%6,%7}, {%8,%9}, {%0,%1,%2,%3};"                \
        : "+f"((c)[0]), "+f"((c)[1]), "+f"((c)[2]), "+f"((c)[3])               \
        : "r"((a)[0]), "r"((a)[1]), "r"((a)[2]), "r"((a)[3]), "r"(b0), "r"(b1))

__device__ __forceinline__ void ldsm_x4(uint32_t* r, uint32_t addr) {
    asm volatile("ldmatrix.sync.aligned.m8n8.x4.shared.b16 {%0,%1,%2,%3}, [%4];"
        : "=r"(r[0]), "=r"(r[1]), "=r"(r[2]), "=r"(r[3]) : "r"(addr));
}
__device__ __forceinline__ uint32_t pack2h(float x, float y) {
    __half2 h = __floats2half2_rn(x, y);
    return *(uint32_t*)&h;
}

// ======================= one-shot split of all inputs ======================
#define X4  ((S_LEN * HID) / 4)
#define W44 ((HID * HID) / 4)
#define W14 ((NKV * HD * HID) / 4)
#define SPLIT_TOTAL (X4 + 2 * W44 + 2 * W14)

__global__ void split_all(const float4* __restrict__ x,
                          uint2* __restrict__ xh, uint2* __restrict__ xl,
                          const float4* __restrict__ wq, uint2* __restrict__ wqo,
                          const float4* __restrict__ wk, uint2* __restrict__ wko,
                          const float4* __restrict__ wv, uint2* __restrict__ wvo,
                          const float4* __restrict__ wo, uint2* __restrict__ woo) {
    const int i = blockIdx.x * blockDim.x + threadIdx.x;
    if (i >= SPLIT_TOTAL) return;
    const int A = X4, B = A + W44, C = B + W14, D = C + W14;
    if (i < A) {
        float4 v = x[i];
        __half h[4], l[4];
        h[0] = __float2half_rn(v.x); l[0] = __float2half_rn(v.x - __half2float(h[0]));
        h[1] = __float2half_rn(v.y); l[1] = __float2half_rn(v.y - __half2float(h[1]));
        h[2] = __float2half_rn(v.z); l[2] = __float2half_rn(v.z - __half2float(h[2]));
        h[3] = __float2half_rn(v.w); l[3] = __float2half_rn(v.w - __half2float(h[3]));
        xh[i] = *(uint2*)h;
        xl[i] = *(uint2*)l;
    } else {
        const float4* src;
        uint2* dst;
        int j;
        if (i < B)      { j = i - A; src = wq; dst = wqo; }
        else if (i < C) { j = i - B; src = wk; dst = wko; }
        else if (i < D) { j = i - C; src = wv; dst = wvo; }
        else            { j = i - D; src = wo; dst = woo; }
        float4 v = src[j];
        __half h[4];
        h[0] = __float2half_rn(v.x);
        h[1] = __float2half_rn(v.y);
        h[2] = __float2half_rn(v.z);
        h[3] = __float2half_rn(v.w);
        dst[j] = *(uint2*)h;
    }
}

// ======================= common tile constants =============================
#define RSTR 112
#define TILE_B (128 * RSTR)            // 14336
#define TILE_A2 (256 * RSTR)           // 28672
#define STAGE2_B (3 * TILE_B)          // 43008 (KV: Xh,Xl,B)
#define STG256S (TILE_A2 + TILE_B)     // 43008 (Q: A256,B)
#define QKV_SMEM (3 * STAGE2_B)        // 129024

// ======================= fused Q+K+V projections (one launch) ==============
// Linear grid of 512 CTAs:
//  bid <  256 : Q tile (256x128, 1-MMA, rope+scale epilogue -> qh16[h][s][d])
//  bid >= 256 : K/V tile (128x128, 2-MMA);
//               K: rope epilogue -> k16[kvh][s][d]
//               V: transpose epilogue -> vt16[kvh][d][s]
__global__ __launch_bounds__(256, 1) void gemm_all(
    const __half* __restrict__ Xh, const __half* __restrict__ Xl,
    const __half* __restrict__ Wq, const __half* __restrict__ Wk,
    const __half* __restrict__ Wv,
    const float* __restrict__ cs, const float* __restrict__ sn,
    __half* __restrict__ Qo, __half* __restrict__ Ko, __half* __restrict__ Vto,
    float scale)
{
    extern __shared__ char sm[];
    const uint32_t smb = smem_u32(sm);

    const int bid = blockIdx.x;
    const int tid = threadIdx.x;
    const int warp = tid >> 5;
    const int lane = tid & 31;
    const int g = lane >> 2;
    const int t = lane & 3;
    const int K = HID;
    const int nk = K >> 5;

    const int a_r  = (lane & 7) + ((lane >> 3) & 1) * 8;
    const int a_c8 = (lane >> 4) * 8;
    const int b_r  = lane & 7;
    const int b_j  = lane >> 4;
    const int b_c8 = ((lane >> 3) & 1) * 8;

    if (bid < 256) {
        // ================= Q path: 256x128, 1-MMA =================
        const int bx = bid & 31;           // col tile (= head index)
        const int by = bid >> 5;           // row tile
        const int bm = by * 256;
        const int bn = bx * 128;
        const int wm = warp >> 1;          // 0..3
        const int wn = warp & 1;           // 0..1

        float acc[4][8][4];
#pragma unroll
        for (int i = 0; i < 4; i++)
#pragma unroll
            for (int j = 0; j < 8; j++)
#pragma unroll
                for (int r = 0; r < 4; r++) acc[i][j][r] = 0.0f;

        auto load_stage = [&](int s, int c) {
            const uint32_t sb = smb + s * STG256S;
            const int k0 = c * 32;
#pragma unroll
            for (int it = 0; it < 4; it++) {
                const int id = tid + it * 256;
                const int r = id >> 2, ch = id & 3;
                const uint32_t off = r * RSTR + ch * 16;
                cp_async16(sb + off, Xh + (size_t)(bm + r) * K + k0 + ch * 8);
            }
#pragma unroll
            for (int it = 0; it < 2; it++) {
                const int id = tid + it * 256;
                const int r = id >> 2, ch = id & 3;
                const uint32_t off = r * RSTR + ch * 16;
                cp_async16(sb + TILE_A2 + off, Wq + (size_t)(bn + r) * K + k0 + ch * 8);
            }
            CP_COMMIT();
        };

        load_stage(0, 0);
        load_stage(1, 1);
        load_stage(2, 2);

        for (int c = 0; c < nk; c++) {
            const int s = c % 3;
            if (c + 2 < nk)      asm volatile("cp.async.wait_group 2;" ::: "memory");
            else if (c + 1 < nk) asm volatile("cp.async.wait_group 1;" ::: "memory");
            else                 asm volatile("cp.async.wait_group 0;" ::: "memory");
            __syncthreads();

            const uint32_t uA = smb + s * STG256S;
            const uint32_t uB = uA + TILE_A2;
#pragma unroll
            for (int ks = 0; ks < 2; ks++) {
                const uint32_t colA = (ks * 16 + a_c8) * 2;
                const uint32_t colB = (ks * 16 + b_c8) * 2;
                uint32_t ah[4][4];
#pragma unroll
                for (int i = 0; i < 4; i++) {
                    const uint32_t ro = (wm * 64 + i * 16 + a_r) * RSTR + colA;
                    ldsm_x4(ah[i], uA + ro);
                }
#pragma unroll
                for (int p = 0; p < 4; p++) {
                    const uint32_t ro = (wn * 64 + (2 * p + b_j) * 8 + b_r) * RSTR + colB;
                    uint32_t bh[4];
                    ldsm_x4(bh, uB + ro);
#pragma unroll
                    for (int i = 0; i < 4; i++) {
                        MMA_F16(acc[i][2*p],   ah[i], bh[0], bh[1]);
                        MMA_F16(acc[i][2*p+1], ah[i], bh[2], bh[3]);
                    }
                }
            }
            __syncthreads();
            if (c + 3 < nk) load_stage(s, c + 3);
        }

        // ---- rope epilogue (two 128-row halves through smem) ----
        float* st = (float*)sm;   // [128][132] fp32 = 67.6 KB
#pragma unroll
        for (int half = 0; half < 2; half++) {
            if ((wm >> 1) == half) {
                const int rw = (wm & 1) * 64;
#pragma unroll
                for (int i = 0; i < 4; i++) {
                    const int r0 = rw + i * 16 + g;
#pragma unroll
                    for (int j = 0; j < 8; j++) {
                        const int col = wn * 64 + j * 8 + 2 * t;
                        *(float2*)&st[r0 * 132 + col] =
                            make_float2(acc[i][j][0], acc[i][j][1]);
                        *(float2*)&st[(r0 + 8) * 132 + col] =
                            make_float2(acc[i][j][2], acc[i][j][3]);
                    }
                }
            }
            __syncthreads();
#pragma unroll
            for (int it = 0; it < 32; it++) {
                const int id = tid + 256 * it;       // 0..8191
                const int srow = id >> 6, d = id & 63;
                const int s = bm + half * 128 + srow;
                const float x1 = st[srow * 132 + d];
                const float x2 = st[srow * 132 + d + 64];
                const float c = cs[s * 64 + d];
                const float si = sn[s * 64 + d];
                const size_t base = ((size_t)bx * S_LEN + s) * HD;
                Qo[base + d]      = __float2half_rn((x1 * c - x2 * si) * scale);
                Qo[base + d + 64] = __float2half_rn((x2 * c + x1 * si) * scale);
            }
            __syncthreads();
        }
    } else {
        // ================= K/V path: 128x128, 2-MMA =================
        const int id2 = bid - 256;
        const int bx = id2 & 15;
        const int by = id2 >> 4;
        const int bm = by * 128;
        const bool isK = bx < 8;
        const int bn = (bx & 7) * 128;
        const __half* B = isK ? Wk : Wv;
        const int wm = warp >> 2;          // 0..1
        const int wn = warp & 3;           // 0..3

        float acc[4][4][4];
#pragma unroll
        for (int i = 0; i < 4; i++)
#pragma unroll
            for (int j = 0; j < 4; j++)
#pragma unroll
                for (int r = 0; r < 4; r++) acc[i][j][r] = 0.0f;

        auto load_stage = [&](int s, int c) {
            const uint32_t sb = smb + s * STAGE2_B;
            const int k0 = c * 32;
#pragma unroll
            for (int it = 0; it < 2; it++) {
                const int id = tid + it * 256;
                const int r = id >> 2, ch = id & 3;
                const uint32_t off = r * RSTR + ch * 16;
                const size_t ga = (size_t)(bm + r) * K + k0 + ch * 8;
                const size_t gb = (size_t)(bn + r) * K + k0 + ch * 8;
                cp_async16(sb + off,              Xh + ga);
                cp_async16(sb + TILE_B + off,     Xl + ga);
                cp_async16(sb + 2 * TILE_B + off, B + gb);
            }
            CP_COMMIT();
        };

        load_stage(0, 0);
        load_stage(1, 1);
        load_stage(2, 2);

        for (int c = 0; c < nk; c++) {
            const int s = c % 3;
            if (c + 2 < nk)      asm volatile("cp.async.wait_group 2;" ::: "memory");
            else if (c + 1 < nk) asm volatile("cp.async.wait_group 1;" ::: "memory");
            else                 asm volatile("cp.async.wait_group 0;" ::: "memory");
            __syncthreads();

            const uint32_t uAh = smb + s * STAGE2_B;
            const uint32_t uAl = uAh + TILE_B;
            const uint32_t uB  = uAh + 2 * TILE_B;
#pragma unroll
            for (int ks = 0; ks < 2; ks++) {
                const uint32_t colA = (ks * 16 + a_c8) * 2;
                const uint32_t colB = (ks * 16 + b_c8) * 2;
                uint32_t ah[4][4], al[4][4];
#pragma unroll
                for (int i = 0; i < 4; i++) {
                    const uint32_t ro = (wm * 64 + i * 16 + a_r) * RSTR + colA;
                    ldsm_x4(ah[i], uAh + ro);
                    ldsm_x4(al[i], uAl + ro);
                }
#pragma unroll
                for (int p = 0; p < 2; p++) {
                    const uint32_t ro = (wn * 32 + (2 * p + b_j) * 8 + b_r) * RSTR + colB;
                    uint32_t bh[4];
                    ldsm_x4(bh, uB + ro);
#pragma unroll
                    for (int i = 0; i < 4; i++) {
                        MMA_F16(acc[i][2*p],   ah[i], bh[0], bh[1]);
                        MMA_F16(acc[i][2*p],   al[i], bh[0], bh[1]);
                        MMA_F16(acc[i][2*p+1], ah[i], bh[2], bh[3]);
                        MMA_F16(acc[i][2*p+1], al[i], bh[2], bh[3]);
                    }
                }
            }
            __syncthreads();
            if (c + 3 < nk) load_stage(s, c + 3);
        }

        const int kvh = bn >> 7;
        if (isK) {
            // ---- K: rope epilogue through smem (fp32 staging) ----
            float* st = (float*)sm;    // [128][132] fp32
#pragma unroll
            for (int i = 0; i < 4; i++) {
                const int r0 = wm * 64 + i * 16 + g;
#pragma unroll
                for (int j = 0; j < 4; j++) {
                    const int col = wn * 32 + j * 8 + 2 * t;
                    *(float2*)&st[r0 * 132 + col] = make_float2(acc[i][j][0], acc[i][j][1]);
                    *(float2*)&st[(r0 + 8) * 132 + col] = make_float2(acc[i][j][2], acc[i][j][3]);
                }
            }
            __syncthreads();
#pragma unroll
            for (int it = 0; it < 32; it++) {
                const int id = tid + 256 * it;
                const int srow = id >> 6, d = id & 63;
                const int s = bm + srow;
                const float x1 = st[srow * 132 + d];
                const float x2 = st[srow * 132 + d + 64];
                const float c = cs[s * 64 + d];
                const float si = sn[s * 64 + d];
                const size_t base = ((size_t)kvh * S_LEN + s) * HD;
                Ko[base + d]      = __float2half_rn(x1 * c - x2 * si);
                Ko[base + d + 64] = __float2half_rn(x2 * c + x1 * si);
            }
        } else {
            // ---- V: fused transpose epilogue -> vt16[kvh][d][s] ----
            __half* st = (__half*)sm;    // [128 d][136 stride] halves
#pragma unroll
            for (int i = 0; i < 4; i++) {
                const int sl = wm * 64 + i * 16 + g;
#pragma unroll
                for (int j = 0; j < 4; j++) {
                    const int d0 = wn * 32 + j * 8 + 2 * t;
                    st[(d0    ) * 136 + sl    ] = __float2half_rn(acc[i][j][0]);
                    st[(d0 + 1) * 136 + sl    ] = __float2half_rn(acc[i][j][1]);
                    st[(d0    ) * 136 + sl + 8] = __float2half_rn(acc[i][j][2]);
                    st[(d0 + 1) * 136 + sl + 8] = __float2half_rn(acc[i][j][3]);
                }
            }
            __syncthreads();
#pragma unroll
            for (int it = 0; it < 8; it++) {
                const int id = tid + 256 * it;      // 0..2047
                const int d = id >> 4, seg = id & 15;
                uint4 val = *(uint4*)&st[d * 136 + seg * 8];
                *(uint4*)(Vto + ((size_t)(kvh * HD + d)) * S_LEN + bm + seg * 8) = val;
            }
        }
    }
}

// ======================= 256x128 fp16 1-MMA GEMM (O projection) ============
#define GEMM256S_SMEM (3 * STG256S)             // 129024

__global__ __launch_bounds__(256, 1) void gemm_tc256s(
    const __half* __restrict__ A, const __half* __restrict__ B,
    float* __restrict__ C, int M, int N, int K)
{
    extern __shared__ char sm[];
    const uint32_t smb = smem_u32(sm);

    const int tid = threadIdx.x;
    const int warp = tid >> 5;
    const int lane = tid & 31;
    const int wm = warp >> 1;
    const int wn = warp & 1;
    const int g = lane >> 2;
    const int t = lane & 3;
    const int bm = blockIdx.y * 256;
    const int bn = blockIdx.x * 128;
    const int nk = K >> 5;

    const int a_r  = (lane & 7) + ((lane >> 3) & 1) * 8;
    const int a_c8 = (lane >> 4) * 8;
    const int b_r  = lane & 7;
    const int b_j  = lane >> 4;
    const int b_c8 = ((lane >> 3) & 1) * 8;

    float acc[4][8][4];
#pragma unroll
    for (int i = 0; i < 4; i++)
#pragma unroll
        for (int j = 0; j < 8; j++)
#pragma unroll
            for (int r = 0; r < 4; r++) acc[i][j][r] = 0.0f;

    auto load_stage = [&](int s, int c) {
        const uint32_t sb = smb + s * STG256S;
        const int k0 = c * 32;
#pragma unroll
        for (int it = 0; it < 4; it++) {
            const int id = tid + it * 256;
            const int r = id >> 2, ch = id & 3;
            const uint32_t off = r * RSTR + ch * 16;
            cp_async16(sb + off, A + (size_t)(bm + r) * K + k0 + ch * 8);
        }
#pragma unroll
        for (int it = 0; it < 2; it++) {
            const int id = tid + it * 256;
            const int r = id >> 2, ch = id & 3;
            const uint32_t off = r * RSTR + ch * 16;
            cp_async16(sb + TILE_A2 + off, B + (size_t)(bn + r) * K + k0 + ch * 8);
        }
        CP_COMMIT();
    };

    load_stage(0, 0);
    if (nk > 1) load_stage(1, 1);
    if (nk > 2) load_stage(2, 2);

    for (int c = 0; c < nk; c++) {
        const int s = c % 3;
        if (c + 2 < nk)      asm volatile("cp.async.wait_group 2;" ::: "memory");
        else if (c + 1 < nk) asm volatile("cp.async.wait_group 1;" ::: "memory");
        else                 asm volatile("cp.async.wait_group 0;" ::: "memory");
        __syncthreads();

        const uint32_t uA = smb + s * STG256S;
        const uint32_t uB = uA + TILE_A2;

#pragma unroll
        for (int ks = 0; ks < 2; ks++) {
            const uint32_t colA = (ks * 16 + a_c8) * 2;
            const uint32_t colB = (ks * 16 + b_c8) * 2;
            uint32_t ah[4][4];
#pragma unroll
            for (int i = 0; i < 4; i++) {
                const uint32_t ro = (wm * 64 + i * 16 + a_r) * RSTR + colA;
                ldsm_x4(ah[i], uA + ro);
            }
#pragma unroll
            for (int p = 0; p < 4; p++) {
                const uint32_t ro = (wn * 64 + (2 * p + b_j) * 8 + b_r) * RSTR + colB;
                uint32_t bh[4];
                ldsm_x4(bh, uB + ro);
#pragma unroll
                for (int i = 0; i < 4; i++) {
                    MMA_F16(acc[i][2*p],   ah[i], bh[0], bh[1]);
                    MMA_F16(acc[i][2*p+1], ah[i], bh[2], bh[3]);
                }
            }
        }
        __syncthreads();
        if (c + 3 < nk) load_stage(s, c + 3);
    }

#pragma unroll
    for (int i = 0; i < 4; i++) {
        const int row0 = bm + wm * 64 + i * 16 + g;
#pragma unroll
        for (int j = 0; j < 8; j++) {
            const int col = bn + wn * 64 + j * 8 + 2 * t;
            *(float2*)(C + (size_t)row0 * N + col) = make_float2(acc[i][j][0], acc[i][j][1]);
            *(float2*)(C + (size_t)(row0 + 8) * N + col) = make_float2(acc[i][j][2], acc[i][j][3]);
        }
    }
}

// ======================= Flash attention (all single-fp16 MMA) =============
#define QSTR 272
#define VSTR 144
#define FA_QB (128 * QSTR)
#define FA_KB (64 * QSTR)
#define FA_VB (128 * VSTR)
#define FA_STAGE (FA_KB + FA_VB)
#define FA_SMEM (FA_QB + 2 * FA_STAGE)     // 106496

__global__ __launch_bounds__(256, 2) void flash_attn_tc(
    const __half* __restrict__ Qf, const __half* __restrict__ Kf,
    const __half* __restrict__ Vt, __half* __restrict__ O)
{
    extern __shared__ char fsm[];
    const uint32_t smb = smem_u32(fsm);
    const int qb = gridDim.x - 1 - blockIdx.x;
    const int h  = blockIdx.y;
    const int kvh = h % NKV;
    const int q0 = qb * 128;
    const int tid = threadIdx.x;
    const int w = tid >> 5;
    const int lane = tid & 31;
    const int g = lane >> 2;
    const int t = lane & 3;

    const int a_r  = (lane & 7) + ((lane >> 3) & 1) * 8;
    const int a_c8 = (lane >> 4) * 8;
    const int b_r  = lane & 7;
    const int b_j  = lane >> 4;
    const int b_c8 = ((lane >> 3) & 1) * 8;

#pragma unroll
    for (int it = 0; it < 8; it++) {
        const int id = tid + 256 * it;
        const int r = id >> 4, ch = id & 15;
        const uint32_t off = r * QSTR + ch * 16;
        const size_t gi = ((size_t)h * S_LEN + q0 + r) * HD + ch * 8;
        cp_async16(smb + off, Qf + gi);
    }

    auto fa_load = [&](int s, int jb) {
        const uint32_t sb = smb + FA_QB + s * FA_STAGE;
        const int k0 = jb * 64;
#pragma unroll
        for (int it = 0; it < 4; it++) {
            const int id = tid + 256 * it;
            const int r = id >> 4, ch = id & 15;
            const uint32_t off = r * QSTR + ch * 16;
            const size_t gi = ((size_t)kvh * S_LEN + k0 + r) * HD + ch * 8;
            cp_async16(sb + off, Kf + gi);
        }
#pragma unroll
        for (int it = 0; it < 4; it++) {
            const int id = tid + 256 * it;
            const int r = id >> 3, ch = id & 7;
            const uint32_t off = r * VSTR + ch * 16;
            const size_t gi = ((size_t)kvh * HD + r) * S_LEN + k0 + ch * 8;
            cp_async16(sb + FA_KB + off, Vt + gi);
        }
    };

    const int njb = 2 * qb + 2;
    fa_load(0, 0);
    CP_COMMIT();
    fa_load(1, 1);
    CP_COMMIT();

    float oacc[16][4];
#pragma unroll
    for (int jd = 0; jd < 16; jd++)
#pragma unroll
        for (int r = 0; r < 4; r++) oacc[jd][r] = 0.0f;
    float m0 = -1e30f, m1 = -1e30f, l0 = 0.0f, l1 = 0.0f;

    const uint32_t uQ = smb;

    for (int jb = 0; jb < njb; jb++) {
        const int s = jb & 1;
        if (jb + 1 < njb) asm volatile("cp.async.wait_group 1;" ::: "memory");
        else              asm volatile("cp.async.wait_group 0;" ::: "memory");
        __syncthreads();

        const uint32_t uK = smb + FA_QB + s * FA_STAGE;
        const uint32_t uV = uK + FA_KB;

        float sv[8][4];
#pragma unroll
        for (int j = 0; j < 8; j++)
#pragma unroll
            for (int r = 0; r < 4; r++) sv[j][r] = 0.0f;

#pragma unroll
        for (int kt = 0; kt < 8; kt++) {
            const uint32_t qro = (16 * w + a_r) * QSTR + (kt * 16 + a_c8) * 2;
            uint32_t qh[4];
            ldsm_x4(qh, uQ + qro);
#pragma unroll
            for (int p = 0; p < 4; p++) {
                const uint32_t kro = ((2 * p + b_j) * 8 + b_r) * QSTR + (kt * 16 + b_c8) * 2;
                uint32_t kh[4];
                ldsm_x4(kh, uK + kro);
                MMA_F16(sv[2*p],   qh, kh[0], kh[1]);
                MMA_F16(sv[2*p+1], qh, kh[2], kh[3]);
            }
        }

        if (jb >= 2 * qb) {
            const int r0g = q0 + 16 * w + g;
            const int r1g = r0g + 8;
            const int kg = jb * 64;
#pragma unroll
            for (int j = 0; j < 8; j++) {
                const int c0 = kg + 8 * j + 2 * t, c1 = c0 + 1;
                if (c0 > r0g) sv[j][0] = -1e30f;
                if (c1 > r0g) sv[j][1] = -1e30f;
                if (c0 > r1g) sv[j][2] = -1e30f;
                if (c1 > r1g) sv[j][3] = -1e30f;
            }
        }

        float mn0 = m0, mn1 = m1;
#pragma unroll
        for (int j = 0; j < 8; j++) {
            mn0 = fmaxf(mn0, fmaxf(sv[j][0], sv[j][1]));
            mn1 = fmaxf(mn1, fmaxf(sv[j][2], sv[j][3]));
        }
        mn0 = fmaxf(mn0, __shfl_xor_sync(0xffffffffu, mn0, 1));
        mn0 = fmaxf(mn0, __shfl_xor_sync(0xffffffffu, mn0, 2));
        mn1 = fmaxf(mn1, __shfl_xor_sync(0xffffffffu, mn1, 1));
        mn1 = fmaxf(mn1, __shfl_xor_sync(0xffffffffu, mn1, 2));

        const float corr0 = __expf(m0 - mn0);
        const float corr1 = __expf(m1 - mn1);
        float rs0 = 0.0f, rs1 = 0.0f;
#pragma unroll
        for (int j = 0; j < 8; j++) {
            sv[j][0] = __expf(sv[j][0] - mn0);
            sv[j][1] = __expf(sv[j][1] - mn0);
            sv[j][2] = __expf(sv[j][2] - mn1);
            sv[j][3] = __expf(sv[j][3] - mn1);
            rs0 += sv[j][0] + sv[j][1];
            rs1 += sv[j][2] + sv[j][3];
        }
        rs0 += __shfl_xor_sync(0xffffffffu, rs0, 1);
        rs0 += __shfl_xor_sync(0xffffffffu, rs0, 2);
        rs1 += __shfl_xor_sync(0xffffffffu, rs1, 1);
        rs1 += __shfl_xor_sync(0xffffffffu, rs1, 2);
        l0 = l0 * corr0 + rs0;
        l1 = l1 * corr1 + rs1;
        m0 = mn0; m1 = mn1;

#pragma unroll
        for (int jd = 0; jd < 16; jd++) {
            oacc[jd][0] *= corr0; oacc[jd][1] *= corr0;
            oacc[jd][2] *= corr1; oacc[jd][3] *= corr1;
        }

#pragma unroll
        for (int kt = 0; kt < 4; kt++) {
            uint32_t ph[4];
            ph[0] = pack2h(sv[2*kt][0],   sv[2*kt][1]);
            ph[1] = pack2h(sv[2*kt][2],   sv[2*kt][3]);
            ph[2] = pack2h(sv[2*kt+1][0], sv[2*kt+1][1]);
            ph[3] = pack2h(sv[2*kt+1][2], sv[2*kt+1][3]);
#pragma unroll
            for (int p = 0; p < 8; p++) {
                const uint32_t vro = ((2 * p + b_j) * 8 + b_r) * VSTR + (kt * 16 + b_c8) * 2;
                uint32_t vh[4];
                ldsm_x4(vh, uV + vro);
                MMA_F16(oacc[2*p],   ph, vh[0], vh[1]);
                MMA_F16(oacc[2*p+1], ph, vh[2], vh[3]);
            }
        }

        __syncthreads();
        if (jb + 2 < njb) { fa_load(s, jb + 2); CP_COMMIT(); }
    }

    const float inv0 = 1.0f / l0;
    const float inv1 = 1.0f / l1;
    const int s0 = q0 + 16 * w + g;
    const int s1 = s0 + 8;
#pragma unroll
    for (int jd = 0; jd < 16; jd++) {
        const int d = 8 * jd + 2 * t;
        const size_t i0 = (size_t)s0 * HID + h * HD + d;
        const size_t i1 = (size_t)s1 * HID + h * HD + d;
        *(uint32_t*)(O + i0) = pack2h(oacc[jd][0] * inv0, oacc[jd][1] * inv0);
        *(uint32_t*)(O + i1) = pack2h(oacc[jd][2] * inv1, oacc[jd][3] * inv1);
    }
}

// ======================= launch ============================================
extern "C" void kernel_launch(void* const* d_in, const int* in_sizes, int n_in,
                              void* d_out, int out_size) {
    const float* x  = (const float*)d_in[0];
    const float* wq = (const float*)d_in[1];
    const float* wk = (const float*)d_in[2];
    const float* wv = (const float*)d_in[3];
    const float* wo = (const float*)d_in[4];
    const float* cs = (const float*)d_in[5];
    const float* sn = (const float*)d_in[6];
    float* out = (float*)d_out;

    __half *xh16, *xl16, *wq16, *wk16, *wv16, *wo16, *att16, *vt16, *qh16, *k16;
    cudaGetSymbolAddress((void**)&xh16, g_xh16); cudaGetSymbolAddress((void**)&xl16, g_xl16);
    cudaGetSymbolAddress((void**)&wq16, g_wq16); cudaGetSymbolAddress((void**)&wk16, g_wk16);
    cudaGetSymbolAddress((void**)&wv16, g_wv16); cudaGetSymbolAddress((void**)&wo16, g_wo16);
    cudaGetSymbolAddress((void**)&att16, g_att16);
    cudaGetSymbolAddress((void**)&vt16, g_vt16);
    cudaGetSymbolAddress((void**)&qh16, g_qh16);
    cudaGetSymbolAddress((void**)&k16, g_k16);

    cudaFuncSetAttribute(gemm_all, cudaFuncAttributeMaxDynamicSharedMemorySize, QKV_SMEM);
    cudaFuncSetAttribute(gemm_tc256s, cudaFuncAttributeMaxDynamicSharedMemorySize, GEMM256S_SMEM);
    cudaFuncSetAttribute(flash_attn_tc, cudaFuncAttributeMaxDynamicSharedMemorySize, FA_SMEM);

    // one-shot split of all inputs
    split_all<<<(SPLIT_TOTAL + 255) / 256, 256>>>(
        (const float4*)x, (uint2*)xh16, (uint2*)xl16,
        (const float4*)wq, (uint2*)wq16,
        (const float4*)wk, (uint2*)wk16,
        (const float4*)wv, (uint2*)wv16,
        (const float4*)wo, (uint2*)wo16);

    // fused Q+K+V projections with rope / transpose epilogues (one launch)
    const float scale = 0.08838834764831845f;
    gemm_all<<<512, 256, QKV_SMEM>>>(
        xh16, xl16, wq16, wk16, wv16, cs, sn, qh16, k16, vt16, scale);

    // tensor-core flash attention
    flash_attn_tc<<<dim3(S_LEN / 128, NH), 256, FA_SMEM>>>(
        qh16, k16, vt16, att16);

    // output projection (fp16 1-MMA, 256-tile, 3-stage)
    gemm_tc256s<<<dim3(HID / 128, S_LEN / 256), 256, GEMM256S_SMEM>>>(
        att16, wo16, out, S_LEN, HID, HID);
}

// round 14
// speedup vs baseline: 6.1375x; 1.0922x over previous
#include <cuda_runtime.h>
#include <cuda_fp16.h>
#include <stdint.h>
#include <math.h>

#define S_LEN 2048
#define HID 4096
#define NH 32
#define NKV 8
#define HD 128

// ---------------- scratch ---------------------------------------------------
__device__ __half g_xh16[S_LEN * HID], g_xl16[S_LEN * HID];
__device__ __half g_wq16[HID * HID];
__device__ __half g_wk16[NKV*HD * HID];
__device__ __half g_wv16[NKV*HD * HID];
__device__ __half g_wo16[HID * HID];
__device__ __half g_att16[S_LEN * HID];
__device__ __half g_vt16[NKV * HD * S_LEN];
__device__ __half g_qh16[NH * S_LEN * HD];
__device__ __half g_k16[NKV * S_LEN * HD];

// ======================= helpers ===========================================
__device__ __forceinline__ uint32_t smem_u32(const void* p) {
    uint32_t a;
    asm("{ .reg .u64 t; cvta.to.shared.u64 t, %1; cvt.u32.u64 %0, t; }" : "=r"(a) : "l"(p));
    return a;
}
__device__ __forceinline__ void cp_async16(uint32_t saddr, const void* g) {
    asm volatile("cp.async.cg.shared.global [%0], [%1], 16;" :: "r"(saddr), "l"(g));
}
#define CP_COMMIT() asm volatile("cp.async.commit_group;" ::: "memory")

#define MMA_F16(c, a, b0, b1)                                                  \
    asm volatile("mma.sync.aligned.m16n8k16.row.col.f32.f16.f16.f32 "          \
        "{%0,%1,%2,%3}, {%4,%5,%6,%7}, {%8,%9}, {%0,%1,%2,%3};"                \
        : "+f"((c)[0]), "+f"((c)[1]), "+f"((c)[2]), "+f"((c)[3])               \
        : "r"((a)[0]), "r"((a)[1]), "r"((a)[2]), "r"((a)[3]), "r"(b0), "r"(b1))

__device__ __forceinline__ void ldsm_x4(uint32_t* r, uint32_t addr) {
    asm volatile("ldmatrix.sync.aligned.m8n8.x4.shared.b16 {%0,%1,%2,%3}, [%4];"
        : "=r"(r[0]), "=r"(r[1]), "=r"(r[2]), "=r"(r[3]) : "r"(addr));
}
__device__ __forceinline__ uint32_t pack2h(float x, float y) {
    __half2 h = __floats2half2_rn(x, y);
    return *(uint32_t*)&h;
}

// ======================= one-shot split of all inputs ======================
#define X4  ((S_LEN * HID) / 4)
#define W44 ((HID * HID) / 4)
#define W14 ((NKV * HD * HID) / 4)
#define SPLIT_TOTAL (X4 + 2 * W44 + 2 * W14)

__global__ void split_all(const float4* __restrict__ x,
                          uint2* __restrict__ xh, uint2* __restrict__ xl,
                          const float4* __restrict__ wq, uint2* __restrict__ wqo,
                          const float4* __restrict__ wk, uint2* __restrict__ wko,
                          const float4* __restrict__ wv, uint2* __restrict__ wvo,
                          const float4* __restrict__ wo, uint2* __restrict__ woo) {
    const int i = blockIdx.x * blockDim.x + threadIdx.x;
    if (i >= SPLIT_TOTAL) return;
    const int A = X4, B = A + W44, C = B + W14, D = C + W14;
    if (i < A) {
        float4 v = x[i];
        __half h[4], l[4];
        h[0] = __float2half_rn(v.x); l[0] = __float2half_rn(v.x - __half2float(h[0]));
        h[1] = __float2half_rn(v.y); l[1] = __float2half_rn(v.y - __half2float(h[1]));
        h[2] = __float2half_rn(v.z); l[2] = __float2half_rn(v.z - __half2float(h[2]));
        h[3] = __float2half_rn(v.w); l[3] = __float2half_rn(v.w - __half2float(h[3]));
        xh[i] = *(uint2*)h;
        xl[i] = *(uint2*)l;
    } else {
        const float4* src;
        uint2* dst;
        int j;
        if (i < B)      { j = i - A; src = wq; dst = wqo; }
        else if (i < C) { j = i - B; src = wk; dst = wko; }
        else if (i < D) { j = i - C; src = wv; dst = wvo; }
        else            { j = i - D; src = wo; dst = woo; }
        float4 v = src[j];
        __half h[4];
        h[0] = __float2half_rn(v.x);
        h[1] = __float2half_rn(v.y);
        h[2] = __float2half_rn(v.z);
        h[3] = __float2half_rn(v.w);
        dst[j] = *(uint2*)h;
    }
}

// ======================= common tile constants =============================
#define RSTR 112
#define TILE_B (128 * RSTR)            // 14336
#define STG_Q  (2 * TILE_B)            // 28672 (Q/O: A,B)
#define STG_KV (3 * TILE_B)            // 43008 (KV: Xh,Xl,B)
#define PROJ_SMEM (2 * STG_KV)         // 86016 (= 3*STG_Q as well)

// ======================= fused Q+K+V projections (one launch) ==============
// All tiles 128x128, 8 warps as 2m x 4n (warp tile 64x32). 2 CTAs/SM.
//  bid <  512 : Q tile (1-MMA, 3-stage, rope+scale epilogue -> qh16[h][s][d])
//  bid >= 512 : K/V tile (2-MMA, 2-stage);
//               K: rope epilogue -> k16[kvh][s][d]
//               V: transpose epilogue -> vt16[kvh][d][s]
__global__ __launch_bounds__(256, 2) void gemm_all(
    const __half* __restrict__ Xh, const __half* __restrict__ Xl,
    const __half* __restrict__ Wq, const __half* __restrict__ Wk,
    const __half* __restrict__ Wv,
    const float* __restrict__ cs, const float* __restrict__ sn,
    __half* __restrict__ Qo, __half* __restrict__ Ko, __half* __restrict__ Vto,
    float scale)
{
    extern __shared__ char sm[];
    const uint32_t smb = smem_u32(sm);

    const int bid = blockIdx.x;
    const int tid = threadIdx.x;
    const int warp = tid >> 5;
    const int lane = tid & 31;
    const int g = lane >> 2;
    const int t = lane & 3;
    const int K = HID;
    const int nk = K >> 5;
    const int wm = warp >> 2;          // 0..1
    const int wn = warp & 3;           // 0..3

    const int a_r  = (lane & 7) + ((lane >> 3) & 1) * 8;
    const int a_c8 = (lane >> 4) * 8;
    const int b_r  = lane & 7;
    const int b_j  = lane >> 4;
    const int b_c8 = ((lane >> 3) & 1) * 8;

    float acc[4][4][4];
#pragma unroll
    for (int i = 0; i < 4; i++)
#pragma unroll
        for (int j = 0; j < 4; j++)
#pragma unroll
            for (int r = 0; r < 4; r++) acc[i][j][r] = 0.0f;

    if (bid < 512) {
        // ================= Q path: 128x128, 1-MMA, 3-stage =================
        const int bx = bid & 31;           // head index
        const int by = bid >> 5;           // row tile
        const int bm = by * 128;
        const int bn = bx * 128;

        auto load_stage = [&](int s, int c) {
            const uint32_t sb = smb + s * STG_Q;
            const int k0 = c * 32;
#pragma unroll
            for (int it = 0; it < 2; it++) {
                const int id = tid + it * 256;
                const int r = id >> 2, ch = id & 3;
                const uint32_t off = r * RSTR + ch * 16;
                cp_async16(sb + off,          Xh + (size_t)(bm + r) * K + k0 + ch * 8);
                cp_async16(sb + TILE_B + off, Wq + (size_t)(bn + r) * K + k0 + ch * 8);
            }
            CP_COMMIT();
        };

        load_stage(0, 0);
        load_stage(1, 1);
        load_stage(2, 2);

        for (int c = 0; c < nk; c++) {
            const int s = c % 3;
            if (c + 2 < nk)      asm volatile("cp.async.wait_group 2;" ::: "memory");
            else if (c + 1 < nk) asm volatile("cp.async.wait_group 1;" ::: "memory");
            else                 asm volatile("cp.async.wait_group 0;" ::: "memory");
            __syncthreads();

            const uint32_t uA = smb + s * STG_Q;
            const uint32_t uB = uA + TILE_B;
#pragma unroll
            for (int ks = 0; ks < 2; ks++) {
                const uint32_t colA = (ks * 16 + a_c8) * 2;
                const uint32_t colB = (ks * 16 + b_c8) * 2;
                uint32_t ah[4][4];
#pragma unroll
                for (int i = 0; i < 4; i++) {
                    const uint32_t ro = (wm * 64 + i * 16 + a_r) * RSTR + colA;
                    ldsm_x4(ah[i], uA + ro);
                }
#pragma unroll
                for (int p = 0; p < 2; p++) {
                    const uint32_t ro = (wn * 32 + (2 * p + b_j) * 8 + b_r) * RSTR + colB;
                    uint32_t bh[4];
                    ldsm_x4(bh, uB + ro);
#pragma unroll
                    for (int i = 0; i < 4; i++) {
                        MMA_F16(acc[i][2*p],   ah[i], bh[0], bh[1]);
                        MMA_F16(acc[i][2*p+1], ah[i], bh[2], bh[3]);
                    }
                }
            }
            __syncthreads();
            if (c + 3 < nk) load_stage(s, c + 3);
        }

        // ---- rope+scale epilogue through smem fp32 staging ----
        float* st = (float*)sm;   // [128][132] fp32 = 67.6 KB
#pragma unroll
        for (int i = 0; i < 4; i++) {
            const int r0 = wm * 64 + i * 16 + g;
#pragma unroll
            for (int j = 0; j < 4; j++) {
                const int col = wn * 32 + j * 8 + 2 * t;
                *(float2*)&st[r0 * 132 + col] = make_float2(acc[i][j][0], acc[i][j][1]);
                *(float2*)&st[(r0 + 8) * 132 + col] = make_float2(acc[i][j][2], acc[i][j][3]);
            }
        }
        __syncthreads();
#pragma unroll
        for (int it = 0; it < 32; it++) {
            const int id = tid + 256 * it;       // 0..8191
            const int srow = id >> 6, d = id & 63;
            const int s = bm + srow;
            const float x1 = st[srow * 132 + d];
            const float x2 = st[srow * 132 + d + 64];
            const float c = cs[s * 64 + d];
            const float si = sn[s * 64 + d];
            const size_t base = ((size_t)bx * S_LEN + s) * HD;
            Qo[base + d]      = __float2half_rn((x1 * c - x2 * si) * scale);
            Qo[base + d + 64] = __float2half_rn((x2 * c + x1 * si) * scale);
        }
    } else {
        // ================= K/V path: 128x128, 2-MMA, 2-stage ================
        const int id2 = bid - 512;
        const int bx = id2 & 15;
        const int by = id2 >> 4;
        const int bm = by * 128;
        const bool isK = bx < 8;
        const int bn = (bx & 7) * 128;
        const __half* B = isK ? Wk : Wv;

        auto load_stage = [&](int s, int c) {
            const uint32_t sb = smb + s * STG_KV;
            const int k0 = c * 32;
#pragma unroll
            for (int it = 0; it < 2; it++) {
                const int id = tid + it * 256;
                const int r = id >> 2, ch = id & 3;
                const uint32_t off = r * RSTR + ch * 16;
                const size_t ga = (size_t)(bm + r) * K + k0 + ch * 8;
                const size_t gb = (size_t)(bn + r) * K + k0 + ch * 8;
                cp_async16(sb + off,              Xh + ga);
                cp_async16(sb + TILE_B + off,     Xl + ga);
                cp_async16(sb + 2 * TILE_B + off, B + gb);
            }
            CP_COMMIT();
        };

        load_stage(0, 0);
        load_stage(1, 1);

        for (int c = 0; c < nk; c++) {
            const int s = c & 1;
            if (c + 1 < nk) asm volatile("cp.async.wait_group 1;" ::: "memory");
            else            asm volatile("cp.async.wait_group 0;" ::: "memory");
            __syncthreads();

            const uint32_t uAh = smb + s * STG_KV;
            const uint32_t uAl = uAh + TILE_B;
            const uint32_t uB  = uAh + 2 * TILE_B;
#pragma unroll
            for (int ks = 0; ks < 2; ks++) {
                const uint32_t colA = (ks * 16 + a_c8) * 2;
                const uint32_t colB = (ks * 16 + b_c8) * 2;
                uint32_t ah[4][4], al[4][4];
#pragma unroll
                for (int i = 0; i < 4; i++) {
                    const uint32_t ro = (wm * 64 + i * 16 + a_r) * RSTR + colA;
                    ldsm_x4(ah[i], uAh + ro);
                    ldsm_x4(al[i], uAl + ro);
                }
#pragma unroll
                for (int p = 0; p < 2; p++) {
                    const uint32_t ro = (wn * 32 + (2 * p + b_j) * 8 + b_r) * RSTR + colB;
                    uint32_t bh[4];
                    ldsm_x4(bh, uB + ro);
#pragma unroll
                    for (int i = 0; i < 4; i++) {
                        MMA_F16(acc[i][2*p],   ah[i], bh[0], bh[1]);
                        MMA_F16(acc[i][2*p],   al[i], bh[0], bh[1]);
                        MMA_F16(acc[i][2*p+1], ah[i], bh[2], bh[3]);
                        MMA_F16(acc[i][2*p+1], al[i], bh[2], bh[3]);
                    }
                }
            }
            __syncthreads();
            if (c + 2 < nk) load_stage(s, c + 2);
        }

        const int kvh = bn >> 7;
        if (isK) {
            // ---- K: rope epilogue through smem fp32 staging ----
            float* st = (float*)sm;
#pragma unroll
            for (int i = 0; i < 4; i++) {
                const int r0 = wm * 64 + i * 16 + g;
#pragma unroll
                for (int j = 0; j < 4; j++) {
                    const int col = wn * 32 + j * 8 + 2 * t;
                    *(float2*)&st[r0 * 132 + col] = make_float2(acc[i][j][0], acc[i][j][1]);
                    *(float2*)&st[(r0 + 8) * 132 + col] = make_float2(acc[i][j][2], acc[i][j][3]);
                }
            }
            __syncthreads();
#pragma unroll
            for (int it = 0; it < 32; it++) {
                const int id = tid + 256 * it;
                const int srow = id >> 6, d = id & 63;
                const int s = bm + srow;
                const float x1 = st[srow * 132 + d];
                const float x2 = st[srow * 132 + d + 64];
                const float c = cs[s * 64 + d];
                const float si = sn[s * 64 + d];
                const size_t base = ((size_t)kvh * S_LEN + s) * HD;
                Ko[base + d]      = __float2half_rn(x1 * c - x2 * si);
                Ko[base + d + 64] = __float2half_rn(x2 * c + x1 * si);
            }
        } else {
            // ---- V: fused transpose epilogue -> vt16[kvh][d][s] ----
            __half* st = (__half*)sm;    // [128 d][136 stride] halves
#pragma unroll
            for (int i = 0; i < 4; i++) {
                const int sl = wm * 64 + i * 16 + g;
#pragma unroll
                for (int j = 0; j < 4; j++) {
                    const int d0 = wn * 32 + j * 8 + 2 * t;
                    st[(d0    ) * 136 + sl    ] = __float2half_rn(acc[i][j][0]);
                    st[(d0 + 1) * 136 + sl    ] = __float2half_rn(acc[i][j][1]);
                    st[(d0    ) * 136 + sl + 8] = __float2half_rn(acc[i][j][2]);
                    st[(d0 + 1) * 136 + sl + 8] = __float2half_rn(acc[i][j][3]);
                }
            }
            __syncthreads();
#pragma unroll
            for (int it = 0; it < 8; it++) {
                const int id = tid + 256 * it;      // 0..2047
                const int d = id >> 4, seg = id & 15;
                uint4 val = *(uint4*)&st[d * 136 + seg * 8];
                *(uint4*)(Vto + ((size_t)(kvh * HD + d)) * S_LEN + bm + seg * 8) = val;
            }
        }
    }
}

// ======================= 128x128 fp16 1-MMA GEMM (O projection) ============
// 8 warps 2x4 (warp 64x32), 3-stage, 2 CTAs/SM.
__global__ __launch_bounds__(256, 2) void gemm_tc128s(
    const __half* __restrict__ A, const __half* __restrict__ B,
    float* __restrict__ C, int M, int N, int K)
{
    extern __shared__ char sm[];
    const uint32_t smb = smem_u32(sm);

    const int tid = threadIdx.x;
    const int warp = tid >> 5;
    const int lane = tid & 31;
    const int wm = warp >> 2;
    const int wn = warp & 3;
    const int g = lane >> 2;
    const int t = lane & 3;
    const int bm = blockIdx.y * 128;
    const int bn = blockIdx.x * 128;
    const int nk = K >> 5;

    const int a_r  = (lane & 7) + ((lane >> 3) & 1) * 8;
    const int a_c8 = (lane >> 4) * 8;
    const int b_r  = lane & 7;
    const int b_j  = lane >> 4;
    const int b_c8 = ((lane >> 3) & 1) * 8;

    float acc[4][4][4];
#pragma unroll
    for (int i = 0; i < 4; i++)
#pragma unroll
        for (int j = 0; j < 4; j++)
#pragma unroll
            for (int r = 0; r < 4; r++) acc[i][j][r] = 0.0f;

    auto load_stage = [&](int s, int c) {
        const uint32_t sb = smb + s * STG_Q;
        const int k0 = c * 32;
#pragma unroll
        for (int it = 0; it < 2; it++) {
            const int id = tid + it * 256;
            const int r = id >> 2, ch = id & 3;
            const uint32_t off = r * RSTR + ch * 16;
            cp_async16(sb + off,          A + (size_t)(bm + r) * K + k0 + ch * 8);
            cp_async16(sb + TILE_B + off, B + (size_t)(bn + r) * K + k0 + ch * 8);
        }
        CP_COMMIT();
    };

    load_stage(0, 0);
    if (nk > 1) load_stage(1, 1);
    if (nk > 2) load_stage(2, 2);

    for (int c = 0; c < nk; c++) {
        const int s = c % 3;
        if (c + 2 < nk)      asm volatile("cp.async.wait_group 2;" ::: "memory");
        else if (c + 1 < nk) asm volatile("cp.async.wait_group 1;" ::: "memory");
        else                 asm volatile("cp.async.wait_group 0;" ::: "memory");
        __syncthreads();

        const uint32_t uA = smb + s * STG_Q;
        const uint32_t uB = uA + TILE_B;

#pragma unroll
        for (int ks = 0; ks < 2; ks++) {
            const uint32_t colA = (ks * 16 + a_c8) * 2;
            const uint32_t colB = (ks * 16 + b_c8) * 2;
            uint32_t ah[4][4];
#pragma unroll
            for (int i = 0; i < 4; i++) {
                const uint32_t ro = (wm * 64 + i * 16 + a_r) * RSTR + colA;
                ldsm_x4(ah[i], uA + ro);
            }
#pragma unroll
            for (int p = 0; p < 2; p++) {
                const uint32_t ro = (wn * 32 + (2 * p + b_j) * 8 + b_r) * RSTR + colB;
                uint32_t bh[4];
                ldsm_x4(bh, uB + ro);
#pragma unroll
                for (int i = 0; i < 4; i++) {
                    MMA_F16(acc[i][2*p],   ah[i], bh[0], bh[1]);
                    MMA_F16(acc[i][2*p+1], ah[i], bh[2], bh[3]);
                }
            }
        }
        __syncthreads();
        if (c + 3 < nk) load_stage(s, c + 3);
    }

#pragma unroll
    for (int i = 0; i < 4; i++) {
        const int row0 = bm + wm * 64 + i * 16 + g;
#pragma unroll
        for (int j = 0; j < 4; j++) {
            const int col = bn + wn * 32 + j * 8 + 2 * t;
            *(float2*)(C + (size_t)row0 * N + col) = make_float2(acc[i][j][0], acc[i][j][1]);
            *(float2*)(C + (size_t)(row0 + 8) * N + col) = make_float2(acc[i][j][2], acc[i][j][3]);
        }
    }
}

// ======================= Flash attention (all single-fp16 MMA) =============
#define QSTR 272
#define VSTR 144
#define FA_QB (128 * QSTR)
#define FA_KB (64 * QSTR)
#define FA_VB (128 * VSTR)
#define FA_STAGE (FA_KB + FA_VB)
#define FA_SMEM (FA_QB + 2 * FA_STAGE)     // 106496

__global__ __launch_bounds__(256, 2) void flash_attn_tc(
    const __half* __restrict__ Qf, const __half* __restrict__ Kf,
    const __half* __restrict__ Vt, __half* __restrict__ O)
{
    extern __shared__ char fsm[];
    const uint32_t smb = smem_u32(fsm);
    const int qb = gridDim.x - 1 - blockIdx.x;
    const int h  = blockIdx.y;
    const int kvh = h % NKV;
    const int q0 = qb * 128;
    const int tid = threadIdx.x;
    const int w = tid >> 5;
    const int lane = tid & 31;
    const int g = lane >> 2;
    const int t = lane & 3;

    const int a_r  = (lane & 7) + ((lane >> 3) & 1) * 8;
    const int a_c8 = (lane >> 4) * 8;
    const int b_r  = lane & 7;
    const int b_j  = lane >> 4;
    const int b_c8 = ((lane >> 3) & 1) * 8;

#pragma unroll
    for (int it = 0; it < 8; it++) {
        const int id = tid + 256 * it;
        const int r = id >> 4, ch = id & 15;
        const uint32_t off = r * QSTR + ch * 16;
        const size_t gi = ((size_t)h * S_LEN + q0 + r) * HD + ch * 8;
        cp_async16(smb + off, Qf + gi);
    }

    auto fa_load = [&](int s, int jb) {
        const uint32_t sb = smb + FA_QB + s * FA_STAGE;
        const int k0 = jb * 64;
#pragma unroll
        for (int it = 0; it < 4; it++) {
            const int id = tid + 256 * it;
            const int r = id >> 4, ch = id & 15;
            const uint32_t off = r * QSTR + ch * 16;
            const size_t gi = ((size_t)kvh * S_LEN + k0 + r) * HD + ch * 8;
            cp_async16(sb + off, Kf + gi);
        }
#pragma unroll
        for (int it = 0; it < 4; it++) {
            const int id = tid + 256 * it;
            const int r = id >> 3, ch = id & 7;
            const uint32_t off = r * VSTR + ch * 16;
            const size_t gi = ((size_t)kvh * HD + r) * S_LEN + k0 + ch * 8;
            cp_async16(sb + FA_KB + off, Vt + gi);
        }
    };

    const int njb = 2 * qb + 2;
    fa_load(0, 0);
    CP_COMMIT();
    fa_load(1, 1);
    CP_COMMIT();

    float oacc[16][4];
#pragma unroll
    for (int jd = 0; jd < 16; jd++)
#pragma unroll
        for (int r = 0; r < 4; r++) oacc[jd][r] = 0.0f;
    float m0 = -1e30f, m1 = -1e30f, l0 = 0.0f, l1 = 0.0f;

    const uint32_t uQ = smb;

    for (int jb = 0; jb < njb; jb++) {
        const int s = jb & 1;
        if (jb + 1 < njb) asm volatile("cp.async.wait_group 1;" ::: "memory");
        else              asm volatile("cp.async.wait_group 0;" ::: "memory");
        __syncthreads();

        const uint32_t uK = smb + FA_QB + s * FA_STAGE;
        const uint32_t uV = uK + FA_KB;

        float sv[8][4];
#pragma unroll
        for (int j = 0; j < 8; j++)
#pragma unroll
            for (int r = 0; r < 4; r++) sv[j][r] = 0.0f;

#pragma unroll
        for (int kt = 0; kt < 8; kt++) {
            const uint32_t qro = (16 * w + a_r) * QSTR + (kt * 16 + a_c8) * 2;
            uint32_t qh[4];
            ldsm_x4(qh, uQ + qro);
#pragma unroll
            for (int p = 0; p < 4; p++) {
                const uint32_t kro = ((2 * p + b_j) * 8 + b_r) * QSTR + (kt * 16 + b_c8) * 2;
                uint32_t kh[4];
                ldsm_x4(kh, uK + kro);
                MMA_F16(sv[2*p],   qh, kh[0], kh[1]);
                MMA_F16(sv[2*p+1], qh, kh[2], kh[3]);
            }
        }

        if (jb >= 2 * qb) {
            const int r0g = q0 + 16 * w + g;
            const int r1g = r0g + 8;
            const int kg = jb * 64;
#pragma unroll
            for (int j = 0; j < 8; j++) {
                const int c0 = kg + 8 * j + 2 * t, c1 = c0 + 1;
                if (c0 > r0g) sv[j][0] = -1e30f;
                if (c1 > r0g) sv[j][1] = -1e30f;
                if (c0 > r1g) sv[j][2] = -1e30f;
                if (c1 > r1g) sv[j][3] = -1e30f;
            }
        }

        float mn0 = m0, mn1 = m1;
#pragma unroll
        for (int j = 0; j < 8; j++) {
            mn0 = fmaxf(mn0, fmaxf(sv[j][0], sv[j][1]));
            mn1 = fmaxf(mn1, fmaxf(sv[j][2], sv[j][3]));
        }
        mn0 = fmaxf(mn0, __shfl_xor_sync(0xffffffffu, mn0, 1));
        mn0 = fmaxf(mn0, __shfl_xor_sync(0xffffffffu, mn0, 2));
        mn1 = fmaxf(mn1, __shfl_xor_sync(0xffffffffu, mn1, 1));
        mn1 = fmaxf(mn1, __shfl_xor_sync(0xffffffffu, mn1, 2));

        const float corr0 = __expf(m0 - mn0);
        const float corr1 = __expf(m1 - mn1);
        float rs0 = 0.0f, rs1 = 0.0f;
#pragma unroll
        for (int j = 0; j < 8; j++) {
            sv[j][0] = __expf(sv[j][0] - mn0);
            sv[j][1] = __expf(sv[j][1] - mn0);
            sv[j][2] = __expf(sv[j][2] - mn1);
            sv[j][3] = __expf(sv[j][3] - mn1);
            rs0 += sv[j][0] + sv[j][1];
            rs1 += sv[j][2] + sv[j][3];
        }
        rs0 += __shfl_xor_sync(0xffffffffu, rs0, 1);
        rs0 += __shfl_xor_sync(0xffffffffu, rs0, 2);
        rs1 += __shfl_xor_sync(0xffffffffu, rs1, 1);
        rs1 += __shfl_xor_sync(0xffffffffu, rs1, 2);
        l0 = l0 * corr0 + rs0;
        l1 = l1 * corr1 + rs1;
        m0 = mn0; m1 = mn1;

#pragma unroll
        for (int jd = 0; jd < 16; jd++) {
            oacc[jd][0] *= corr0; oacc[jd][1] *= corr0;
            oacc[jd][2] *= corr1; oacc[jd][3] *= corr1;
        }

#pragma unroll
        for (int kt = 0; kt < 4; kt++) {
            uint32_t ph[4];
            ph[0] = pack2h(sv[2*kt][0],   sv[2*kt][1]);
            ph[1] = pack2h(sv[2*kt][2],   sv[2*kt][3]);
            ph[2] = pack2h(sv[2*kt+1][0], sv[2*kt+1][1]);
            ph[3] = pack2h(sv[2*kt+1][2], sv[2*kt+1][3]);
#pragma unroll
            for (int p = 0; p < 8; p++) {
                const uint32_t vro = ((2 * p + b_j) * 8 + b_r) * VSTR + (kt * 16 + b_c8) * 2;
                uint32_t vh[4];
                ldsm_x4(vh, uV + vro);
                MMA_F16(oacc[2*p],   ph, vh[0], vh[1]);
                MMA_F16(oacc[2*p+1], ph, vh[2], vh[3]);
            }
        }

        __syncthreads();
        if (jb + 2 < njb) { fa_load(s, jb + 2); CP_COMMIT(); }
    }

    const float inv0 = 1.0f / l0;
    const float inv1 = 1.0f / l1;
    const int s0 = q0 + 16 * w + g;
    const int s1 = s0 + 8;
#pragma unroll
    for (int jd = 0; jd < 16; jd++) {
        const int d = 8 * jd + 2 * t;
        const size_t i0 = (size_t)s0 * HID + h * HD + d;
        const size_t i1 = (size_t)s1 * HID + h * HD + d;
        *(uint32_t*)(O + i0) = pack2h(oacc[jd][0] * inv0, oacc[jd][1] * inv0);
        *(uint32_t*)(O + i1) = pack2h(oacc[jd][2] * inv1, oacc[jd][3] * inv1);
    }
}

// ======================= launch ============================================
extern "C" void kernel_launch(void* const* d_in, const int* in_sizes, int n_in,
                              void* d_out, int out_size) {
    const float* x  = (const float*)d_in[0];
    const float* wq = (const float*)d_in[1];
    const float* wk = (const float*)d_in[2];
    const float* wv = (const float*)d_in[3];
    const float* wo = (const float*)d_in[4];
    const float* cs = (const float*)d_in[5];
    const float* sn = (const float*)d_in[6];
    float* out = (float*)d_out;

    __half *xh16, *xl16, *wq16, *wk16, *wv16, *wo16, *att16, *vt16, *qh16, *k16;
    cudaGetSymbolAddress((void**)&xh16, g_xh16); cudaGetSymbolAddress((void**)&xl16, g_xl16);
    cudaGetSymbolAddress((void**)&wq16, g_wq16); cudaGetSymbolAddress((void**)&wk16, g_wk16);
    cudaGetSymbolAddress((void**)&wv16, g_wv16); cudaGetSymbolAddress((void**)&wo16, g_wo16);
    cudaGetSymbolAddress((void**)&att16, g_att16);
    cudaGetSymbolAddress((void**)&vt16, g_vt16);
    cudaGetSymbolAddress((void**)&qh16, g_qh16);
    cudaGetSymbolAddress((void**)&k16, g_k16);

    cudaFuncSetAttribute(gemm_all, cudaFuncAttributeMaxDynamicSharedMemorySize, PROJ_SMEM);
    cudaFuncSetAttribute(gemm_tc128s, cudaFuncAttributeMaxDynamicSharedMemorySize, PROJ_SMEM);
    cudaFuncSetAttribute(flash_attn_tc, cudaFuncAttributeMaxDynamicSharedMemorySize, FA_SMEM);

    // one-shot split of all inputs
    split_all<<<(SPLIT_TOTAL + 255) / 256, 256>>>(
        (const float4*)x, (uint2*)xh16, (uint2*)xl16,
        (const float4*)wq, (uint2*)wq16,
        (const float4*)wk, (uint2*)wk16,
        (const float4*)wv, (uint2*)wv16,
        (const float4*)wo, (uint2*)wo16);

    // fused Q+K+V projections, 2 CTAs/SM
    const float scale = 0.08838834764831845f;
    gemm_all<<<768, 256, PROJ_SMEM>>>(
        xh16, xl16, wq16, wk16, wv16, cs, sn, qh16, k16, vt16, scale);

    // tensor-core flash attention
    flash_attn_tc<<<dim3(S_LEN / 128, NH), 256, FA_SMEM>>>(
        qh16, k16, vt16, att16);

    // output projection (128-tile, 2 CTAs/SM)
    gemm_tc128s<<<dim3(HID / 128, S_LEN / 128), 256, PROJ_SMEM>>>(
        att16, wo16, out, S_LEN, HID, HID);
}

// round 15
// speedup vs baseline: 6.6172x; 1.0782x over previous
#include <cuda_runtime.h>
#include <cuda_fp16.h>
#include <stdint.h>
#include <math.h>

#define S_LEN 2048
#define HID 4096
#define NH 32
#define NKV 8
#define HD 128

// ---------------- scratch ---------------------------------------------------
__device__ __half g_xh16[S_LEN * HID], g_xl16[S_LEN * HID];
__device__ __half g_wq16[HID * HID];
__device__ __half g_wk16[NKV*HD * HID];
__device__ __half g_wv16[NKV*HD * HID];
__device__ __half g_wo16[HID * HID];
__device__ __half g_att16[S_LEN * HID];
__device__ __half g_vt16[NKV * HD * S_LEN];
__device__ __half g_qh16[NH * S_LEN * HD];
__device__ __half g_k16[NKV * S_LEN * HD];

// ======================= helpers ===========================================
__device__ __forceinline__ uint32_t smem_u32(const void* p) {
    uint32_t a;
    asm("{ .reg .u64 t; cvta.to.shared.u64 t, %1; cvt.u32.u64 %0, t; }" : "=r"(a) : "l"(p));
    return a;
}
__device__ __forceinline__ void cp_async16(uint32_t saddr, const void* g) {
    asm volatile("cp.async.cg.shared.global [%0], [%1], 16;" :: "r"(saddr), "l"(g));
}
#define CP_COMMIT() asm volatile("cp.async.commit_group;" ::: "memory")

#define MMA_F16(c, a, b0, b1)                                                  \
    asm volatile("mma.sync.aligned.m16n8k16.row.col.f32.f16.f16.f32 "          \
        "{%0,%1,%2,%3}, {%4,%5,%6,%7}, {%8,%9}, {%0,%1,%2,%3};"                \
        : "+f"((c)[0]), "+f"((c)[1]), "+f"((c)[2]), "+f"((c)[3])               \
        : "r"((a)[0]), "r"((a)[1]), "r"((a)[2]), "r"((a)[3]), "r"(b0), "r"(b1))

__device__ __forceinline__ void ldsm_x4(uint32_t* r, uint32_t addr) {
    asm volatile("ldmatrix.sync.aligned.m8n8.x4.shared.b16 {%0,%1,%2,%3}, [%4];"
        : "=r"(r[0]), "=r"(r[1]), "=r"(r[2]), "=r"(r[3]) : "r"(addr));
}
__device__ __forceinline__ uint32_t pack2h(float x, float y) {
    __half2 h = __floats2half2_rn(x, y);
    return *(uint32_t*)&h;
}

// ======================= one-shot split of all inputs (MLP=4) ==============
#define X4  ((S_LEN * HID) / 4)
#define W44 ((HID * HID) / 4)
#define W14 ((NKV * HD * HID) / 4)
#define SPLIT_TOTAL (X4 + 2 * W44 + 2 * W14)

__global__ void split_all(const float4* __restrict__ x,
                          uint2* __restrict__ xh, uint2* __restrict__ xl,
                          const float4* __restrict__ wq, uint2* __restrict__ wqo,
                          const float4* __restrict__ wk, uint2* __restrict__ wko,
                          const float4* __restrict__ wv, uint2* __restrict__ wvo,
                          const float4* __restrict__ wo, uint2* __restrict__ woo) {
    const int base = blockIdx.x * 1024 + threadIdx.x;
    const int A = X4, B = A + W44, C = B + W14, D = C + W14;
#pragma unroll
    for (int u = 0; u < 4; u++) {
        const int i = base + u * 256;
        if (i >= SPLIT_TOTAL) break;
        if (i < A) {
            float4 v = x[i];
            __half h[4], l[4];
            h[0] = __float2half_rn(v.x); l[0] = __float2half_rn(v.x - __half2float(h[0]));
            h[1] = __float2half_rn(v.y); l[1] = __float2half_rn(v.y - __half2float(h[1]));
            h[2] = __float2half_rn(v.z); l[2] = __float2half_rn(v.z - __half2float(h[2]));
            h[3] = __float2half_rn(v.w); l[3] = __float2half_rn(v.w - __half2float(h[3]));
            xh[i] = *(uint2*)h;
            xl[i] = *(uint2*)l;
        } else {
            const float4* src;
            uint2* dst;
            int j;
            if (i < B)      { j = i - A; src = wq; dst = wqo; }
            else if (i < C) { j = i - B; src = wk; dst = wko; }
            else if (i < D) { j = i - C; src = wv; dst = wvo; }
            else            { j = i - D; src = wo; dst = woo; }
            float4 v = src[j];
            __half h[4];
            h[0] = __float2half_rn(v.x);
            h[1] = __float2half_rn(v.y);
            h[2] = __float2half_rn(v.z);
            h[3] = __float2half_rn(v.w);
            dst[j] = *(uint2*)h;
        }
    }
}

// ======================= common tile constants =============================
#define RSTR 112
#define TILE_B (128 * RSTR)            // 14336
#define STG_Q  (2 * TILE_B)            // 28672 (Q/O: A,B)
#define STG_KV (3 * TILE_B)            // 43008 (KV: Xh,Xl,B)
#define PROJ_SMEM (4 * STG_Q)          // 114688 (2 CTAs/SM: 224KB <= 228KB)

// ======================= fused Q+K+V projections (one launch) ==============
// All tiles 128x128, 8 warps 2m x 4n. 2 CTAs/SM.
//  bid <  256 : K/V tile (2-MMA, 2-stage) — heavy, scheduled FIRST
//  bid >= 256 : Q tile (1-MMA, 4-stage single-barrier, rope+scale epilogue)
__global__ __launch_bounds__(256, 2) void gemm_all(
    const __half* __restrict__ Xh, const __half* __restrict__ Xl,
    const __half* __restrict__ Wq, const __half* __restrict__ Wk,
    const __half* __restrict__ Wv,
    const float* __restrict__ cs, const float* __restrict__ sn,
    __half* __restrict__ Qo, __half* __restrict__ Ko, __half* __restrict__ Vto,
    float scale)
{
    extern __shared__ char sm[];
    const uint32_t smb = smem_u32(sm);

    const int bid = blockIdx.x;
    const int tid = threadIdx.x;
    const int warp = tid >> 5;
    const int lane = tid & 31;
    const int g = lane >> 2;
    const int t = lane & 3;
    const int K = HID;
    const int nk = K >> 5;
    const int wm = warp >> 2;          // 0..1
    const int wn = warp & 3;           // 0..3

    const int a_r  = (lane & 7) + ((lane >> 3) & 1) * 8;
    const int a_c8 = (lane >> 4) * 8;
    const int b_r  = lane & 7;
    const int b_j  = lane >> 4;
    const int b_c8 = ((lane >> 3) & 1) * 8;

    float acc[4][4][4];
#pragma unroll
    for (int i = 0; i < 4; i++)
#pragma unroll
        for (int j = 0; j < 4; j++)
#pragma unroll
            for (int r = 0; r < 4; r++) acc[i][j][r] = 0.0f;

    if (bid >= 256) {
        // ============ Q path: 128x128, 1-MMA, 4-stage single-barrier ========
        const int qid = bid - 256;
        const int bx = qid & 31;           // head index
        const int by = qid >> 5;           // row tile
        const int bm = by * 128;
        const int bn = bx * 128;

        auto load_stage = [&](int s, int c) {
            const uint32_t sb = smb + s * STG_Q;
            const int k0 = c * 32;
#pragma unroll
            for (int it = 0; it < 2; it++) {
                const int id = tid + it * 256;
                const int r = id >> 2, ch = id & 3;
                const uint32_t off = r * RSTR + ch * 16;
                cp_async16(sb + off,          Xh + (size_t)(bm + r) * K + k0 + ch * 8);
                cp_async16(sb + TILE_B + off, Wq + (size_t)(bn + r) * K + k0 + ch * 8);
            }
            CP_COMMIT();
        };

        load_stage(0, 0);
        load_stage(1, 1);
        load_stage(2, 2);

        for (int c = 0; c < nk; c++) {
            if (c + 2 < nk)      asm volatile("cp.async.wait_group 2;" ::: "memory");
            else if (c + 1 < nk) asm volatile("cp.async.wait_group 1;" ::: "memory");
            else                 asm volatile("cp.async.wait_group 0;" ::: "memory");
            __syncthreads();
            if (c + 3 < nk) load_stage((c + 3) & 3, c + 3);

            const uint32_t uA = smb + (c & 3) * STG_Q;
            const uint32_t uB = uA + TILE_B;
#pragma unroll
            for (int ks = 0; ks < 2; ks++) {
                const uint32_t colA = (ks * 16 + a_c8) * 2;
                const uint32_t colB = (ks * 16 + b_c8) * 2;
                uint32_t ah[4][4];
#pragma unroll
                for (int i = 0; i < 4; i++) {
                    const uint32_t ro = (wm * 64 + i * 16 + a_r) * RSTR + colA;
                    ldsm_x4(ah[i], uA + ro);
                }
#pragma unroll
                for (int p = 0; p < 2; p++) {
                    const uint32_t ro = (wn * 32 + (2 * p + b_j) * 8 + b_r) * RSTR + colB;
                    uint32_t bh[4];
                    ldsm_x4(bh, uB + ro);
#pragma unroll
                    for (int i = 0; i < 4; i++) {
                        MMA_F16(acc[i][2*p],   ah[i], bh[0], bh[1]);
                        MMA_F16(acc[i][2*p+1], ah[i], bh[2], bh[3]);
                    }
                }
            }
        }
        __syncthreads();   // all warps done reading smem before epilogue reuse

        // ---- rope+scale epilogue through smem fp32 staging ----
        float* st = (float*)sm;   // [128][132] fp32 = 67.6 KB
#pragma unroll
        for (int i = 0; i < 4; i++) {
            const int r0 = wm * 64 + i * 16 + g;
#pragma unroll
            for (int j = 0; j < 4; j++) {
                const int col = wn * 32 + j * 8 + 2 * t;
                *(float2*)&st[r0 * 132 + col] = make_float2(acc[i][j][0], acc[i][j][1]);
                *(float2*)&st[(r0 + 8) * 132 + col] = make_float2(acc[i][j][2], acc[i][j][3]);
            }
        }
        __syncthreads();
#pragma unroll
        for (int it = 0; it < 32; it++) {
            const int id = tid + 256 * it;       // 0..8191
            const int srow = id >> 6, d = id & 63;
            const int s = bm + srow;
            const float x1 = st[srow * 132 + d];
            const float x2 = st[srow * 132 + d + 64];
            const float c = cs[s * 64 + d];
            const float si = sn[s * 64 + d];
            const size_t base = ((size_t)bx * S_LEN + s) * HD;
            Qo[base + d]      = __float2half_rn((x1 * c - x2 * si) * scale);
            Qo[base + d + 64] = __float2half_rn((x2 * c + x1 * si) * scale);
        }
    } else {
        // ================= K/V path: 128x128, 2-MMA, 2-stage ================
        const int bx = bid & 15;
        const int by = bid >> 4;
        const int bm = by * 128;
        const bool isK = bx < 8;
        const int bn = (bx & 7) * 128;
        const __half* B = isK ? Wk : Wv;

        auto load_stage = [&](int s, int c) {
            const uint32_t sb = smb + s * STG_KV;
            const int k0 = c * 32;
#pragma unroll
            for (int it = 0; it < 2; it++) {
                const int id = tid + it * 256;
                const int r = id >> 2, ch = id & 3;
                const uint32_t off = r * RSTR + ch * 16;
                const size_t ga = (size_t)(bm + r) * K + k0 + ch * 8;
                const size_t gb = (size_t)(bn + r) * K + k0 + ch * 8;
                cp_async16(sb + off,              Xh + ga);
                cp_async16(sb + TILE_B + off,     Xl + ga);
                cp_async16(sb + 2 * TILE_B + off, B + gb);
            }
            CP_COMMIT();
        };

        load_stage(0, 0);
        load_stage(1, 1);

        for (int c = 0; c < nk; c++) {
            const int s = c & 1;
            if (c + 1 < nk) asm volatile("cp.async.wait_group 1;" ::: "memory");
            else            asm volatile("cp.async.wait_group 0;" ::: "memory");
            __syncthreads();

            const uint32_t uAh = smb + s * STG_KV;
            const uint32_t uAl = uAh + TILE_B;
            const uint32_t uB  = uAh + 2 * TILE_B;
#pragma unroll
            for (int ks = 0; ks < 2; ks++) {
                const uint32_t colA = (ks * 16 + a_c8) * 2;
                const uint32_t colB = (ks * 16 + b_c8) * 2;
                uint32_t ah[4][4], al[4][4];
#pragma unroll
                for (int i = 0; i < 4; i++) {
                    const uint32_t ro = (wm * 64 + i * 16 + a_r) * RSTR + colA;
                    ldsm_x4(ah[i], uAh + ro);
                    ldsm_x4(al[i], uAl + ro);
                }
#pragma unroll
                for (int p = 0; p < 2; p++) {
                    const uint32_t ro = (wn * 32 + (2 * p + b_j) * 8 + b_r) * RSTR + colB;
                    uint32_t bh[4];
                    ldsm_x4(bh, uB + ro);
#pragma unroll
                    for (int i = 0; i < 4; i++) {
                        MMA_F16(acc[i][2*p],   ah[i], bh[0], bh[1]);
                        MMA_F16(acc[i][2*p],   al[i], bh[0], bh[1]);
                        MMA_F16(acc[i][2*p+1], ah[i], bh[2], bh[3]);
                        MMA_F16(acc[i][2*p+1], al[i], bh[2], bh[3]);
                    }
                }
            }
            __syncthreads();
            if (c + 2 < nk) load_stage(s, c + 2);
        }

        const int kvh = bn >> 7;
        if (isK) {
            // ---- K: rope epilogue through smem fp32 staging ----
            float* st = (float*)sm;
#pragma unroll
            for (int i = 0; i < 4; i++) {
                const int r0 = wm * 64 + i * 16 + g;
#pragma unroll
                for (int j = 0; j < 4; j++) {
                    const int col = wn * 32 + j * 8 + 2 * t;
                    *(float2*)&st[r0 * 132 + col] = make_float2(acc[i][j][0], acc[i][j][1]);
                    *(float2*)&st[(r0 + 8) * 132 + col] = make_float2(acc[i][j][2], acc[i][j][3]);
                }
            }
            __syncthreads();
#pragma unroll
            for (int it = 0; it < 32; it++) {
                const int id = tid + 256 * it;
                const int srow = id >> 6, d = id & 63;
                const int s = bm + srow;
                const float x1 = st[srow * 132 + d];
                const float x2 = st[srow * 132 + d + 64];
                const float c = cs[s * 64 + d];
                const float si = sn[s * 64 + d];
                const size_t base = ((size_t)kvh * S_LEN + s) * HD;
                Ko[base + d]      = __float2half_rn(x1 * c - x2 * si);
                Ko[base + d + 64] = __float2half_rn(x2 * c + x1 * si);
            }
        } else {
            // ---- V: fused transpose epilogue -> vt16[kvh][d][s] ----
            __half* st = (__half*)sm;    // [128 d][136 stride] halves
#pragma unroll
            for (int i = 0; i < 4; i++) {
                const int sl = wm * 64 + i * 16 + g;
#pragma unroll
                for (int j = 0; j < 4; j++) {
                    const int d0 = wn * 32 + j * 8 + 2 * t;
                    st[(d0    ) * 136 + sl    ] = __float2half_rn(acc[i][j][0]);
                    st[(d0 + 1) * 136 + sl    ] = __float2half_rn(acc[i][j][1]);
                    st[(d0    ) * 136 + sl + 8] = __float2half_rn(acc[i][j][2]);
                    st[(d0 + 1) * 136 + sl + 8] = __float2half_rn(acc[i][j][3]);
                }
            }
            __syncthreads();
#pragma unroll
            for (int it = 0; it < 8; it++) {
                const int id = tid + 256 * it;      // 0..2047
                const int d = id >> 4, seg = id & 15;
                uint4 val = *(uint4*)&st[d * 136 + seg * 8];
                *(uint4*)(Vto + ((size_t)(kvh * HD + d)) * S_LEN + bm + seg * 8) = val;
            }
        }
    }
}

// ======================= 128x128 fp16 1-MMA GEMM (O projection) ============
// 4-stage single-barrier, 2 CTAs/SM.
__global__ __launch_bounds__(256, 2) void gemm_tc128s(
    const __half* __restrict__ A, const __half* __restrict__ B,
    float* __restrict__ C, int M, int N, int K)
{
    extern __shared__ char sm[];
    const uint32_t smb = smem_u32(sm);

    const int tid = threadIdx.x;
    const int warp = tid >> 5;
    const int lane = tid & 31;
    const int wm = warp >> 2;
    const int wn = warp & 3;
    const int g = lane >> 2;
    const int t = lane & 3;
    const int bm = blockIdx.y * 128;
    const int bn = blockIdx.x * 128;
    const int nk = K >> 5;

    const int a_r  = (lane & 7) + ((lane >> 3) & 1) * 8;
    const int a_c8 = (lane >> 4) * 8;
    const int b_r  = lane & 7;
    const int b_j  = lane >> 4;
    const int b_c8 = ((lane >> 3) & 1) * 8;

    float acc[4][4][4];
#pragma unroll
    for (int i = 0; i < 4; i++)
#pragma unroll
        for (int j = 0; j < 4; j++)
#pragma unroll
            for (int r = 0; r < 4; r++) acc[i][j][r] = 0.0f;

    auto load_stage = [&](int s, int c) {
        const uint32_t sb = smb + s * STG_Q;
        const int k0 = c * 32;
#pragma unroll
        for (int it = 0; it < 2; it++) {
            const int id = tid + it * 256;
            const int r = id >> 2, ch = id & 3;
            const uint32_t off = r * RSTR + ch * 16;
            cp_async16(sb + off,          A + (size_t)(bm + r) * K + k0 + ch * 8);
            cp_async16(sb + TILE_B + off, B + (size_t)(bn + r) * K + k0 + ch * 8);
        }
        CP_COMMIT();
    };

    load_stage(0, 0);
    if (nk > 1) load_stage(1, 1);
    if (nk > 2) load_stage(2, 2);

    for (int c = 0; c < nk; c++) {
        if (c + 2 < nk)      asm volatile("cp.async.wait_group 2;" ::: "memory");
        else if (c + 1 < nk) asm volatile("cp.async.wait_group 1;" ::: "memory");
        else                 asm volatile("cp.async.wait_group 0;" ::: "memory");
        __syncthreads();
        if (c + 3 < nk) load_stage((c + 3) & 3, c + 3);

        const uint32_t uA = smb + (c & 3) * STG_Q;
        const uint32_t uB = uA + TILE_B;

#pragma unroll
        for (int ks = 0; ks < 2; ks++) {
            const uint32_t colA = (ks * 16 + a_c8) * 2;
            const uint32_t colB = (ks * 16 + b_c8) * 2;
            uint32_t ah[4][4];
#pragma unroll
            for (int i = 0; i < 4; i++) {
                const uint32_t ro = (wm * 64 + i * 16 + a_r) * RSTR + colA;
                ldsm_x4(ah[i], uA + ro);
            }
#pragma unroll
            for (int p = 0; p < 2; p++) {
                const uint32_t ro = (wn * 32 + (2 * p + b_j) * 8 + b_r) * RSTR + colB;
                uint32_t bh[4];
                ldsm_x4(bh, uB + ro);
#pragma unroll
                for (int i = 0; i < 4; i++) {
                    MMA_F16(acc[i][2*p],   ah[i], bh[0], bh[1]);
                    MMA_F16(acc[i][2*p+1], ah[i], bh[2], bh[3]);
                }
            }
        }
    }

#pragma unroll
    for (int i = 0; i < 4; i++) {
        const int row0 = bm + wm * 64 + i * 16 + g;
#pragma unroll
        for (int j = 0; j < 4; j++) {
            const int col = bn + wn * 32 + j * 8 + 2 * t;
            *(float2*)(C + (size_t)row0 * N + col) = make_float2(acc[i][j][0], acc[i][j][1]);
            *(float2*)(C + (size_t)(row0 + 8) * N + col) = make_float2(acc[i][j][2], acc[i][j][3]);
        }
    }
}

// ======================= Flash attention (all single-fp16 MMA) =============
#define QSTR 272
#define VSTR 144
#define FA_QB (128 * QSTR)
#define FA_KB (64 * QSTR)
#define FA_VB (128 * VSTR)
#define FA_STAGE (FA_KB + FA_VB)
#define FA_SMEM (FA_QB + 2 * FA_STAGE)     // 106496

__global__ __launch_bounds__(256, 2) void flash_attn_tc(
    const __half* __restrict__ Qf, const __half* __restrict__ Kf,
    const __half* __restrict__ Vt, __half* __restrict__ O)
{
    extern __shared__ char fsm[];
    const uint32_t smb = smem_u32(fsm);
    const int qb = gridDim.x - 1 - blockIdx.x;
    const int h  = blockIdx.y;
    const int kvh = h % NKV;
    const int q0 = qb * 128;
    const int tid = threadIdx.x;
    const int w = tid >> 5;
    const int lane = tid & 31;
    const int g = lane >> 2;
    const int t = lane & 3;

    const int a_r  = (lane & 7) + ((lane >> 3) & 1) * 8;
    const int a_c8 = (lane >> 4) * 8;
    const int b_r  = lane & 7;
    const int b_j  = lane >> 4;
    const int b_c8 = ((lane >> 3) & 1) * 8;

#pragma unroll
    for (int it = 0; it < 8; it++) {
        const int id = tid + 256 * it;
        const int r = id >> 4, ch = id & 15;
        const uint32_t off = r * QSTR + ch * 16;
        const size_t gi = ((size_t)h * S_LEN + q0 + r) * HD + ch * 8;
        cp_async16(smb + off, Qf + gi);
    }

    auto fa_load = [&](int s, int jb) {
        const uint32_t sb = smb + FA_QB + s * FA_STAGE;
        const int k0 = jb * 64;
#pragma unroll
        for (int it = 0; it < 4; it++) {
            const int id = tid + 256 * it;
            const int r = id >> 4, ch = id & 15;
            const uint32_t off = r * QSTR + ch * 16;
            const size_t gi = ((size_t)kvh * S_LEN + k0 + r) * HD + ch * 8;
            cp_async16(sb + off, Kf + gi);
        }
#pragma unroll
        for (int it = 0; it < 4; it++) {
            const int id = tid + 256 * it;
            const int r = id >> 3, ch = id & 7;
            const uint32_t off = r * VSTR + ch * 16;
            const size_t gi = ((size_t)kvh * HD + r) * S_LEN + k0 + ch * 8;
            cp_async16(sb + FA_KB + off, Vt + gi);
        }
    };

    const int njb = 2 * qb + 2;
    fa_load(0, 0);
    CP_COMMIT();
    fa_load(1, 1);
    CP_COMMIT();

    float oacc[16][4];
#pragma unroll
    for (int jd = 0; jd < 16; jd++)
#pragma unroll
        for (int r = 0; r < 4; r++) oacc[jd][r] = 0.0f;
    float m0 = -1e30f, m1 = -1e30f, l0 = 0.0f, l1 = 0.0f;

    const uint32_t uQ = smb;

    for (int jb = 0; jb < njb; jb++) {
        const int s = jb & 1;
        if (jb + 1 < njb) asm volatile("cp.async.wait_group 1;" ::: "memory");
        else              asm volatile("cp.async.wait_group 0;" ::: "memory");
        __syncthreads();

        const uint32_t uK = smb + FA_QB + s * FA_STAGE;
        const uint32_t uV = uK + FA_KB;

        float sv[8][4];
#pragma unroll
        for (int j = 0; j < 8; j++)
#pragma unroll
            for (int r = 0; r < 4; r++) sv[j][r] = 0.0f;

#pragma unroll
        for (int kt = 0; kt < 8; kt++) {
            const uint32_t qro = (16 * w + a_r) * QSTR + (kt * 16 + a_c8) * 2;
            uint32_t qh[4];
            ldsm_x4(qh, uQ + qro);
#pragma unroll
            for (int p = 0; p < 4; p++) {
                const uint32_t kro = ((2 * p + b_j) * 8 + b_r) * QSTR + (kt * 16 + b_c8) * 2;
                uint32_t kh[4];
                ldsm_x4(kh, uK + kro);
                MMA_F16(sv[2*p],   qh, kh[0], kh[1]);
                MMA_F16(sv[2*p+1], qh, kh[2], kh[3]);
            }
        }

        if (jb >= 2 * qb) {
            const int r0g = q0 + 16 * w + g;
            const int r1g = r0g + 8;
            const int kg = jb * 64;
#pragma unroll
            for (int j = 0; j < 8; j++) {
                const int c0 = kg + 8 * j + 2 * t, c1 = c0 + 1;
                if (c0 > r0g) sv[j][0] = -1e30f;
                if (c1 > r0g) sv[j][1] = -1e30f;
                if (c0 > r1g) sv[j][2] = -1e30f;
                if (c1 > r1g) sv[j][3] = -1e30f;
            }
        }

        float mn0 = m0, mn1 = m1;
#pragma unroll
        for (int j = 0; j < 8; j++) {
            mn0 = fmaxf(mn0, fmaxf(sv[j][0], sv[j][1]));
            mn1 = fmaxf(mn1, fmaxf(sv[j][2], sv[j][3]));
        }
        mn0 = fmaxf(mn0, __shfl_xor_sync(0xffffffffu, mn0, 1));
        mn0 = fmaxf(mn0, __shfl_xor_sync(0xffffffffu, mn0, 2));
        mn1 = fmaxf(mn1, __shfl_xor_sync(0xffffffffu, mn1, 1));
        mn1 = fmaxf(mn1, __shfl_xor_sync(0xffffffffu, mn1, 2));

        const float corr0 = __expf(m0 - mn0);
        const float corr1 = __expf(m1 - mn1);
        float rs0 = 0.0f, rs1 = 0.0f;
#pragma unroll
        for (int j = 0; j < 8; j++) {
            sv[j][0] = __expf(sv[j][0] - mn0);
            sv[j][1] = __expf(sv[j][1] - mn0);
            sv[j][2] = __expf(sv[j][2] - mn1);
            sv[j][3] = __expf(sv[j][3] - mn1);
            rs0 += sv[j][0] + sv[j][1];
            rs1 += sv[j][2] + sv[j][3];
        }
        rs0 += __shfl_xor_sync(0xffffffffu, rs0, 1);
        rs0 += __shfl_xor_sync(0xffffffffu, rs0, 2);
        rs1 += __shfl_xor_sync(0xffffffffu, rs1, 1);
        rs1 += __shfl_xor_sync(0xffffffffu, rs1, 2);
        l0 = l0 * corr0 + rs0;
        l1 = l1 * corr1 + rs1;
        m0 = mn0; m1 = mn1;

#pragma unroll
        for (int jd = 0; jd < 16; jd++) {
            oacc[jd][0] *= corr0; oacc[jd][1] *= corr0;
            oacc[jd][2] *= corr1; oacc[jd][3] *= corr1;
        }

#pragma unroll
        for (int kt = 0; kt < 4; kt++) {
            uint32_t ph[4];
            ph[0] = pack2h(sv[2*kt][0],   sv[2*kt][1]);
            ph[1] = pack2h(sv[2*kt][2],   sv[2*kt][3]);
            ph[2] = pack2h(sv[2*kt+1][0], sv[2*kt+1][1]);
            ph[3] = pack2h(sv[2*kt+1][2], sv[2*kt+1][3]);
#pragma unroll
            for (int p = 0; p < 8; p++) {
                const uint32_t vro = ((2 * p + b_j) * 8 + b_r) * VSTR + (kt * 16 + b_c8) * 2;
                uint32_t vh[4];
                ldsm_x4(vh, uV + vro);
                MMA_F16(oacc[2*p],   ph, vh[0], vh[1]);
                MMA_F16(oacc[2*p+1], ph, vh[2], vh[3]);
            }
        }

        __syncthreads();
        if (jb + 2 < njb) { fa_load(s, jb + 2); CP_COMMIT(); }
    }

    const float inv0 = 1.0f / l0;
    const float inv1 = 1.0f / l1;
    const int s0 = q0 + 16 * w + g;
    const int s1 = s0 + 8;
#pragma unroll
    for (int jd = 0; jd < 16; jd++) {
        const int d = 8 * jd + 2 * t;
        const size_t i0 = (size_t)s0 * HID + h * HD + d;
        const size_t i1 = (size_t)s1 * HID + h * HD + d;
        *(uint32_t*)(O + i0) = pack2h(oacc[jd][0] * inv0, oacc[jd][1] * inv0);
        *(uint32_t*)(O + i1) = pack2h(oacc[jd][2] * inv1, oacc[jd][3] * inv1);
    }
}

// ======================= launch ============================================
extern "C" void kernel_launch(void* const* d_in, const int* in_sizes, int n_in,
                              void* d_out, int out_size) {
    const float* x  = (const float*)d_in[0];
    const float* wq = (const float*)d_in[1];
    const float* wk = (const float*)d_in[2];
    const float* wv = (const float*)d_in[3];
    const float* wo = (const float*)d_in[4];
    const float* cs = (const float*)d_in[5];
    const float* sn = (const float*)d_in[6];
    float* out = (float*)d_out;

    __half *xh16, *xl16, *wq16, *wk16, *wv16, *wo16, *att16, *vt16, *qh16, *k16;
    cudaGetSymbolAddress((void**)&xh16, g_xh16); cudaGetSymbolAddress((void**)&xl16, g_xl16);
    cudaGetSymbolAddress((void**)&wq16, g_wq16); cudaGetSymbolAddress((void**)&wk16, g_wk16);
    cudaGetSymbolAddress((void**)&wv16, g_wv16); cudaGetSymbolAddress((void**)&wo16, g_wo16);
    cudaGetSymbolAddress((void**)&att16, g_att16);
    cudaGetSymbolAddress((void**)&vt16, g_vt16);
    cudaGetSymbolAddress((void**)&qh16, g_qh16);
    cudaGetSymbolAddress((void**)&k16, g_k16);

    cudaFuncSetAttribute(gemm_all, cudaFuncAttributeMaxDynamicSharedMemorySize, PROJ_SMEM);
    cudaFuncSetAttribute(gemm_tc128s, cudaFuncAttributeMaxDynamicSharedMemorySize, PROJ_SMEM);
    cudaFuncSetAttribute(flash_attn_tc, cudaFuncAttributeMaxDynamicSharedMemorySize, FA_SMEM);

    // one-shot split of all inputs (MLP=4)
    split_all<<<SPLIT_TOTAL / 1024, 256>>>(
        (const float4*)x, (uint2*)xh16, (uint2*)xl16,
        (const float4*)wq, (uint2*)wq16,
        (const float4*)wk, (uint2*)wk16,
        (const float4*)wv, (uint2*)wv16,
        (const float4*)wo, (uint2*)wo16);

    // fused Q+K+V projections (K/V heavy tiles first), 2 CTAs/SM
    const float scale = 0.08838834764831845f;
    gemm_all<<<768, 256, PROJ_SMEM>>>(
        xh16, xl16, wq16, wk16, wv16, cs, sn, qh16, k16, vt16, scale);

    // tensor-core flash attention
    flash_attn_tc<<<dim3(S_LEN / 128, NH), 256, FA_SMEM>>>(
        qh16, k16, vt16, att16);

    // output projection (4-stage single-barrier, 2 CTAs/SM)
    gemm_tc128s<<<dim3(HID / 128, S_LEN / 128), 256, PROJ_SMEM>>>(
        att16, wo16, out, S_LEN, HID, HID);
}

// round 16
// speedup vs baseline: 7.1216x; 1.0762x over previous
#include <cuda_runtime.h>
#include <cuda_fp16.h>
#include <stdint.h>
#include <math.h>

#define S_LEN 2048
#define HID 4096
#define NH 32
#define NKV 8
#define HD 128

// ---------------- scratch ---------------------------------------------------
__device__ __half g_xh16[S_LEN * HID], g_xl16[S_LEN * HID];
__device__ __half g_wq16[HID * HID];
__device__ __half g_wk16[NKV*HD * HID];
__device__ __half g_wv16[NKV*HD * HID];
__device__ __half g_wo16[HID * HID];
__device__ __half g_att16[S_LEN * HID];
__device__ __half g_vt16[NKV * HD * S_LEN];
__device__ __half g_qh16[NH * S_LEN * HD];
__device__ __half g_k16[NKV * S_LEN * HD];

// ======================= helpers ===========================================
__device__ __forceinline__ uint32_t smem_u32(const void* p) {
    uint32_t a;
    asm("{ .reg .u64 t; cvta.to.shared.u64 t, %1; cvt.u32.u64 %0, t; }" : "=r"(a) : "l"(p));
    return a;
}
__device__ __forceinline__ void cp_async16(uint32_t saddr, const void* g) {
    asm volatile("cp.async.cg.shared.global [%0], [%1], 16;" :: "r"(saddr), "l"(g));
}
#define CP_COMMIT() asm volatile("cp.async.commit_group;" ::: "memory")

#define MMA_F16(c, a, b0, b1)                                                  \
    asm volatile("mma.sync.aligned.m16n8k16.row.col.f32.f16.f16.f32 "          \
        "{%0,%1,%2,%3}, {%4,%5,%6,%7}, {%8,%9}, {%0,%1,%2,%3};"                \
        : "+f"((c)[0]), "+f"((c)[1]), "+f"((c)[2]), "+f"((c)[3])               \
        : "r"((a)[0]), "r"((a)[1]), "r"((a)[2]), "r"((a)[3]), "r"(b0), "r"(b1))

__device__ __forceinline__ void ldsm_x4(uint32_t* r, uint32_t addr) {
    asm volatile("ldmatrix.sync.aligned.m8n8.x4.shared.b16 {%0,%1,%2,%3}, [%4];"
        : "=r"(r[0]), "=r"(r[1]), "=r"(r[2]), "=r"(r[3]) : "r"(addr));
}
__device__ __forceinline__ uint32_t pack2h(float x, float y) {
    __half2 h = __floats2half2_rn(x, y);
    return *(uint32_t*)&h;
}

// ======================= one-shot split of all inputs (MLP=4) ==============
#define X4  ((S_LEN * HID) / 4)
#define W44 ((HID * HID) / 4)
#define W14 ((NKV * HD * HID) / 4)
#define SPLIT_TOTAL (X4 + 2 * W44 + 2 * W14)

__global__ void split_all(const float4* __restrict__ x,
                          uint2* __restrict__ xh, uint2* __restrict__ xl,
                          const float4* __restrict__ wq, uint2* __restrict__ wqo,
                          const float4* __restrict__ wk, uint2* __restrict__ wko,
                          const float4* __restrict__ wv, uint2* __restrict__ wvo,
                          const float4* __restrict__ wo, uint2* __restrict__ woo) {
    const int base = blockIdx.x * 1024 + threadIdx.x;
    const int A = X4, B = A + W44, C = B + W14, D = C + W14;
#pragma unroll
    for (int u = 0; u < 4; u++) {
        const int i = base + u * 256;
        if (i >= SPLIT_TOTAL) break;
        if (i < A) {
            float4 v = x[i];
            __half h[4], l[4];
            h[0] = __float2half_rn(v.x); l[0] = __float2half_rn(v.x - __half2float(h[0]));
            h[1] = __float2half_rn(v.y); l[1] = __float2half_rn(v.y - __half2float(h[1]));
            h[2] = __float2half_rn(v.z); l[2] = __float2half_rn(v.z - __half2float(h[2]));
            h[3] = __float2half_rn(v.w); l[3] = __float2half_rn(v.w - __half2float(h[3]));
            xh[i] = *(uint2*)h;
            xl[i] = *(uint2*)l;
        } else {
            const float4* src;
            uint2* dst;
            int j;
            if (i < B)      { j = i - A; src = wq; dst = wqo; }
            else if (i < C) { j = i - B; src = wk; dst = wko; }
            else if (i < D) { j = i - C; src = wv; dst = wvo; }
            else            { j = i - D; src = wo; dst = woo; }
            float4 v = src[j];
            __half h[4];
            h[0] = __float2half_rn(v.x);
            h[1] = __float2half_rn(v.y);
            h[2] = __float2half_rn(v.z);
            h[3] = __float2half_rn(v.w);
            dst[j] = *(uint2*)h;
        }
    }
}

// ======================= common tile constants =============================
// K-chunk 64: rows are 128B, stride 144B (FA-V validated ldsm pattern).
#define R64 144
#define T64 (128 * R64)                // 18432 per tile buffer
#define STGQ (2 * T64)                 // 36864 (Q/O: A,B)
#define STGKV (3 * T64)                // 55296 (KV: Xh,Xl,B)
#define PROJ_SMEM (3 * STGQ)           // 110592 (== 2*STGKV); 2 CTAs/SM

// ======================= fused Q+K+V projections (one launch) ==============
//  bid <  256 : K/V tile (2-MMA, Kc=64, 2-stage) — heavy, scheduled FIRST
//  bid >= 256 : Q tile (1-MMA, Kc=64, 3-stage single-barrier, rope epilogue)
__global__ __launch_bounds__(256, 2) void gemm_all(
    const __half* __restrict__ Xh, const __half* __restrict__ Xl,
    const __half* __restrict__ Wq, const __half* __restrict__ Wk,
    const __half* __restrict__ Wv,
    const float* __restrict__ cs, const float* __restrict__ sn,
    __half* __restrict__ Qo, __half* __restrict__ Ko, __half* __restrict__ Vto,
    float scale)
{
    extern __shared__ char sm[];
    const uint32_t smb = smem_u32(sm);

    const int bid = blockIdx.x;
    const int tid = threadIdx.x;
    const int warp = tid >> 5;
    const int lane = tid & 31;
    const int g = lane >> 2;
    const int t = lane & 3;
    const int K = HID;
    const int nc = K >> 6;             // 64 chunks
    const int wm = warp >> 2;          // 0..1
    const int wn = warp & 3;           // 0..3

    const int a_r  = (lane & 7) + ((lane >> 3) & 1) * 8;
    const int a_c8 = (lane >> 4) * 8;
    const int b_r  = lane & 7;
    const int b_j  = lane >> 4;
    const int b_c8 = ((lane >> 3) & 1) * 8;

    float acc[4][4][4];
#pragma unroll
    for (int i = 0; i < 4; i++)
#pragma unroll
        for (int j = 0; j < 4; j++)
#pragma unroll
            for (int r = 0; r < 4; r++) acc[i][j][r] = 0.0f;

    if (bid >= 256) {
        // ===== Q path: 128x128, 1-MMA, Kc=64, 3-stage single-barrier ========
        const int qid = bid - 256;
        const int bx = qid & 31;           // head index
        const int by = qid >> 5;           // row tile
        const int bm = by * 128;
        const int bn = bx * 128;

        auto load_stage = [&](int s, int c) {
            const uint32_t sb = smb + s * STGQ;
            const int k0 = c * 64;
#pragma unroll
            for (int it = 0; it < 4; it++) {
                const int id = tid + it * 256;       // 0..1023
                const int r = id >> 3, ch = id & 7;
                const uint32_t off = r * R64 + ch * 16;
                cp_async16(sb + off,       Xh + (size_t)(bm + r) * K + k0 + ch * 8);
                cp_async16(sb + T64 + off, Wq + (size_t)(bn + r) * K + k0 + ch * 8);
            }
            CP_COMMIT();
        };

        load_stage(0, 0);
        load_stage(1, 1);

        for (int c = 0; c < nc; c++) {
            if (c + 1 < nc) asm volatile("cp.async.wait_group 1;" ::: "memory");
            else            asm volatile("cp.async.wait_group 0;" ::: "memory");
            __syncthreads();
            if (c + 2 < nc) load_stage((c + 2) % 3, c + 2);

            const uint32_t uA = smb + (c % 3) * STGQ;
            const uint32_t uB = uA + T64;
#pragma unroll
            for (int ks = 0; ks < 4; ks++) {
                const uint32_t colA = (ks * 16 + a_c8) * 2;
                const uint32_t colB = (ks * 16 + b_c8) * 2;
                uint32_t ah[4][4];
#pragma unroll
                for (int i = 0; i < 4; i++) {
                    const uint32_t ro = (wm * 64 + i * 16 + a_r) * R64 + colA;
                    ldsm_x4(ah[i], uA + ro);
                }
#pragma unroll
                for (int p = 0; p < 2; p++) {
                    const uint32_t ro = (wn * 32 + (2 * p + b_j) * 8 + b_r) * R64 + colB;
                    uint32_t bh[4];
                    ldsm_x4(bh, uB + ro);
#pragma unroll
                    for (int i = 0; i < 4; i++) {
                        MMA_F16(acc[i][2*p],   ah[i], bh[0], bh[1]);
                        MMA_F16(acc[i][2*p+1], ah[i], bh[2], bh[3]);
                    }
                }
            }
        }
        __syncthreads();

        // ---- rope+scale epilogue through smem fp32 staging ----
        float* st = (float*)sm;   // [128][132] fp32 = 67.6 KB
#pragma unroll
        for (int i = 0; i < 4; i++) {
            const int r0 = wm * 64 + i * 16 + g;
#pragma unroll
            for (int j = 0; j < 4; j++) {
                const int col = wn * 32 + j * 8 + 2 * t;
                *(float2*)&st[r0 * 132 + col] = make_float2(acc[i][j][0], acc[i][j][1]);
                *(float2*)&st[(r0 + 8) * 132 + col] = make_float2(acc[i][j][2], acc[i][j][3]);
            }
        }
        __syncthreads();
#pragma unroll
        for (int it = 0; it < 32; it++) {
            const int id = tid + 256 * it;       // 0..8191
            const int srow = id >> 6, d = id & 63;
            const int s = bm + srow;
            const float x1 = st[srow * 132 + d];
            const float x2 = st[srow * 132 + d + 64];
            const float c = cs[s * 64 + d];
            const float si = sn[s * 64 + d];
            const size_t base = ((size_t)bx * S_LEN + s) * HD;
            Qo[base + d]      = __float2half_rn((x1 * c - x2 * si) * scale);
            Qo[base + d + 64] = __float2half_rn((x2 * c + x1 * si) * scale);
        }
    } else {
        // ===== K/V path: 128x128, 2-MMA, Kc=64, 2-stage =====================
        const int bx = bid & 15;
        const int by = bid >> 4;
        const int bm = by * 128;
        const bool isK = bx < 8;
        const int bn = (bx & 7) * 128;
        const __half* B = isK ? Wk : Wv;

        auto load_stage = [&](int s, int c) {
            const uint32_t sb = smb + s * STGKV;
            const int k0 = c * 64;
#pragma unroll
            for (int it = 0; it < 4; it++) {
                const int id = tid + it * 256;
                const int r = id >> 3, ch = id & 7;
                const uint32_t off = r * R64 + ch * 16;
                const size_t ga = (size_t)(bm + r) * K + k0 + ch * 8;
                const size_t gb = (size_t)(bn + r) * K + k0 + ch * 8;
                cp_async16(sb + off,           Xh + ga);
                cp_async16(sb + T64 + off,     Xl + ga);
                cp_async16(sb + 2 * T64 + off, B + gb);
            }
            CP_COMMIT();
        };

        load_stage(0, 0);
        load_stage(1, 1);

        for (int c = 0; c < nc; c++) {
            const int s = c & 1;
            if (c + 1 < nc) asm volatile("cp.async.wait_group 1;" ::: "memory");
            else            asm volatile("cp.async.wait_group 0;" ::: "memory");
            __syncthreads();

            const uint32_t uAh = smb + s * STGKV;
            const uint32_t uAl = uAh + T64;
            const uint32_t uB  = uAh + 2 * T64;
#pragma unroll
            for (int ks = 0; ks < 4; ks++) {
                const uint32_t colA = (ks * 16 + a_c8) * 2;
                const uint32_t colB = (ks * 16 + b_c8) * 2;
                uint32_t ah[4][4], al[4][4];
#pragma unroll
                for (int i = 0; i < 4; i++) {
                    const uint32_t ro = (wm * 64 + i * 16 + a_r) * R64 + colA;
                    ldsm_x4(ah[i], uAh + ro);
                    ldsm_x4(al[i], uAl + ro);
                }
#pragma unroll
                for (int p = 0; p < 2; p++) {
                    const uint32_t ro = (wn * 32 + (2 * p + b_j) * 8 + b_r) * R64 + colB;
                    uint32_t bh[4];
                    ldsm_x4(bh, uB + ro);
#pragma unroll
                    for (int i = 0; i < 4; i++) {
                        MMA_F16(acc[i][2*p],   ah[i], bh[0], bh[1]);
                        MMA_F16(acc[i][2*p],   al[i], bh[0], bh[1]);
                        MMA_F16(acc[i][2*p+1], ah[i], bh[2], bh[3]);
                        MMA_F16(acc[i][2*p+1], al[i], bh[2], bh[3]);
                    }
                }
            }
            __syncthreads();
            if (c + 2 < nc) load_stage(s, c + 2);
        }

        const int kvh = bn >> 7;
        if (isK) {
            // ---- K: rope epilogue through smem fp32 staging ----
            float* st = (float*)sm;
#pragma unroll
            for (int i = 0; i < 4; i++) {
                const int r0 = wm * 64 + i * 16 + g;
#pragma unroll
                for (int j = 0; j < 4; j++) {
                    const int col = wn * 32 + j * 8 + 2 * t;
                    *(float2*)&st[r0 * 132 + col] = make_float2(acc[i][j][0], acc[i][j][1]);
                    *(float2*)&st[(r0 + 8) * 132 + col] = make_float2(acc[i][j][2], acc[i][j][3]);
                }
            }
            __syncthreads();
#pragma unroll
            for (int it = 0; it < 32; it++) {
                const int id = tid + 256 * it;
                const int srow = id >> 6, d = id & 63;
                const int s = bm + srow;
                const float x1 = st[srow * 132 + d];
                const float x2 = st[srow * 132 + d + 64];
                const float c = cs[s * 64 + d];
                const float si = sn[s * 64 + d];
                const size_t base = ((size_t)kvh * S_LEN + s) * HD;
                Ko[base + d]      = __float2half_rn(x1 * c - x2 * si);
                Ko[base + d + 64] = __float2half_rn(x2 * c + x1 * si);
            }
        } else {
            // ---- V: fused transpose epilogue -> vt16[kvh][d][s] ----
            __half* st = (__half*)sm;    // [128 d][136 stride] halves
#pragma unroll
            for (int i = 0; i < 4; i++) {
                const int sl = wm * 64 + i * 16 + g;
#pragma unroll
                for (int j = 0; j < 4; j++) {
                    const int d0 = wn * 32 + j * 8 + 2 * t;
                    st[(d0    ) * 136 + sl    ] = __float2half_rn(acc[i][j][0]);
                    st[(d0 + 1) * 136 + sl    ] = __float2half_rn(acc[i][j][1]);
                    st[(d0    ) * 136 + sl + 8] = __float2half_rn(acc[i][j][2]);
                    st[(d0 + 1) * 136 + sl + 8] = __float2half_rn(acc[i][j][3]);
                }
            }
            __syncthreads();
#pragma unroll
            for (int it = 0; it < 8; it++) {
                const int id = tid + 256 * it;      // 0..2047
                const int d = id >> 4, seg = id & 15;
                uint4 val = *(uint4*)&st[d * 136 + seg * 8];
                *(uint4*)(Vto + ((size_t)(kvh * HD + d)) * S_LEN + bm + seg * 8) = val;
            }
        }
    }
}

// ======================= 128x128 fp16 1-MMA GEMM (O projection) ============
// Kc=64, 3-stage single-barrier, 2 CTAs/SM.
__global__ __launch_bounds__(256, 2) void gemm_tc128s(
    const __half* __restrict__ A, const __half* __restrict__ B,
    float* __restrict__ C, int M, int N, int K)
{
    extern __shared__ char sm[];
    const uint32_t smb = smem_u32(sm);

    const int tid = threadIdx.x;
    const int warp = tid >> 5;
    const int lane = tid & 31;
    const int wm = warp >> 2;
    const int wn = warp & 3;
    const int g = lane >> 2;
    const int t = lane & 3;
    const int bm = blockIdx.y * 128;
    const int bn = blockIdx.x * 128;
    const int nc = K >> 6;

    const int a_r  = (lane & 7) + ((lane >> 3) & 1) * 8;
    const int a_c8 = (lane >> 4) * 8;
    const int b_r  = lane & 7;
    const int b_j  = lane >> 4;
    const int b_c8 = ((lane >> 3) & 1) * 8;

    float acc[4][4][4];
#pragma unroll
    for (int i = 0; i < 4; i++)
#pragma unroll
        for (int j = 0; j < 4; j++)
#pragma unroll
            for (int r = 0; r < 4; r++) acc[i][j][r] = 0.0f;

    auto load_stage = [&](int s, int c) {
        const uint32_t sb = smb + s * STGQ;
        const int k0 = c * 64;
#pragma unroll
        for (int it = 0; it < 4; it++) {
            const int id = tid + it * 256;
            const int r = id >> 3, ch = id & 7;
            const uint32_t off = r * R64 + ch * 16;
            cp_async16(sb + off,       A + (size_t)(bm + r) * K + k0 + ch * 8);
            cp_async16(sb + T64 + off, B + (size_t)(bn + r) * K + k0 + ch * 8);
        }
        CP_COMMIT();
    };

    load_stage(0, 0);
    if (nc > 1) load_stage(1, 1);

    for (int c = 0; c < nc; c++) {
        if (c + 1 < nc) asm volatile("cp.async.wait_group 1;" ::: "memory");
        else            asm volatile("cp.async.wait_group 0;" ::: "memory");
        __syncthreads();
        if (c + 2 < nc) load_stage((c + 2) % 3, c + 2);

        const uint32_t uA = smb + (c % 3) * STGQ;
        const uint32_t uB = uA + T64;

#pragma unroll
        for (int ks = 0; ks < 4; ks++) {
            const uint32_t colA = (ks * 16 + a_c8) * 2;
            const uint32_t colB = (ks * 16 + b_c8) * 2;
            uint32_t ah[4][4];
#pragma unroll
            for (int i = 0; i < 4; i++) {
                const uint32_t ro = (wm * 64 + i * 16 + a_r) * R64 + colA;
                ldsm_x4(ah[i], uA + ro);
            }
#pragma unroll
            for (int p = 0; p < 2; p++) {
                const uint32_t ro = (wn * 32 + (2 * p + b_j) * 8 + b_r) * R64 + colB;
                uint32_t bh[4];
                ldsm_x4(bh, uB + ro);
#pragma unroll
                for (int i = 0; i < 4; i++) {
                    MMA_F16(acc[i][2*p],   ah[i], bh[0], bh[1]);
                    MMA_F16(acc[i][2*p+1], ah[i], bh[2], bh[3]);
                }
            }
        }
    }

#pragma unroll
    for (int i = 0; i < 4; i++) {
        const int row0 = bm + wm * 64 + i * 16 + g;
#pragma unroll
        for (int j = 0; j < 4; j++) {
            const int col = bn + wn * 32 + j * 8 + 2 * t;
            *(float2*)(C + (size_t)row0 * N + col) = make_float2(acc[i][j][0], acc[i][j][1]);
            *(float2*)(C + (size_t)(row0 + 8) * N + col) = make_float2(acc[i][j][2], acc[i][j][3]);
        }
    }
}

// ======================= Flash attention (all single-fp16 MMA) =============
#define QSTR 272
#define VSTR 144
#define FA_QB (128 * QSTR)
#define FA_KB (64 * QSTR)
#define FA_VB (128 * VSTR)
#define FA_STAGE (FA_KB + FA_VB)
#define FA_SMEM (FA_QB + 2 * FA_STAGE)     // 106496

__global__ __launch_bounds__(256, 2) void flash_attn_tc(
    const __half* __restrict__ Qf, const __half* __restrict__ Kf,
    const __half* __restrict__ Vt, __half* __restrict__ O)
{
    extern __shared__ char fsm[];
    const uint32_t smb = smem_u32(fsm);
    const int qb = gridDim.x - 1 - blockIdx.x;
    const int h  = blockIdx.y;
    const int kvh = h % NKV;
    const int q0 = qb * 128;
    const int tid = threadIdx.x;
    const int w = tid >> 5;
    const int lane = tid & 31;
    const int g = lane >> 2;
    const int t = lane & 3;

    const int a_r  = (lane & 7) + ((lane >> 3) & 1) * 8;
    const int a_c8 = (lane >> 4) * 8;
    const int b_r  = lane & 7;
    const int b_j  = lane >> 4;
    const int b_c8 = ((lane >> 3) & 1) * 8;

#pragma unroll
    for (int it = 0; it < 8; it++) {
        const int id = tid + 256 * it;
        const int r = id >> 4, ch = id & 15;
        const uint32_t off = r * QSTR + ch * 16;
        const size_t gi = ((size_t)h * S_LEN + q0 + r) * HD + ch * 8;
        cp_async16(smb + off, Qf + gi);
    }

    auto fa_load = [&](int s, int jb) {
        const uint32_t sb = smb + FA_QB + s * FA_STAGE;
        const int k0 = jb * 64;
#pragma unroll
        for (int it = 0; it < 4; it++) {
            const int id = tid + 256 * it;
            const int r = id >> 4, ch = id & 15;
            const uint32_t off = r * QSTR + ch * 16;
            const size_t gi = ((size_t)kvh * S_LEN + k0 + r) * HD + ch * 8;
            cp_async16(sb + off, Kf + gi);
        }
#pragma unroll
        for (int it = 0; it < 4; it++) {
            const int id = tid + 256 * it;
            const int r = id >> 3, ch = id & 7;
            const uint32_t off = r * VSTR + ch * 16;
            const size_t gi = ((size_t)kvh * HD + r) * S_LEN + k0 + ch * 8;
            cp_async16(sb + FA_KB + off, Vt + gi);
        }
    };

    const int njb = 2 * qb + 2;
    fa_load(0, 0);
    CP_COMMIT();
    fa_load(1, 1);
    CP_COMMIT();

    float oacc[16][4];
#pragma unroll
    for (int jd = 0; jd < 16; jd++)
#pragma unroll
        for (int r = 0; r < 4; r++) oacc[jd][r] = 0.0f;
    float m0 = -1e30f, m1 = -1e30f, l0 = 0.0f, l1 = 0.0f;

    const uint32_t uQ = smb;

    for (int jb = 0; jb < njb; jb++) {
        const int s = jb & 1;
        if (jb + 1 < njb) asm volatile("cp.async.wait_group 1;" ::: "memory");
        else              asm volatile("cp.async.wait_group 0;" ::: "memory");
        __syncthreads();

        const uint32_t uK = smb + FA_QB + s * FA_STAGE;
        const uint32_t uV = uK + FA_KB;

        float sv[8][4];
#pragma unroll
        for (int j = 0; j < 8; j++)
#pragma unroll
            for (int r = 0; r < 4; r++) sv[j][r] = 0.0f;

#pragma unroll
        for (int kt = 0; kt < 8; kt++) {
            const uint32_t qro = (16 * w + a_r) * QSTR + (kt * 16 + a_c8) * 2;
            uint32_t qh[4];
            ldsm_x4(qh, uQ + qro);
#pragma unroll
            for (int p = 0; p < 4; p++) {
                const uint32_t kro = ((2 * p + b_j) * 8 + b_r) * QSTR + (kt * 16 + b_c8) * 2;
                uint32_t kh[4];
                ldsm_x4(kh, uK + kro);
                MMA_F16(sv[2*p],   qh, kh[0], kh[1]);
                MMA_F16(sv[2*p+1], qh, kh[2], kh[3]);
            }
        }

        if (jb >= 2 * qb) {
            const int r0g = q0 + 16 * w + g;
            const int r1g = r0g + 8;
            const int kg = jb * 64;
#pragma unroll
            for (int j = 0; j < 8; j++) {
                const int c0 = kg + 8 * j + 2 * t, c1 = c0 + 1;
                if (c0 > r0g) sv[j][0] = -1e30f;
                if (c1 > r0g) sv[j][1] = -1e30f;
                if (c0 > r1g) sv[j][2] = -1e30f;
                if (c1 > r1g) sv[j][3] = -1e30f;
            }
        }

        float mn0 = m0, mn1 = m1;
#pragma unroll
        for (int j = 0; j < 8; j++) {
            mn0 = fmaxf(mn0, fmaxf(sv[j][0], sv[j][1]));
            mn1 = fmaxf(mn1, fmaxf(sv[j][2], sv[j][3]));
        }
        mn0 = fmaxf(mn0, __shfl_xor_sync(0xffffffffu, mn0, 1));
        mn0 = fmaxf(mn0, __shfl_xor_sync(0xffffffffu, mn0, 2));
        mn1 = fmaxf(mn1, __shfl_xor_sync(0xffffffffu, mn1, 1));
        mn1 = fmaxf(mn1, __shfl_xor_sync(0xffffffffu, mn1, 2));

        const float corr0 = __expf(m0 - mn0);
        const float corr1 = __expf(m1 - mn1);
        float rs0 = 0.0f, rs1 = 0.0f;
#pragma unroll
        for (int j = 0; j < 8; j++) {
            sv[j][0] = __expf(sv[j][0] - mn0);
            sv[j][1] = __expf(sv[j][1] - mn0);
            sv[j][2] = __expf(sv[j][2] - mn1);
            sv[j][3] = __expf(sv[j][3] - mn1);
            rs0 += sv[j][0] + sv[j][1];
            rs1 += sv[j][2] + sv[j][3];
        }
        rs0 += __shfl_xor_sync(0xffffffffu, rs0, 1);
        rs0 += __shfl_xor_sync(0xffffffffu, rs0, 2);
        rs1 += __shfl_xor_sync(0xffffffffu, rs1, 1);
        rs1 += __shfl_xor_sync(0xffffffffu, rs1, 2);
        l0 = l0 * corr0 + rs0;
        l1 = l1 * corr1 + rs1;
        m0 = mn0; m1 = mn1;

#pragma unroll
        for (int jd = 0; jd < 16; jd++) {
            oacc[jd][0] *= corr0; oacc[jd][1] *= corr0;
            oacc[jd][2] *= corr1; oacc[jd][3] *= corr1;
        }

#pragma unroll
        for (int kt = 0; kt < 4; kt++) {
            uint32_t ph[4];
            ph[0] = pack2h(sv[2*kt][0],   sv[2*kt][1]);
            ph[1] = pack2h(sv[2*kt][2],   sv[2*kt][3]);
            ph[2] = pack2h(sv[2*kt+1][0], sv[2*kt+1][1]);
            ph[3] = pack2h(sv[2*kt+1][2], sv[2*kt+1][3]);
#pragma unroll
            for (int p = 0; p < 8; p++) {
                const uint32_t vro = ((2 * p + b_j) * 8 + b_r) * VSTR + (kt * 16 + b_c8) * 2;
                uint32_t vh[4];
                ldsm_x4(vh, uV + vro);
                MMA_F16(oacc[2*p],   ph, vh[0], vh[1]);
                MMA_F16(oacc[2*p+1], ph, vh[2], vh[3]);
            }
        }

        __syncthreads();
        if (jb + 2 < njb) { fa_load(s, jb + 2); CP_COMMIT(); }
    }

    const float inv0 = 1.0f / l0;
    const float inv1 = 1.0f / l1;
    const int s0 = q0 + 16 * w + g;
    const int s1 = s0 + 8;
#pragma unroll
    for (int jd = 0; jd < 16; jd++) {
        const int d = 8 * jd + 2 * t;
        const size_t i0 = (size_t)s0 * HID + h * HD + d;
        const size_t i1 = (size_t)s1 * HID + h * HD + d;
        *(uint32_t*)(O + i0) = pack2h(oacc[jd][0] * inv0, oacc[jd][1] * inv0);
        *(uint32_t*)(O + i1) = pack2h(oacc[jd][2] * inv1, oacc[jd][3] * inv1);
    }
}

// ======================= launch ============================================
extern "C" void kernel_launch(void* const* d_in, const int* in_sizes, int n_in,
                              void* d_out, int out_size) {
    const float* x  = (const float*)d_in[0];
    const float* wq = (const float*)d_in[1];
    const float* wk = (const float*)d_in[2];
    const float* wv = (const float*)d_in[3];
    const float* wo = (const float*)d_in[4];
    const float* cs = (const float*)d_in[5];
    const float* sn = (const float*)d_in[6];
    float* out = (float*)d_out;

    __half *xh16, *xl16, *wq16, *wk16, *wv16, *wo16, *att16, *vt16, *qh16, *k16;
    cudaGetSymbolAddress((void**)&xh16, g_xh16); cudaGetSymbolAddress((void**)&xl16, g_xl16);
    cudaGetSymbolAddress((void**)&wq16, g_wq16); cudaGetSymbolAddress((void**)&wk16, g_wk16);
    cudaGetSymbolAddress((void**)&wv16, g_wv16); cudaGetSymbolAddress((void**)&wo16, g_wo16);
    cudaGetSymbolAddress((void**)&att16, g_att16);
    cudaGetSymbolAddress((void**)&vt16, g_vt16);
    cudaGetSymbolAddress((void**)&qh16, g_qh16);
    cudaGetSymbolAddress((void**)&k16, g_k16);

    cudaFuncSetAttribute(gemm_all, cudaFuncAttributeMaxDynamicSharedMemorySize, PROJ_SMEM);
    cudaFuncSetAttribute(gemm_tc128s, cudaFuncAttributeMaxDynamicSharedMemorySize, PROJ_SMEM);
    cudaFuncSetAttribute(flash_attn_tc, cudaFuncAttributeMaxDynamicSharedMemorySize, FA_SMEM);

    // one-shot split of all inputs (MLP=4)
    split_all<<<SPLIT_TOTAL / 1024, 256>>>(
        (const float4*)x, (uint2*)xh16, (uint2*)xl16,
        (const float4*)wq, (uint2*)wq16,
        (const float4*)wk, (uint2*)wk16,
        (const float4*)wv, (uint2*)wv16,
        (const float4*)wo, (uint2*)wo16);

    // fused Q+K+V projections (K/V heavy tiles first), Kc=64, 2 CTAs/SM
    const float scale = 0.08838834764831845f;
    gemm_all<<<768, 256, PROJ_SMEM>>>(
        xh16, xl16, wq16, wk16, wv16, cs, sn, qh16, k16, vt16, scale);

    // tensor-core flash attention
    flash_attn_tc<<<dim3(S_LEN / 128, NH), 256, FA_SMEM>>>(
        qh16, k16, vt16, att16);

    // output projection (Kc=64, 3-stage single-barrier, 2 CTAs/SM)
    gemm_tc128s<<<dim3(HID / 128, S_LEN / 128), 256, PROJ_SMEM>>>(
        att16, wo16, out, S_LEN, HID, HID);
}